// round 4
// baseline (speedup 1.0000x reference)
#include <cuda_runtime.h>
#include <cuda_bf16.h>
#include <cstdint>

// Problem constants
#define B_   4
#define T_   2048
#define D_   1024
#define H_   16
#define L_   64
#define BT_  (B_*T_)        // 8192
#define BH_  (B_*H_)        // 64
#define CHUNK 128
#define NC   (T_/CHUNK)     // 16

// ---------------------------------------------------------------------------
// Scratch (device globals; no allocation allowed)
// ---------------------------------------------------------------------------
__device__ float g_qkv[(size_t)BT_ * 3 * D_];        // (8192, 3072)  q|k|v fp32
__device__ float g_Sc [(size_t)BH_ * NC * L_ * L_];  // chunk states -> excl prefix
__device__ float g_ks [(size_t)BH_ * NC * L_];       // chunk k-sums -> excl prefix
__device__ __nv_bfloat16 g_xhi[(size_t)BT_ * D_];
__device__ __nv_bfloat16 g_xlo[(size_t)BT_ * D_];
__device__ __nv_bfloat16 g_whi[(size_t)3 * D_ * D_];
__device__ __nv_bfloat16 g_wlo[(size_t)3 * D_ * D_];
__device__ __nv_bfloat16 g_wothi[(size_t)D_ * D_];   // w_out^T
__device__ __nv_bfloat16 g_wotlo[(size_t)D_ * D_];
__device__ __nv_bfloat16 g_yhi[(size_t)BT_ * D_];
__device__ __nv_bfloat16 g_ylo[(size_t)BT_ * D_];

// ---------------------------------------------------------------------------
// PTX helpers (baseline sm_80+ instructions only — harness targets plain sm_103)
// ---------------------------------------------------------------------------
__device__ __forceinline__ uint32_t smem_u32(const void* p) {
    uint32_t a;
    asm("{ .reg .u64 t; cvta.to.shared.u64 t, %1; cvt.u32.u64 %0, t; }" : "=r"(a) : "l"(p));
    return a;
}

__device__ __forceinline__ void cp_async16(uint32_t dst, const void* src) {
    asm volatile("cp.async.cg.shared.global [%0], [%1], 16;" :: "r"(dst), "l"(src) : "memory");
}
__device__ __forceinline__ void cp_commit() {
    asm volatile("cp.async.commit_group;" ::: "memory");
}
__device__ __forceinline__ void cp_wait1() {
    asm volatile("cp.async.wait_group 1;" ::: "memory");
}

__device__ __forceinline__ void ldsm_x4(uint32_t addr, uint32_t& r0, uint32_t& r1,
                                        uint32_t& r2, uint32_t& r3) {
    asm volatile("ldmatrix.sync.aligned.m8n8.x4.shared.b16 {%0,%1,%2,%3}, [%4];"
                 : "=r"(r0), "=r"(r1), "=r"(r2), "=r"(r3) : "r"(addr));
}

__device__ __forceinline__ void mma_bf16(float* c, const uint32_t* a, const uint32_t* b) {
    asm volatile(
        "mma.sync.aligned.m16n8k16.row.col.f32.bf16.bf16.f32 "
        "{%0,%1,%2,%3}, {%4,%5,%6,%7}, {%8,%9}, {%0,%1,%2,%3};"
        : "+f"(c[0]), "+f"(c[1]), "+f"(c[2]), "+f"(c[3])
        : "r"(a[0]), "r"(a[1]), "r"(a[2]), "r"(a[3]), "r"(b[0]), "r"(b[1]));
}

// ---------------------------------------------------------------------------
// Split fp32 -> bf16 hi/lo (vectorized)
// ---------------------------------------------------------------------------
__global__ void split_kernel(const float* __restrict__ src,
                             __nv_bfloat16* __restrict__ hi,
                             __nv_bfloat16* __restrict__ lo, int n4)
{
    int i = blockIdx.x * blockDim.x + threadIdx.x;
    if (i >= n4) return;
    float4 v = ((const float4*)src)[i];
    __nv_bfloat16 h0 = __float2bfloat16(v.x), h1 = __float2bfloat16(v.y);
    __nv_bfloat16 h2 = __float2bfloat16(v.z), h3 = __float2bfloat16(v.w);
    __nv_bfloat16 l0 = __float2bfloat16(v.x - __bfloat162float(h0));
    __nv_bfloat16 l1 = __float2bfloat16(v.y - __bfloat162float(h1));
    __nv_bfloat16 l2 = __float2bfloat16(v.z - __bfloat162float(h2));
    __nv_bfloat16 l3 = __float2bfloat16(v.w - __bfloat162float(h3));
    ((__nv_bfloat162*)hi)[2 * i]     = __halves2bfloat162(h0, h1);
    ((__nv_bfloat162*)hi)[2 * i + 1] = __halves2bfloat162(h2, h3);
    ((__nv_bfloat162*)lo)[2 * i]     = __halves2bfloat162(l0, l1);
    ((__nv_bfloat162*)lo)[2 * i + 1] = __halves2bfloat162(l2, l3);
}

// Transpose + split w_out (1024x1024): dst[n][k] = split(src[k][n])
__global__ void split_transpose_kernel(const float* __restrict__ src,
                                       __nv_bfloat16* __restrict__ hi,
                                       __nv_bfloat16* __restrict__ lo)
{
    __shared__ float tile[32][33];
    int n0 = blockIdx.x * 32, k0 = blockIdx.y * 32;
    int tx = threadIdx.x, ty = threadIdx.y;
    for (int r = ty; r < 32; r += 8)
        tile[r][tx] = src[(size_t)(k0 + r) * D_ + n0 + tx];
    __syncthreads();
    for (int r = ty; r < 32; r += 8) {
        float v = tile[tx][r];   // src[k0+tx][n0+r] -> dst[n0+r][k0+tx]
        __nv_bfloat16 h = __float2bfloat16(v);
        size_t idx = (size_t)(n0 + r) * D_ + k0 + tx;
        hi[idx] = h;
        lo[idx] = __float2bfloat16(v - __bfloat162float(h));
    }
}

// ---------------------------------------------------------------------------
// HMMA bf16 split GEMM: C[M,N] = A*B^T fp32 via 3-term bf16 split.
// A (M,K) hi/lo row-major; B (N,K) hi/lo row-major.
// 128x256 block tile, BK=64, 256 threads (8 warps, 2x4), warp tile 64x64.
// cp.async double-buffered; xor swizzle; ldmatrix.x4 for both operands.
// ---------------------------------------------------------------------------
#define GT_A_TILE  16384                 // 128 rows x 128B
#define GT_B_TILE  32768                 // 256 rows x 128B
#define GT_STAGE   (2*GT_A_TILE + 2*GT_B_TILE)   // 98304
#define GT_SMEM_TOTAL (2 * GT_STAGE)             // 196608

__global__ void __launch_bounds__(256, 1)
gemm_mma(const __nv_bfloat16* __restrict__ Ahi, const __nv_bfloat16* __restrict__ Alo,
         const __nv_bfloat16* __restrict__ Bhi, const __nv_bfloat16* __restrict__ Blo,
         float* __restrict__ C, int N, int K)
{
    extern __shared__ char smem[];
    const uint32_t smem_base = smem_u32(smem);
    const int tid = threadIdx.x;
    const int wid = tid >> 5, lane = tid & 31;
    const int m0 = blockIdx.y * 128, n0 = blockIdx.x * 256;
    const int wm = (wid & 1) * 64;          // warp row offset (2 m-halves)
    const int wn = (wid >> 1) * 64;         // warp col offset (4 n-quarters)

    auto load_stage = [&](int kt, int s) {
        const int k0 = kt << 6;
        const uint32_t sb = smem_base + s * GT_STAGE;
        // A hi/lo: 128 rows
#pragma unroll
        for (int tI = 0; tI < 2; tI++) {
            const __nv_bfloat16* src = tI ? Alo : Ahi;
            const uint32_t tb = sb + tI * GT_A_TILE;
#pragma unroll
            for (int ii = 0; ii < 4; ii++) {
                int j = tid + ii * 256;          // 0..1023
                int r = j >> 3, c = j & 7;
                const void* g = &src[(size_t)(m0 + r) * K + k0 + c * 8];
                cp_async16(tb + (uint32_t)(r * 128 + ((c ^ (r & 7)) << 4)), g);
            }
        }
        // B hi/lo: 256 rows
#pragma unroll
        for (int tI = 0; tI < 2; tI++) {
            const __nv_bfloat16* src = tI ? Blo : Bhi;
            const uint32_t tb = sb + 2 * GT_A_TILE + tI * GT_B_TILE;
#pragma unroll
            for (int ii = 0; ii < 8; ii++) {
                int j = tid + ii * 256;          // 0..2047
                int r = j >> 3, c = j & 7;
                const void* g = &src[(size_t)(n0 + r) * K + k0 + c * 8];
                cp_async16(tb + (uint32_t)(r * 128 + ((c ^ (r & 7)) << 4)), g);
            }
        }
    };

    float acc[4][8][4];
#pragma unroll
    for (int mt = 0; mt < 4; mt++)
#pragma unroll
        for (int nt = 0; nt < 8; nt++)
#pragma unroll
            for (int e = 0; e < 4; e++) acc[mt][nt][e] = 0.f;

    const int NKT = K >> 6;   // 16
    load_stage(0, 0); cp_commit();
    load_stage(1, 1); cp_commit();

    const int a_row = (lane & 15);
    const int a_khalf = lane >> 4;
    const int b_grp = (lane >> 4) & 1;
    const int b_khalf = (lane >> 3) & 1;
    const int b_row = lane & 7;

    for (int kt = 0; kt < NKT; kt++) {
        const int s = kt & 1;
        const uint32_t st = smem_base + s * GT_STAGE;
        cp_wait1();
        __syncthreads();

        const uint32_t aA = st;
        const uint32_t aB = st + 2 * GT_A_TILE;

#pragma unroll
        for (int kk = 0; kk < 4; kk++) {
            uint32_t ah[4][4], al[4][4];
#pragma unroll
            for (int mt = 0; mt < 4; mt++) {
                int row = wm + mt * 16 + a_row;
                int chunk = 2 * kk + a_khalf;
                uint32_t off = (uint32_t)(row * 128 + ((chunk ^ (row & 7)) << 4));
                ldsm_x4(aA + off, ah[mt][0], ah[mt][1], ah[mt][2], ah[mt][3]);
                ldsm_x4(aA + GT_A_TILE + off, al[mt][0], al[mt][1], al[mt][2], al[mt][3]);
            }
#pragma unroll
            for (int np = 0; np < 4; np++) {
                uint32_t bh[4], bl[4];
                int row = wn + np * 16 + b_grp * 8 + b_row;
                int chunk = 2 * kk + b_khalf;
                uint32_t off = (uint32_t)(row * 128 + ((chunk ^ (row & 7)) << 4));
                ldsm_x4(aB + off, bh[0], bh[1], bh[2], bh[3]);
                ldsm_x4(aB + GT_B_TILE + off, bl[0], bl[1], bl[2], bl[3]);
#pragma unroll
                for (int mt = 0; mt < 4; mt++)
#pragma unroll
                    for (int sub = 0; sub < 2; sub++) {
                        float* a_ = acc[mt][2 * np + sub];
                        mma_bf16(a_, ah[mt], &bh[2 * sub]);   // hi*hi
                        mma_bf16(a_, ah[mt], &bl[2 * sub]);   // hi*lo
                        mma_bf16(a_, al[mt], &bh[2 * sub]);   // lo*hi
                    }
            }
        }
        __syncthreads();
        if (kt + 2 < NKT) load_stage(kt + 2, s);
        cp_commit();
    }

    // Epilogue
    const int g = lane >> 2, tig = lane & 3;
#pragma unroll
    for (int mt = 0; mt < 4; mt++) {
        int row = m0 + wm + mt * 16 + g;
#pragma unroll
        for (int nt = 0; nt < 8; nt++) {
            int col = n0 + wn + nt * 8 + 2 * tig;
            float* c = acc[mt][nt];
            *(float2*)&C[(size_t)row * N + col]       = make_float2(c[0], c[1]);
            *(float2*)&C[(size_t)(row + 8) * N + col] = make_float2(c[2], c[3]);
        }
    }
}

// ---------------------------------------------------------------------------
// Pointwise prep: softmax(q*scale) per head, exp(k*scale)+1e-6, in place.
// ---------------------------------------------------------------------------
__global__ void prep_kernel(float* __restrict__ qkv)
{
    const size_t base = (size_t)blockIdx.x * (3 * D_);
    const int h = threadIdx.x >> 5;
    const int lane = threadIdx.x & 31;
    float* qp = qkv + base + h * L_;
    float* kp = qkv + base + D_ + h * L_;

    float q0 = qp[lane] * 0.125f;
    float q1 = qp[lane + 32] * 0.125f;
    float mx = fmaxf(q0, q1);
#pragma unroll
    for (int off = 16; off > 0; off >>= 1)
        mx = fmaxf(mx, __shfl_xor_sync(0xffffffffu, mx, off));
    float e0 = expf(q0 - mx), e1 = expf(q1 - mx);
    float s = e0 + e1;
#pragma unroll
    for (int off = 16; off > 0; off >>= 1)
        s += __shfl_xor_sync(0xffffffffu, s, off);
    float inv = 1.0f / s;
    qp[lane]      = e0 * inv;
    qp[lane + 32] = e1 * inv;

    float k0 = kp[lane], k1 = kp[lane + 32];
    kp[lane]      = expf(k0 * 0.125f) + 1e-6f;
    kp[lane + 32] = expf(k1 * 0.125f) + 1e-6f;
}

// ---------------------------------------------------------------------------
// Per-chunk state: S_c[l][m] = sum_t K[t][l]*V[t][m]; ksum_c[l].
// ---------------------------------------------------------------------------
__global__ void __launch_bounds__(256)
chunkstate_kernel(const float* __restrict__ qkv,
                  float* __restrict__ Sc, float* __restrict__ ks)
{
    extern __shared__ float sm[];
    float* Ks = sm;
    float* Vs = sm + CHUNK * L_;
    const int c = blockIdx.x, bh = blockIdx.y;
    const int b = bh >> 4, h = bh & 15;
    const size_t rowbase = ((size_t)(b * T_ + c * CHUNK)) * (3 * D_) + h * L_;

    for (int i = threadIdx.x; i < CHUNK * 16; i += 256) {
        int t = i >> 4, f = (i & 15) << 2;
        size_t g = rowbase + (size_t)t * (3 * D_) + f;
        *(float4*)&Ks[t * L_ + f] = *(const float4*)&qkv[g + D_];
        *(float4*)&Vs[t * L_ + f] = *(const float4*)&qkv[g + 2 * D_];
    }
    __syncthreads();

    const int l0 = (threadIdx.x >> 4) << 2;
    const int m0 = (threadIdx.x & 15) << 2;
    float acc[4][4];
#pragma unroll
    for (int i = 0; i < 4; i++)
#pragma unroll
        for (int j = 0; j < 4; j++) acc[i][j] = 0.f;
    for (int t = 0; t < CHUNK; t++) {
        float a[4], v[4];
#pragma unroll
        for (int i = 0; i < 4; i++) a[i] = Ks[t * L_ + l0 + i];
#pragma unroll
        for (int j = 0; j < 4; j++) v[j] = Vs[t * L_ + m0 + j];
#pragma unroll
        for (int i = 0; i < 4; i++)
#pragma unroll
            for (int j = 0; j < 4; j++) acc[i][j] += a[i] * v[j];
    }
    const size_t sbase = ((size_t)bh * NC + c) * (L_ * L_);
#pragma unroll
    for (int i = 0; i < 4; i++)
#pragma unroll
        for (int j = 0; j < 4; j++)
            Sc[sbase + (size_t)(l0 + i) * L_ + m0 + j] = acc[i][j];

    if (threadIdx.x < L_) {
        float s = 0.f;
        for (int t = 0; t < CHUNK; t++) s += Ks[t * L_ + threadIdx.x];
        ks[((size_t)bh * NC + c) * L_ + threadIdx.x] = s;
    }
}

// ---------------------------------------------------------------------------
// Exclusive prefix over chunks, in place. grid (BH, 16) x 256.
// ---------------------------------------------------------------------------
__global__ void prefix_kernel(float* __restrict__ Sc, float* __restrict__ ks)
{
    const int bh = blockIdx.x;
    const int e = blockIdx.y * 256 + threadIdx.x;   // 0..4095
    const size_t base = (size_t)bh * NC * (L_ * L_);
    {
        float acc = 0.f;
#pragma unroll
        for (int c = 0; c < NC; c++) {
            size_t idx = base + (size_t)c * (L_ * L_) + e;
            float tmp = Sc[idx];
            Sc[idx] = acc;
            acc += tmp;
        }
    }
    if (blockIdx.y == 0 && threadIdx.x < L_) {
        const size_t kb = (size_t)bh * NC * L_;
        float acc = 0.f;
#pragma unroll
        for (int c = 0; c < NC; c++) {
            size_t idx = kb + (size_t)c * L_ + threadIdx.x;
            float tmp = ks[idx];
            ks[idx] = acc;
            acc += tmp;
        }
    }
}

// ---------------------------------------------------------------------------
// Chunk attention: Y = qs @ S_prev + causal(qs @ K^T) @ V, bf16 hi/lo output.
// 256 threads: 2 threads per row t; intra-chunk s-loop split by parity,
// inter-chunk l-loop split by half; reduction through smem (reuses Qs).
// ---------------------------------------------------------------------------
__global__ void __launch_bounds__(256)
attn_kernel(const float* __restrict__ qkv, const float* __restrict__ Sprev,
            const float* __restrict__ kpre,
            __nv_bfloat16* __restrict__ yhi, __nv_bfloat16* __restrict__ ylo)
{
    extern __shared__ float sm[];
    float* Qs = sm;                 // 128*64  (becomes reduction buffer later)
    float* Ks = sm + 8192;          // 128*64
    float* Vs = sm + 16384;         // 128*64
    float* Sp = sm + 24576;         // 64*64
    const int c = blockIdx.x, bh = blockIdx.y;
    const int b = bh >> 4, h = bh & 15;
    const int tid = threadIdx.x;
    const int t = tid >> 1, half = tid & 1;
    const size_t rowbase = ((size_t)(b * T_ + c * CHUNK)) * (3 * D_) + h * L_;

    for (int i = tid; i < CHUNK * 16; i += 256) {
        int tt = i >> 4, f = (i & 15) << 2;
        size_t g = rowbase + (size_t)tt * (3 * D_) + f;
        *(float4*)&Qs[tt * L_ + f] = *(const float4*)&qkv[g];
        *(float4*)&Ks[tt * L_ + f] = *(const float4*)&qkv[g + D_];
        *(float4*)&Vs[tt * L_ + f] = *(const float4*)&qkv[g + 2 * D_];
    }
    const size_t sbase = ((size_t)bh * NC + c) * (L_ * L_);
    for (int i = tid; i < L_ * L_; i += 256) Sp[i] = Sprev[sbase + i];
    __syncthreads();

    if (tid < L_) {
        float acc = kpre[((size_t)bh * NC + c) * L_ + tid];
        for (int tt = 0; tt < CHUNK; tt++) {
            acc += Ks[tt * L_ + tid];
            Qs[tt * L_ + tid] /= acc;
        }
    }
    __syncthreads();

    float q[L_];
#pragma unroll
    for (int l = 0; l < L_; l++) q[l] = Qs[t * L_ + l];

    float4 yv[16];
#pragma unroll
    for (int f = 0; f < 16; f++) yv[f] = make_float4(0.f, 0.f, 0.f, 0.f);

    // inter-chunk: half 0 -> l in [0,32), half 1 -> l in [32,64)
    {
        const int lb = half * 32;
#pragma unroll
        for (int li = 0; li < 32; li++) {
            int l = lb + li;
            float ql = q[l];
            const float4* sp = (const float4*)&Sp[l * L_];
#pragma unroll
            for (int f = 0; f < 16; f++) {
                float4 s = sp[f];
                yv[f].x += ql * s.x; yv[f].y += ql * s.y;
                yv[f].z += ql * s.z; yv[f].w += ql * s.w;
            }
        }
    }

    // intra-chunk causal (inclusive), split by s parity
    for (int s = half; s <= t; s += 2) {
        const float4* kp = (const float4*)&Ks[s * L_];
        float a = 0.f;
#pragma unroll
        for (int lf = 0; lf < 16; lf++) {
            float4 kv = kp[lf];
            a += q[lf*4+0]*kv.x + q[lf*4+1]*kv.y + q[lf*4+2]*kv.z + q[lf*4+3]*kv.w;
        }
        const float4* vp = (const float4*)&Vs[s * L_];
#pragma unroll
        for (int f = 0; f < 16; f++) {
            float4 vv = vp[f];
            yv[f].x += a * vv.x; yv[f].y += a * vv.y;
            yv[f].z += a * vv.z; yv[f].w += a * vv.w;
        }
    }

    // reduce halves through Qs (dead after q-load): red[t][0..63]
    __syncthreads();
    if (half == 1) {
#pragma unroll
        for (int f = 0; f < 16; f++) *(float4*)&Qs[t * L_ + f * 4] = yv[f];
    }
    __syncthreads();
    if (half == 0) {
        const size_t ybase = ((size_t)(b * T_ + c * CHUNK + t)) * D_ + h * L_;
#pragma unroll
        for (int f = 0; f < 16; f++) {
            float4 o = *(const float4*)&Qs[t * L_ + f * 4];
            float4 v = make_float4(yv[f].x + o.x, yv[f].y + o.y,
                                   yv[f].z + o.z, yv[f].w + o.w);
            __nv_bfloat16 h0 = __float2bfloat16(v.x), h1 = __float2bfloat16(v.y);
            __nv_bfloat16 h2 = __float2bfloat16(v.z), h3 = __float2bfloat16(v.w);
            __nv_bfloat16 l0 = __float2bfloat16(v.x - __bfloat162float(h0));
            __nv_bfloat16 l1 = __float2bfloat16(v.y - __bfloat162float(h1));
            __nv_bfloat16 l2 = __float2bfloat16(v.z - __bfloat162float(h2));
            __nv_bfloat16 l3 = __float2bfloat16(v.w - __bfloat162float(h3));
            __nv_bfloat162* ph = (__nv_bfloat162*)&yhi[ybase + f * 4];
            __nv_bfloat162* pl = (__nv_bfloat162*)&ylo[ybase + f * 4];
            ph[0] = __halves2bfloat162(h0, h1); ph[1] = __halves2bfloat162(h2, h3);
            pl[0] = __halves2bfloat162(l0, l1); pl[1] = __halves2bfloat162(l2, l3);
        }
    }
}

// ---------------------------------------------------------------------------
extern "C" void kernel_launch(void* const* d_in, const int* in_sizes, int n_in,
                              void* d_out, int out_size)
{
    const float* x  = (const float*)d_in[0];   // (4,2048,1024)
    const float* w  = (const float*)d_in[1];   // (3072,1024)
    const float* wo = (const float*)d_in[2];   // (1024,1024)
    float* out = (float*)d_out;                // (4,2048,1024)

    float *qkv, *Sc, *ks;
    __nv_bfloat16 *xhi, *xlo, *whi, *wlo, *wothi, *wotlo, *yhi, *ylo;
    cudaGetSymbolAddress((void**)&qkv, g_qkv);
    cudaGetSymbolAddress((void**)&Sc,  g_Sc);
    cudaGetSymbolAddress((void**)&ks,  g_ks);
    cudaGetSymbolAddress((void**)&xhi, g_xhi);
    cudaGetSymbolAddress((void**)&xlo, g_xlo);
    cudaGetSymbolAddress((void**)&whi, g_whi);
    cudaGetSymbolAddress((void**)&wlo, g_wlo);
    cudaGetSymbolAddress((void**)&wothi, g_wothi);
    cudaGetSymbolAddress((void**)&wotlo, g_wotlo);
    cudaGetSymbolAddress((void**)&yhi, g_yhi);
    cudaGetSymbolAddress((void**)&ylo, g_ylo);

    cudaFuncSetAttribute(gemm_mma,
                         cudaFuncAttributeMaxDynamicSharedMemorySize, GT_SMEM_TOTAL);
    cudaFuncSetAttribute(chunkstate_kernel,
                         cudaFuncAttributeMaxDynamicSharedMemorySize, 65536);
    cudaFuncSetAttribute(attn_kernel,
                         cudaFuncAttributeMaxDynamicSharedMemorySize, 114688);

    // 0) split inputs into bf16 hi/lo
    split_kernel<<<(BT_ * D_ / 4 + 255) / 256, 256>>>(x, xhi, xlo, BT_ * D_ / 4);
    split_kernel<<<(3 * D_ * D_ / 4 + 255) / 256, 256>>>(w, whi, wlo, 3 * D_ * D_ / 4);
    split_transpose_kernel<<<dim3(D_ / 32, D_ / 32), dim3(32, 8)>>>(wo, wothi, wotlo);

    // 1) qkv = x @ w^T   (M=8192, N=3072, K=1024) on tensor cores (HMMA)
    gemm_mma<<<dim3(3 * D_ / 256, BT_ / 128), 256, GT_SMEM_TOTAL>>>(
        xhi, xlo, whi, wlo, qkv, 3 * D_, D_);
    // 2) softmax(q), exp(k)+1e-6 in place
    prep_kernel<<<BT_, 512>>>(qkv);
    // 3) per-chunk states + k sums
    chunkstate_kernel<<<dim3(NC, BH_), 256, 65536>>>(qkv, Sc, ks);
    // 4) exclusive prefix over chunks
    prefix_kernel<<<dim3(BH_, 16), 256>>>(Sc, ks);
    // 5) chunk attention -> y (bf16 split)
    attn_kernel<<<dim3(NC, BH_), 256, 114688>>>(qkv, Sc, ks, yhi, ylo);
    // 6) out = y @ w_out  (M=8192, N=1024, K=1024), B = w_out^T pre-split
    gemm_mma<<<dim3(D_ / 256, BT_ / 128), 256, GT_SMEM_TOTAL>>>(
        yhi, ylo, wothi, wotlo, out, D_, D_);
}

// round 5
// speedup vs baseline: 1.1334x; 1.1334x over previous
#include <cuda_runtime.h>
#include <cuda_bf16.h>
#include <cstdint>

// Problem constants
#define B_   4
#define T_   2048
#define D_   1024
#define H_   16
#define L_   64
#define BT_  (B_*T_)        // 8192
#define BH_  (B_*H_)        // 64
#define CHUNK 128
#define NC   (T_/CHUNK)     // 16

// ---------------------------------------------------------------------------
// Scratch (device globals; no allocation allowed)
// ---------------------------------------------------------------------------
__device__ float g_qkv[(size_t)BT_ * 3 * D_];        // (8192, 3072)  q|k|v fp32
__device__ float g_Sc [(size_t)BH_ * NC * L_ * L_];  // chunk states -> excl prefix
__device__ float g_ks [(size_t)BH_ * NC * L_];       // chunk k-sums -> excl prefix
__device__ __nv_bfloat16 g_xhi[(size_t)BT_ * D_];
__device__ __nv_bfloat16 g_xlo[(size_t)BT_ * D_];
__device__ __nv_bfloat16 g_whi[(size_t)3 * D_ * D_];
__device__ __nv_bfloat16 g_wlo[(size_t)3 * D_ * D_];
__device__ __nv_bfloat16 g_wothi[(size_t)D_ * D_];   // w_out^T
__device__ __nv_bfloat16 g_wotlo[(size_t)D_ * D_];
__device__ __nv_bfloat16 g_yhi[(size_t)BT_ * D_];
__device__ __nv_bfloat16 g_ylo[(size_t)BT_ * D_];

// ---------------------------------------------------------------------------
// PTX helpers (baseline sm_80+ instructions only — harness targets plain sm_103)
// ---------------------------------------------------------------------------
__device__ __forceinline__ uint32_t smem_u32(const void* p) {
    uint32_t a;
    asm("{ .reg .u64 t; cvta.to.shared.u64 t, %1; cvt.u32.u64 %0, t; }" : "=r"(a) : "l"(p));
    return a;
}

__device__ __forceinline__ void cp_async16(uint32_t dst, const void* src) {
    asm volatile("cp.async.cg.shared.global [%0], [%1], 16;" :: "r"(dst), "l"(src) : "memory");
}
__device__ __forceinline__ void cp_commit() {
    asm volatile("cp.async.commit_group;" ::: "memory");
}
__device__ __forceinline__ void cp_wait1() {
    asm volatile("cp.async.wait_group 1;" ::: "memory");
}

__device__ __forceinline__ void ldsm_x4(uint32_t addr, uint32_t& r0, uint32_t& r1,
                                        uint32_t& r2, uint32_t& r3) {
    asm volatile("ldmatrix.sync.aligned.m8n8.x4.shared.b16 {%0,%1,%2,%3}, [%4];"
                 : "=r"(r0), "=r"(r1), "=r"(r2), "=r"(r3) : "r"(addr));
}

__device__ __forceinline__ void mma_bf16(float* c, const uint32_t* a, const uint32_t* b) {
    asm volatile(
        "mma.sync.aligned.m16n8k16.row.col.f32.bf16.bf16.f32 "
        "{%0,%1,%2,%3}, {%4,%5,%6,%7}, {%8,%9}, {%0,%1,%2,%3};"
        : "+f"(c[0]), "+f"(c[1]), "+f"(c[2]), "+f"(c[3])
        : "r"(a[0]), "r"(a[1]), "r"(a[2]), "r"(a[3]), "r"(b[0]), "r"(b[1]));
}

// ---------------------------------------------------------------------------
// Split fp32 -> bf16 hi/lo (vectorized)
// ---------------------------------------------------------------------------
__global__ void split_kernel(const float* __restrict__ src,
                             __nv_bfloat16* __restrict__ hi,
                             __nv_bfloat16* __restrict__ lo, int n4)
{
    int i = blockIdx.x * blockDim.x + threadIdx.x;
    if (i >= n4) return;
    float4 v = ((const float4*)src)[i];
    __nv_bfloat16 h0 = __float2bfloat16(v.x), h1 = __float2bfloat16(v.y);
    __nv_bfloat16 h2 = __float2bfloat16(v.z), h3 = __float2bfloat16(v.w);
    __nv_bfloat16 l0 = __float2bfloat16(v.x - __bfloat162float(h0));
    __nv_bfloat16 l1 = __float2bfloat16(v.y - __bfloat162float(h1));
    __nv_bfloat16 l2 = __float2bfloat16(v.z - __bfloat162float(h2));
    __nv_bfloat16 l3 = __float2bfloat16(v.w - __bfloat162float(h3));
    ((__nv_bfloat162*)hi)[2 * i]     = __halves2bfloat162(h0, h1);
    ((__nv_bfloat162*)hi)[2 * i + 1] = __halves2bfloat162(h2, h3);
    ((__nv_bfloat162*)lo)[2 * i]     = __halves2bfloat162(l0, l1);
    ((__nv_bfloat162*)lo)[2 * i + 1] = __halves2bfloat162(l2, l3);
}

// Transpose + split w_out (1024x1024): dst[n][k] = split(src[k][n])
__global__ void split_transpose_kernel(const float* __restrict__ src,
                                       __nv_bfloat16* __restrict__ hi,
                                       __nv_bfloat16* __restrict__ lo)
{
    __shared__ float tile[32][33];
    int n0 = blockIdx.x * 32, k0 = blockIdx.y * 32;
    int tx = threadIdx.x, ty = threadIdx.y;
    for (int r = ty; r < 32; r += 8)
        tile[r][tx] = src[(size_t)(k0 + r) * D_ + n0 + tx];
    __syncthreads();
    for (int r = ty; r < 32; r += 8) {
        float v = tile[tx][r];   // src[k0+tx][n0+r] -> dst[n0+r][k0+tx]
        __nv_bfloat16 h = __float2bfloat16(v);
        size_t idx = (size_t)(n0 + r) * D_ + k0 + tx;
        hi[idx] = h;
        lo[idx] = __float2bfloat16(v - __bfloat162float(h));
    }
}

// ---------------------------------------------------------------------------
// HMMA bf16 split GEMM: C[M,N] = A*B^T fp32 via 3-term bf16 split.
// A (M,K) hi/lo row-major; B (N,K) hi/lo row-major.
// 128x128 block tile, BK=64, 256 threads (8 warps, 4x2), warp tile 32x64.
// cp.async double-buffered stages; xor swizzle; REGISTER-double-buffered
// ldmatrix fragments (prefetch kk+1 before kk's MMAs).
// ---------------------------------------------------------------------------
#define GT_TILE_BYTES  16384           // 128 rows x 128B (64 bf16)
#define GT_STAGE_BYTES (4 * GT_TILE_BYTES)   // Ahi, Alo, Bhi, Blo
#define GT_SMEM_TOTAL  (2 * GT_STAGE_BYTES)  // 131072

__global__ void __launch_bounds__(256, 1)
gemm_mma(const __nv_bfloat16* __restrict__ Ahi, const __nv_bfloat16* __restrict__ Alo,
         const __nv_bfloat16* __restrict__ Bhi, const __nv_bfloat16* __restrict__ Blo,
         float* __restrict__ C, int N, int K)
{
    extern __shared__ char smem[];
    const uint32_t smem_base = smem_u32(smem);
    const int tid = threadIdx.x;
    const int wid = tid >> 5, lane = tid & 31;
    const int m0 = blockIdx.y * 128, n0 = blockIdx.x * 128;
    const int wm = (wid & 3) * 32;          // warp row offset within tile
    const int wn = (wid >> 2) * 64;         // warp col offset within tile

    const __nv_bfloat16* srcs[4] = { Ahi, Alo, Bhi, Blo };

    auto load_stage = [&](int kt, int s) {
        const int k0 = kt << 6;
#pragma unroll
        for (int tI = 0; tI < 4; tI++) {
            const __nv_bfloat16* src = srcs[tI];
            const int rb = (tI < 2) ? m0 : n0;
            const uint32_t tb = smem_base + s * GT_STAGE_BYTES + tI * GT_TILE_BYTES;
#pragma unroll
            for (int ii = 0; ii < 4; ii++) {
                int j = tid + ii * 256;
                int r = j >> 3, c = j & 7;
                const void* g = &src[(size_t)(rb + r) * K + k0 + c * 8];
                uint32_t d = tb + (uint32_t)(r * 128 + ((c ^ (r & 7)) << 4));
                cp_async16(d, g);
            }
        }
    };

    float acc[2][8][4];
#pragma unroll
    for (int mt = 0; mt < 2; mt++)
#pragma unroll
        for (int nt = 0; nt < 8; nt++)
#pragma unroll
            for (int e = 0; e < 4; e++) acc[mt][nt][e] = 0.f;

    const int NKT = K >> 6;   // 16
    load_stage(0, 0); cp_commit();
    load_stage(1, 1); cp_commit();

    // ldmatrix lane addressing
    const int a_row = (lane & 15);
    const int a_khalf = lane >> 4;
    const int b_grp = (lane >> 4) & 1;
    const int b_khalf = (lane >> 3) & 1;
    const int b_row = lane & 7;

    // double-buffered fragments
    uint32_t ah[2][2][4], al[2][2][4];   // [buf][mt][reg]
    uint32_t bh[2][4][4], bl[2][4][4];   // [buf][np][reg]

    for (int kt = 0; kt < NKT; kt++) {
        const int s = kt & 1;
        const uint32_t st = smem_base + s * GT_STAGE_BYTES;
        cp_wait1();
        __syncthreads();

        const uint32_t aA = st;
        const uint32_t aB = st + 2 * GT_TILE_BYTES;

        auto load_frag = [&](int kk, int buf) {
#pragma unroll
            for (int mt = 0; mt < 2; mt++) {
                int row = wm + mt * 16 + a_row;
                int chunk = 2 * kk + a_khalf;
                uint32_t off = (uint32_t)(row * 128 + ((chunk ^ (row & 7)) << 4));
                ldsm_x4(aA + off, ah[buf][mt][0], ah[buf][mt][1], ah[buf][mt][2], ah[buf][mt][3]);
                ldsm_x4(aA + GT_TILE_BYTES + off,
                        al[buf][mt][0], al[buf][mt][1], al[buf][mt][2], al[buf][mt][3]);
            }
#pragma unroll
            for (int np = 0; np < 4; np++) {
                int row = wn + np * 16 + b_grp * 8 + b_row;
                int chunk = 2 * kk + b_khalf;
                uint32_t off = (uint32_t)(row * 128 + ((chunk ^ (row & 7)) << 4));
                ldsm_x4(aB + off, bh[buf][np][0], bh[buf][np][1], bh[buf][np][2], bh[buf][np][3]);
                ldsm_x4(aB + GT_TILE_BYTES + off,
                        bl[buf][np][0], bl[buf][np][1], bl[buf][np][2], bl[buf][np][3]);
            }
        };

        load_frag(0, 0);
#pragma unroll
        for (int kk = 0; kk < 4; kk++) {
            const int cur = kk & 1;
            if (kk < 3) load_frag(kk + 1, cur ^ 1);   // prefetch hides LDS latency
#pragma unroll
            for (int mt = 0; mt < 2; mt++)
#pragma unroll
                for (int nt = 0; nt < 8; nt++) {
                    const uint32_t* bhf = &bh[cur][nt >> 1][(nt & 1) * 2];
                    const uint32_t* blf = &bl[cur][nt >> 1][(nt & 1) * 2];
                    mma_bf16(acc[mt][nt], ah[cur][mt], bhf);   // hi*hi
                    mma_bf16(acc[mt][nt], ah[cur][mt], blf);   // hi*lo
                    mma_bf16(acc[mt][nt], al[cur][mt], bhf);   // lo*hi
                }
        }
        __syncthreads();
        if (kt + 2 < NKT) load_stage(kt + 2, s);
        cp_commit();
    }

    // Epilogue: c0,c1 -> (row g, cols 2tig,2tig+1); c2,c3 -> row g+8
    const int g = lane >> 2, tig = lane & 3;
#pragma unroll
    for (int mt = 0; mt < 2; mt++) {
        int row = m0 + wm + mt * 16 + g;
#pragma unroll
        for (int nt = 0; nt < 8; nt++) {
            int col = n0 + wn + nt * 8 + 2 * tig;
            float* c = acc[mt][nt];
            *(float2*)&C[(size_t)row * N + col]       = make_float2(c[0], c[1]);
            *(float2*)&C[(size_t)(row + 8) * N + col] = make_float2(c[2], c[3]);
        }
    }
}

// ---------------------------------------------------------------------------
// Pointwise prep: softmax(q*scale) per head, exp(k*scale)+1e-6, in place.
// ---------------------------------------------------------------------------
__global__ void prep_kernel(float* __restrict__ qkv)
{
    const size_t base = (size_t)blockIdx.x * (3 * D_);
    const int h = threadIdx.x >> 5;
    const int lane = threadIdx.x & 31;
    float* qp = qkv + base + h * L_;
    float* kp = qkv + base + D_ + h * L_;

    float q0 = qp[lane] * 0.125f;
    float q1 = qp[lane + 32] * 0.125f;
    float mx = fmaxf(q0, q1);
#pragma unroll
    for (int off = 16; off > 0; off >>= 1)
        mx = fmaxf(mx, __shfl_xor_sync(0xffffffffu, mx, off));
    float e0 = expf(q0 - mx), e1 = expf(q1 - mx);
    float s = e0 + e1;
#pragma unroll
    for (int off = 16; off > 0; off >>= 1)
        s += __shfl_xor_sync(0xffffffffu, s, off);
    float inv = 1.0f / s;
    qp[lane]      = e0 * inv;
    qp[lane + 32] = e1 * inv;

    float k0 = kp[lane], k1 = kp[lane + 32];
    kp[lane]      = expf(k0 * 0.125f) + 1e-6f;
    kp[lane + 32] = expf(k1 * 0.125f) + 1e-6f;
}

// ---------------------------------------------------------------------------
// Per-chunk state: S_c[l][m] = sum_t K[t][l]*V[t][m]; ksum_c[l].
// ---------------------------------------------------------------------------
__global__ void __launch_bounds__(256)
chunkstate_kernel(const float* __restrict__ qkv,
                  float* __restrict__ Sc, float* __restrict__ ks)
{
    extern __shared__ float sm[];
    float* Ks = sm;
    float* Vs = sm + CHUNK * L_;
    const int c = blockIdx.x, bh = blockIdx.y;
    const int b = bh >> 4, h = bh & 15;
    const size_t rowbase = ((size_t)(b * T_ + c * CHUNK)) * (3 * D_) + h * L_;

    for (int i = threadIdx.x; i < CHUNK * 16; i += 256) {
        int t = i >> 4, f = (i & 15) << 2;
        size_t g = rowbase + (size_t)t * (3 * D_) + f;
        *(float4*)&Ks[t * L_ + f] = *(const float4*)&qkv[g + D_];
        *(float4*)&Vs[t * L_ + f] = *(const float4*)&qkv[g + 2 * D_];
    }
    __syncthreads();

    const int l0 = (threadIdx.x >> 4) << 2;
    const int m0 = (threadIdx.x & 15) << 2;
    float acc[4][4];
#pragma unroll
    for (int i = 0; i < 4; i++)
#pragma unroll
        for (int j = 0; j < 4; j++) acc[i][j] = 0.f;
    for (int t = 0; t < CHUNK; t++) {
        float a[4], v[4];
#pragma unroll
        for (int i = 0; i < 4; i++) a[i] = Ks[t * L_ + l0 + i];
#pragma unroll
        for (int j = 0; j < 4; j++) v[j] = Vs[t * L_ + m0 + j];
#pragma unroll
        for (int i = 0; i < 4; i++)
#pragma unroll
            for (int j = 0; j < 4; j++) acc[i][j] += a[i] * v[j];
    }
    const size_t sbase = ((size_t)bh * NC + c) * (L_ * L_);
#pragma unroll
    for (int i = 0; i < 4; i++)
#pragma unroll
        for (int j = 0; j < 4; j++)
            Sc[sbase + (size_t)(l0 + i) * L_ + m0 + j] = acc[i][j];

    if (threadIdx.x < L_) {
        float s = 0.f;
        for (int t = 0; t < CHUNK; t++) s += Ks[t * L_ + threadIdx.x];
        ks[((size_t)bh * NC + c) * L_ + threadIdx.x] = s;
    }
}

// ---------------------------------------------------------------------------
// Exclusive prefix over chunks, in place. grid (BH, 16) x 256.
// ---------------------------------------------------------------------------
__global__ void prefix_kernel(float* __restrict__ Sc, float* __restrict__ ks)
{
    const int bh = blockIdx.x;
    const int e = blockIdx.y * 256 + threadIdx.x;   // 0..4095
    const size_t base = (size_t)bh * NC * (L_ * L_);
    {
        float acc = 0.f;
#pragma unroll
        for (int c = 0; c < NC; c++) {
            size_t idx = base + (size_t)c * (L_ * L_) + e;
            float tmp = Sc[idx];
            Sc[idx] = acc;
            acc += tmp;
        }
    }
    if (blockIdx.y == 0 && threadIdx.x < L_) {
        const size_t kb = (size_t)bh * NC * L_;
        float acc = 0.f;
#pragma unroll
        for (int c = 0; c < NC; c++) {
            size_t idx = kb + (size_t)c * L_ + threadIdx.x;
            float tmp = ks[idx];
            ks[idx] = acc;
            acc += tmp;
        }
    }
}

// ---------------------------------------------------------------------------
// Chunk attention: Y = qs @ S_prev + causal(qs @ K^T) @ V, written bf16 hi/lo.
// ---------------------------------------------------------------------------
__global__ void __launch_bounds__(128)
attn_kernel(const float* __restrict__ qkv, const float* __restrict__ Sprev,
            const float* __restrict__ kpre,
            __nv_bfloat16* __restrict__ yhi, __nv_bfloat16* __restrict__ ylo)
{
    extern __shared__ float sm[];
    float* Qs = sm;                 // 128*64
    float* Ks = sm + 8192;          // 128*64
    float* Vs = sm + 16384;         // 128*64
    float* Sp = sm + 24576;         // 64*64
    const int c = blockIdx.x, bh = blockIdx.y;
    const int b = bh >> 4, h = bh & 15;
    const int tid = threadIdx.x;
    const size_t rowbase = ((size_t)(b * T_ + c * CHUNK)) * (3 * D_) + h * L_;

    for (int i = tid; i < CHUNK * 16; i += 128) {
        int t = i >> 4, f = (i & 15) << 2;
        size_t g = rowbase + (size_t)t * (3 * D_) + f;
        *(float4*)&Qs[t * L_ + f] = *(const float4*)&qkv[g];
        *(float4*)&Ks[t * L_ + f] = *(const float4*)&qkv[g + D_];
        *(float4*)&Vs[t * L_ + f] = *(const float4*)&qkv[g + 2 * D_];
    }
    const size_t sbase = ((size_t)bh * NC + c) * (L_ * L_);
    for (int i = tid; i < L_ * L_; i += 128) Sp[i] = Sprev[sbase + i];
    __syncthreads();

    if (tid < L_) {
        float acc = kpre[((size_t)bh * NC + c) * L_ + tid];
        for (int t = 0; t < CHUNK; t++) {
            acc += Ks[t * L_ + tid];
            Qs[t * L_ + tid] /= acc;
        }
    }
    __syncthreads();

    const int t = tid;
    float q[L_];
#pragma unroll
    for (int l = 0; l < L_; l++) q[l] = Qs[t * L_ + l];

    float4 yv[16];
#pragma unroll
    for (int f = 0; f < 16; f++) yv[f] = make_float4(0.f, 0.f, 0.f, 0.f);

    // inter-chunk: qs @ S_prev
#pragma unroll
    for (int l = 0; l < L_; l++) {
        float ql = q[l];
        const float4* sp = (const float4*)&Sp[l * L_];
#pragma unroll
        for (int f = 0; f < 16; f++) {
            float4 s = sp[f];
            yv[f].x += ql * s.x; yv[f].y += ql * s.y;
            yv[f].z += ql * s.z; yv[f].w += ql * s.w;
        }
    }

    // intra-chunk causal (inclusive)
    for (int s = 0; s <= t; s++) {
        const float4* kp = (const float4*)&Ks[s * L_];
        float a = 0.f;
#pragma unroll
        for (int lf = 0; lf < 16; lf++) {
            float4 kv = kp[lf];
            a += q[lf*4+0]*kv.x + q[lf*4+1]*kv.y + q[lf*4+2]*kv.z + q[lf*4+3]*kv.w;
        }
        const float4* vp = (const float4*)&Vs[s * L_];
#pragma unroll
        for (int f = 0; f < 16; f++) {
            float4 vv = vp[f];
            yv[f].x += a * vv.x; yv[f].y += a * vv.y;
            yv[f].z += a * vv.z; yv[f].w += a * vv.w;
        }
    }

    const size_t ybase = ((size_t)(b * T_ + c * CHUNK + t)) * D_ + h * L_;
#pragma unroll
    for (int f = 0; f < 16; f++) {
        float4 v = yv[f];
        __nv_bfloat16 h0 = __float2bfloat16(v.x), h1 = __float2bfloat16(v.y);
        __nv_bfloat16 h2 = __float2bfloat16(v.z), h3 = __float2bfloat16(v.w);
        __nv_bfloat16 l0 = __float2bfloat16(v.x - __bfloat162float(h0));
        __nv_bfloat16 l1 = __float2bfloat16(v.y - __bfloat162float(h1));
        __nv_bfloat16 l2 = __float2bfloat16(v.z - __bfloat162float(h2));
        __nv_bfloat16 l3 = __float2bfloat16(v.w - __bfloat162float(h3));
        __nv_bfloat162* ph = (__nv_bfloat162*)&yhi[ybase + f * 4];
        __nv_bfloat162* pl = (__nv_bfloat162*)&ylo[ybase + f * 4];
        ph[0] = __halves2bfloat162(h0, h1); ph[1] = __halves2bfloat162(h2, h3);
        pl[0] = __halves2bfloat162(l0, l1); pl[1] = __halves2bfloat162(l2, l3);
    }
}

// ---------------------------------------------------------------------------
extern "C" void kernel_launch(void* const* d_in, const int* in_sizes, int n_in,
                              void* d_out, int out_size)
{
    const float* x  = (const float*)d_in[0];   // (4,2048,1024)
    const float* w  = (const float*)d_in[1];   // (3072,1024)
    const float* wo = (const float*)d_in[2];   // (1024,1024)
    float* out = (float*)d_out;                // (4,2048,1024)

    float *qkv, *Sc, *ks;
    __nv_bfloat16 *xhi, *xlo, *whi, *wlo, *wothi, *wotlo, *yhi, *ylo;
    cudaGetSymbolAddress((void**)&qkv, g_qkv);
    cudaGetSymbolAddress((void**)&Sc,  g_Sc);
    cudaGetSymbolAddress((void**)&ks,  g_ks);
    cudaGetSymbolAddress((void**)&xhi, g_xhi);
    cudaGetSymbolAddress((void**)&xlo, g_xlo);
    cudaGetSymbolAddress((void**)&whi, g_whi);
    cudaGetSymbolAddress((void**)&wlo, g_wlo);
    cudaGetSymbolAddress((void**)&wothi, g_wothi);
    cudaGetSymbolAddress((void**)&wotlo, g_wotlo);
    cudaGetSymbolAddress((void**)&yhi, g_yhi);
    cudaGetSymbolAddress((void**)&ylo, g_ylo);

    cudaFuncSetAttribute(gemm_mma,
                         cudaFuncAttributeMaxDynamicSharedMemorySize, GT_SMEM_TOTAL);
    cudaFuncSetAttribute(chunkstate_kernel,
                         cudaFuncAttributeMaxDynamicSharedMemorySize, 65536);
    cudaFuncSetAttribute(attn_kernel,
                         cudaFuncAttributeMaxDynamicSharedMemorySize, 114688);

    // 0) split inputs into bf16 hi/lo
    split_kernel<<<(BT_ * D_ / 4 + 255) / 256, 256>>>(x, xhi, xlo, BT_ * D_ / 4);
    split_kernel<<<(3 * D_ * D_ / 4 + 255) / 256, 256>>>(w, whi, wlo, 3 * D_ * D_ / 4);
    split_transpose_kernel<<<dim3(D_ / 32, D_ / 32), dim3(32, 8)>>>(wo, wothi, wotlo);

    // 1) qkv = x @ w^T   (M=8192, N=3072, K=1024) on tensor cores (HMMA)
    gemm_mma<<<dim3(3 * D_ / 128, BT_ / 128), 256, GT_SMEM_TOTAL>>>(
        xhi, xlo, whi, wlo, qkv, 3 * D_, D_);
    // 2) softmax(q), exp(k)+1e-6 in place
    prep_kernel<<<BT_, 512>>>(qkv);
    // 3) per-chunk states + k sums
    chunkstate_kernel<<<dim3(NC, BH_), 256, 65536>>>(qkv, Sc, ks);
    // 4) exclusive prefix over chunks
    prefix_kernel<<<dim3(BH_, 16), 256>>>(Sc, ks);
    // 5) chunk attention -> y (bf16 split)
    attn_kernel<<<dim3(NC, BH_), 128, 114688>>>(qkv, Sc, ks, yhi, ylo);
    // 6) out = y @ w_out  (M=8192, N=1024, K=1024), B = w_out^T pre-split
    gemm_mma<<<dim3(D_ / 128, BT_ / 128), 256, GT_SMEM_TOTAL>>>(
        yhi, ylo, wothi, wotlo, out, D_, D_);
}

// round 6
// speedup vs baseline: 1.1648x; 1.0277x over previous
#include <cuda_runtime.h>
#include <cuda_bf16.h>
#include <cstdint>

// Problem constants
#define B_   4
#define T_   2048
#define D_   1024
#define H_   16
#define L_   64
#define BT_  (B_*T_)        // 8192
#define BH_  (B_*H_)        // 64
#define CHUNK 128
#define NC   (T_/CHUNK)     // 16

// ---------------------------------------------------------------------------
// Scratch (device globals; no allocation allowed)
// ---------------------------------------------------------------------------
__device__ float g_qkv[(size_t)BT_ * 3 * D_];        // (8192, 3072)  q|k|v fp32
__device__ float g_Sc [(size_t)BH_ * NC * L_ * L_];  // chunk states -> excl prefix
__device__ float g_ks [(size_t)BH_ * NC * L_];       // chunk k-sums -> excl prefix
__device__ __nv_bfloat16 g_xhi[(size_t)BT_ * D_];
__device__ __nv_bfloat16 g_xlo[(size_t)BT_ * D_];
__device__ __nv_bfloat16 g_whi[(size_t)3 * D_ * D_];
__device__ __nv_bfloat16 g_wlo[(size_t)3 * D_ * D_];
__device__ __nv_bfloat16 g_wothi[(size_t)D_ * D_];   // w_out^T
__device__ __nv_bfloat16 g_wotlo[(size_t)D_ * D_];
__device__ __nv_bfloat16 g_yhi[(size_t)BT_ * D_];
__device__ __nv_bfloat16 g_ylo[(size_t)BT_ * D_];

// ---------------------------------------------------------------------------
// PTX helpers (baseline sm_80+ instructions only — harness targets plain sm_103)
// ---------------------------------------------------------------------------
__device__ __forceinline__ uint32_t smem_u32(const void* p) {
    uint32_t a;
    asm("{ .reg .u64 t; cvta.to.shared.u64 t, %1; cvt.u32.u64 %0, t; }" : "=r"(a) : "l"(p));
    return a;
}

__device__ __forceinline__ void cp_async16(uint32_t dst, const void* src) {
    asm volatile("cp.async.cg.shared.global [%0], [%1], 16;" :: "r"(dst), "l"(src) : "memory");
}
__device__ __forceinline__ void cp_commit() {
    asm volatile("cp.async.commit_group;" ::: "memory");
}
__device__ __forceinline__ void cp_wait1() {
    asm volatile("cp.async.wait_group 1;" ::: "memory");
}

__device__ __forceinline__ void ldsm_x4(uint32_t addr, uint32_t& r0, uint32_t& r1,
                                        uint32_t& r2, uint32_t& r3) {
    asm volatile("ldmatrix.sync.aligned.m8n8.x4.shared.b16 {%0,%1,%2,%3}, [%4];"
                 : "=r"(r0), "=r"(r1), "=r"(r2), "=r"(r3) : "r"(addr));
}

__device__ __forceinline__ void mma_bf16(float* c, const uint32_t* a, const uint32_t* b) {
    asm volatile(
        "mma.sync.aligned.m16n8k16.row.col.f32.bf16.bf16.f32 "
        "{%0,%1,%2,%3}, {%4,%5,%6,%7}, {%8,%9}, {%0,%1,%2,%3};"
        : "+f"(c[0]), "+f"(c[1]), "+f"(c[2]), "+f"(c[3])
        : "r"(a[0]), "r"(a[1]), "r"(a[2]), "r"(a[3]), "r"(b[0]), "r"(b[1]));
}

// ---------------------------------------------------------------------------
// Split fp32 -> bf16 hi/lo (vectorized)
// ---------------------------------------------------------------------------
__global__ void split_kernel(const float* __restrict__ src,
                             __nv_bfloat16* __restrict__ hi,
                             __nv_bfloat16* __restrict__ lo, int n4)
{
    int i = blockIdx.x * blockDim.x + threadIdx.x;
    if (i >= n4) return;
    float4 v = ((const float4*)src)[i];
    __nv_bfloat16 h0 = __float2bfloat16(v.x), h1 = __float2bfloat16(v.y);
    __nv_bfloat16 h2 = __float2bfloat16(v.z), h3 = __float2bfloat16(v.w);
    __nv_bfloat16 l0 = __float2bfloat16(v.x - __bfloat162float(h0));
    __nv_bfloat16 l1 = __float2bfloat16(v.y - __bfloat162float(h1));
    __nv_bfloat16 l2 = __float2bfloat16(v.z - __bfloat162float(h2));
    __nv_bfloat16 l3 = __float2bfloat16(v.w - __bfloat162float(h3));
    ((__nv_bfloat162*)hi)[2 * i]     = __halves2bfloat162(h0, h1);
    ((__nv_bfloat162*)hi)[2 * i + 1] = __halves2bfloat162(h2, h3);
    ((__nv_bfloat162*)lo)[2 * i]     = __halves2bfloat162(l0, l1);
    ((__nv_bfloat162*)lo)[2 * i + 1] = __halves2bfloat162(l2, l3);
}

// Transpose + split w_out (1024x1024): dst[n][k] = split(src[k][n])
__global__ void split_transpose_kernel(const float* __restrict__ src,
                                       __nv_bfloat16* __restrict__ hi,
                                       __nv_bfloat16* __restrict__ lo)
{
    __shared__ float tile[32][33];
    int n0 = blockIdx.x * 32, k0 = blockIdx.y * 32;
    int tx = threadIdx.x, ty = threadIdx.y;
    for (int r = ty; r < 32; r += 8)
        tile[r][tx] = src[(size_t)(k0 + r) * D_ + n0 + tx];
    __syncthreads();
    for (int r = ty; r < 32; r += 8) {
        float v = tile[tx][r];   // src[k0+tx][n0+r] -> dst[n0+r][k0+tx]
        __nv_bfloat16 h = __float2bfloat16(v);
        size_t idx = (size_t)(n0 + r) * D_ + k0 + tx;
        hi[idx] = h;
        lo[idx] = __float2bfloat16(v - __bfloat162float(h));
    }
}

// ---------------------------------------------------------------------------
// HMMA bf16 split GEMM: C[M,N] = A*B^T fp32 via 3-term bf16 split.
// A (M,K) hi/lo row-major; B (N,K) hi/lo row-major.
// 128x128 block tile, BK=64, 256 threads (8 warps, 4x2), warp tile 32x64.
// 3-stage cp.async pipeline, ONE __syncthreads per k-tile; loads for kt+2
// issued before the MMA block so LSU work overlaps tensor work.
// ---------------------------------------------------------------------------
#define GT_TILE_BYTES  16384           // 128 rows x 128B (64 bf16)
#define GT_STAGE_BYTES (4 * GT_TILE_BYTES)   // Ahi, Alo, Bhi, Blo = 65536
#define GT_SMEM_TOTAL  (3 * GT_STAGE_BYTES)  // 196608

__global__ void __launch_bounds__(256, 1)
gemm_mma(const __nv_bfloat16* __restrict__ Ahi, const __nv_bfloat16* __restrict__ Alo,
         const __nv_bfloat16* __restrict__ Bhi, const __nv_bfloat16* __restrict__ Blo,
         float* __restrict__ C, int N, int K)
{
    extern __shared__ char smem[];
    const uint32_t smem_base = smem_u32(smem);
    const int tid = threadIdx.x;
    const int wid = tid >> 5, lane = tid & 31;
    const int m0 = blockIdx.y * 128, n0 = blockIdx.x * 128;
    const int wm = (wid & 3) * 32;          // warp row offset within tile
    const int wn = (wid >> 2) * 64;         // warp col offset within tile

    const __nv_bfloat16* srcs[4] = { Ahi, Alo, Bhi, Blo };

    auto load_stage = [&](int kt, int s) {
        const int k0 = kt << 6;
#pragma unroll
        for (int tI = 0; tI < 4; tI++) {
            const __nv_bfloat16* src = srcs[tI];
            const int rb = (tI < 2) ? m0 : n0;
            const uint32_t tb = smem_base + s * GT_STAGE_BYTES + tI * GT_TILE_BYTES;
#pragma unroll
            for (int ii = 0; ii < 4; ii++) {
                int j = tid + ii * 256;
                int r = j >> 3, c = j & 7;
                const void* g = &src[(size_t)(rb + r) * K + k0 + c * 8];
                uint32_t d = tb + (uint32_t)(r * 128 + ((c ^ (r & 7)) << 4));
                cp_async16(d, g);
            }
        }
    };

    float acc[2][8][4];
#pragma unroll
    for (int mt = 0; mt < 2; mt++)
#pragma unroll
        for (int nt = 0; nt < 8; nt++)
#pragma unroll
            for (int e = 0; e < 4; e++) acc[mt][nt][e] = 0.f;

    const int NKT = K >> 6;   // 16
    load_stage(0, 0); cp_commit();
    load_stage(1, 1); cp_commit();

    // ldmatrix lane addressing
    const int a_row = (lane & 15);
    const int a_khalf = lane >> 4;
    const int b_grp = (lane >> 4) & 1;
    const int b_khalf = (lane >> 3) & 1;
    const int b_row = lane & 7;

    int s = 0;        // stage of current kt (cycles 0,1,2)
    int sload = 2;    // stage for kt+2
    for (int kt = 0; kt < NKT; kt++) {
        const uint32_t st = smem_base + s * GT_STAGE_BYTES;
        // one group committed per iteration => wait_group 1 guarantees stage kt
        // is resident (group kt done; group kt+1 may still be in flight).
        cp_wait1();
        __syncthreads();

        // issue next-next stage loads FIRST so they overlap this kt's MMAs.
        if (kt + 2 < NKT) load_stage(kt + 2, sload);
        cp_commit();   // empty group in the tail keeps accounting uniform

        const uint32_t aA = st;
        const uint32_t aB = st + 2 * GT_TILE_BYTES;

#pragma unroll
        for (int kk = 0; kk < 4; kk++) {
            uint32_t ah[2][4], al[2][4];
#pragma unroll
            for (int mt = 0; mt < 2; mt++) {
                int row = wm + mt * 16 + a_row;
                int chunk = 2 * kk + a_khalf;
                uint32_t off = (uint32_t)(row * 128 + ((chunk ^ (row & 7)) << 4));
                ldsm_x4(aA + off, ah[mt][0], ah[mt][1], ah[mt][2], ah[mt][3]);
                ldsm_x4(aA + GT_TILE_BYTES + off, al[mt][0], al[mt][1], al[mt][2], al[mt][3]);
            }
            uint32_t bh[4][4], bl[4][4];
#pragma unroll
            for (int np = 0; np < 4; np++) {
                int row = wn + np * 16 + b_grp * 8 + b_row;
                int chunk = 2 * kk + b_khalf;
                uint32_t off = (uint32_t)(row * 128 + ((chunk ^ (row & 7)) << 4));
                ldsm_x4(aB + off, bh[np][0], bh[np][1], bh[np][2], bh[np][3]);
                ldsm_x4(aB + GT_TILE_BYTES + off, bl[np][0], bl[np][1], bl[np][2], bl[np][3]);
            }
#pragma unroll
            for (int mt = 0; mt < 2; mt++)
#pragma unroll
                for (int nt = 0; nt < 8; nt++) {
                    const uint32_t* bhf = &bh[nt >> 1][(nt & 1) * 2];
                    const uint32_t* blf = &bl[nt >> 1][(nt & 1) * 2];
                    mma_bf16(acc[mt][nt], ah[mt], bhf);   // hi*hi
                    mma_bf16(acc[mt][nt], ah[mt], blf);   // hi*lo
                    mma_bf16(acc[mt][nt], al[mt], bhf);   // lo*hi
                }
        }
        s = (s == 2) ? 0 : s + 1;
        sload = (sload == 2) ? 0 : sload + 1;
    }

    // Epilogue: c0,c1 -> (row g, cols 2tig,2tig+1); c2,c3 -> row g+8
    const int g = lane >> 2, tig = lane & 3;
#pragma unroll
    for (int mt = 0; mt < 2; mt++) {
        int row = m0 + wm + mt * 16 + g;
#pragma unroll
        for (int nt = 0; nt < 8; nt++) {
            int col = n0 + wn + nt * 8 + 2 * tig;
            float* c = acc[mt][nt];
            *(float2*)&C[(size_t)row * N + col]       = make_float2(c[0], c[1]);
            *(float2*)&C[(size_t)(row + 8) * N + col] = make_float2(c[2], c[3]);
        }
    }
}

// ---------------------------------------------------------------------------
// Pointwise prep: softmax(q*scale) per head, exp(k*scale)+1e-6, in place.
// ---------------------------------------------------------------------------
__global__ void prep_kernel(float* __restrict__ qkv)
{
    const size_t base = (size_t)blockIdx.x * (3 * D_);
    const int h = threadIdx.x >> 5;
    const int lane = threadIdx.x & 31;
    float* qp = qkv + base + h * L_;
    float* kp = qkv + base + D_ + h * L_;

    float q0 = qp[lane] * 0.125f;
    float q1 = qp[lane + 32] * 0.125f;
    float mx = fmaxf(q0, q1);
#pragma unroll
    for (int off = 16; off > 0; off >>= 1)
        mx = fmaxf(mx, __shfl_xor_sync(0xffffffffu, mx, off));
    float e0 = expf(q0 - mx), e1 = expf(q1 - mx);
    float s = e0 + e1;
#pragma unroll
    for (int off = 16; off > 0; off >>= 1)
        s += __shfl_xor_sync(0xffffffffu, s, off);
    float inv = 1.0f / s;
    qp[lane]      = e0 * inv;
    qp[lane + 32] = e1 * inv;

    float k0 = kp[lane], k1 = kp[lane + 32];
    kp[lane]      = expf(k0 * 0.125f) + 1e-6f;
    kp[lane + 32] = expf(k1 * 0.125f) + 1e-6f;
}

// ---------------------------------------------------------------------------
// Per-chunk state: S_c[l][m] = sum_t K[t][l]*V[t][m]; ksum_c[l].
// ---------------------------------------------------------------------------
__global__ void __launch_bounds__(256)
chunkstate_kernel(const float* __restrict__ qkv,
                  float* __restrict__ Sc, float* __restrict__ ks)
{
    extern __shared__ float sm[];
    float* Ks = sm;
    float* Vs = sm + CHUNK * L_;
    const int c = blockIdx.x, bh = blockIdx.y;
    const int b = bh >> 4, h = bh & 15;
    const size_t rowbase = ((size_t)(b * T_ + c * CHUNK)) * (3 * D_) + h * L_;

    for (int i = threadIdx.x; i < CHUNK * 16; i += 256) {
        int t = i >> 4, f = (i & 15) << 2;
        size_t g = rowbase + (size_t)t * (3 * D_) + f;
        *(float4*)&Ks[t * L_ + f] = *(const float4*)&qkv[g + D_];
        *(float4*)&Vs[t * L_ + f] = *(const float4*)&qkv[g + 2 * D_];
    }
    __syncthreads();

    const int l0 = (threadIdx.x >> 4) << 2;
    const int m0 = (threadIdx.x & 15) << 2;
    float acc[4][4];
#pragma unroll
    for (int i = 0; i < 4; i++)
#pragma unroll
        for (int j = 0; j < 4; j++) acc[i][j] = 0.f;
    for (int t = 0; t < CHUNK; t++) {
        float a[4], v[4];
#pragma unroll
        for (int i = 0; i < 4; i++) a[i] = Ks[t * L_ + l0 + i];
#pragma unroll
        for (int j = 0; j < 4; j++) v[j] = Vs[t * L_ + m0 + j];
#pragma unroll
        for (int i = 0; i < 4; i++)
#pragma unroll
            for (int j = 0; j < 4; j++) acc[i][j] += a[i] * v[j];
    }
    const size_t sbase = ((size_t)bh * NC + c) * (L_ * L_);
#pragma unroll
    for (int i = 0; i < 4; i++)
#pragma unroll
        for (int j = 0; j < 4; j++)
            Sc[sbase + (size_t)(l0 + i) * L_ + m0 + j] = acc[i][j];

    if (threadIdx.x < L_) {
        float s = 0.f;
        for (int t = 0; t < CHUNK; t++) s += Ks[t * L_ + threadIdx.x];
        ks[((size_t)bh * NC + c) * L_ + threadIdx.x] = s;
    }
}

// ---------------------------------------------------------------------------
// Exclusive prefix over chunks, in place. grid (BH, 16) x 256.
// ---------------------------------------------------------------------------
__global__ void prefix_kernel(float* __restrict__ Sc, float* __restrict__ ks)
{
    const int bh = blockIdx.x;
    const int e = blockIdx.y * 256 + threadIdx.x;   // 0..4095
    const size_t base = (size_t)bh * NC * (L_ * L_);
    {
        float acc = 0.f;
#pragma unroll
        for (int c = 0; c < NC; c++) {
            size_t idx = base + (size_t)c * (L_ * L_) + e;
            float tmp = Sc[idx];
            Sc[idx] = acc;
            acc += tmp;
        }
    }
    if (blockIdx.y == 0 && threadIdx.x < L_) {
        const size_t kb = (size_t)bh * NC * L_;
        float acc = 0.f;
#pragma unroll
        for (int c = 0; c < NC; c++) {
            size_t idx = kb + (size_t)c * L_ + threadIdx.x;
            float tmp = ks[idx];
            ks[idx] = acc;
            acc += tmp;
        }
    }
}

// ---------------------------------------------------------------------------
// Chunk attention: Y = qs @ S_prev + causal(qs @ K^T) @ V, written bf16 hi/lo.
// ---------------------------------------------------------------------------
__global__ void __launch_bounds__(128)
attn_kernel(const float* __restrict__ qkv, const float* __restrict__ Sprev,
            const float* __restrict__ kpre,
            __nv_bfloat16* __restrict__ yhi, __nv_bfloat16* __restrict__ ylo)
{
    extern __shared__ float sm[];
    float* Qs = sm;                 // 128*64
    float* Ks = sm + 8192;          // 128*64
    float* Vs = sm + 16384;         // 128*64
    float* Sp = sm + 24576;         // 64*64
    const int c = blockIdx.x, bh = blockIdx.y;
    const int b = bh >> 4, h = bh & 15;
    const int tid = threadIdx.x;
    const size_t rowbase = ((size_t)(b * T_ + c * CHUNK)) * (3 * D_) + h * L_;

    for (int i = tid; i < CHUNK * 16; i += 128) {
        int t = i >> 4, f = (i & 15) << 2;
        size_t g = rowbase + (size_t)t * (3 * D_) + f;
        *(float4*)&Qs[t * L_ + f] = *(const float4*)&qkv[g];
        *(float4*)&Ks[t * L_ + f] = *(const float4*)&qkv[g + D_];
        *(float4*)&Vs[t * L_ + f] = *(const float4*)&qkv[g + 2 * D_];
    }
    const size_t sbase = ((size_t)bh * NC + c) * (L_ * L_);
    for (int i = tid; i < L_ * L_; i += 128) Sp[i] = Sprev[sbase + i];
    __syncthreads();

    // normalize: qs[t][l] = q[t][l] / (kpre[l] + cumsum_{s<=t} K[s][l])
    // 128 threads: 2 per l, halves of the t range (same summation order).
    {
        const int l = tid & 63;
        const int half = tid >> 6;
        float acc = kpre[((size_t)bh * NC + c) * L_ + l];
        if (half == 0) {
            for (int t = 0; t < 64; t++) {
                acc += Ks[t * L_ + l];
                Qs[t * L_ + l] = __fdividef(Qs[t * L_ + l], acc);
            }
        } else {
#pragma unroll 8
            for (int t = 0; t < 64; t++) acc += Ks[t * L_ + l];
            for (int t = 64; t < 128; t++) {
                acc += Ks[t * L_ + l];
                Qs[t * L_ + l] = __fdividef(Qs[t * L_ + l], acc);
            }
        }
    }
    __syncthreads();

    const int t = tid;
    float q[L_];
#pragma unroll
    for (int l = 0; l < L_; l++) q[l] = Qs[t * L_ + l];

    float4 yv[16];
#pragma unroll
    for (int f = 0; f < 16; f++) yv[f] = make_float4(0.f, 0.f, 0.f, 0.f);

    // inter-chunk: qs @ S_prev
#pragma unroll
    for (int l = 0; l < L_; l++) {
        float ql = q[l];
        const float4* sp = (const float4*)&Sp[l * L_];
#pragma unroll
        for (int f = 0; f < 16; f++) {
            float4 s = sp[f];
            yv[f].x += ql * s.x; yv[f].y += ql * s.y;
            yv[f].z += ql * s.z; yv[f].w += ql * s.w;
        }
    }

    // intra-chunk causal (inclusive)
    for (int s = 0; s <= t; s++) {
        const float4* kp = (const float4*)&Ks[s * L_];
        float a = 0.f;
#pragma unroll
        for (int lf = 0; lf < 16; lf++) {
            float4 kv = kp[lf];
            a += q[lf*4+0]*kv.x + q[lf*4+1]*kv.y + q[lf*4+2]*kv.z + q[lf*4+3]*kv.w;
        }
        const float4* vp = (const float4*)&Vs[s * L_];
#pragma unroll
        for (int f = 0; f < 16; f++) {
            float4 vv = vp[f];
            yv[f].x += a * vv.x; yv[f].y += a * vv.y;
            yv[f].z += a * vv.z; yv[f].w += a * vv.w;
        }
    }

    const size_t ybase = ((size_t)(b * T_ + c * CHUNK + t)) * D_ + h * L_;
#pragma unroll
    for (int f = 0; f < 16; f++) {
        float4 v = yv[f];
        __nv_bfloat16 h0 = __float2bfloat16(v.x), h1 = __float2bfloat16(v.y);
        __nv_bfloat16 h2 = __float2bfloat16(v.z), h3 = __float2bfloat16(v.w);
        __nv_bfloat16 l0 = __float2bfloat16(v.x - __bfloat162float(h0));
        __nv_bfloat16 l1 = __float2bfloat16(v.y - __bfloat162float(h1));
        __nv_bfloat16 l2 = __float2bfloat16(v.z - __bfloat162float(h2));
        __nv_bfloat16 l3 = __float2bfloat16(v.w - __bfloat162float(h3));
        __nv_bfloat162* ph = (__nv_bfloat162*)&yhi[ybase + f * 4];
        __nv_bfloat162* pl = (__nv_bfloat162*)&ylo[ybase + f * 4];
        ph[0] = __halves2bfloat162(h0, h1); ph[1] = __halves2bfloat162(h2, h3);
        pl[0] = __halves2bfloat162(l0, l1); pl[1] = __halves2bfloat162(l2, l3);
    }
}

// ---------------------------------------------------------------------------
extern "C" void kernel_launch(void* const* d_in, const int* in_sizes, int n_in,
                              void* d_out, int out_size)
{
    const float* x  = (const float*)d_in[0];   // (4,2048,1024)
    const float* w  = (const float*)d_in[1];   // (3072,1024)
    const float* wo = (const float*)d_in[2];   // (1024,1024)
    float* out = (float*)d_out;                // (4,2048,1024)

    float *qkv, *Sc, *ks;
    __nv_bfloat16 *xhi, *xlo, *whi, *wlo, *wothi, *wotlo, *yhi, *ylo;
    cudaGetSymbolAddress((void**)&qkv, g_qkv);
    cudaGetSymbolAddress((void**)&Sc,  g_Sc);
    cudaGetSymbolAddress((void**)&ks,  g_ks);
    cudaGetSymbolAddress((void**)&xhi, g_xhi);
    cudaGetSymbolAddress((void**)&xlo, g_xlo);
    cudaGetSymbolAddress((void**)&whi, g_whi);
    cudaGetSymbolAddress((void**)&wlo, g_wlo);
    cudaGetSymbolAddress((void**)&wothi, g_wothi);
    cudaGetSymbolAddress((void**)&wotlo, g_wotlo);
    cudaGetSymbolAddress((void**)&yhi, g_yhi);
    cudaGetSymbolAddress((void**)&ylo, g_ylo);

    cudaFuncSetAttribute(gemm_mma,
                         cudaFuncAttributeMaxDynamicSharedMemorySize, GT_SMEM_TOTAL);
    cudaFuncSetAttribute(chunkstate_kernel,
                         cudaFuncAttributeMaxDynamicSharedMemorySize, 65536);
    cudaFuncSetAttribute(attn_kernel,
                         cudaFuncAttributeMaxDynamicSharedMemorySize, 114688);

    // 0) split inputs into bf16 hi/lo
    split_kernel<<<(BT_ * D_ / 4 + 255) / 256, 256>>>(x, xhi, xlo, BT_ * D_ / 4);
    split_kernel<<<(3 * D_ * D_ / 4 + 255) / 256, 256>>>(w, whi, wlo, 3 * D_ * D_ / 4);
    split_transpose_kernel<<<dim3(D_ / 32, D_ / 32), dim3(32, 8)>>>(wo, wothi, wotlo);

    // 1) qkv = x @ w^T   (M=8192, N=3072, K=1024) on tensor cores (HMMA)
    gemm_mma<<<dim3(3 * D_ / 128, BT_ / 128), 256, GT_SMEM_TOTAL>>>(
        xhi, xlo, whi, wlo, qkv, 3 * D_, D_);
    // 2) softmax(q), exp(k)+1e-6 in place
    prep_kernel<<<BT_, 512>>>(qkv);
    // 3) per-chunk states + k sums
    chunkstate_kernel<<<dim3(NC, BH_), 256, 65536>>>(qkv, Sc, ks);
    // 4) exclusive prefix over chunks
    prefix_kernel<<<dim3(BH_, 16), 256>>>(Sc, ks);
    // 5) chunk attention -> y (bf16 split)
    attn_kernel<<<dim3(NC, BH_), 128, 114688>>>(qkv, Sc, ks, yhi, ylo);
    // 6) out = y @ w_out  (M=8192, N=1024, K=1024), B = w_out^T pre-split
    gemm_mma<<<dim3(D_ / 128, BT_ / 128), 256, GT_SMEM_TOTAL>>>(
        yhi, ylo, wothi, wotlo, out, D_, D_);
}

// round 7
// speedup vs baseline: 1.1674x; 1.0022x over previous
#include <cuda_runtime.h>
#include <cuda_bf16.h>
#include <cstdint>

// Problem constants
#define B_   4
#define T_   2048
#define D_   1024
#define H_   16
#define L_   64
#define BT_  (B_*T_)        // 8192
#define BH_  (B_*H_)        // 64
#define CHUNK 128
#define NC   (T_/CHUNK)     // 16

// ---------------------------------------------------------------------------
// Scratch (device globals; no allocation allowed)
// ---------------------------------------------------------------------------
__device__ float g_qkv[(size_t)BT_ * 3 * D_];        // (8192, 3072)  q|k|v fp32
__device__ float g_Sc [(size_t)BH_ * NC * L_ * L_];  // chunk states -> excl prefix
__device__ float g_ks [(size_t)BH_ * NC * L_];       // chunk k-sums -> excl prefix
__device__ __nv_bfloat16 g_xhi[(size_t)BT_ * D_];
__device__ __nv_bfloat16 g_xlo[(size_t)BT_ * D_];
__device__ __nv_bfloat16 g_whi[(size_t)3 * D_ * D_];
__device__ __nv_bfloat16 g_wlo[(size_t)3 * D_ * D_];
__device__ __nv_bfloat16 g_wothi[(size_t)D_ * D_];   // w_out^T
__device__ __nv_bfloat16 g_wotlo[(size_t)D_ * D_];
__device__ __nv_bfloat16 g_yhi[(size_t)BT_ * D_];
__device__ __nv_bfloat16 g_ylo[(size_t)BT_ * D_];

// ---------------------------------------------------------------------------
// PTX helpers (baseline sm_80+ instructions only — harness targets plain sm_103)
// ---------------------------------------------------------------------------
__device__ __forceinline__ uint32_t smem_u32(const void* p) {
    uint32_t a;
    asm("{ .reg .u64 t; cvta.to.shared.u64 t, %1; cvt.u32.u64 %0, t; }" : "=r"(a) : "l"(p));
    return a;
}

__device__ __forceinline__ void cp_async16(uint32_t dst, const void* src) {
    asm volatile("cp.async.cg.shared.global [%0], [%1], 16;" :: "r"(dst), "l"(src) : "memory");
}
__device__ __forceinline__ void cp_commit() {
    asm volatile("cp.async.commit_group;" ::: "memory");
}
__device__ __forceinline__ void cp_wait1() {
    asm volatile("cp.async.wait_group 1;" ::: "memory");
}

__device__ __forceinline__ void ldsm_x4(uint32_t addr, uint32_t& r0, uint32_t& r1,
                                        uint32_t& r2, uint32_t& r3) {
    asm volatile("ldmatrix.sync.aligned.m8n8.x4.shared.b16 {%0,%1,%2,%3}, [%4];"
                 : "=r"(r0), "=r"(r1), "=r"(r2), "=r"(r3) : "r"(addr));
}

__device__ __forceinline__ void mma_bf16(float* c, const uint32_t* a, const uint32_t* b) {
    asm volatile(
        "mma.sync.aligned.m16n8k16.row.col.f32.bf16.bf16.f32 "
        "{%0,%1,%2,%3}, {%4,%5,%6,%7}, {%8,%9}, {%0,%1,%2,%3};"
        : "+f"(c[0]), "+f"(c[1]), "+f"(c[2]), "+f"(c[3])
        : "r"(a[0]), "r"(a[1]), "r"(a[2]), "r"(a[3]), "r"(b[0]), "r"(b[1]));
}

// ---------------------------------------------------------------------------
// Split fp32 -> bf16 hi/lo (vectorized)
// ---------------------------------------------------------------------------
__global__ void split_kernel(const float* __restrict__ src,
                             __nv_bfloat16* __restrict__ hi,
                             __nv_bfloat16* __restrict__ lo, int n4)
{
    int i = blockIdx.x * blockDim.x + threadIdx.x;
    if (i >= n4) return;
    float4 v = ((const float4*)src)[i];
    __nv_bfloat16 h0 = __float2bfloat16(v.x), h1 = __float2bfloat16(v.y);
    __nv_bfloat16 h2 = __float2bfloat16(v.z), h3 = __float2bfloat16(v.w);
    __nv_bfloat16 l0 = __float2bfloat16(v.x - __bfloat162float(h0));
    __nv_bfloat16 l1 = __float2bfloat16(v.y - __bfloat162float(h1));
    __nv_bfloat16 l2 = __float2bfloat16(v.z - __bfloat162float(h2));
    __nv_bfloat16 l3 = __float2bfloat16(v.w - __bfloat162float(h3));
    ((__nv_bfloat162*)hi)[2 * i]     = __halves2bfloat162(h0, h1);
    ((__nv_bfloat162*)hi)[2 * i + 1] = __halves2bfloat162(h2, h3);
    ((__nv_bfloat162*)lo)[2 * i]     = __halves2bfloat162(l0, l1);
    ((__nv_bfloat162*)lo)[2 * i + 1] = __halves2bfloat162(l2, l3);
}

// Transpose + split w_out (1024x1024): dst[n][k] = split(src[k][n])
__global__ void split_transpose_kernel(const float* __restrict__ src,
                                       __nv_bfloat16* __restrict__ hi,
                                       __nv_bfloat16* __restrict__ lo)
{
    __shared__ float tile[32][33];
    int n0 = blockIdx.x * 32, k0 = blockIdx.y * 32;
    int tx = threadIdx.x, ty = threadIdx.y;
    for (int r = ty; r < 32; r += 8)
        tile[r][tx] = src[(size_t)(k0 + r) * D_ + n0 + tx];
    __syncthreads();
    for (int r = ty; r < 32; r += 8) {
        float v = tile[tx][r];   // src[k0+tx][n0+r] -> dst[n0+r][k0+tx]
        __nv_bfloat16 h = __float2bfloat16(v);
        size_t idx = (size_t)(n0 + r) * D_ + k0 + tx;
        hi[idx] = h;
        lo[idx] = __float2bfloat16(v - __bfloat162float(h));
    }
}

// ---------------------------------------------------------------------------
// HMMA bf16 split GEMM: C[M,N] = A*B^T fp32 via 3-term bf16 split.
// A (M,K) hi/lo row-major; B (N,K) hi/lo row-major.
// 128x128 block tile, BK=64, 256 threads (8 warps, 4x2), warp tile 32x64.
// 3-stage cp.async pipeline, one __syncthreads per k-tile.
// Split-pass loop is OUTERMOST in the kk-body: each accumulator is reused
// only every 16 MMAs, breaking HMMA RAW chains.
// ---------------------------------------------------------------------------
#define GT_TILE_BYTES  16384           // 128 rows x 128B (64 bf16)
#define GT_STAGE_BYTES (4 * GT_TILE_BYTES)   // Ahi, Alo, Bhi, Blo = 65536
#define GT_SMEM_TOTAL  (3 * GT_STAGE_BYTES)  // 196608

__global__ void __launch_bounds__(256, 1)
gemm_mma(const __nv_bfloat16* __restrict__ Ahi, const __nv_bfloat16* __restrict__ Alo,
         const __nv_bfloat16* __restrict__ Bhi, const __nv_bfloat16* __restrict__ Blo,
         float* __restrict__ C, int N, int K)
{
    extern __shared__ char smem[];
    const uint32_t smem_base = smem_u32(smem);
    const int tid = threadIdx.x;
    const int wid = tid >> 5, lane = tid & 31;
    const int m0 = blockIdx.y * 128, n0 = blockIdx.x * 128;
    const int wm = (wid & 3) * 32;          // warp row offset within tile
    const int wn = (wid >> 2) * 64;         // warp col offset within tile

    const __nv_bfloat16* srcs[4] = { Ahi, Alo, Bhi, Blo };

    auto load_stage = [&](int kt, int s) {
        const int k0 = kt << 6;
#pragma unroll
        for (int tI = 0; tI < 4; tI++) {
            const __nv_bfloat16* src = srcs[tI];
            const int rb = (tI < 2) ? m0 : n0;
            const uint32_t tb = smem_base + s * GT_STAGE_BYTES + tI * GT_TILE_BYTES;
#pragma unroll
            for (int ii = 0; ii < 4; ii++) {
                int j = tid + ii * 256;
                int r = j >> 3, c = j & 7;
                const void* g = &src[(size_t)(rb + r) * K + k0 + c * 8];
                uint32_t d = tb + (uint32_t)(r * 128 + ((c ^ (r & 7)) << 4));
                cp_async16(d, g);
            }
        }
    };

    float acc[2][8][4];
#pragma unroll
    for (int mt = 0; mt < 2; mt++)
#pragma unroll
        for (int nt = 0; nt < 8; nt++)
#pragma unroll
            for (int e = 0; e < 4; e++) acc[mt][nt][e] = 0.f;

    const int NKT = K >> 6;   // 16
    load_stage(0, 0); cp_commit();
    load_stage(1, 1); cp_commit();

    // ldmatrix lane addressing
    const int a_row = (lane & 15);
    const int a_khalf = lane >> 4;
    const int b_grp = (lane >> 4) & 1;
    const int b_khalf = (lane >> 3) & 1;
    const int b_row = lane & 7;

    int s = 0;        // stage of current kt (cycles 0,1,2)
    int sload = 2;    // stage for kt+2
    for (int kt = 0; kt < NKT; kt++) {
        const uint32_t st = smem_base + s * GT_STAGE_BYTES;
        cp_wait1();
        __syncthreads();

        // issue next-next stage loads FIRST so they overlap this kt's MMAs.
        if (kt + 2 < NKT) load_stage(kt + 2, sload);
        cp_commit();   // empty group in the tail keeps accounting uniform

        const uint32_t aA = st;
        const uint32_t aB = st + 2 * GT_TILE_BYTES;

#pragma unroll
        for (int kk = 0; kk < 4; kk++) {
            uint32_t ah[2][4], al[2][4];
#pragma unroll
            for (int mt = 0; mt < 2; mt++) {
                int row = wm + mt * 16 + a_row;
                int chunk = 2 * kk + a_khalf;
                uint32_t off = (uint32_t)(row * 128 + ((chunk ^ (row & 7)) << 4));
                ldsm_x4(aA + off, ah[mt][0], ah[mt][1], ah[mt][2], ah[mt][3]);
                ldsm_x4(aA + GT_TILE_BYTES + off, al[mt][0], al[mt][1], al[mt][2], al[mt][3]);
            }
            uint32_t bh[4][4], bl[4][4];
#pragma unroll
            for (int np = 0; np < 4; np++) {
                int row = wn + np * 16 + b_grp * 8 + b_row;
                int chunk = 2 * kk + b_khalf;
                uint32_t off = (uint32_t)(row * 128 + ((chunk ^ (row & 7)) << 4));
                ldsm_x4(aB + off, bh[np][0], bh[np][1], bh[np][2], bh[np][3]);
                ldsm_x4(aB + GT_TILE_BYTES + off, bl[np][0], bl[np][1], bl[np][2], bl[np][3]);
            }
            // pass loop OUTERMOST: accumulator reuse distance = 16 MMAs
#pragma unroll
            for (int p = 0; p < 3; p++) {
#pragma unroll
                for (int mt = 0; mt < 2; mt++) {
                    const uint32_t* af = (p == 2) ? al[mt] : ah[mt];
#pragma unroll
                    for (int nt = 0; nt < 8; nt++) {
                        const uint32_t* bf = (p == 1) ? &bl[nt >> 1][(nt & 1) * 2]
                                                      : &bh[nt >> 1][(nt & 1) * 2];
                        mma_bf16(acc[mt][nt], af, bf);
                    }
                }
            }
        }
        s = (s == 2) ? 0 : s + 1;
        sload = (sload == 2) ? 0 : sload + 1;
    }

    // Epilogue: c0,c1 -> (row g, cols 2tig,2tig+1); c2,c3 -> row g+8
    const int g = lane >> 2, tig = lane & 3;
#pragma unroll
    for (int mt = 0; mt < 2; mt++) {
        int row = m0 + wm + mt * 16 + g;
#pragma unroll
        for (int nt = 0; nt < 8; nt++) {
            int col = n0 + wn + nt * 8 + 2 * tig;
            float* c = acc[mt][nt];
            *(float2*)&C[(size_t)row * N + col]       = make_float2(c[0], c[1]);
            *(float2*)&C[(size_t)(row + 8) * N + col] = make_float2(c[2], c[3]);
        }
    }
}

// ---------------------------------------------------------------------------
// Pointwise prep: softmax(q*scale) per head, exp(k*scale)+1e-6, in place.
// ---------------------------------------------------------------------------
__global__ void prep_kernel(float* __restrict__ qkv)
{
    const size_t base = (size_t)blockIdx.x * (3 * D_);
    const int h = threadIdx.x >> 5;
    const int lane = threadIdx.x & 31;
    float* qp = qkv + base + h * L_;
    float* kp = qkv + base + D_ + h * L_;

    float q0 = qp[lane] * 0.125f;
    float q1 = qp[lane + 32] * 0.125f;
    float mx = fmaxf(q0, q1);
#pragma unroll
    for (int off = 16; off > 0; off >>= 1)
        mx = fmaxf(mx, __shfl_xor_sync(0xffffffffu, mx, off));
    float e0 = expf(q0 - mx), e1 = expf(q1 - mx);
    float s = e0 + e1;
#pragma unroll
    for (int off = 16; off > 0; off >>= 1)
        s += __shfl_xor_sync(0xffffffffu, s, off);
    float inv = 1.0f / s;
    qp[lane]      = e0 * inv;
    qp[lane + 32] = e1 * inv;

    float k0 = kp[lane], k1 = kp[lane + 32];
    kp[lane]      = expf(k0 * 0.125f) + 1e-6f;
    kp[lane + 32] = expf(k1 * 0.125f) + 1e-6f;
}

// ---------------------------------------------------------------------------
// Per-chunk state: S_c[l][m] = sum_t K[t][l]*V[t][m]; ksum_c[l].
// ---------------------------------------------------------------------------
__global__ void __launch_bounds__(256)
chunkstate_kernel(const float* __restrict__ qkv,
                  float* __restrict__ Sc, float* __restrict__ ks)
{
    extern __shared__ float sm[];
    float* Ks = sm;
    float* Vs = sm + CHUNK * L_;
    const int c = blockIdx.x, bh = blockIdx.y;
    const int b = bh >> 4, h = bh & 15;
    const size_t rowbase = ((size_t)(b * T_ + c * CHUNK)) * (3 * D_) + h * L_;

    for (int i = threadIdx.x; i < CHUNK * 16; i += 256) {
        int t = i >> 4, f = (i & 15) << 2;
        size_t g = rowbase + (size_t)t * (3 * D_) + f;
        *(float4*)&Ks[t * L_ + f] = *(const float4*)&qkv[g + D_];
        *(float4*)&Vs[t * L_ + f] = *(const float4*)&qkv[g + 2 * D_];
    }
    __syncthreads();

    const int l0 = (threadIdx.x >> 4) << 2;
    const int m0 = (threadIdx.x & 15) << 2;
    float acc[4][4];
#pragma unroll
    for (int i = 0; i < 4; i++)
#pragma unroll
        for (int j = 0; j < 4; j++) acc[i][j] = 0.f;
    for (int t = 0; t < CHUNK; t++) {
        float a[4], v[4];
#pragma unroll
        for (int i = 0; i < 4; i++) a[i] = Ks[t * L_ + l0 + i];
#pragma unroll
        for (int j = 0; j < 4; j++) v[j] = Vs[t * L_ + m0 + j];
#pragma unroll
        for (int i = 0; i < 4; i++)
#pragma unroll
            for (int j = 0; j < 4; j++) acc[i][j] += a[i] * v[j];
    }
    const size_t sbase = ((size_t)bh * NC + c) * (L_ * L_);
#pragma unroll
    for (int i = 0; i < 4; i++)
#pragma unroll
        for (int j = 0; j < 4; j++)
            Sc[sbase + (size_t)(l0 + i) * L_ + m0 + j] = acc[i][j];

    if (threadIdx.x < L_) {
        float s = 0.f;
        for (int t = 0; t < CHUNK; t++) s += Ks[t * L_ + threadIdx.x];
        ks[((size_t)bh * NC + c) * L_ + threadIdx.x] = s;
    }
}

// ---------------------------------------------------------------------------
// Exclusive prefix over chunks, in place. grid (BH, 16) x 256.
// ---------------------------------------------------------------------------
__global__ void prefix_kernel(float* __restrict__ Sc, float* __restrict__ ks)
{
    const int bh = blockIdx.x;
    const int e = blockIdx.y * 256 + threadIdx.x;   // 0..4095
    const size_t base = (size_t)bh * NC * (L_ * L_);
    {
        float acc = 0.f;
#pragma unroll
        for (int c = 0; c < NC; c++) {
            size_t idx = base + (size_t)c * (L_ * L_) + e;
            float tmp = Sc[idx];
            Sc[idx] = acc;
            acc += tmp;
        }
    }
    if (blockIdx.y == 0 && threadIdx.x < L_) {
        const size_t kb = (size_t)bh * NC * L_;
        float acc = 0.f;
#pragma unroll
        for (int c = 0; c < NC; c++) {
            size_t idx = kb + (size_t)c * L_ + threadIdx.x;
            float tmp = ks[idx];
            ks[idx] = acc;
            acc += tmp;
        }
    }
}

// ---------------------------------------------------------------------------
// Chunk attention: Y = qs @ S_prev + causal(qs @ K^T) @ V, written bf16 hi/lo.
// ---------------------------------------------------------------------------
__global__ void __launch_bounds__(128)
attn_kernel(const float* __restrict__ qkv, const float* __restrict__ Sprev,
            const float* __restrict__ kpre,
            __nv_bfloat16* __restrict__ yhi, __nv_bfloat16* __restrict__ ylo)
{
    extern __shared__ float sm[];
    float* Qs = sm;                 // 128*64
    float* Ks = sm + 8192;          // 128*64
    float* Vs = sm + 16384;         // 128*64
    float* Sp = sm + 24576;         // 64*64
    const int c = blockIdx.x, bh = blockIdx.y;
    const int b = bh >> 4, h = bh & 15;
    const int tid = threadIdx.x;
    const size_t rowbase = ((size_t)(b * T_ + c * CHUNK)) * (3 * D_) + h * L_;

    for (int i = tid; i < CHUNK * 16; i += 128) {
        int t = i >> 4, f = (i & 15) << 2;
        size_t g = rowbase + (size_t)t * (3 * D_) + f;
        *(float4*)&Qs[t * L_ + f] = *(const float4*)&qkv[g];
        *(float4*)&Ks[t * L_ + f] = *(const float4*)&qkv[g + D_];
        *(float4*)&Vs[t * L_ + f] = *(const float4*)&qkv[g + 2 * D_];
    }
    const size_t sbase = ((size_t)bh * NC + c) * (L_ * L_);
    for (int i = tid; i < L_ * L_; i += 128) Sp[i] = Sprev[sbase + i];
    __syncthreads();

    // normalize: qs[t][l] = q[t][l] / (kpre[l] + cumsum_{s<=t} K[s][l])
    // 128 threads: 2 per l, halves of the t range (same summation order).
    {
        const int l = tid & 63;
        const int half = tid >> 6;
        float acc = kpre[((size_t)bh * NC + c) * L_ + l];
        if (half == 0) {
            for (int t = 0; t < 64; t++) {
                acc += Ks[t * L_ + l];
                Qs[t * L_ + l] = __fdividef(Qs[t * L_ + l], acc);
            }
        } else {
#pragma unroll 8
            for (int t = 0; t < 64; t++) acc += Ks[t * L_ + l];
            for (int t = 64; t < 128; t++) {
                acc += Ks[t * L_ + l];
                Qs[t * L_ + l] = __fdividef(Qs[t * L_ + l], acc);
            }
        }
    }
    __syncthreads();

    const int t = tid;
    float q[L_];
#pragma unroll
    for (int l = 0; l < L_; l++) q[l] = Qs[t * L_ + l];

    float4 yv[16];
#pragma unroll
    for (int f = 0; f < 16; f++) yv[f] = make_float4(0.f, 0.f, 0.f, 0.f);

    // inter-chunk: qs @ S_prev
#pragma unroll
    for (int l = 0; l < L_; l++) {
        float ql = q[l];
        const float4* sp = (const float4*)&Sp[l * L_];
#pragma unroll
        for (int f = 0; f < 16; f++) {
            float4 s = sp[f];
            yv[f].x += ql * s.x; yv[f].y += ql * s.y;
            yv[f].z += ql * s.z; yv[f].w += ql * s.w;
        }
    }

    // intra-chunk causal (inclusive)
    for (int s = 0; s <= t; s++) {
        const float4* kp = (const float4*)&Ks[s * L_];
        float a = 0.f;
#pragma unroll
        for (int lf = 0; lf < 16; lf++) {
            float4 kv = kp[lf];
            a += q[lf*4+0]*kv.x + q[lf*4+1]*kv.y + q[lf*4+2]*kv.z + q[lf*4+3]*kv.w;
        }
        const float4* vp = (const float4*)&Vs[s * L_];
#pragma unroll
        for (int f = 0; f < 16; f++) {
            float4 vv = vp[f];
            yv[f].x += a * vv.x; yv[f].y += a * vv.y;
            yv[f].z += a * vv.z; yv[f].w += a * vv.w;
        }
    }

    const size_t ybase = ((size_t)(b * T_ + c * CHUNK + t)) * D_ + h * L_;
#pragma unroll
    for (int f = 0; f < 16; f++) {
        float4 v = yv[f];
        __nv_bfloat16 h0 = __float2bfloat16(v.x), h1 = __float2bfloat16(v.y);
        __nv_bfloat16 h2 = __float2bfloat16(v.z), h3 = __float2bfloat16(v.w);
        __nv_bfloat16 l0 = __float2bfloat16(v.x - __bfloat162float(h0));
        __nv_bfloat16 l1 = __float2bfloat16(v.y - __bfloat162float(h1));
        __nv_bfloat16 l2 = __float2bfloat16(v.z - __bfloat162float(h2));
        __nv_bfloat16 l3 = __float2bfloat16(v.w - __bfloat162float(h3));
        __nv_bfloat162* ph = (__nv_bfloat162*)&yhi[ybase + f * 4];
        __nv_bfloat162* pl = (__nv_bfloat162*)&ylo[ybase + f * 4];
        ph[0] = __halves2bfloat162(h0, h1); ph[1] = __halves2bfloat162(h2, h3);
        pl[0] = __halves2bfloat162(l0, l1); pl[1] = __halves2bfloat162(l2, l3);
    }
}

// ---------------------------------------------------------------------------
extern "C" void kernel_launch(void* const* d_in, const int* in_sizes, int n_in,
                              void* d_out, int out_size)
{
    const float* x  = (const float*)d_in[0];   // (4,2048,1024)
    const float* w  = (const float*)d_in[1];   // (3072,1024)
    const float* wo = (const float*)d_in[2];   // (1024,1024)
    float* out = (float*)d_out;                // (4,2048,1024)

    float *qkv, *Sc, *ks;
    __nv_bfloat16 *xhi, *xlo, *whi, *wlo, *wothi, *wotlo, *yhi, *ylo;
    cudaGetSymbolAddress((void**)&qkv, g_qkv);
    cudaGetSymbolAddress((void**)&Sc,  g_Sc);
    cudaGetSymbolAddress((void**)&ks,  g_ks);
    cudaGetSymbolAddress((void**)&xhi, g_xhi);
    cudaGetSymbolAddress((void**)&xlo, g_xlo);
    cudaGetSymbolAddress((void**)&whi, g_whi);
    cudaGetSymbolAddress((void**)&wlo, g_wlo);
    cudaGetSymbolAddress((void**)&wothi, g_wothi);
    cudaGetSymbolAddress((void**)&wotlo, g_wotlo);
    cudaGetSymbolAddress((void**)&yhi, g_yhi);
    cudaGetSymbolAddress((void**)&ylo, g_ylo);

    cudaFuncSetAttribute(gemm_mma,
                         cudaFuncAttributeMaxDynamicSharedMemorySize, GT_SMEM_TOTAL);
    cudaFuncSetAttribute(chunkstate_kernel,
                         cudaFuncAttributeMaxDynamicSharedMemorySize, 65536);
    cudaFuncSetAttribute(attn_kernel,
                         cudaFuncAttributeMaxDynamicSharedMemorySize, 114688);

    // 0) split inputs into bf16 hi/lo
    split_kernel<<<(BT_ * D_ / 4 + 255) / 256, 256>>>(x, xhi, xlo, BT_ * D_ / 4);
    split_kernel<<<(3 * D_ * D_ / 4 + 255) / 256, 256>>>(w, whi, wlo, 3 * D_ * D_ / 4);
    split_transpose_kernel<<<dim3(D_ / 32, D_ / 32), dim3(32, 8)>>>(wo, wothi, wotlo);

    // 1) qkv = x @ w^T   (M=8192, N=3072, K=1024) on tensor cores (HMMA)
    gemm_mma<<<dim3(3 * D_ / 128, BT_ / 128), 256, GT_SMEM_TOTAL>>>(
        xhi, xlo, whi, wlo, qkv, 3 * D_, D_);
    // 2) softmax(q), exp(k)+1e-6 in place
    prep_kernel<<<BT_, 512>>>(qkv);
    // 3) per-chunk states + k sums
    chunkstate_kernel<<<dim3(NC, BH_), 256, 65536>>>(qkv, Sc, ks);
    // 4) exclusive prefix over chunks
    prefix_kernel<<<dim3(BH_, 16), 256>>>(Sc, ks);
    // 5) chunk attention -> y (bf16 split)
    attn_kernel<<<dim3(NC, BH_), 128, 114688>>>(qkv, Sc, ks, yhi, ylo);
    // 6) out = y @ w_out  (M=8192, N=1024, K=1024), B = w_out^T pre-split
    gemm_mma<<<dim3(D_ / 128, BT_ / 128), 256, GT_SMEM_TOTAL>>>(
        yhi, ylo, wothi, wotlo, out, D_, D_);
}

// round 8
// speedup vs baseline: 1.1957x; 1.0243x over previous
#include <cuda_runtime.h>
#include <cuda_bf16.h>
#include <cstdint>

// Problem constants
#define B_   4
#define T_   2048
#define D_   1024
#define H_   16
#define L_   64
#define BT_  (B_*T_)        // 8192
#define BH_  (B_*H_)        // 64
#define CHUNK 64
#define NC   (T_/CHUNK)     // 32

// ---------------------------------------------------------------------------
// Scratch (device globals; no allocation allowed)
// ---------------------------------------------------------------------------
__device__ float g_qkv[(size_t)BT_ * 3 * D_];        // (8192, 3072)  qs|k_exp|v fp32
__device__ float g_Sc [(size_t)BH_ * NC * L_ * L_];  // chunk states -> excl prefix
__device__ float g_ks [(size_t)BH_ * NC * L_];       // chunk k-sums -> excl prefix
__device__ __nv_bfloat16 g_xhi[(size_t)BT_ * D_];
__device__ __nv_bfloat16 g_xlo[(size_t)BT_ * D_];
__device__ __nv_bfloat16 g_whi[(size_t)3 * D_ * D_];
__device__ __nv_bfloat16 g_wlo[(size_t)3 * D_ * D_];
__device__ __nv_bfloat16 g_wothi[(size_t)D_ * D_];   // w_out^T
__device__ __nv_bfloat16 g_wotlo[(size_t)D_ * D_];
__device__ __nv_bfloat16 g_yhi[(size_t)BT_ * D_];
__device__ __nv_bfloat16 g_ylo[(size_t)BT_ * D_];

// ---------------------------------------------------------------------------
// PTX helpers (baseline sm_80+ instructions only — harness targets plain sm_103)
// ---------------------------------------------------------------------------
__device__ __forceinline__ uint32_t smem_u32(const void* p) {
    uint32_t a;
    asm("{ .reg .u64 t; cvta.to.shared.u64 t, %1; cvt.u32.u64 %0, t; }" : "=r"(a) : "l"(p));
    return a;
}

__device__ __forceinline__ void cp_async16(uint32_t dst, const void* src) {
    asm volatile("cp.async.cg.shared.global [%0], [%1], 16;" :: "r"(dst), "l"(src) : "memory");
}
__device__ __forceinline__ void cp_commit() {
    asm volatile("cp.async.commit_group;" ::: "memory");
}
__device__ __forceinline__ void cp_wait1() {
    asm volatile("cp.async.wait_group 1;" ::: "memory");
}

__device__ __forceinline__ void ldsm_x4(uint32_t addr, uint32_t& r0, uint32_t& r1,
                                        uint32_t& r2, uint32_t& r3) {
    asm volatile("ldmatrix.sync.aligned.m8n8.x4.shared.b16 {%0,%1,%2,%3}, [%4];"
                 : "=r"(r0), "=r"(r1), "=r"(r2), "=r"(r3) : "r"(addr));
}

__device__ __forceinline__ void mma_bf16(float* c, const uint32_t* a, const uint32_t* b) {
    asm volatile(
        "mma.sync.aligned.m16n8k16.row.col.f32.bf16.bf16.f32 "
        "{%0,%1,%2,%3}, {%4,%5,%6,%7}, {%8,%9}, {%0,%1,%2,%3};"
        : "+f"(c[0]), "+f"(c[1]), "+f"(c[2]), "+f"(c[3])
        : "r"(a[0]), "r"(a[1]), "r"(a[2]), "r"(a[3]), "r"(b[0]), "r"(b[1]));
}

// ---------------------------------------------------------------------------
// Split fp32 -> bf16 hi/lo (vectorized)
// ---------------------------------------------------------------------------
__global__ void split_kernel(const float* __restrict__ src,
                             __nv_bfloat16* __restrict__ hi,
                             __nv_bfloat16* __restrict__ lo, int n4)
{
    int i = blockIdx.x * blockDim.x + threadIdx.x;
    if (i >= n4) return;
    float4 v = ((const float4*)src)[i];
    __nv_bfloat16 h0 = __float2bfloat16(v.x), h1 = __float2bfloat16(v.y);
    __nv_bfloat16 h2 = __float2bfloat16(v.z), h3 = __float2bfloat16(v.w);
    __nv_bfloat16 l0 = __float2bfloat16(v.x - __bfloat162float(h0));
    __nv_bfloat16 l1 = __float2bfloat16(v.y - __bfloat162float(h1));
    __nv_bfloat16 l2 = __float2bfloat16(v.z - __bfloat162float(h2));
    __nv_bfloat16 l3 = __float2bfloat16(v.w - __bfloat162float(h3));
    ((__nv_bfloat162*)hi)[2 * i]     = __halves2bfloat162(h0, h1);
    ((__nv_bfloat162*)hi)[2 * i + 1] = __halves2bfloat162(h2, h3);
    ((__nv_bfloat162*)lo)[2 * i]     = __halves2bfloat162(l0, l1);
    ((__nv_bfloat162*)lo)[2 * i + 1] = __halves2bfloat162(l2, l3);
}

// Transpose + split w_out (1024x1024): dst[n][k] = split(src[k][n])
__global__ void split_transpose_kernel(const float* __restrict__ src,
                                       __nv_bfloat16* __restrict__ hi,
                                       __nv_bfloat16* __restrict__ lo)
{
    __shared__ float tile[32][33];
    int n0 = blockIdx.x * 32, k0 = blockIdx.y * 32;
    int tx = threadIdx.x, ty = threadIdx.y;
    for (int r = ty; r < 32; r += 8)
        tile[r][tx] = src[(size_t)(k0 + r) * D_ + n0 + tx];
    __syncthreads();
    for (int r = ty; r < 32; r += 8) {
        float v = tile[tx][r];   // src[k0+tx][n0+r] -> dst[n0+r][k0+tx]
        __nv_bfloat16 h = __float2bfloat16(v);
        size_t idx = (size_t)(n0 + r) * D_ + k0 + tx;
        hi[idx] = h;
        lo[idx] = __float2bfloat16(v - __bfloat162float(h));
    }
}

// ---------------------------------------------------------------------------
// HMMA bf16 split GEMM: C[M,N] = A*B^T fp32 via 3-term bf16 split.
// 128x128 block tile, BK=64, 256 threads (8 warps, 4x2), warp tile 32x64.
// 3-stage cp.async pipeline. MODE=1: fused qkv epilogue —
//   cols [0,1024): per-head softmax(v*0.125) (head == the warp's 64-col span),
//   cols [1024,2048): exp(v*0.125)+1e-6, cols [2048,3072): passthrough.
// MODE=0: plain store.
// ---------------------------------------------------------------------------
#define GT_TILE_BYTES  16384           // 128 rows x 128B (64 bf16)
#define GT_STAGE_BYTES (4 * GT_TILE_BYTES)   // Ahi, Alo, Bhi, Blo = 65536
#define GT_SMEM_TOTAL  (3 * GT_STAGE_BYTES)  // 196608

template<int MODE>
__global__ void __launch_bounds__(256, 1)
gemm_mma(const __nv_bfloat16* __restrict__ Ahi, const __nv_bfloat16* __restrict__ Alo,
         const __nv_bfloat16* __restrict__ Bhi, const __nv_bfloat16* __restrict__ Blo,
         float* __restrict__ C, int N, int K)
{
    extern __shared__ char smem[];
    const uint32_t smem_base = smem_u32(smem);
    const int tid = threadIdx.x;
    const int wid = tid >> 5, lane = tid & 31;
    const int m0 = blockIdx.y * 128, n0 = blockIdx.x * 128;
    const int wm = (wid & 3) * 32;          // warp row offset within tile
    const int wn = (wid >> 2) * 64;         // warp col offset within tile

    const __nv_bfloat16* srcs[4] = { Ahi, Alo, Bhi, Blo };

    auto load_stage = [&](int kt, int s) {
        const int k0 = kt << 6;
#pragma unroll
        for (int tI = 0; tI < 4; tI++) {
            const __nv_bfloat16* src = srcs[tI];
            const int rb = (tI < 2) ? m0 : n0;
            const uint32_t tb = smem_base + s * GT_STAGE_BYTES + tI * GT_TILE_BYTES;
#pragma unroll
            for (int ii = 0; ii < 4; ii++) {
                int j = tid + ii * 256;
                int r = j >> 3, c = j & 7;
                const void* g = &src[(size_t)(rb + r) * K + k0 + c * 8];
                uint32_t d = tb + (uint32_t)(r * 128 + ((c ^ (r & 7)) << 4));
                cp_async16(d, g);
            }
        }
    };

    float acc[2][8][4];
#pragma unroll
    for (int mt = 0; mt < 2; mt++)
#pragma unroll
        for (int nt = 0; nt < 8; nt++)
#pragma unroll
            for (int e = 0; e < 4; e++) acc[mt][nt][e] = 0.f;

    const int NKT = K >> 6;   // 16
    load_stage(0, 0); cp_commit();
    load_stage(1, 1); cp_commit();

    const int a_row = (lane & 15);
    const int a_khalf = lane >> 4;
    const int b_grp = (lane >> 4) & 1;
    const int b_khalf = (lane >> 3) & 1;
    const int b_row = lane & 7;

    int s = 0;        // stage of current kt (cycles 0,1,2)
    int sload = 2;    // stage for kt+2
    for (int kt = 0; kt < NKT; kt++) {
        const uint32_t st = smem_base + s * GT_STAGE_BYTES;
        cp_wait1();
        __syncthreads();

        if (kt + 2 < NKT) load_stage(kt + 2, sload);
        cp_commit();

        const uint32_t aA = st;
        const uint32_t aB = st + 2 * GT_TILE_BYTES;

#pragma unroll
        for (int kk = 0; kk < 4; kk++) {
            uint32_t ah[2][4], al[2][4];
#pragma unroll
            for (int mt = 0; mt < 2; mt++) {
                int row = wm + mt * 16 + a_row;
                int chunk = 2 * kk + a_khalf;
                uint32_t off = (uint32_t)(row * 128 + ((chunk ^ (row & 7)) << 4));
                ldsm_x4(aA + off, ah[mt][0], ah[mt][1], ah[mt][2], ah[mt][3]);
                ldsm_x4(aA + GT_TILE_BYTES + off, al[mt][0], al[mt][1], al[mt][2], al[mt][3]);
            }
            uint32_t bh[4][4], bl[4][4];
#pragma unroll
            for (int np = 0; np < 4; np++) {
                int row = wn + np * 16 + b_grp * 8 + b_row;
                int chunk = 2 * kk + b_khalf;
                uint32_t off = (uint32_t)(row * 128 + ((chunk ^ (row & 7)) << 4));
                ldsm_x4(aB + off, bh[np][0], bh[np][1], bh[np][2], bh[np][3]);
                ldsm_x4(aB + GT_TILE_BYTES + off, bl[np][0], bl[np][1], bl[np][2], bl[np][3]);
            }
#pragma unroll
            for (int p = 0; p < 3; p++) {
#pragma unroll
                for (int mt = 0; mt < 2; mt++) {
                    const uint32_t* af = (p == 2) ? al[mt] : ah[mt];
#pragma unroll
                    for (int nt = 0; nt < 8; nt++) {
                        const uint32_t* bf = (p == 1) ? &bl[nt >> 1][(nt & 1) * 2]
                                                      : &bh[nt >> 1][(nt & 1) * 2];
                        mma_bf16(acc[mt][nt], af, bf);
                    }
                }
            }
        }
        s = (s == 2) ? 0 : s + 1;
        sload = (sload == 2) ? 0 : sload + 1;
    }

    // Epilogue. Thread owns, per mt: rows (g, g+8), 16 cols each (nt*8+2tig, +1).
    const int g = lane >> 2, tig = lane & 3;
    const int gcol0 = n0 + wn;      // warp's 64-col span (one full head in MODE 1)

    if (MODE == 1 && gcol0 < D_) {
        // q region: softmax over the head's 64 cols (quad shfl reduction).
#pragma unroll
        for (int mt = 0; mt < 2; mt++) {
            float vA[16], vB[16];
#pragma unroll
            for (int nt = 0; nt < 8; nt++) {
                vA[2*nt]   = acc[mt][nt][0] * 0.125f;
                vA[2*nt+1] = acc[mt][nt][1] * 0.125f;
                vB[2*nt]   = acc[mt][nt][2] * 0.125f;
                vB[2*nt+1] = acc[mt][nt][3] * 0.125f;
            }
            float mA = vA[0], mB = vB[0];
#pragma unroll
            for (int i = 1; i < 16; i++) { mA = fmaxf(mA, vA[i]); mB = fmaxf(mB, vB[i]); }
            mA = fmaxf(mA, __shfl_xor_sync(0xffffffffu, mA, 1));
            mA = fmaxf(mA, __shfl_xor_sync(0xffffffffu, mA, 2));
            mB = fmaxf(mB, __shfl_xor_sync(0xffffffffu, mB, 1));
            mB = fmaxf(mB, __shfl_xor_sync(0xffffffffu, mB, 2));
            float sA = 0.f, sB = 0.f;
#pragma unroll
            for (int i = 0; i < 16; i++) {
                vA[i] = expf(vA[i] - mA); sA += vA[i];
                vB[i] = expf(vB[i] - mB); sB += vB[i];
            }
            sA += __shfl_xor_sync(0xffffffffu, sA, 1);
            sA += __shfl_xor_sync(0xffffffffu, sA, 2);
            sB += __shfl_xor_sync(0xffffffffu, sB, 1);
            sB += __shfl_xor_sync(0xffffffffu, sB, 2);
            float iA = 1.f / sA, iB = 1.f / sB;
            int row = m0 + wm + mt * 16 + g;
#pragma unroll
            for (int nt = 0; nt < 8; nt++) {
                int col = gcol0 + nt * 8 + 2 * tig;
                *(float2*)&C[(size_t)row * N + col]       = make_float2(vA[2*nt]*iA, vA[2*nt+1]*iA);
                *(float2*)&C[(size_t)(row + 8) * N + col] = make_float2(vB[2*nt]*iB, vB[2*nt+1]*iB);
            }
        }
    } else if (MODE == 1 && gcol0 < 2 * D_) {
        // k region: exp(v*0.125)+1e-6
#pragma unroll
        for (int mt = 0; mt < 2; mt++) {
            int row = m0 + wm + mt * 16 + g;
#pragma unroll
            for (int nt = 0; nt < 8; nt++) {
                int col = gcol0 + nt * 8 + 2 * tig;
                float* c = acc[mt][nt];
                *(float2*)&C[(size_t)row * N + col] =
                    make_float2(expf(c[0]*0.125f)+1e-6f, expf(c[1]*0.125f)+1e-6f);
                *(float2*)&C[(size_t)(row + 8) * N + col] =
                    make_float2(expf(c[2]*0.125f)+1e-6f, expf(c[3]*0.125f)+1e-6f);
            }
        }
    } else {
        // v region / MODE 0: plain store
#pragma unroll
        for (int mt = 0; mt < 2; mt++) {
            int row = m0 + wm + mt * 16 + g;
#pragma unroll
            for (int nt = 0; nt < 8; nt++) {
                int col = gcol0 + nt * 8 + 2 * tig;
                float* c = acc[mt][nt];
                *(float2*)&C[(size_t)row * N + col]       = make_float2(c[0], c[1]);
                *(float2*)&C[(size_t)(row + 8) * N + col] = make_float2(c[2], c[3]);
            }
        }
    }
}

// ---------------------------------------------------------------------------
// Per-chunk state (CHUNK=64): S_c[l][m] = sum_t K[t][l]*V[t][m]; ksum_c[l].
// grid (NC, BH), 256 threads, 32KB smem.
// ---------------------------------------------------------------------------
__global__ void __launch_bounds__(256)
chunkstate_kernel(const float* __restrict__ qkv,
                  float* __restrict__ Sc, float* __restrict__ ks)
{
    extern __shared__ float sm[];
    float* Ks = sm;            // 64*64
    float* Vs = sm + CHUNK * L_;
    const int c = blockIdx.x, bh = blockIdx.y;
    const int b = bh >> 4, h = bh & 15;
    const size_t rowbase = ((size_t)(b * T_ + c * CHUNK)) * (3 * D_) + h * L_;

    for (int i = threadIdx.x; i < CHUNK * 16; i += 256) {
        int t = i >> 4, f = (i & 15) << 2;
        size_t g = rowbase + (size_t)t * (3 * D_) + f;
        *(float4*)&Ks[t * L_ + f] = *(const float4*)&qkv[g + D_];
        *(float4*)&Vs[t * L_ + f] = *(const float4*)&qkv[g + 2 * D_];
    }
    __syncthreads();

    const int l0 = (threadIdx.x >> 4) << 2;
    const int m0 = (threadIdx.x & 15) << 2;
    float acc[4][4];
#pragma unroll
    for (int i = 0; i < 4; i++)
#pragma unroll
        for (int j = 0; j < 4; j++) acc[i][j] = 0.f;
    for (int t = 0; t < CHUNK; t++) {
        float a[4], v[4];
#pragma unroll
        for (int i = 0; i < 4; i++) a[i] = Ks[t * L_ + l0 + i];
#pragma unroll
        for (int j = 0; j < 4; j++) v[j] = Vs[t * L_ + m0 + j];
#pragma unroll
        for (int i = 0; i < 4; i++)
#pragma unroll
            for (int j = 0; j < 4; j++) acc[i][j] += a[i] * v[j];
    }
    const size_t sbase = ((size_t)bh * NC + c) * (L_ * L_);
#pragma unroll
    for (int i = 0; i < 4; i++)
#pragma unroll
        for (int j = 0; j < 4; j++)
            Sc[sbase + (size_t)(l0 + i) * L_ + m0 + j] = acc[i][j];

    if (threadIdx.x < L_) {
        float s = 0.f;
        for (int t = 0; t < CHUNK; t++) s += Ks[t * L_ + threadIdx.x];
        ks[((size_t)bh * NC + c) * L_ + threadIdx.x] = s;
    }
}

// ---------------------------------------------------------------------------
// Exclusive prefix over chunks, in place. grid (BH, 16) x 256.
// ---------------------------------------------------------------------------
__global__ void prefix_kernel(float* __restrict__ Sc, float* __restrict__ ks)
{
    const int bh = blockIdx.x;
    const int e = blockIdx.y * 256 + threadIdx.x;   // 0..4095
    const size_t base = (size_t)bh * NC * (L_ * L_);
    {
        float acc = 0.f;
#pragma unroll
        for (int c = 0; c < NC; c++) {
            size_t idx = base + (size_t)c * (L_ * L_) + e;
            float tmp = Sc[idx];
            Sc[idx] = acc;
            acc += tmp;
        }
    }
    if (blockIdx.y == 0 && threadIdx.x < L_) {
        const size_t kb = (size_t)bh * NC * L_;
        float acc = 0.f;
#pragma unroll
        for (int c = 0; c < NC; c++) {
            size_t idx = kb + (size_t)c * L_ + threadIdx.x;
            float tmp = ks[idx];
            ks[idx] = acc;
            acc += tmp;
        }
    }
}

// ---------------------------------------------------------------------------
// Chunk attention (CHUNK=64): Y = qs @ S_prev + causal(qs @ K^T) @ V.
// 64 threads (thread = row t), 64KB smem -> 3 blocks/SM.
// ---------------------------------------------------------------------------
__global__ void __launch_bounds__(64)
attn_kernel(const float* __restrict__ qkv, const float* __restrict__ Sprev,
            const float* __restrict__ kpre,
            __nv_bfloat16* __restrict__ yhi, __nv_bfloat16* __restrict__ ylo)
{
    extern __shared__ float sm[];
    float* Qs = sm;                  // 64*64
    float* Ks = sm + 4096;           // 64*64
    float* Vs = sm + 8192;           // 64*64
    float* Sp = sm + 12288;          // 64*64
    const int c = blockIdx.x, bh = blockIdx.y;
    const int b = bh >> 4, h = bh & 15;
    const int tid = threadIdx.x;
    const size_t rowbase = ((size_t)(b * T_ + c * CHUNK)) * (3 * D_) + h * L_;

    for (int i = tid; i < CHUNK * 16; i += 64) {
        int t = i >> 4, f = (i & 15) << 2;
        size_t g = rowbase + (size_t)t * (3 * D_) + f;
        *(float4*)&Qs[t * L_ + f] = *(const float4*)&qkv[g];
        *(float4*)&Ks[t * L_ + f] = *(const float4*)&qkv[g + D_];
        *(float4*)&Vs[t * L_ + f] = *(const float4*)&qkv[g + 2 * D_];
    }
    const size_t sbase = ((size_t)bh * NC + c) * (L_ * L_);
    for (int i = tid; i < (L_ * L_) / 4; i += 64)
        *(float4*)&Sp[i * 4] = *(const float4*)&Sprev[sbase + i * 4];
    __syncthreads();

    // normalize: qs[t][l] = q[t][l] / (kpre[l] + cumsum_{s<=t} K[s][l]); thread = l
    {
        const int l = tid;
        float acc = kpre[((size_t)bh * NC + c) * L_ + l];
        for (int t = 0; t < CHUNK; t++) {
            acc += Ks[t * L_ + l];
            Qs[t * L_ + l] = __fdividef(Qs[t * L_ + l], acc);
        }
    }
    __syncthreads();

    const int t = tid;
    float q[L_];
#pragma unroll
    for (int l = 0; l < L_; l++) q[l] = Qs[t * L_ + l];

    float4 yv[16];
#pragma unroll
    for (int f = 0; f < 16; f++) yv[f] = make_float4(0.f, 0.f, 0.f, 0.f);

    // inter-chunk: qs @ S_prev
#pragma unroll
    for (int l = 0; l < L_; l++) {
        float ql = q[l];
        const float4* sp = (const float4*)&Sp[l * L_];
#pragma unroll
        for (int f = 0; f < 16; f++) {
            float4 s = sp[f];
            yv[f].x += ql * s.x; yv[f].y += ql * s.y;
            yv[f].z += ql * s.z; yv[f].w += ql * s.w;
        }
    }

    // intra-chunk causal (inclusive)
    for (int s = 0; s <= t; s++) {
        const float4* kp = (const float4*)&Ks[s * L_];
        float a = 0.f;
#pragma unroll
        for (int lf = 0; lf < 16; lf++) {
            float4 kv = kp[lf];
            a += q[lf*4+0]*kv.x + q[lf*4+1]*kv.y + q[lf*4+2]*kv.z + q[lf*4+3]*kv.w;
        }
        const float4* vp = (const float4*)&Vs[s * L_];
#pragma unroll
        for (int f = 0; f < 16; f++) {
            float4 vv = vp[f];
            yv[f].x += a * vv.x; yv[f].y += a * vv.y;
            yv[f].z += a * vv.z; yv[f].w += a * vv.w;
        }
    }

    const size_t ybase = ((size_t)(b * T_ + c * CHUNK + t)) * D_ + h * L_;
#pragma unroll
    for (int f = 0; f < 16; f++) {
        float4 v = yv[f];
        __nv_bfloat16 h0 = __float2bfloat16(v.x), h1 = __float2bfloat16(v.y);
        __nv_bfloat16 h2 = __float2bfloat16(v.z), h3 = __float2bfloat16(v.w);
        __nv_bfloat16 l0 = __float2bfloat16(v.x - __bfloat162float(h0));
        __nv_bfloat16 l1 = __float2bfloat16(v.y - __bfloat162float(h1));
        __nv_bfloat16 l2 = __float2bfloat16(v.z - __bfloat162float(h2));
        __nv_bfloat16 l3 = __float2bfloat16(v.w - __bfloat162float(h3));
        __nv_bfloat162* ph = (__nv_bfloat162*)&yhi[ybase + f * 4];
        __nv_bfloat162* pl = (__nv_bfloat162*)&ylo[ybase + f * 4];
        ph[0] = __halves2bfloat162(h0, h1); ph[1] = __halves2bfloat162(h2, h3);
        pl[0] = __halves2bfloat162(l0, l1); pl[1] = __halves2bfloat162(l2, l3);
    }
}

// ---------------------------------------------------------------------------
extern "C" void kernel_launch(void* const* d_in, const int* in_sizes, int n_in,
                              void* d_out, int out_size)
{
    const float* x  = (const float*)d_in[0];   // (4,2048,1024)
    const float* w  = (const float*)d_in[1];   // (3072,1024)
    const float* wo = (const float*)d_in[2];   // (1024,1024)
    float* out = (float*)d_out;                // (4,2048,1024)

    float *qkv, *Sc, *ks;
    __nv_bfloat16 *xhi, *xlo, *whi, *wlo, *wothi, *wotlo, *yhi, *ylo;
    cudaGetSymbolAddress((void**)&qkv, g_qkv);
    cudaGetSymbolAddress((void**)&Sc,  g_Sc);
    cudaGetSymbolAddress((void**)&ks,  g_ks);
    cudaGetSymbolAddress((void**)&xhi, g_xhi);
    cudaGetSymbolAddress((void**)&xlo, g_xlo);
    cudaGetSymbolAddress((void**)&whi, g_whi);
    cudaGetSymbolAddress((void**)&wlo, g_wlo);
    cudaGetSymbolAddress((void**)&wothi, g_wothi);
    cudaGetSymbolAddress((void**)&wotlo, g_wotlo);
    cudaGetSymbolAddress((void**)&yhi, g_yhi);
    cudaGetSymbolAddress((void**)&ylo, g_ylo);

    cudaFuncSetAttribute(gemm_mma<0>,
                         cudaFuncAttributeMaxDynamicSharedMemorySize, GT_SMEM_TOTAL);
    cudaFuncSetAttribute(gemm_mma<1>,
                         cudaFuncAttributeMaxDynamicSharedMemorySize, GT_SMEM_TOTAL);
    cudaFuncSetAttribute(attn_kernel,
                         cudaFuncAttributeMaxDynamicSharedMemorySize, 65536);

    // 0) split inputs into bf16 hi/lo
    split_kernel<<<(BT_ * D_ / 4 + 255) / 256, 256>>>(x, xhi, xlo, BT_ * D_ / 4);
    split_kernel<<<(3 * D_ * D_ / 4 + 255) / 256, 256>>>(w, whi, wlo, 3 * D_ * D_ / 4);
    split_transpose_kernel<<<dim3(D_ / 32, D_ / 32), dim3(32, 8)>>>(wo, wothi, wotlo);

    // 1) qkv = x @ w^T with FUSED softmax(q)/exp(k) epilogue
    gemm_mma<1><<<dim3(3 * D_ / 128, BT_ / 128), 256, GT_SMEM_TOTAL>>>(
        xhi, xlo, whi, wlo, qkv, 3 * D_, D_);
    // 2) per-chunk states + k sums (CHUNK=64)
    chunkstate_kernel<<<dim3(NC, BH_), 256, 32768>>>(qkv, Sc, ks);
    // 3) exclusive prefix over chunks
    prefix_kernel<<<dim3(BH_, 16), 256>>>(Sc, ks);
    // 4) chunk attention -> y (bf16 split)
    attn_kernel<<<dim3(NC, BH_), 64, 65536>>>(qkv, Sc, ks, yhi, ylo);
    // 5) out = y @ w_out
    gemm_mma<0><<<dim3(D_ / 128, BT_ / 128), 256, GT_SMEM_TOTAL>>>(
        yhi, ylo, wothi, wotlo, out, D_, D_);
}

// round 9
// speedup vs baseline: 1.2625x; 1.0558x over previous
#include <cuda_runtime.h>
#include <cuda_bf16.h>
#include <cstdint>

// Problem constants
#define B_   4
#define T_   2048
#define D_   1024
#define H_   16
#define L_   64
#define BT_  (B_*T_)        // 8192
#define BH_  (B_*H_)        // 64
#define CHUNK 64
#define NC   (T_/CHUNK)     // 32

// ---------------------------------------------------------------------------
// Scratch (device globals; no allocation allowed)
// ---------------------------------------------------------------------------
__device__ float g_qkv[(size_t)BT_ * 3 * D_];        // (8192, 3072)  qs|k_exp|v fp32
__device__ float g_Sc [(size_t)BH_ * NC * L_ * L_];  // chunk states -> excl prefix
__device__ float g_ks [(size_t)BH_ * NC * L_];       // chunk k-sums -> excl prefix
__device__ __nv_bfloat16 g_xhi[(size_t)BT_ * D_];
__device__ __nv_bfloat16 g_xlo[(size_t)BT_ * D_];
__device__ __nv_bfloat16 g_whi[(size_t)3 * D_ * D_];
__device__ __nv_bfloat16 g_wlo[(size_t)3 * D_ * D_];
__device__ __nv_bfloat16 g_wothi[(size_t)D_ * D_];   // w_out^T
__device__ __nv_bfloat16 g_wotlo[(size_t)D_ * D_];
__device__ __nv_bfloat16 g_yhi[(size_t)BT_ * D_];
__device__ __nv_bfloat16 g_ylo[(size_t)BT_ * D_];

// ---------------------------------------------------------------------------
// PTX helpers (baseline sm_80+ instructions only — harness targets plain sm_103)
// ---------------------------------------------------------------------------
__device__ __forceinline__ uint32_t smem_u32(const void* p) {
    uint32_t a;
    asm("{ .reg .u64 t; cvta.to.shared.u64 t, %1; cvt.u32.u64 %0, t; }" : "=r"(a) : "l"(p));
    return a;
}

__device__ __forceinline__ void cp_async16(uint32_t dst, const void* src) {
    asm volatile("cp.async.cg.shared.global [%0], [%1], 16;" :: "r"(dst), "l"(src) : "memory");
}
__device__ __forceinline__ void cp_commit() {
    asm volatile("cp.async.commit_group;" ::: "memory");
}
__device__ __forceinline__ void cp_wait1() {
    asm volatile("cp.async.wait_group 1;" ::: "memory");
}

__device__ __forceinline__ void ldsm_x4(uint32_t addr, uint32_t& r0, uint32_t& r1,
                                        uint32_t& r2, uint32_t& r3) {
    asm volatile("ldmatrix.sync.aligned.m8n8.x4.shared.b16 {%0,%1,%2,%3}, [%4];"
                 : "=r"(r0), "=r"(r1), "=r"(r2), "=r"(r3) : "r"(addr));
}

__device__ __forceinline__ void mma_bf16(float* c, const uint32_t* a, const uint32_t* b) {
    asm volatile(
        "mma.sync.aligned.m16n8k16.row.col.f32.bf16.bf16.f32 "
        "{%0,%1,%2,%3}, {%4,%5,%6,%7}, {%8,%9}, {%0,%1,%2,%3};"
        : "+f"(c[0]), "+f"(c[1]), "+f"(c[2]), "+f"(c[3])
        : "r"(a[0]), "r"(a[1]), "r"(a[2]), "r"(a[3]), "r"(b[0]), "r"(b[1]));
}

// ---------------------------------------------------------------------------
// ONE fused input-prep kernel (3 launch -> 1):
//   blocks [0, NBX)            : split x           (float4 grain)
//   blocks [NBX, NBX+NBW)      : split w
//   blocks [NBX+NBW, +1024)    : transpose+split w_out (32x32 tiles)
// ---------------------------------------------------------------------------
#define NBX (BT_ * D_ / 4 / 256)          // 8192
#define NBW (3 * D_ * D_ / 4 / 256)       // 3072

__global__ void __launch_bounds__(256)
prep_inputs_kernel(const float* __restrict__ x, const float* __restrict__ w,
                   const float* __restrict__ wo)
{
    const int bid = blockIdx.x;
    if (bid < NBX + NBW) {
        const float* src;
        __nv_bfloat16 *hi, *lo;
        int i;
        if (bid < NBX) {
            src = x; hi = g_xhi; lo = g_xlo;
            i = bid * 256 + threadIdx.x;
        } else {
            src = w; hi = g_whi; lo = g_wlo;
            i = (bid - NBX) * 256 + threadIdx.x;
        }
        float4 v = ((const float4*)src)[i];
        __nv_bfloat16 h0 = __float2bfloat16(v.x), h1 = __float2bfloat16(v.y);
        __nv_bfloat16 h2 = __float2bfloat16(v.z), h3 = __float2bfloat16(v.w);
        __nv_bfloat16 l0 = __float2bfloat16(v.x - __bfloat162float(h0));
        __nv_bfloat16 l1 = __float2bfloat16(v.y - __bfloat162float(h1));
        __nv_bfloat16 l2 = __float2bfloat16(v.z - __bfloat162float(h2));
        __nv_bfloat16 l3 = __float2bfloat16(v.w - __bfloat162float(h3));
        ((__nv_bfloat162*)hi)[2 * i]     = __halves2bfloat162(h0, h1);
        ((__nv_bfloat162*)hi)[2 * i + 1] = __halves2bfloat162(h2, h3);
        ((__nv_bfloat162*)lo)[2 * i]     = __halves2bfloat162(l0, l1);
        ((__nv_bfloat162*)lo)[2 * i + 1] = __halves2bfloat162(l2, l3);
    } else {
        // w_out transpose+split: 1024 tile-blocks of 32x32
        __shared__ float tile[32][33];
        int tb = bid - NBX - NBW;            // 0..1023
        int n0 = (tb & 31) * 32, k0 = (tb >> 5) * 32;
        int tx = threadIdx.x & 31, ty = threadIdx.x >> 5;   // (32,8)
        for (int r = ty; r < 32; r += 8)
            tile[r][tx] = wo[(size_t)(k0 + r) * D_ + n0 + tx];
        __syncthreads();
        for (int r = ty; r < 32; r += 8) {
            float v = tile[tx][r];           // wo[k0+tx][n0+r] -> dst[n0+r][k0+tx]
            __nv_bfloat16 h = __float2bfloat16(v);
            size_t idx = (size_t)(n0 + r) * D_ + k0 + tx;
            g_wothi[idx] = h;
            g_wotlo[idx] = __float2bfloat16(v - __bfloat162float(h));
        }
    }
}

// ---------------------------------------------------------------------------
// HMMA bf16 split GEMM (unchanged from R8): 128x128 tile, BK=64, 8 warps,
// 3-stage cp.async pipeline. MODE=1 fuses softmax(q)/exp(k) epilogue.
// ---------------------------------------------------------------------------
#define GT_TILE_BYTES  16384           // 128 rows x 128B (64 bf16)
#define GT_STAGE_BYTES (4 * GT_TILE_BYTES)   // Ahi, Alo, Bhi, Blo = 65536
#define GT_SMEM_TOTAL  (3 * GT_STAGE_BYTES)  // 196608

template<int MODE>
__global__ void __launch_bounds__(256, 1)
gemm_mma(const __nv_bfloat16* __restrict__ Ahi, const __nv_bfloat16* __restrict__ Alo,
         const __nv_bfloat16* __restrict__ Bhi, const __nv_bfloat16* __restrict__ Blo,
         float* __restrict__ C, int N, int K)
{
    extern __shared__ char smem[];
    const uint32_t smem_base = smem_u32(smem);
    const int tid = threadIdx.x;
    const int wid = tid >> 5, lane = tid & 31;
    const int m0 = blockIdx.y * 128, n0 = blockIdx.x * 128;
    const int wm = (wid & 3) * 32;
    const int wn = (wid >> 2) * 64;

    const __nv_bfloat16* srcs[4] = { Ahi, Alo, Bhi, Blo };

    auto load_stage = [&](int kt, int s) {
        const int k0 = kt << 6;
#pragma unroll
        for (int tI = 0; tI < 4; tI++) {
            const __nv_bfloat16* src = srcs[tI];
            const int rb = (tI < 2) ? m0 : n0;
            const uint32_t tb = smem_base + s * GT_STAGE_BYTES + tI * GT_TILE_BYTES;
#pragma unroll
            for (int ii = 0; ii < 4; ii++) {
                int j = tid + ii * 256;
                int r = j >> 3, c = j & 7;
                const void* g = &src[(size_t)(rb + r) * K + k0 + c * 8];
                uint32_t d = tb + (uint32_t)(r * 128 + ((c ^ (r & 7)) << 4));
                cp_async16(d, g);
            }
        }
    };

    float acc[2][8][4];
#pragma unroll
    for (int mt = 0; mt < 2; mt++)
#pragma unroll
        for (int nt = 0; nt < 8; nt++)
#pragma unroll
            for (int e = 0; e < 4; e++) acc[mt][nt][e] = 0.f;

    const int NKT = K >> 6;   // 16
    load_stage(0, 0); cp_commit();
    load_stage(1, 1); cp_commit();

    const int a_row = (lane & 15);
    const int a_khalf = lane >> 4;
    const int b_grp = (lane >> 4) & 1;
    const int b_khalf = (lane >> 3) & 1;
    const int b_row = lane & 7;

    int s = 0, sload = 2;
    for (int kt = 0; kt < NKT; kt++) {
        const uint32_t st = smem_base + s * GT_STAGE_BYTES;
        cp_wait1();
        __syncthreads();

        if (kt + 2 < NKT) load_stage(kt + 2, sload);
        cp_commit();

        const uint32_t aA = st;
        const uint32_t aB = st + 2 * GT_TILE_BYTES;

#pragma unroll
        for (int kk = 0; kk < 4; kk++) {
            uint32_t ah[2][4], al[2][4];
#pragma unroll
            for (int mt = 0; mt < 2; mt++) {
                int row = wm + mt * 16 + a_row;
                int chunk = 2 * kk + a_khalf;
                uint32_t off = (uint32_t)(row * 128 + ((chunk ^ (row & 7)) << 4));
                ldsm_x4(aA + off, ah[mt][0], ah[mt][1], ah[mt][2], ah[mt][3]);
                ldsm_x4(aA + GT_TILE_BYTES + off, al[mt][0], al[mt][1], al[mt][2], al[mt][3]);
            }
            uint32_t bh[4][4], bl[4][4];
#pragma unroll
            for (int np = 0; np < 4; np++) {
                int row = wn + np * 16 + b_grp * 8 + b_row;
                int chunk = 2 * kk + b_khalf;
                uint32_t off = (uint32_t)(row * 128 + ((chunk ^ (row & 7)) << 4));
                ldsm_x4(aB + off, bh[np][0], bh[np][1], bh[np][2], bh[np][3]);
                ldsm_x4(aB + GT_TILE_BYTES + off, bl[np][0], bl[np][1], bl[np][2], bl[np][3]);
            }
#pragma unroll
            for (int p = 0; p < 3; p++) {
#pragma unroll
                for (int mt = 0; mt < 2; mt++) {
                    const uint32_t* af = (p == 2) ? al[mt] : ah[mt];
#pragma unroll
                    for (int nt = 0; nt < 8; nt++) {
                        const uint32_t* bf = (p == 1) ? &bl[nt >> 1][(nt & 1) * 2]
                                                      : &bh[nt >> 1][(nt & 1) * 2];
                        mma_bf16(acc[mt][nt], af, bf);
                    }
                }
            }
        }
        s = (s == 2) ? 0 : s + 1;
        sload = (sload == 2) ? 0 : sload + 1;
    }

    const int g = lane >> 2, tig = lane & 3;
    const int gcol0 = n0 + wn;

    if (MODE == 1 && gcol0 < D_) {
#pragma unroll
        for (int mt = 0; mt < 2; mt++) {
            float vA[16], vB[16];
#pragma unroll
            for (int nt = 0; nt < 8; nt++) {
                vA[2*nt]   = acc[mt][nt][0] * 0.125f;
                vA[2*nt+1] = acc[mt][nt][1] * 0.125f;
                vB[2*nt]   = acc[mt][nt][2] * 0.125f;
                vB[2*nt+1] = acc[mt][nt][3] * 0.125f;
            }
            float mA = vA[0], mB = vB[0];
#pragma unroll
            for (int i = 1; i < 16; i++) { mA = fmaxf(mA, vA[i]); mB = fmaxf(mB, vB[i]); }
            mA = fmaxf(mA, __shfl_xor_sync(0xffffffffu, mA, 1));
            mA = fmaxf(mA, __shfl_xor_sync(0xffffffffu, mA, 2));
            mB = fmaxf(mB, __shfl_xor_sync(0xffffffffu, mB, 1));
            mB = fmaxf(mB, __shfl_xor_sync(0xffffffffu, mB, 2));
            float sA = 0.f, sB = 0.f;
#pragma unroll
            for (int i = 0; i < 16; i++) {
                vA[i] = expf(vA[i] - mA); sA += vA[i];
                vB[i] = expf(vB[i] - mB); sB += vB[i];
            }
            sA += __shfl_xor_sync(0xffffffffu, sA, 1);
            sA += __shfl_xor_sync(0xffffffffu, sA, 2);
            sB += __shfl_xor_sync(0xffffffffu, sB, 1);
            sB += __shfl_xor_sync(0xffffffffu, sB, 2);
            float iA = 1.f / sA, iB = 1.f / sB;
            int row = m0 + wm + mt * 16 + g;
#pragma unroll
            for (int nt = 0; nt < 8; nt++) {
                int col = gcol0 + nt * 8 + 2 * tig;
                *(float2*)&C[(size_t)row * N + col]       = make_float2(vA[2*nt]*iA, vA[2*nt+1]*iA);
                *(float2*)&C[(size_t)(row + 8) * N + col] = make_float2(vB[2*nt]*iB, vB[2*nt+1]*iB);
            }
        }
    } else if (MODE == 1 && gcol0 < 2 * D_) {
#pragma unroll
        for (int mt = 0; mt < 2; mt++) {
            int row = m0 + wm + mt * 16 + g;
#pragma unroll
            for (int nt = 0; nt < 8; nt++) {
                int col = gcol0 + nt * 8 + 2 * tig;
                float* c = acc[mt][nt];
                *(float2*)&C[(size_t)row * N + col] =
                    make_float2(expf(c[0]*0.125f)+1e-6f, expf(c[1]*0.125f)+1e-6f);
                *(float2*)&C[(size_t)(row + 8) * N + col] =
                    make_float2(expf(c[2]*0.125f)+1e-6f, expf(c[3]*0.125f)+1e-6f);
            }
        }
    } else {
#pragma unroll
        for (int mt = 0; mt < 2; mt++) {
            int row = m0 + wm + mt * 16 + g;
#pragma unroll
            for (int nt = 0; nt < 8; nt++) {
                int col = gcol0 + nt * 8 + 2 * tig;
                float* c = acc[mt][nt];
                *(float2*)&C[(size_t)row * N + col]       = make_float2(c[0], c[1]);
                *(float2*)&C[(size_t)(row + 8) * N + col] = make_float2(c[2], c[3]);
            }
        }
    }
}

// ---------------------------------------------------------------------------
// Per-chunk state (CHUNK=64): S_c[l][m] = sum_t K[t][l]*V[t][m]; ksum_c[l].
// ---------------------------------------------------------------------------
__global__ void __launch_bounds__(256)
chunkstate_kernel(const float* __restrict__ qkv,
                  float* __restrict__ Sc, float* __restrict__ ks)
{
    extern __shared__ float sm[];
    float* Ks = sm;            // 64*64
    float* Vs = sm + CHUNK * L_;
    const int c = blockIdx.x, bh = blockIdx.y;
    const int b = bh >> 4, h = bh & 15;
    const size_t rowbase = ((size_t)(b * T_ + c * CHUNK)) * (3 * D_) + h * L_;

    for (int i = threadIdx.x; i < CHUNK * 16; i += 256) {
        int t = i >> 4, f = (i & 15) << 2;
        size_t g = rowbase + (size_t)t * (3 * D_) + f;
        *(float4*)&Ks[t * L_ + f] = *(const float4*)&qkv[g + D_];
        *(float4*)&Vs[t * L_ + f] = *(const float4*)&qkv[g + 2 * D_];
    }
    __syncthreads();

    const int l0 = (threadIdx.x >> 4) << 2;
    const int m0 = (threadIdx.x & 15) << 2;
    float acc[4][4];
#pragma unroll
    for (int i = 0; i < 4; i++)
#pragma unroll
        for (int j = 0; j < 4; j++) acc[i][j] = 0.f;
    for (int t = 0; t < CHUNK; t++) {
        float a[4], v[4];
#pragma unroll
        for (int i = 0; i < 4; i++) a[i] = Ks[t * L_ + l0 + i];
#pragma unroll
        for (int j = 0; j < 4; j++) v[j] = Vs[t * L_ + m0 + j];
#pragma unroll
        for (int i = 0; i < 4; i++)
#pragma unroll
            for (int j = 0; j < 4; j++) acc[i][j] += a[i] * v[j];
    }
    const size_t sbase = ((size_t)bh * NC + c) * (L_ * L_);
#pragma unroll
    for (int i = 0; i < 4; i++)
#pragma unroll
        for (int j = 0; j < 4; j++)
            Sc[sbase + (size_t)(l0 + i) * L_ + m0 + j] = acc[i][j];

    if (threadIdx.x < L_) {
        float s = 0.f;
        for (int t = 0; t < CHUNK; t++) s += Ks[t * L_ + threadIdx.x];
        ks[((size_t)bh * NC + c) * L_ + threadIdx.x] = s;
    }
}

// ---------------------------------------------------------------------------
// Exclusive prefix over chunks, in place. grid (BH, 16) x 256.
// ---------------------------------------------------------------------------
__global__ void prefix_kernel(float* __restrict__ Sc, float* __restrict__ ks)
{
    const int bh = blockIdx.x;
    const int e = blockIdx.y * 256 + threadIdx.x;   // 0..4095
    const size_t base = (size_t)bh * NC * (L_ * L_);
    {
        float acc = 0.f;
#pragma unroll
        for (int c = 0; c < NC; c++) {
            size_t idx = base + (size_t)c * (L_ * L_) + e;
            float tmp = Sc[idx];
            Sc[idx] = acc;
            acc += tmp;
        }
    }
    if (blockIdx.y == 0 && threadIdx.x < L_) {
        const size_t kb = (size_t)bh * NC * L_;
        float acc = 0.f;
#pragma unroll
        for (int c = 0; c < NC; c++) {
            size_t idx = kb + (size_t)c * L_ + threadIdx.x;
            float tmp = ks[idx];
            ks[idx] = acc;
            acc += tmp;
        }
    }
}

// ---------------------------------------------------------------------------
// Chunk attention (CHUNK=64): Y = qs @ S_prev + causal(qs @ K^T) @ V.
// 128 threads: thread=(half, t). Each half computes cols [half*32, +32).
// Dot product uses 4 partial accumulators (chain 64 -> 16 FMAs).
// 64KB smem -> 3 blocks/SM, 12 warps.
// ---------------------------------------------------------------------------
__global__ void __launch_bounds__(128)
attn_kernel(const float* __restrict__ qkv, const float* __restrict__ Sprev,
            const float* __restrict__ kpre,
            __nv_bfloat16* __restrict__ yhi, __nv_bfloat16* __restrict__ ylo)
{
    extern __shared__ float sm[];
    float* Qs = sm;                  // 64*64
    float* Ks = sm + 4096;           // 64*64
    float* Vs = sm + 8192;           // 64*64
    float* Sp = sm + 12288;          // 64*64
    const int c = blockIdx.x, bh = blockIdx.y;
    const int b = bh >> 4, h = bh & 15;
    const int tid = threadIdx.x;
    const int t = tid & 63, half = tid >> 6;
    const size_t rowbase = ((size_t)(b * T_ + c * CHUNK)) * (3 * D_) + h * L_;

    for (int i = tid; i < CHUNK * 16; i += 128) {
        int tt = i >> 4, f = (i & 15) << 2;
        size_t g = rowbase + (size_t)tt * (3 * D_) + f;
        *(float4*)&Qs[tt * L_ + f] = *(const float4*)&qkv[g];
        *(float4*)&Ks[tt * L_ + f] = *(const float4*)&qkv[g + D_];
        *(float4*)&Vs[tt * L_ + f] = *(const float4*)&qkv[g + 2 * D_];
    }
    const size_t sbase = ((size_t)bh * NC + c) * (L_ * L_);
    for (int i = tid; i < (L_ * L_) / 4; i += 128)
        *(float4*)&Sp[i * 4] = *(const float4*)&Sprev[sbase + i * 4];
    __syncthreads();

    // normalize: qs[t][l] = q[t][l] / (kpre[l] + cumsum_{s<=t} K[s][l]); thread = l
    if (tid < L_) {
        const int l = tid;
        float acc = kpre[((size_t)bh * NC + c) * L_ + l];
        for (int tt = 0; tt < CHUNK; tt++) {
            acc += Ks[tt * L_ + l];
            Qs[tt * L_ + l] = __fdividef(Qs[tt * L_ + l], acc);
        }
    }
    __syncthreads();

    float q[L_];
#pragma unroll
    for (int l = 0; l < L_; l++) q[l] = Qs[t * L_ + l];

    float4 yv[8];
#pragma unroll
    for (int f = 0; f < 8; f++) yv[f] = make_float4(0.f, 0.f, 0.f, 0.f);
    const int cbase = half * 8;      // float4 column offset

    // inter-chunk: qs @ S_prev (this half's 32 cols)
#pragma unroll
    for (int l = 0; l < L_; l++) {
        float ql = q[l];
        const float4* sp = (const float4*)&Sp[l * L_] + cbase;
#pragma unroll
        for (int f = 0; f < 8; f++) {
            float4 s = sp[f];
            yv[f].x += ql * s.x; yv[f].y += ql * s.y;
            yv[f].z += ql * s.z; yv[f].w += ql * s.w;
        }
    }

    // intra-chunk causal (inclusive); dot split into 4 partials
    for (int s = 0; s <= t; s++) {
        const float4* kp = (const float4*)&Ks[s * L_];
        float a0 = 0.f, a1 = 0.f, a2 = 0.f, a3 = 0.f;
#pragma unroll
        for (int lf = 0; lf < 16; lf++) {
            float4 kv = kp[lf];
            a0 += q[lf*4+0]*kv.x; a1 += q[lf*4+1]*kv.y;
            a2 += q[lf*4+2]*kv.z; a3 += q[lf*4+3]*kv.w;
        }
        float a = (a0 + a1) + (a2 + a3);
        const float4* vp = (const float4*)&Vs[s * L_] + cbase;
#pragma unroll
        for (int f = 0; f < 8; f++) {
            float4 vv = vp[f];
            yv[f].x += a * vv.x; yv[f].y += a * vv.y;
            yv[f].z += a * vv.z; yv[f].w += a * vv.w;
        }
    }

    const size_t ybase = ((size_t)(b * T_ + c * CHUNK + t)) * D_ + h * L_ + half * 32;
#pragma unroll
    for (int f = 0; f < 8; f++) {
        float4 v = yv[f];
        __nv_bfloat16 h0 = __float2bfloat16(v.x), h1 = __float2bfloat16(v.y);
        __nv_bfloat16 h2 = __float2bfloat16(v.z), h3 = __float2bfloat16(v.w);
        __nv_bfloat16 l0 = __float2bfloat16(v.x - __bfloat162float(h0));
        __nv_bfloat16 l1 = __float2bfloat16(v.y - __bfloat162float(h1));
        __nv_bfloat16 l2 = __float2bfloat16(v.z - __bfloat162float(h2));
        __nv_bfloat16 l3 = __float2bfloat16(v.w - __bfloat162float(h3));
        __nv_bfloat162* ph = (__nv_bfloat162*)&yhi[ybase + f * 4];
        __nv_bfloat162* pl = (__nv_bfloat162*)&ylo[ybase + f * 4];
        ph[0] = __halves2bfloat162(h0, h1); ph[1] = __halves2bfloat162(h2, h3);
        pl[0] = __halves2bfloat162(l0, l1); pl[1] = __halves2bfloat162(l2, l3);
    }
}

// ---------------------------------------------------------------------------
extern "C" void kernel_launch(void* const* d_in, const int* in_sizes, int n_in,
                              void* d_out, int out_size)
{
    const float* x  = (const float*)d_in[0];   // (4,2048,1024)
    const float* w  = (const float*)d_in[1];   // (3072,1024)
    const float* wo = (const float*)d_in[2];   // (1024,1024)
    float* out = (float*)d_out;                // (4,2048,1024)

    float *qkv, *Sc, *ks;
    __nv_bfloat16 *xhi, *xlo, *whi, *wlo, *wothi, *wotlo, *yhi, *ylo;
    cudaGetSymbolAddress((void**)&qkv, g_qkv);
    cudaGetSymbolAddress((void**)&Sc,  g_Sc);
    cudaGetSymbolAddress((void**)&ks,  g_ks);
    cudaGetSymbolAddress((void**)&xhi, g_xhi);
    cudaGetSymbolAddress((void**)&xlo, g_xlo);
    cudaGetSymbolAddress((void**)&whi, g_whi);
    cudaGetSymbolAddress((void**)&wlo, g_wlo);
    cudaGetSymbolAddress((void**)&wothi, g_wothi);
    cudaGetSymbolAddress((void**)&wotlo, g_wotlo);
    cudaGetSymbolAddress((void**)&yhi, g_yhi);
    cudaGetSymbolAddress((void**)&ylo, g_ylo);

    cudaFuncSetAttribute(gemm_mma<0>,
                         cudaFuncAttributeMaxDynamicSharedMemorySize, GT_SMEM_TOTAL);
    cudaFuncSetAttribute(gemm_mma<1>,
                         cudaFuncAttributeMaxDynamicSharedMemorySize, GT_SMEM_TOTAL);
    cudaFuncSetAttribute(attn_kernel,
                         cudaFuncAttributeMaxDynamicSharedMemorySize, 65536);

    // 0) fused split of x, w, w_out^T (one launch)
    prep_inputs_kernel<<<NBX + NBW + 1024, 256>>>(x, w, wo);
    // 1) qkv = x @ w^T with FUSED softmax(q)/exp(k) epilogue
    gemm_mma<1><<<dim3(3 * D_ / 128, BT_ / 128), 256, GT_SMEM_TOTAL>>>(
        xhi, xlo, whi, wlo, qkv, 3 * D_, D_);
    // 2) per-chunk states + k sums (CHUNK=64)
    chunkstate_kernel<<<dim3(NC, BH_), 256, 32768>>>(qkv, Sc, ks);
    // 3) exclusive prefix over chunks
    prefix_kernel<<<dim3(BH_, 16), 256>>>(Sc, ks);
    // 4) chunk attention -> y (bf16 split)
    attn_kernel<<<dim3(NC, BH_), 128, 65536>>>(qkv, Sc, ks, yhi, ylo);
    // 5) out = y @ w_out
    gemm_mma<0><<<dim3(D_ / 128, BT_ / 128), 256, GT_SMEM_TOTAL>>>(
        yhi, ylo, wothi, wotlo, out, D_, D_);
}

// round 10
// speedup vs baseline: 1.3268x; 1.0510x over previous
#include <cuda_runtime.h>
#include <cuda_bf16.h>
#include <cstdint>

// Problem constants
#define B_   4
#define T_   2048
#define D_   1024
#define H_   16
#define L_   64
#define BT_  (B_*T_)        // 8192
#define BH_  (B_*H_)        // 64
#define CHUNK 64
#define NC   (T_/CHUNK)     // 32

// ---------------------------------------------------------------------------
// Scratch (device globals; no allocation allowed)
// ---------------------------------------------------------------------------
__device__ float g_qkv[(size_t)BT_ * 3 * D_];        // (8192, 3072)  qs|k_exp|v fp32
__device__ float g_Sc [(size_t)BH_ * NC * L_ * L_];  // chunk states -> excl prefix
__device__ float g_ks [(size_t)BH_ * NC * L_];       // chunk k-sums -> excl prefix
__device__ __nv_bfloat16 g_xhi[(size_t)BT_ * D_];
__device__ __nv_bfloat16 g_xlo[(size_t)BT_ * D_];
__device__ __nv_bfloat16 g_whi[(size_t)3 * D_ * D_];
__device__ __nv_bfloat16 g_wlo[(size_t)3 * D_ * D_];
__device__ __nv_bfloat16 g_wothi[(size_t)D_ * D_];   // w_out^T
__device__ __nv_bfloat16 g_wotlo[(size_t)D_ * D_];
__device__ __nv_bfloat16 g_yhi[(size_t)BT_ * D_];
__device__ __nv_bfloat16 g_ylo[(size_t)BT_ * D_];

// ---------------------------------------------------------------------------
// PTX helpers (baseline sm_80+ instructions only — harness targets plain sm_103)
// ---------------------------------------------------------------------------
__device__ __forceinline__ uint32_t smem_u32(const void* p) {
    uint32_t a;
    asm("{ .reg .u64 t; cvta.to.shared.u64 t, %1; cvt.u32.u64 %0, t; }" : "=r"(a) : "l"(p));
    return a;
}

__device__ __forceinline__ void cp_async16(uint32_t dst, const void* src) {
    asm volatile("cp.async.cg.shared.global [%0], [%1], 16;" :: "r"(dst), "l"(src) : "memory");
}
__device__ __forceinline__ void cp_commit() {
    asm volatile("cp.async.commit_group;" ::: "memory");
}
__device__ __forceinline__ void cp_wait1() {
    asm volatile("cp.async.wait_group 1;" ::: "memory");
}

__device__ __forceinline__ void ldsm_x4(uint32_t addr, uint32_t& r0, uint32_t& r1,
                                        uint32_t& r2, uint32_t& r3) {
    asm volatile("ldmatrix.sync.aligned.m8n8.x4.shared.b16 {%0,%1,%2,%3}, [%4];"
                 : "=r"(r0), "=r"(r1), "=r"(r2), "=r"(r3) : "r"(addr));
}

__device__ __forceinline__ void mma_bf16(float* c, const uint32_t* a, const uint32_t* b) {
    asm volatile(
        "mma.sync.aligned.m16n8k16.row.col.f32.bf16.bf16.f32 "
        "{%0,%1,%2,%3}, {%4,%5,%6,%7}, {%8,%9}, {%0,%1,%2,%3};"
        : "+f"(c[0]), "+f"(c[1]), "+f"(c[2]), "+f"(c[3])
        : "r"(a[0]), "r"(a[1]), "r"(a[2]), "r"(a[3]), "r"(b[0]), "r"(b[1]));
}

__device__ __forceinline__ void sts32(uint32_t addr, uint32_t v) {
    asm volatile("st.shared.b32 [%0], %1;" :: "r"(addr), "r"(v) : "memory");
}

// split two floats -> packed bf16x2 hi and lo words
__device__ __forceinline__ void split2(float a, float b, uint32_t& hp, uint32_t& lp) {
    __nv_bfloat16 h0 = __float2bfloat16(a), h1 = __float2bfloat16(b);
    __nv_bfloat16 l0 = __float2bfloat16(a - __bfloat162float(h0));
    __nv_bfloat16 l1 = __float2bfloat16(b - __bfloat162float(h1));
    __nv_bfloat162 hv = __halves2bfloat162(h0, h1);
    __nv_bfloat162 lv = __halves2bfloat162(l0, l1);
    hp = *(uint32_t*)&hv;
    lp = *(uint32_t*)&lv;
}

// swizzled byte address of bf16 (row, col) in a 64-row x 64-col K-major tile
__device__ __forceinline__ uint32_t sw_addr(uint32_t base, int row, int col) {
    return base + (uint32_t)(row * 128 + ((((col >> 3) ^ (row & 7))) << 4) + ((col & 7) * 2));
}

// ---------------------------------------------------------------------------
// ONE fused input-prep kernel
// ---------------------------------------------------------------------------
#define NBX (BT_ * D_ / 4 / 256)          // 8192
#define NBW (3 * D_ * D_ / 4 / 256)       // 3072

__global__ void __launch_bounds__(256)
prep_inputs_kernel(const float* __restrict__ x, const float* __restrict__ w,
                   const float* __restrict__ wo)
{
    const int bid = blockIdx.x;
    if (bid < NBX + NBW) {
        const float* src;
        __nv_bfloat16 *hi, *lo;
        int i;
        if (bid < NBX) {
            src = x; hi = g_xhi; lo = g_xlo;
            i = bid * 256 + threadIdx.x;
        } else {
            src = w; hi = g_whi; lo = g_wlo;
            i = (bid - NBX) * 256 + threadIdx.x;
        }
        float4 v = ((const float4*)src)[i];
        uint32_t h01, l01, h23, l23;
        split2(v.x, v.y, h01, l01);
        split2(v.z, v.w, h23, l23);
        ((uint32_t*)hi)[2 * i]     = h01;
        ((uint32_t*)hi)[2 * i + 1] = h23;
        ((uint32_t*)lo)[2 * i]     = l01;
        ((uint32_t*)lo)[2 * i + 1] = l23;
    } else {
        __shared__ float tile[32][33];
        int tb = bid - NBX - NBW;            // 0..1023
        int n0 = (tb & 31) * 32, k0 = (tb >> 5) * 32;
        int tx = threadIdx.x & 31, ty = threadIdx.x >> 5;   // (32,8)
        for (int r = ty; r < 32; r += 8)
            tile[r][tx] = wo[(size_t)(k0 + r) * D_ + n0 + tx];
        __syncthreads();
        for (int r = ty; r < 32; r += 8) {
            float v = tile[tx][r];
            __nv_bfloat16 h = __float2bfloat16(v);
            size_t idx = (size_t)(n0 + r) * D_ + k0 + tx;
            g_wothi[idx] = h;
            g_wotlo[idx] = __float2bfloat16(v - __bfloat162float(h));
        }
    }
}

// ---------------------------------------------------------------------------
// HMMA bf16 split GEMM (unchanged): 128x128 tile, BK=64, 8 warps,
// 3-stage cp.async pipeline. MODE=1 fuses softmax(q)/exp(k) epilogue.
// ---------------------------------------------------------------------------
#define GT_TILE_BYTES  16384
#define GT_STAGE_BYTES (4 * GT_TILE_BYTES)
#define GT_SMEM_TOTAL  (3 * GT_STAGE_BYTES)

template<int MODE>
__global__ void __launch_bounds__(256, 1)
gemm_mma(const __nv_bfloat16* __restrict__ Ahi, const __nv_bfloat16* __restrict__ Alo,
         const __nv_bfloat16* __restrict__ Bhi, const __nv_bfloat16* __restrict__ Blo,
         float* __restrict__ C, int N, int K)
{
    extern __shared__ char smem[];
    const uint32_t smem_base = smem_u32(smem);
    const int tid = threadIdx.x;
    const int wid = tid >> 5, lane = tid & 31;
    const int m0 = blockIdx.y * 128, n0 = blockIdx.x * 128;
    const int wm = (wid & 3) * 32;
    const int wn = (wid >> 2) * 64;

    const __nv_bfloat16* srcs[4] = { Ahi, Alo, Bhi, Blo };

    auto load_stage = [&](int kt, int s) {
        const int k0 = kt << 6;
#pragma unroll
        for (int tI = 0; tI < 4; tI++) {
            const __nv_bfloat16* src = srcs[tI];
            const int rb = (tI < 2) ? m0 : n0;
            const uint32_t tb = smem_base + s * GT_STAGE_BYTES + tI * GT_TILE_BYTES;
#pragma unroll
            for (int ii = 0; ii < 4; ii++) {
                int j = tid + ii * 256;
                int r = j >> 3, c = j & 7;
                const void* g = &src[(size_t)(rb + r) * K + k0 + c * 8];
                uint32_t d = tb + (uint32_t)(r * 128 + ((c ^ (r & 7)) << 4));
                cp_async16(d, g);
            }
        }
    };

    float acc[2][8][4];
#pragma unroll
    for (int mt = 0; mt < 2; mt++)
#pragma unroll
        for (int nt = 0; nt < 8; nt++)
#pragma unroll
            for (int e = 0; e < 4; e++) acc[mt][nt][e] = 0.f;

    const int NKT = K >> 6;
    load_stage(0, 0); cp_commit();
    load_stage(1, 1); cp_commit();

    const int a_row = (lane & 15);
    const int a_khalf = lane >> 4;
    const int b_grp = (lane >> 4) & 1;
    const int b_khalf = (lane >> 3) & 1;
    const int b_row = lane & 7;

    int s = 0, sload = 2;
    for (int kt = 0; kt < NKT; kt++) {
        const uint32_t st = smem_base + s * GT_STAGE_BYTES;
        cp_wait1();
        __syncthreads();

        if (kt + 2 < NKT) load_stage(kt + 2, sload);
        cp_commit();

        const uint32_t aA = st;
        const uint32_t aB = st + 2 * GT_TILE_BYTES;

#pragma unroll
        for (int kk = 0; kk < 4; kk++) {
            uint32_t ah[2][4], al[2][4];
#pragma unroll
            for (int mt = 0; mt < 2; mt++) {
                int row = wm + mt * 16 + a_row;
                int chunk = 2 * kk + a_khalf;
                uint32_t off = (uint32_t)(row * 128 + ((chunk ^ (row & 7)) << 4));
                ldsm_x4(aA + off, ah[mt][0], ah[mt][1], ah[mt][2], ah[mt][3]);
                ldsm_x4(aA + GT_TILE_BYTES + off, al[mt][0], al[mt][1], al[mt][2], al[mt][3]);
            }
            uint32_t bh[4][4], bl[4][4];
#pragma unroll
            for (int np = 0; np < 4; np++) {
                int row = wn + np * 16 + b_grp * 8 + b_row;
                int chunk = 2 * kk + b_khalf;
                uint32_t off = (uint32_t)(row * 128 + ((chunk ^ (row & 7)) << 4));
                ldsm_x4(aB + off, bh[np][0], bh[np][1], bh[np][2], bh[np][3]);
                ldsm_x4(aB + GT_TILE_BYTES + off, bl[np][0], bl[np][1], bl[np][2], bl[np][3]);
            }
#pragma unroll
            for (int p = 0; p < 3; p++) {
#pragma unroll
                for (int mt = 0; mt < 2; mt++) {
                    const uint32_t* af = (p == 2) ? al[mt] : ah[mt];
#pragma unroll
                    for (int nt = 0; nt < 8; nt++) {
                        const uint32_t* bf = (p == 1) ? &bl[nt >> 1][(nt & 1) * 2]
                                                      : &bh[nt >> 1][(nt & 1) * 2];
                        mma_bf16(acc[mt][nt], af, bf);
                    }
                }
            }
        }
        s = (s == 2) ? 0 : s + 1;
        sload = (sload == 2) ? 0 : sload + 1;
    }

    const int g = lane >> 2, tig = lane & 3;
    const int gcol0 = n0 + wn;

    if (MODE == 1 && gcol0 < D_) {
#pragma unroll
        for (int mt = 0; mt < 2; mt++) {
            float vA[16], vB[16];
#pragma unroll
            for (int nt = 0; nt < 8; nt++) {
                vA[2*nt]   = acc[mt][nt][0] * 0.125f;
                vA[2*nt+1] = acc[mt][nt][1] * 0.125f;
                vB[2*nt]   = acc[mt][nt][2] * 0.125f;
                vB[2*nt+1] = acc[mt][nt][3] * 0.125f;
            }
            float mA = vA[0], mB = vB[0];
#pragma unroll
            for (int i = 1; i < 16; i++) { mA = fmaxf(mA, vA[i]); mB = fmaxf(mB, vB[i]); }
            mA = fmaxf(mA, __shfl_xor_sync(0xffffffffu, mA, 1));
            mA = fmaxf(mA, __shfl_xor_sync(0xffffffffu, mA, 2));
            mB = fmaxf(mB, __shfl_xor_sync(0xffffffffu, mB, 1));
            mB = fmaxf(mB, __shfl_xor_sync(0xffffffffu, mB, 2));
            float sA = 0.f, sB = 0.f;
#pragma unroll
            for (int i = 0; i < 16; i++) {
                vA[i] = expf(vA[i] - mA); sA += vA[i];
                vB[i] = expf(vB[i] - mB); sB += vB[i];
            }
            sA += __shfl_xor_sync(0xffffffffu, sA, 1);
            sA += __shfl_xor_sync(0xffffffffu, sA, 2);
            sB += __shfl_xor_sync(0xffffffffu, sB, 1);
            sB += __shfl_xor_sync(0xffffffffu, sB, 2);
            float iA = 1.f / sA, iB = 1.f / sB;
            int row = m0 + wm + mt * 16 + g;
#pragma unroll
            for (int nt = 0; nt < 8; nt++) {
                int col = gcol0 + nt * 8 + 2 * tig;
                *(float2*)&C[(size_t)row * N + col]       = make_float2(vA[2*nt]*iA, vA[2*nt+1]*iA);
                *(float2*)&C[(size_t)(row + 8) * N + col] = make_float2(vB[2*nt]*iB, vB[2*nt+1]*iB);
            }
        }
    } else if (MODE == 1 && gcol0 < 2 * D_) {
#pragma unroll
        for (int mt = 0; mt < 2; mt++) {
            int row = m0 + wm + mt * 16 + g;
#pragma unroll
            for (int nt = 0; nt < 8; nt++) {
                int col = gcol0 + nt * 8 + 2 * tig;
                float* c = acc[mt][nt];
                *(float2*)&C[(size_t)row * N + col] =
                    make_float2(expf(c[0]*0.125f)+1e-6f, expf(c[1]*0.125f)+1e-6f);
                *(float2*)&C[(size_t)(row + 8) * N + col] =
                    make_float2(expf(c[2]*0.125f)+1e-6f, expf(c[3]*0.125f)+1e-6f);
            }
        }
    } else {
#pragma unroll
        for (int mt = 0; mt < 2; mt++) {
            int row = m0 + wm + mt * 16 + g;
#pragma unroll
            for (int nt = 0; nt < 8; nt++) {
                int col = gcol0 + nt * 8 + 2 * tig;
                float* c = acc[mt][nt];
                *(float2*)&C[(size_t)row * N + col]       = make_float2(c[0], c[1]);
                *(float2*)&C[(size_t)(row + 8) * N + col] = make_float2(c[2], c[3]);
            }
        }
    }
}

// ---------------------------------------------------------------------------
// Per-chunk state (CHUNK=64) — unchanged
// ---------------------------------------------------------------------------
__global__ void __launch_bounds__(256)
chunkstate_kernel(const float* __restrict__ qkv,
                  float* __restrict__ Sc, float* __restrict__ ks)
{
    extern __shared__ float sm[];
    float* Ks = sm;
    float* Vs = sm + CHUNK * L_;
    const int c = blockIdx.x, bh = blockIdx.y;
    const int b = bh >> 4, h = bh & 15;
    const size_t rowbase = ((size_t)(b * T_ + c * CHUNK)) * (3 * D_) + h * L_;

    for (int i = threadIdx.x; i < CHUNK * 16; i += 256) {
        int t = i >> 4, f = (i & 15) << 2;
        size_t g = rowbase + (size_t)t * (3 * D_) + f;
        *(float4*)&Ks[t * L_ + f] = *(const float4*)&qkv[g + D_];
        *(float4*)&Vs[t * L_ + f] = *(const float4*)&qkv[g + 2 * D_];
    }
    __syncthreads();

    const int l0 = (threadIdx.x >> 4) << 2;
    const int m0 = (threadIdx.x & 15) << 2;
    float acc[4][4];
#pragma unroll
    for (int i = 0; i < 4; i++)
#pragma unroll
        for (int j = 0; j < 4; j++) acc[i][j] = 0.f;
    for (int t = 0; t < CHUNK; t++) {
        float a[4], v[4];
#pragma unroll
        for (int i = 0; i < 4; i++) a[i] = Ks[t * L_ + l0 + i];
#pragma unroll
        for (int j = 0; j < 4; j++) v[j] = Vs[t * L_ + m0 + j];
#pragma unroll
        for (int i = 0; i < 4; i++)
#pragma unroll
            for (int j = 0; j < 4; j++) acc[i][j] += a[i] * v[j];
    }
    const size_t sbase = ((size_t)bh * NC + c) * (L_ * L_);
#pragma unroll
    for (int i = 0; i < 4; i++)
#pragma unroll
        for (int j = 0; j < 4; j++)
            Sc[sbase + (size_t)(l0 + i) * L_ + m0 + j] = acc[i][j];

    if (threadIdx.x < L_) {
        float s = 0.f;
        for (int t = 0; t < CHUNK; t++) s += Ks[t * L_ + threadIdx.x];
        ks[((size_t)bh * NC + c) * L_ + threadIdx.x] = s;
    }
}

// ---------------------------------------------------------------------------
// Exclusive prefix over chunks — unchanged
// ---------------------------------------------------------------------------
__global__ void prefix_kernel(float* __restrict__ Sc, float* __restrict__ ks)
{
    const int bh = blockIdx.x;
    const int e = blockIdx.y * 256 + threadIdx.x;
    const size_t base = (size_t)bh * NC * (L_ * L_);
    {
        float acc = 0.f;
#pragma unroll
        for (int c = 0; c < NC; c++) {
            size_t idx = base + (size_t)c * (L_ * L_) + e;
            float tmp = Sc[idx];
            Sc[idx] = acc;
            acc += tmp;
        }
    }
    if (blockIdx.y == 0 && threadIdx.x < L_) {
        const size_t kb = (size_t)bh * NC * L_;
        float acc = 0.f;
#pragma unroll
        for (int c = 0; c < NC; c++) {
            size_t idx = kb + (size_t)c * L_ + threadIdx.x;
            float tmp = ks[idx];
            ks[idx] = acc;
            acc += tmp;
        }
    }
}

// ---------------------------------------------------------------------------
// Tensor-core chunk attention (CHUNK=64, 128 threads = 4 warps):
//   P = causal(qs_norm @ K^T)     (64x64x64, bf16 3-pass split, fp32 acc)
//   Y = P @ V + qs_norm @ S_prev  (64x64x128 concatenated, same machinery)
// All operands converted to swizzled bf16 hi/lo tiles in smem.
// smem map (bytes):
//   [0:16384)      qsf fp32            -> later PH [0:8192) PL [8192:16384)
//   [16384:32768)  kf fp32
//   [32768:49152)  vf fp32             -> later STH [32768:40960) STL [40960:49152)
//   [49152:65536)  spf fp32 (S_prev)
//   [65536:73728)  QH   [73728:81920)  QL
//   [81920:90112)  KH   [90112:98304)  KL
//   [98304:106496) VTH  [106496:114688) VTL
// ---------------------------------------------------------------------------
#define AT_SMEM 114688

__global__ void __launch_bounds__(128)
attn_kernel(const float* __restrict__ qkv, const float* __restrict__ Sprev,
            const float* __restrict__ kpre,
            __nv_bfloat16* __restrict__ yhi, __nv_bfloat16* __restrict__ ylo)
{
    extern __shared__ char smc[];
    float* qsf = (float*)smc;
    float* kf  = (float*)(smc + 16384);
    float* vf  = (float*)(smc + 32768);
    float* spf = (float*)(smc + 49152);
    const uint32_t sb  = smem_u32(smc);
    const uint32_t PH  = sb,           PL  = sb + 8192;
    const uint32_t STH = sb + 32768,   STL = sb + 40960;
    const uint32_t QH  = sb + 65536,   QL  = sb + 73728;
    const uint32_t KH  = sb + 81920,   KL  = sb + 90112;
    const uint32_t VTH = sb + 98304,   VTL = sb + 106496;

    const int c = blockIdx.x, bh = blockIdx.y;
    const int b = bh >> 4, h = bh & 15;
    const int tid = threadIdx.x;
    const int wid = tid >> 5, lane = tid & 31;
    const size_t rowbase = ((size_t)(b * T_ + c * CHUNK)) * (3 * D_) + h * L_;

    // -- load fp32 tiles --
    for (int i = tid; i < CHUNK * 16; i += 128) {
        int t = i >> 4, f = (i & 15) << 2;
        size_t g = rowbase + (size_t)t * (3 * D_) + f;
        *(float4*)&qsf[t * L_ + f] = *(const float4*)&qkv[g];
        *(float4*)&kf [t * L_ + f] = *(const float4*)&qkv[g + D_];
        *(float4*)&vf [t * L_ + f] = *(const float4*)&qkv[g + 2 * D_];
    }
    const size_t sbase = ((size_t)bh * NC + c) * (L_ * L_);
    for (int i = tid; i < (L_ * L_) / 4; i += 128)
        *(float4*)&spf[i * 4] = *(const float4*)&Sprev[sbase + i * 4];
    __syncthreads();

    // -- normalize qs by causal k cumsum (thread = l) --
    if (tid < L_) {
        const int l = tid;
        float acc = kpre[((size_t)bh * NC + c) * L_ + l];
        for (int t = 0; t < CHUNK; t++) {
            acc += kf[t * L_ + l];
            qsf[t * L_ + l] = __fdividef(qsf[t * L_ + l], acc);
        }
    }
    __syncthreads();

    // -- convert qs, k (row,col) and v (transposed) to bf16 hi/lo tiles --
    for (int i = tid; i < 2048; i += 128) {
        int row = i >> 5, col = (i & 31) * 2;
        uint32_t hp, lp;
        // qs
        split2(qsf[row * L_ + col], qsf[row * L_ + col + 1], hp, lp);
        sts32(sw_addr(QH, row, col), hp);
        sts32(sw_addr(QL, row, col), lp);
        // k
        split2(kf[row * L_ + col], kf[row * L_ + col + 1], hp, lp);
        sts32(sw_addr(KH, row, col), hp);
        sts32(sw_addr(KL, row, col), lp);
        // v^T : dest (row=m, col=t)
        split2(vf[col * L_ + row], vf[(col + 1) * L_ + row], hp, lp);
        sts32(sw_addr(VTH, row, col), hp);
        sts32(sw_addr(VTL, row, col), lp);
    }
    __syncthreads();
    // -- convert S_prev^T into the (now dead) vf region --
    for (int i = tid; i < 2048; i += 128) {
        int row = i >> 5, col = (i & 31) * 2;   // row=m, col=l
        uint32_t hp, lp;
        split2(spf[col * L_ + row], spf[(col + 1) * L_ + row], hp, lp);
        sts32(sw_addr(STH, row, col), hp);
        sts32(sw_addr(STL, row, col), lp);
    }
    __syncthreads();

    const int wm = wid * 16;                 // 4 warps x 16 output rows
    const int a_row = (lane & 15);
    const int a_khalf = lane >> 4;
    const int b_grp = (lane >> 4) & 1;
    const int b_khalf = (lane >> 3) & 1;
    const int b_row = lane & 7;
    const int g = lane >> 2, tig = lane & 3;

    // ---- P = qs_norm @ K^T ----
    float accP[8][4];
#pragma unroll
    for (int nt = 0; nt < 8; nt++)
#pragma unroll
        for (int e = 0; e < 4; e++) accP[nt][e] = 0.f;

#pragma unroll
    for (int kk = 0; kk < 4; kk++) {
        uint32_t ah[4], al[4];
        {
            int row = wm + a_row;
            int chunk = 2 * kk + a_khalf;
            uint32_t off = (uint32_t)(row * 128 + ((chunk ^ (row & 7)) << 4));
            ldsm_x4(QH + off, ah[0], ah[1], ah[2], ah[3]);
            ldsm_x4(QL + off, al[0], al[1], al[2], al[3]);
        }
        uint32_t bh_[4][4], bl_[4][4];
#pragma unroll
        for (int np = 0; np < 4; np++) {
            int row = np * 16 + b_grp * 8 + b_row;
            int chunk = 2 * kk + b_khalf;
            uint32_t off = (uint32_t)(row * 128 + ((chunk ^ (row & 7)) << 4));
            ldsm_x4(KH + off, bh_[np][0], bh_[np][1], bh_[np][2], bh_[np][3]);
            ldsm_x4(KL + off, bl_[np][0], bl_[np][1], bl_[np][2], bl_[np][3]);
        }
#pragma unroll
        for (int p = 0; p < 3; p++) {
            const uint32_t* af = (p == 2) ? al : ah;
#pragma unroll
            for (int nt = 0; nt < 8; nt++) {
                const uint32_t* bf = (p == 1) ? &bl_[nt >> 1][(nt & 1) * 2]
                                              : &bh_[nt >> 1][(nt & 1) * 2];
                mma_bf16(accP[nt], af, bf);
            }
        }
    }

    // ---- causal mask + split-store P into smem (region A) ----
    {
        int r0 = wm + g, r1 = wm + g + 8;
#pragma unroll
        for (int nt = 0; nt < 8; nt++) {
            int colp = nt * 8 + 2 * tig;
            float p00 = (colp     <= r0) ? accP[nt][0] : 0.f;
            float p01 = (colp + 1 <= r0) ? accP[nt][1] : 0.f;
            float p10 = (colp     <= r1) ? accP[nt][2] : 0.f;
            float p11 = (colp + 1 <= r1) ? accP[nt][3] : 0.f;
            uint32_t hp, lp;
            split2(p00, p01, hp, lp);
            sts32(sw_addr(PH, r0, colp), hp);
            sts32(sw_addr(PL, r0, colp), lp);
            split2(p10, p11, hp, lp);
            sts32(sw_addr(PH, r1, colp), hp);
            sts32(sw_addr(PL, r1, colp), lp);
        }
    }
    __syncthreads();

    // ---- Y = P @ V + qs_norm @ S_prev ----
    float acc[8][4];
#pragma unroll
    for (int nt = 0; nt < 8; nt++)
#pragma unroll
        for (int e = 0; e < 4; e++) acc[nt][e] = 0.f;

#pragma unroll
    for (int half = 0; half < 2; half++) {
        const uint32_t AH = half ? QH : PH, AL = half ? QL : PL;
        const uint32_t BH = half ? STH : VTH, BL = half ? STL : VTL;
#pragma unroll
        for (int kk = 0; kk < 4; kk++) {
            uint32_t ah[4], al[4];
            {
                int row = wm + a_row;
                int chunk = 2 * kk + a_khalf;
                uint32_t off = (uint32_t)(row * 128 + ((chunk ^ (row & 7)) << 4));
                ldsm_x4(AH + off, ah[0], ah[1], ah[2], ah[3]);
                ldsm_x4(AL + off, al[0], al[1], al[2], al[3]);
            }
            uint32_t bh_[4][4], bl_[4][4];
#pragma unroll
            for (int np = 0; np < 4; np++) {
                int row = np * 16 + b_grp * 8 + b_row;
                int chunk = 2 * kk + b_khalf;
                uint32_t off = (uint32_t)(row * 128 + ((chunk ^ (row & 7)) << 4));
                ldsm_x4(BH + off, bh_[np][0], bh_[np][1], bh_[np][2], bh_[np][3]);
                ldsm_x4(BL + off, bl_[np][0], bl_[np][1], bl_[np][2], bl_[np][3]);
            }
#pragma unroll
            for (int p = 0; p < 3; p++) {
                const uint32_t* af = (p == 2) ? al : ah;
#pragma unroll
                for (int nt = 0; nt < 8; nt++) {
                    const uint32_t* bf = (p == 1) ? &bl_[nt >> 1][(nt & 1) * 2]
                                                  : &bh_[nt >> 1][(nt & 1) * 2];
                    mma_bf16(acc[nt], af, bf);
                }
            }
        }
    }

    // ---- epilogue: split y -> global bf16 hi/lo ----
    {
        int r0 = wm + g;
#pragma unroll
        for (int dr = 0; dr < 2; dr++) {
            int row = r0 + dr * 8;
            size_t ybase = ((size_t)(b * T_ + c * CHUNK + row)) * D_ + h * L_;
#pragma unroll
            for (int nt = 0; nt < 8; nt++) {
                int colp = nt * 8 + 2 * tig;
                float v0 = acc[nt][2 * dr], v1 = acc[nt][2 * dr + 1];
                uint32_t hp, lp;
                split2(v0, v1, hp, lp);
                *(uint32_t*)&yhi[ybase + colp] = hp;
                *(uint32_t*)&ylo[ybase + colp] = lp;
            }
        }
    }
}

// ---------------------------------------------------------------------------
extern "C" void kernel_launch(void* const* d_in, const int* in_sizes, int n_in,
                              void* d_out, int out_size)
{
    const float* x  = (const float*)d_in[0];
    const float* w  = (const float*)d_in[1];
    const float* wo = (const float*)d_in[2];
    float* out = (float*)d_out;

    float *qkv, *Sc, *ks;
    __nv_bfloat16 *xhi, *xlo, *whi, *wlo, *wothi, *wotlo, *yhi, *ylo;
    cudaGetSymbolAddress((void**)&qkv, g_qkv);
    cudaGetSymbolAddress((void**)&Sc,  g_Sc);
    cudaGetSymbolAddress((void**)&ks,  g_ks);
    cudaGetSymbolAddress((void**)&xhi, g_xhi);
    cudaGetSymbolAddress((void**)&xlo, g_xlo);
    cudaGetSymbolAddress((void**)&whi, g_whi);
    cudaGetSymbolAddress((void**)&wlo, g_wlo);
    cudaGetSymbolAddress((void**)&wothi, g_wothi);
    cudaGetSymbolAddress((void**)&wotlo, g_wotlo);
    cudaGetSymbolAddress((void**)&yhi, g_yhi);
    cudaGetSymbolAddress((void**)&ylo, g_ylo);

    cudaFuncSetAttribute(gemm_mma<0>,
                         cudaFuncAttributeMaxDynamicSharedMemorySize, GT_SMEM_TOTAL);
    cudaFuncSetAttribute(gemm_mma<1>,
                         cudaFuncAttributeMaxDynamicSharedMemorySize, GT_SMEM_TOTAL);
    cudaFuncSetAttribute(chunkstate_kernel,
                         cudaFuncAttributeMaxDynamicSharedMemorySize, 32768);
    cudaFuncSetAttribute(attn_kernel,
                         cudaFuncAttributeMaxDynamicSharedMemorySize, AT_SMEM);

    // 0) fused split of x, w, w_out^T
    prep_inputs_kernel<<<NBX + NBW + 1024, 256>>>(x, w, wo);
    // 1) qkv = x @ w^T with fused softmax(q)/exp(k) epilogue
    gemm_mma<1><<<dim3(3 * D_ / 128, BT_ / 128), 256, GT_SMEM_TOTAL>>>(
        xhi, xlo, whi, wlo, qkv, 3 * D_, D_);
    // 2) per-chunk states + k sums
    chunkstate_kernel<<<dim3(NC, BH_), 256, 32768>>>(qkv, Sc, ks);
    // 3) exclusive prefix over chunks
    prefix_kernel<<<dim3(BH_, 16), 256>>>(Sc, ks);
    // 4) tensor-core chunk attention -> y (bf16 split)
    attn_kernel<<<dim3(NC, BH_), 128, AT_SMEM>>>(qkv, Sc, ks, yhi, ylo);
    // 5) out = y @ w_out
    gemm_mma<0><<<dim3(D_ / 128, BT_ / 128), 256, GT_SMEM_TOTAL>>>(
        yhi, ylo, wothi, wotlo, out, D_, D_);
}

// round 11
// speedup vs baseline: 1.3541x; 1.0206x over previous
#include <cuda_runtime.h>
#include <cuda_bf16.h>
#include <cstdint>

// Problem constants
#define B_   4
#define T_   2048
#define D_   1024
#define H_   16
#define L_   64
#define BT_  (B_*T_)        // 8192
#define BH_  (B_*H_)        // 64
#define CHUNK 64
#define NC   (T_/CHUNK)     // 32

// ---------------------------------------------------------------------------
// Scratch (device globals; no allocation allowed)
// ---------------------------------------------------------------------------
__device__ float g_qkv[(size_t)BT_ * 3 * D_];        // (8192, 3072)  qs|k_exp|v fp32
__device__ float g_Sc [(size_t)BH_ * NC * L_ * L_];  // chunk states -> excl prefix
__device__ float g_ks [(size_t)BH_ * NC * L_];       // chunk k-sums -> excl prefix
__device__ __nv_bfloat16 g_xhi[(size_t)BT_ * D_];
__device__ __nv_bfloat16 g_xlo[(size_t)BT_ * D_];
__device__ __nv_bfloat16 g_whi[(size_t)3 * D_ * D_];
__device__ __nv_bfloat16 g_wlo[(size_t)3 * D_ * D_];
__device__ __nv_bfloat16 g_wothi[(size_t)D_ * D_];   // w_out^T
__device__ __nv_bfloat16 g_wotlo[(size_t)D_ * D_];
__device__ __nv_bfloat16 g_yhi[(size_t)BT_ * D_];
__device__ __nv_bfloat16 g_ylo[(size_t)BT_ * D_];

// ---------------------------------------------------------------------------
// PTX helpers (baseline sm_80+ instructions only — harness targets plain sm_103)
// ---------------------------------------------------------------------------
__device__ __forceinline__ uint32_t smem_u32(const void* p) {
    uint32_t a;
    asm("{ .reg .u64 t; cvta.to.shared.u64 t, %1; cvt.u32.u64 %0, t; }" : "=r"(a) : "l"(p));
    return a;
}

__device__ __forceinline__ void cp_async16(uint32_t dst, const void* src) {
    asm volatile("cp.async.cg.shared.global [%0], [%1], 16;" :: "r"(dst), "l"(src) : "memory");
}
__device__ __forceinline__ void cp_commit() {
    asm volatile("cp.async.commit_group;" ::: "memory");
}
__device__ __forceinline__ void cp_wait1() {
    asm volatile("cp.async.wait_group 1;" ::: "memory");
}

__device__ __forceinline__ void ldsm_x4(uint32_t addr, uint32_t& r0, uint32_t& r1,
                                        uint32_t& r2, uint32_t& r3) {
    asm volatile("ldmatrix.sync.aligned.m8n8.x4.shared.b16 {%0,%1,%2,%3}, [%4];"
                 : "=r"(r0), "=r"(r1), "=r"(r2), "=r"(r3) : "r"(addr));
}

__device__ __forceinline__ void mma_bf16(float* c, const uint32_t* a, const uint32_t* b) {
    asm volatile(
        "mma.sync.aligned.m16n8k16.row.col.f32.bf16.bf16.f32 "
        "{%0,%1,%2,%3}, {%4,%5,%6,%7}, {%8,%9}, {%0,%1,%2,%3};"
        : "+f"(c[0]), "+f"(c[1]), "+f"(c[2]), "+f"(c[3])
        : "r"(a[0]), "r"(a[1]), "r"(a[2]), "r"(a[3]), "r"(b[0]), "r"(b[1]));
}

__device__ __forceinline__ void sts32(uint32_t addr, uint32_t v) {
    asm volatile("st.shared.b32 [%0], %1;" :: "r"(addr), "r"(v) : "memory");
}

__device__ __forceinline__ float lds_bf16(uint32_t addr) {
    uint16_t v;
    asm volatile("ld.shared.u16 %0, [%1];" : "=h"(v) : "r"(addr));
    __nv_bfloat16 b = *(__nv_bfloat16*)&v;
    return __bfloat162float(b);
}

// split two floats -> packed bf16x2 hi and lo words
__device__ __forceinline__ void split2(float a, float b, uint32_t& hp, uint32_t& lp) {
    __nv_bfloat16 h0 = __float2bfloat16(a), h1 = __float2bfloat16(b);
    __nv_bfloat16 l0 = __float2bfloat16(a - __bfloat162float(h0));
    __nv_bfloat16 l1 = __float2bfloat16(b - __bfloat162float(h1));
    __nv_bfloat162 hv = __halves2bfloat162(h0, h1);
    __nv_bfloat162 lv = __halves2bfloat162(l0, l1);
    hp = *(uint32_t*)&hv;
    lp = *(uint32_t*)&lv;
}

// swizzled byte address of bf16 (row, col) in a 64-row x 64-col K-major tile
__device__ __forceinline__ uint32_t sw_addr(uint32_t base, int row, int col) {
    return base + (uint32_t)(row * 128 + ((((col >> 3) ^ (row & 7))) << 4) + ((col & 7) * 2));
}

// ---------------------------------------------------------------------------
// ONE fused input-prep kernel
// ---------------------------------------------------------------------------
#define NBX (BT_ * D_ / 4 / 256)          // 8192
#define NBW (3 * D_ * D_ / 4 / 256)       // 3072

__global__ void __launch_bounds__(256)
prep_inputs_kernel(const float* __restrict__ x, const float* __restrict__ w,
                   const float* __restrict__ wo)
{
    const int bid = blockIdx.x;
    if (bid < NBX + NBW) {
        const float* src;
        __nv_bfloat16 *hi, *lo;
        int i;
        if (bid < NBX) {
            src = x; hi = g_xhi; lo = g_xlo;
            i = bid * 256 + threadIdx.x;
        } else {
            src = w; hi = g_whi; lo = g_wlo;
            i = (bid - NBX) * 256 + threadIdx.x;
        }
        float4 v = ((const float4*)src)[i];
        uint32_t h01, l01, h23, l23;
        split2(v.x, v.y, h01, l01);
        split2(v.z, v.w, h23, l23);
        ((uint32_t*)hi)[2 * i]     = h01;
        ((uint32_t*)hi)[2 * i + 1] = h23;
        ((uint32_t*)lo)[2 * i]     = l01;
        ((uint32_t*)lo)[2 * i + 1] = l23;
    } else {
        __shared__ float tile[32][33];
        int tb = bid - NBX - NBW;            // 0..1023
        int n0 = (tb & 31) * 32, k0 = (tb >> 5) * 32;
        int tx = threadIdx.x & 31, ty = threadIdx.x >> 5;   // (32,8)
        for (int r = ty; r < 32; r += 8)
            tile[r][tx] = wo[(size_t)(k0 + r) * D_ + n0 + tx];
        __syncthreads();
        for (int r = ty; r < 32; r += 8) {
            float v = tile[tx][r];
            __nv_bfloat16 h = __float2bfloat16(v);
            size_t idx = (size_t)(n0 + r) * D_ + k0 + tx;
            g_wothi[idx] = h;
            g_wotlo[idx] = __float2bfloat16(v - __bfloat162float(h));
        }
    }
}

// ---------------------------------------------------------------------------
// HMMA bf16 split GEMM (unchanged): 128x128 tile, BK=64, 8 warps,
// 3-stage cp.async pipeline. MODE=1 fuses softmax(q)/exp(k) epilogue.
// ---------------------------------------------------------------------------
#define GT_TILE_BYTES  16384
#define GT_STAGE_BYTES (4 * GT_TILE_BYTES)
#define GT_SMEM_TOTAL  (3 * GT_STAGE_BYTES)

template<int MODE>
__global__ void __launch_bounds__(256, 1)
gemm_mma(const __nv_bfloat16* __restrict__ Ahi, const __nv_bfloat16* __restrict__ Alo,
         const __nv_bfloat16* __restrict__ Bhi, const __nv_bfloat16* __restrict__ Blo,
         float* __restrict__ C, int N, int K)
{
    extern __shared__ char smem[];
    const uint32_t smem_base = smem_u32(smem);
    const int tid = threadIdx.x;
    const int wid = tid >> 5, lane = tid & 31;
    const int m0 = blockIdx.y * 128, n0 = blockIdx.x * 128;
    const int wm = (wid & 3) * 32;
    const int wn = (wid >> 2) * 64;

    const __nv_bfloat16* srcs[4] = { Ahi, Alo, Bhi, Blo };

    auto load_stage = [&](int kt, int s) {
        const int k0 = kt << 6;
#pragma unroll
        for (int tI = 0; tI < 4; tI++) {
            const __nv_bfloat16* src = srcs[tI];
            const int rb = (tI < 2) ? m0 : n0;
            const uint32_t tb = smem_base + s * GT_STAGE_BYTES + tI * GT_TILE_BYTES;
#pragma unroll
            for (int ii = 0; ii < 4; ii++) {
                int j = tid + ii * 256;
                int r = j >> 3, c = j & 7;
                const void* g = &src[(size_t)(rb + r) * K + k0 + c * 8];
                uint32_t d = tb + (uint32_t)(r * 128 + ((c ^ (r & 7)) << 4));
                cp_async16(d, g);
            }
        }
    };

    float acc[2][8][4];
#pragma unroll
    for (int mt = 0; mt < 2; mt++)
#pragma unroll
        for (int nt = 0; nt < 8; nt++)
#pragma unroll
            for (int e = 0; e < 4; e++) acc[mt][nt][e] = 0.f;

    const int NKT = K >> 6;
    load_stage(0, 0); cp_commit();
    load_stage(1, 1); cp_commit();

    const int a_row = (lane & 15);
    const int a_khalf = lane >> 4;
    const int b_grp = (lane >> 4) & 1;
    const int b_khalf = (lane >> 3) & 1;
    const int b_row = lane & 7;

    int s = 0, sload = 2;
    for (int kt = 0; kt < NKT; kt++) {
        const uint32_t st = smem_base + s * GT_STAGE_BYTES;
        cp_wait1();
        __syncthreads();

        if (kt + 2 < NKT) load_stage(kt + 2, sload);
        cp_commit();

        const uint32_t aA = st;
        const uint32_t aB = st + 2 * GT_TILE_BYTES;

#pragma unroll
        for (int kk = 0; kk < 4; kk++) {
            uint32_t ah[2][4], al[2][4];
#pragma unroll
            for (int mt = 0; mt < 2; mt++) {
                int row = wm + mt * 16 + a_row;
                int chunk = 2 * kk + a_khalf;
                uint32_t off = (uint32_t)(row * 128 + ((chunk ^ (row & 7)) << 4));
                ldsm_x4(aA + off, ah[mt][0], ah[mt][1], ah[mt][2], ah[mt][3]);
                ldsm_x4(aA + GT_TILE_BYTES + off, al[mt][0], al[mt][1], al[mt][2], al[mt][3]);
            }
            uint32_t bh[4][4], bl[4][4];
#pragma unroll
            for (int np = 0; np < 4; np++) {
                int row = wn + np * 16 + b_grp * 8 + b_row;
                int chunk = 2 * kk + b_khalf;
                uint32_t off = (uint32_t)(row * 128 + ((chunk ^ (row & 7)) << 4));
                ldsm_x4(aB + off, bh[np][0], bh[np][1], bh[np][2], bh[np][3]);
                ldsm_x4(aB + GT_TILE_BYTES + off, bl[np][0], bl[np][1], bl[np][2], bl[np][3]);
            }
#pragma unroll
            for (int p = 0; p < 3; p++) {
#pragma unroll
                for (int mt = 0; mt < 2; mt++) {
                    const uint32_t* af = (p == 2) ? al[mt] : ah[mt];
#pragma unroll
                    for (int nt = 0; nt < 8; nt++) {
                        const uint32_t* bf = (p == 1) ? &bl[nt >> 1][(nt & 1) * 2]
                                                      : &bh[nt >> 1][(nt & 1) * 2];
                        mma_bf16(acc[mt][nt], af, bf);
                    }
                }
            }
        }
        s = (s == 2) ? 0 : s + 1;
        sload = (sload == 2) ? 0 : sload + 1;
    }

    const int g = lane >> 2, tig = lane & 3;
    const int gcol0 = n0 + wn;

    if (MODE == 1 && gcol0 < D_) {
#pragma unroll
        for (int mt = 0; mt < 2; mt++) {
            float vA[16], vB[16];
#pragma unroll
            for (int nt = 0; nt < 8; nt++) {
                vA[2*nt]   = acc[mt][nt][0] * 0.125f;
                vA[2*nt+1] = acc[mt][nt][1] * 0.125f;
                vB[2*nt]   = acc[mt][nt][2] * 0.125f;
                vB[2*nt+1] = acc[mt][nt][3] * 0.125f;
            }
            float mA = vA[0], mB = vB[0];
#pragma unroll
            for (int i = 1; i < 16; i++) { mA = fmaxf(mA, vA[i]); mB = fmaxf(mB, vB[i]); }
            mA = fmaxf(mA, __shfl_xor_sync(0xffffffffu, mA, 1));
            mA = fmaxf(mA, __shfl_xor_sync(0xffffffffu, mA, 2));
            mB = fmaxf(mB, __shfl_xor_sync(0xffffffffu, mB, 1));
            mB = fmaxf(mB, __shfl_xor_sync(0xffffffffu, mB, 2));
            float sA = 0.f, sB = 0.f;
#pragma unroll
            for (int i = 0; i < 16; i++) {
                vA[i] = expf(vA[i] - mA); sA += vA[i];
                vB[i] = expf(vB[i] - mB); sB += vB[i];
            }
            sA += __shfl_xor_sync(0xffffffffu, sA, 1);
            sA += __shfl_xor_sync(0xffffffffu, sA, 2);
            sB += __shfl_xor_sync(0xffffffffu, sB, 1);
            sB += __shfl_xor_sync(0xffffffffu, sB, 2);
            float iA = 1.f / sA, iB = 1.f / sB;
            int row = m0 + wm + mt * 16 + g;
#pragma unroll
            for (int nt = 0; nt < 8; nt++) {
                int col = gcol0 + nt * 8 + 2 * tig;
                *(float2*)&C[(size_t)row * N + col]       = make_float2(vA[2*nt]*iA, vA[2*nt+1]*iA);
                *(float2*)&C[(size_t)(row + 8) * N + col] = make_float2(vB[2*nt]*iB, vB[2*nt+1]*iB);
            }
        }
    } else if (MODE == 1 && gcol0 < 2 * D_) {
#pragma unroll
        for (int mt = 0; mt < 2; mt++) {
            int row = m0 + wm + mt * 16 + g;
#pragma unroll
            for (int nt = 0; nt < 8; nt++) {
                int col = gcol0 + nt * 8 + 2 * tig;
                float* c = acc[mt][nt];
                *(float2*)&C[(size_t)row * N + col] =
                    make_float2(expf(c[0]*0.125f)+1e-6f, expf(c[1]*0.125f)+1e-6f);
                *(float2*)&C[(size_t)(row + 8) * N + col] =
                    make_float2(expf(c[2]*0.125f)+1e-6f, expf(c[3]*0.125f)+1e-6f);
            }
        }
    } else {
#pragma unroll
        for (int mt = 0; mt < 2; mt++) {
            int row = m0 + wm + mt * 16 + g;
#pragma unroll
            for (int nt = 0; nt < 8; nt++) {
                int col = gcol0 + nt * 8 + 2 * tig;
                float* c = acc[mt][nt];
                *(float2*)&C[(size_t)row * N + col]       = make_float2(c[0], c[1]);
                *(float2*)&C[(size_t)(row + 8) * N + col] = make_float2(c[2], c[3]);
            }
        }
    }
}

// ---------------------------------------------------------------------------
// Per-chunk state (CHUNK=64) — unchanged
// ---------------------------------------------------------------------------
__global__ void __launch_bounds__(256)
chunkstate_kernel(const float* __restrict__ qkv,
                  float* __restrict__ Sc, float* __restrict__ ks)
{
    extern __shared__ float sm[];
    float* Ks = sm;
    float* Vs = sm + CHUNK * L_;
    const int c = blockIdx.x, bh = blockIdx.y;
    const int b = bh >> 4, h = bh & 15;
    const size_t rowbase = ((size_t)(b * T_ + c * CHUNK)) * (3 * D_) + h * L_;

    for (int i = threadIdx.x; i < CHUNK * 16; i += 256) {
        int t = i >> 4, f = (i & 15) << 2;
        size_t g = rowbase + (size_t)t * (3 * D_) + f;
        *(float4*)&Ks[t * L_ + f] = *(const float4*)&qkv[g + D_];
        *(float4*)&Vs[t * L_ + f] = *(const float4*)&qkv[g + 2 * D_];
    }
    __syncthreads();

    const int l0 = (threadIdx.x >> 4) << 2;
    const int m0 = (threadIdx.x & 15) << 2;
    float acc[4][4];
#pragma unroll
    for (int i = 0; i < 4; i++)
#pragma unroll
        for (int j = 0; j < 4; j++) acc[i][j] = 0.f;
    for (int t = 0; t < CHUNK; t++) {
        float a[4], v[4];
#pragma unroll
        for (int i = 0; i < 4; i++) a[i] = Ks[t * L_ + l0 + i];
#pragma unroll
        for (int j = 0; j < 4; j++) v[j] = Vs[t * L_ + m0 + j];
#pragma unroll
        for (int i = 0; i < 4; i++)
#pragma unroll
            for (int j = 0; j < 4; j++) acc[i][j] += a[i] * v[j];
    }
    const size_t sbase = ((size_t)bh * NC + c) * (L_ * L_);
#pragma unroll
    for (int i = 0; i < 4; i++)
#pragma unroll
        for (int j = 0; j < 4; j++)
            Sc[sbase + (size_t)(l0 + i) * L_ + m0 + j] = acc[i][j];

    if (threadIdx.x < L_) {
        float s = 0.f;
        for (int t = 0; t < CHUNK; t++) s += Ks[t * L_ + threadIdx.x];
        ks[((size_t)bh * NC + c) * L_ + threadIdx.x] = s;
    }
}

// ---------------------------------------------------------------------------
// Exclusive prefix over chunks — unchanged
// ---------------------------------------------------------------------------
__global__ void prefix_kernel(float* __restrict__ Sc, float* __restrict__ ks)
{
    const int bh = blockIdx.x;
    const int e = blockIdx.y * 256 + threadIdx.x;
    const size_t base = (size_t)bh * NC * (L_ * L_);
    {
        float acc = 0.f;
#pragma unroll
        for (int c = 0; c < NC; c++) {
            size_t idx = base + (size_t)c * (L_ * L_) + e;
            float tmp = Sc[idx];
            Sc[idx] = acc;
            acc += tmp;
        }
    }
    if (blockIdx.y == 0 && threadIdx.x < L_) {
        const size_t kb = (size_t)bh * NC * L_;
        float acc = 0.f;
#pragma unroll
        for (int c = 0; c < NC; c++) {
            size_t idx = kb + (size_t)c * L_ + threadIdx.x;
            float tmp = ks[idx];
            ks[idx] = acc;
            acc += tmp;
        }
    }
}

// ---------------------------------------------------------------------------
// Tensor-core chunk attention, v2 (CHUNK=64, 128 threads = 4 warps):
// K, V^T, S_prev^T converted DIRECTLY global->swizzled bf16 hi/lo smem.
// qs staged fp32 (needs causal normalizer first), then converted; its
// region is reused for P. Normalizer reconstructs k from KH+KL.
// smem map (bytes, total 81920 -> 2 blocks/SM):
//   [0:16384)      qsf fp32      -> later PH [0:8192) PL [8192:16384)
//   [16384:32768)  QH | QL
//   [32768:49152)  KH | KL
//   [49152:65536)  VTH | VTL
//   [65536:81920)  STH | STL
// ---------------------------------------------------------------------------
#define AT_SMEM 81920

__global__ void __launch_bounds__(128)
attn_kernel(const float* __restrict__ qkv, const float* __restrict__ Sprev,
            const float* __restrict__ kpre,
            __nv_bfloat16* __restrict__ yhi, __nv_bfloat16* __restrict__ ylo)
{
    extern __shared__ char smc[];
    float* qsf = (float*)smc;
    const uint32_t sb  = smem_u32(smc);
    const uint32_t PH  = sb,           PL  = sb + 8192;
    const uint32_t QH  = sb + 16384,   QL  = sb + 24576;
    const uint32_t KH  = sb + 32768,   KL  = sb + 40960;
    const uint32_t VTH = sb + 49152,   VTL = sb + 57344;
    const uint32_t STH = sb + 65536,   STL = sb + 73728;

    const int c = blockIdx.x, bh = blockIdx.y;
    const int b = bh >> 4, h = bh & 15;
    const int tid = threadIdx.x;
    const int wid = tid >> 5, lane = tid & 31;
    const size_t rowbase = ((size_t)(b * T_ + c * CHUNK)) * (3 * D_) + h * L_;
    const size_t sbase = ((size_t)bh * NC + c) * (L_ * L_);

    // -- qs: fp32 stage (normalization comes first) --
    for (int i = tid; i < CHUNK * 16; i += 128) {
        int t = i >> 4, f = (i & 15) << 2;
        *(float4*)&qsf[t * L_ + f] =
            *(const float4*)&qkv[rowbase + (size_t)t * (3 * D_) + f];
    }
    // -- K: direct convert (row-major pairs along columns) --
    for (int i = tid; i < 1024; i += 128) {
        int t = i >> 4, f = (i & 15) << 2;
        float4 kv4 = *(const float4*)&qkv[rowbase + (size_t)t * (3 * D_) + D_ + f];
        uint32_t hp, lp;
        split2(kv4.x, kv4.y, hp, lp);
        sts32(sw_addr(KH, t, f), hp);     sts32(sw_addr(KL, t, f), lp);
        split2(kv4.z, kv4.w, hp, lp);
        sts32(sw_addr(KH, t, f + 2), hp); sts32(sw_addr(KL, t, f + 2), lp);
    }
    // -- V^T: read rows t0,t0+1; hi/lo words pack column pairs (t0,t0+1) --
    for (int i = tid; i < 512; i += 128) {
        int t0 = (i >> 4) * 2;            // 0,2,..,62
        int m0 = (i & 15) << 2;           // 0,4,..,60
        const float* v0 = &qkv[rowbase + (size_t)t0 * (3 * D_) + 2 * D_];
        float4 a = *(const float4*)&v0[m0];
        float4 bvec = *(const float4*)&v0[3 * D_ + m0];
        uint32_t hp, lp;
        split2(a.x, bvec.x, hp, lp);
        sts32(sw_addr(VTH, m0 + 0, t0), hp); sts32(sw_addr(VTL, m0 + 0, t0), lp);
        split2(a.y, bvec.y, hp, lp);
        sts32(sw_addr(VTH, m0 + 1, t0), hp); sts32(sw_addr(VTL, m0 + 1, t0), lp);
        split2(a.z, bvec.z, hp, lp);
        sts32(sw_addr(VTH, m0 + 2, t0), hp); sts32(sw_addr(VTL, m0 + 2, t0), lp);
        split2(a.w, bvec.w, hp, lp);
        sts32(sw_addr(VTH, m0 + 3, t0), hp); sts32(sw_addr(VTL, m0 + 3, t0), lp);
    }
    // -- S_prev^T: same pattern (rows l0,l0+1 of S_prev -> cols of ST) --
    for (int i = tid; i < 512; i += 128) {
        int l0 = (i >> 4) * 2;
        int m0 = (i & 15) << 2;
        const float* s0 = &Sprev[sbase + (size_t)l0 * L_];
        float4 a = *(const float4*)&s0[m0];
        float4 bvec = *(const float4*)&s0[L_ + m0];
        uint32_t hp, lp;
        split2(a.x, bvec.x, hp, lp);
        sts32(sw_addr(STH, m0 + 0, l0), hp); sts32(sw_addr(STL, m0 + 0, l0), lp);
        split2(a.y, bvec.y, hp, lp);
        sts32(sw_addr(STH, m0 + 1, l0), hp); sts32(sw_addr(STL, m0 + 1, l0), lp);
        split2(a.z, bvec.z, hp, lp);
        sts32(sw_addr(STH, m0 + 2, l0), hp); sts32(sw_addr(STL, m0 + 2, l0), lp);
        split2(a.w, bvec.w, hp, lp);
        sts32(sw_addr(STH, m0 + 3, l0), hp); sts32(sw_addr(STL, m0 + 3, l0), lp);
    }
    __syncthreads();

    // -- normalize qs: acc = kpre + cumsum k (k = KH+KL reconstruct); thread = l --
    if (tid < L_) {
        const int l = tid;
        float acc = kpre[((size_t)bh * NC + c) * L_ + l];
        for (int t = 0; t < CHUNK; t++) {
            acc += lds_bf16(sw_addr(KH, t, l)) + lds_bf16(sw_addr(KL, t, l));
            qsf[t * L_ + l] = __fdividef(qsf[t * L_ + l], acc);
        }
    }
    __syncthreads();

    // -- convert qs -> QH/QL --
    for (int i = tid; i < 2048; i += 128) {
        int row = i >> 5, col = (i & 31) * 2;
        uint32_t hp, lp;
        split2(qsf[row * L_ + col], qsf[row * L_ + col + 1], hp, lp);
        sts32(sw_addr(QH, row, col), hp);
        sts32(sw_addr(QL, row, col), lp);
    }
    __syncthreads();    // qsf dead after this point; its region becomes P

    const int wm = wid * 16;
    const int a_row = (lane & 15);
    const int a_khalf = lane >> 4;
    const int b_grp = (lane >> 4) & 1;
    const int b_khalf = (lane >> 3) & 1;
    const int b_row = lane & 7;
    const int g = lane >> 2, tig = lane & 3;

    // ---- P = qs_norm @ K^T ----
    float accP[8][4];
#pragma unroll
    for (int nt = 0; nt < 8; nt++)
#pragma unroll
        for (int e = 0; e < 4; e++) accP[nt][e] = 0.f;

#pragma unroll
    for (int kk = 0; kk < 4; kk++) {
        uint32_t ah[4], al[4];
        {
            int row = wm + a_row;
            int chunk = 2 * kk + a_khalf;
            uint32_t off = (uint32_t)(row * 128 + ((chunk ^ (row & 7)) << 4));
            ldsm_x4(QH + off, ah[0], ah[1], ah[2], ah[3]);
            ldsm_x4(QL + off, al[0], al[1], al[2], al[3]);
        }
        uint32_t bh_[4][4], bl_[4][4];
#pragma unroll
        for (int np = 0; np < 4; np++) {
            int row = np * 16 + b_grp * 8 + b_row;
            int chunk = 2 * kk + b_khalf;
            uint32_t off = (uint32_t)(row * 128 + ((chunk ^ (row & 7)) << 4));
            ldsm_x4(KH + off, bh_[np][0], bh_[np][1], bh_[np][2], bh_[np][3]);
            ldsm_x4(KL + off, bl_[np][0], bl_[np][1], bl_[np][2], bl_[np][3]);
        }
#pragma unroll
        for (int p = 0; p < 3; p++) {
            const uint32_t* af = (p == 2) ? al : ah;
#pragma unroll
            for (int nt = 0; nt < 8; nt++) {
                const uint32_t* bf = (p == 1) ? &bl_[nt >> 1][(nt & 1) * 2]
                                              : &bh_[nt >> 1][(nt & 1) * 2];
                mma_bf16(accP[nt], af, bf);
            }
        }
    }

    // ---- causal mask + split-store P (into former qsf region) ----
    {
        int r0 = wm + g, r1 = wm + g + 8;
#pragma unroll
        for (int nt = 0; nt < 8; nt++) {
            int colp = nt * 8 + 2 * tig;
            float p00 = (colp     <= r0) ? accP[nt][0] : 0.f;
            float p01 = (colp + 1 <= r0) ? accP[nt][1] : 0.f;
            float p10 = (colp     <= r1) ? accP[nt][2] : 0.f;
            float p11 = (colp + 1 <= r1) ? accP[nt][3] : 0.f;
            uint32_t hp, lp;
            split2(p00, p01, hp, lp);
            sts32(sw_addr(PH, r0, colp), hp);
            sts32(sw_addr(PL, r0, colp), lp);
            split2(p10, p11, hp, lp);
            sts32(sw_addr(PH, r1, colp), hp);
            sts32(sw_addr(PL, r1, colp), lp);
        }
    }
    __syncthreads();

    // ---- Y = P @ V + qs_norm @ S_prev ----
    float acc[8][4];
#pragma unroll
    for (int nt = 0; nt < 8; nt++)
#pragma unroll
        for (int e = 0; e < 4; e++) acc[nt][e] = 0.f;

#pragma unroll
    for (int half = 0; half < 2; half++) {
        const uint32_t AH = half ? QH : PH, AL = half ? QL : PL;
        const uint32_t BH = half ? STH : VTH, BL = half ? STL : VTL;
#pragma unroll
        for (int kk = 0; kk < 4; kk++) {
            uint32_t ah[4], al[4];
            {
                int row = wm + a_row;
                int chunk = 2 * kk + a_khalf;
                uint32_t off = (uint32_t)(row * 128 + ((chunk ^ (row & 7)) << 4));
                ldsm_x4(AH + off, ah[0], ah[1], ah[2], ah[3]);
                ldsm_x4(AL + off, al[0], al[1], al[2], al[3]);
            }
            uint32_t bh_[4][4], bl_[4][4];
#pragma unroll
            for (int np = 0; np < 4; np++) {
                int row = np * 16 + b_grp * 8 + b_row;
                int chunk = 2 * kk + b_khalf;
                uint32_t off = (uint32_t)(row * 128 + ((chunk ^ (row & 7)) << 4));
                ldsm_x4(BH + off, bh_[np][0], bh_[np][1], bh_[np][2], bh_[np][3]);
                ldsm_x4(BL + off, bl_[np][0], bl_[np][1], bl_[np][2], bl_[np][3]);
            }
#pragma unroll
            for (int p = 0; p < 3; p++) {
                const uint32_t* af = (p == 2) ? al : ah;
#pragma unroll
                for (int nt = 0; nt < 8; nt++) {
                    const uint32_t* bf = (p == 1) ? &bl_[nt >> 1][(nt & 1) * 2]
                                                  : &bh_[nt >> 1][(nt & 1) * 2];
                    mma_bf16(acc[nt], af, bf);
                }
            }
        }
    }

    // ---- epilogue: split y -> global bf16 hi/lo ----
    {
        int r0 = wm + g;
#pragma unroll
        for (int dr = 0; dr < 2; dr++) {
            int row = r0 + dr * 8;
            size_t ybase = ((size_t)(b * T_ + c * CHUNK + row)) * D_ + h * L_;
#pragma unroll
            for (int nt = 0; nt < 8; nt++) {
                int colp = nt * 8 + 2 * tig;
                float v0 = acc[nt][2 * dr], v1 = acc[nt][2 * dr + 1];
                uint32_t hp, lp;
                split2(v0, v1, hp, lp);
                *(uint32_t*)&yhi[ybase + colp] = hp;
                *(uint32_t*)&ylo[ybase + colp] = lp;
            }
        }
    }
}

// ---------------------------------------------------------------------------
extern "C" void kernel_launch(void* const* d_in, const int* in_sizes, int n_in,
                              void* d_out, int out_size)
{
    const float* x  = (const float*)d_in[0];
    const float* w  = (const float*)d_in[1];
    const float* wo = (const float*)d_in[2];
    float* out = (float*)d_out;

    float *qkv, *Sc, *ks;
    __nv_bfloat16 *xhi, *xlo, *whi, *wlo, *wothi, *wotlo, *yhi, *ylo;
    cudaGetSymbolAddress((void**)&qkv, g_qkv);
    cudaGetSymbolAddress((void**)&Sc,  g_Sc);
    cudaGetSymbolAddress((void**)&ks,  g_ks);
    cudaGetSymbolAddress((void**)&xhi, g_xhi);
    cudaGetSymbolAddress((void**)&xlo, g_xlo);
    cudaGetSymbolAddress((void**)&whi, g_whi);
    cudaGetSymbolAddress((void**)&wlo, g_wlo);
    cudaGetSymbolAddress((void**)&wothi, g_wothi);
    cudaGetSymbolAddress((void**)&wotlo, g_wotlo);
    cudaGetSymbolAddress((void**)&yhi, g_yhi);
    cudaGetSymbolAddress((void**)&ylo, g_ylo);

    cudaFuncSetAttribute(gemm_mma<0>,
                         cudaFuncAttributeMaxDynamicSharedMemorySize, GT_SMEM_TOTAL);
    cudaFuncSetAttribute(gemm_mma<1>,
                         cudaFuncAttributeMaxDynamicSharedMemorySize, GT_SMEM_TOTAL);
    cudaFuncSetAttribute(chunkstate_kernel,
                         cudaFuncAttributeMaxDynamicSharedMemorySize, 32768);
    cudaFuncSetAttribute(attn_kernel,
                         cudaFuncAttributeMaxDynamicSharedMemorySize, AT_SMEM);

    // 0) fused split of x, w, w_out^T
    prep_inputs_kernel<<<NBX + NBW + 1024, 256>>>(x, w, wo);
    // 1) qkv = x @ w^T with fused softmax(q)/exp(k) epilogue
    gemm_mma<1><<<dim3(3 * D_ / 128, BT_ / 128), 256, GT_SMEM_TOTAL>>>(
        xhi, xlo, whi, wlo, qkv, 3 * D_, D_);
    // 2) per-chunk states + k sums
    chunkstate_kernel<<<dim3(NC, BH_), 256, 32768>>>(qkv, Sc, ks);
    // 3) exclusive prefix over chunks
    prefix_kernel<<<dim3(BH_, 16), 256>>>(Sc, ks);
    // 4) tensor-core chunk attention -> y (bf16 split)
    attn_kernel<<<dim3(NC, BH_), 128, AT_SMEM>>>(qkv, Sc, ks, yhi, ylo);
    // 5) out = y @ w_out
    gemm_mma<0><<<dim3(D_ / 128, BT_ / 128), 256, GT_SMEM_TOTAL>>>(
        yhi, ylo, wothi, wotlo, out, D_, D_);
}

// round 12
// speedup vs baseline: 1.4895x; 1.1000x over previous
#include <cuda_runtime.h>
#include <cuda_bf16.h>
#include <cstdint>

// Problem constants
#define B_   4
#define T_   2048
#define D_   1024
#define H_   16
#define L_   64
#define BT_  (B_*T_)        // 8192
#define BH_  (B_*H_)        // 64
#define CHUNK 64
#define NC   (T_/CHUNK)     // 32

// ---------------------------------------------------------------------------
// Scratch (device globals; no allocation allowed)
// ---------------------------------------------------------------------------
__device__ float g_qkv[(size_t)BT_ * 3 * D_];        // (8192, 3072)  qs|k_exp|v fp32
__device__ float g_Sc [(size_t)BH_ * NC * L_ * L_];  // chunk states -> excl prefix
__device__ float g_ks [(size_t)BH_ * NC * L_];       // chunk k-sums -> excl prefix
__device__ __nv_bfloat16 g_xhi[(size_t)BT_ * D_];
__device__ __nv_bfloat16 g_xlo[(size_t)BT_ * D_];
__device__ __nv_bfloat16 g_whi[(size_t)3 * D_ * D_];
__device__ __nv_bfloat16 g_wlo[(size_t)3 * D_ * D_];
__device__ __nv_bfloat16 g_wothi[(size_t)D_ * D_];   // w_out^T
__device__ __nv_bfloat16 g_wotlo[(size_t)D_ * D_];
__device__ __nv_bfloat16 g_yhi[(size_t)BT_ * D_];
__device__ __nv_bfloat16 g_ylo[(size_t)BT_ * D_];

// ---------------------------------------------------------------------------
// PTX helpers (baseline sm_80+ instructions only — harness targets plain sm_103)
// ---------------------------------------------------------------------------
__device__ __forceinline__ uint32_t smem_u32(const void* p) {
    uint32_t a;
    asm("{ .reg .u64 t; cvta.to.shared.u64 t, %1; cvt.u32.u64 %0, t; }" : "=r"(a) : "l"(p));
    return a;
}

__device__ __forceinline__ void cp_async16(uint32_t dst, const void* src) {
    asm volatile("cp.async.cg.shared.global [%0], [%1], 16;" :: "r"(dst), "l"(src) : "memory");
}
__device__ __forceinline__ void cp_commit() {
    asm volatile("cp.async.commit_group;" ::: "memory");
}
__device__ __forceinline__ void cp_wait1() {
    asm volatile("cp.async.wait_group 1;" ::: "memory");
}
__device__ __forceinline__ void cp_wait0() {
    asm volatile("cp.async.wait_group 0;" ::: "memory");
}

__device__ __forceinline__ void ldsm_x4(uint32_t addr, uint32_t& r0, uint32_t& r1,
                                        uint32_t& r2, uint32_t& r3) {
    asm volatile("ldmatrix.sync.aligned.m8n8.x4.shared.b16 {%0,%1,%2,%3}, [%4];"
                 : "=r"(r0), "=r"(r1), "=r"(r2), "=r"(r3) : "r"(addr));
}

__device__ __forceinline__ void mma_bf16(float* c, const uint32_t* a, const uint32_t* b) {
    asm volatile(
        "mma.sync.aligned.m16n8k16.row.col.f32.bf16.bf16.f32 "
        "{%0,%1,%2,%3}, {%4,%5,%6,%7}, {%8,%9}, {%0,%1,%2,%3};"
        : "+f"(c[0]), "+f"(c[1]), "+f"(c[2]), "+f"(c[3])
        : "r"(a[0]), "r"(a[1]), "r"(a[2]), "r"(a[3]), "r"(b[0]), "r"(b[1]));
}

__device__ __forceinline__ void sts32(uint32_t addr, uint32_t v) {
    asm volatile("st.shared.b32 [%0], %1;" :: "r"(addr), "r"(v) : "memory");
}

__device__ __forceinline__ float lds_bf16(uint32_t addr) {
    uint16_t v;
    asm volatile("ld.shared.u16 %0, [%1];" : "=h"(v) : "r"(addr));
    __nv_bfloat16 b = *(__nv_bfloat16*)&v;
    return __bfloat162float(b);
}

// split two floats -> packed bf16x2 hi and lo words
__device__ __forceinline__ void split2(float a, float b, uint32_t& hp, uint32_t& lp) {
    __nv_bfloat16 h0 = __float2bfloat16(a), h1 = __float2bfloat16(b);
    __nv_bfloat16 l0 = __float2bfloat16(a - __bfloat162float(h0));
    __nv_bfloat16 l1 = __float2bfloat16(b - __bfloat162float(h1));
    __nv_bfloat162 hv = __halves2bfloat162(h0, h1);
    __nv_bfloat162 lv = __halves2bfloat162(l0, l1);
    hp = *(uint32_t*)&hv;
    lp = *(uint32_t*)&lv;
}

// swizzled byte address of bf16 (row, col) in a 64-row x 64-col K-major tile
__device__ __forceinline__ uint32_t sw_addr(uint32_t base, int row, int col) {
    return base + (uint32_t)(row * 128 + ((((col >> 3) ^ (row & 7))) << 4) + ((col & 7) * 2));
}

// ---------------------------------------------------------------------------
// ONE fused input-prep kernel
// ---------------------------------------------------------------------------
#define NBX (BT_ * D_ / 4 / 256)          // 8192
#define NBW (3 * D_ * D_ / 4 / 256)       // 3072

__global__ void __launch_bounds__(256)
prep_inputs_kernel(const float* __restrict__ x, const float* __restrict__ w,
                   const float* __restrict__ wo)
{
    const int bid = blockIdx.x;
    if (bid < NBX + NBW) {
        const float* src;
        __nv_bfloat16 *hi, *lo;
        int i;
        if (bid < NBX) {
            src = x; hi = g_xhi; lo = g_xlo;
            i = bid * 256 + threadIdx.x;
        } else {
            src = w; hi = g_whi; lo = g_wlo;
            i = (bid - NBX) * 256 + threadIdx.x;
        }
        float4 v = ((const float4*)src)[i];
        uint32_t h01, l01, h23, l23;
        split2(v.x, v.y, h01, l01);
        split2(v.z, v.w, h23, l23);
        ((uint32_t*)hi)[2 * i]     = h01;
        ((uint32_t*)hi)[2 * i + 1] = h23;
        ((uint32_t*)lo)[2 * i]     = l01;
        ((uint32_t*)lo)[2 * i + 1] = l23;
    } else {
        __shared__ float tile[32][33];
        int tb = bid - NBX - NBW;            // 0..1023
        int n0 = (tb & 31) * 32, k0 = (tb >> 5) * 32;
        int tx = threadIdx.x & 31, ty = threadIdx.x >> 5;   // (32,8)
        for (int r = ty; r < 32; r += 8)
            tile[r][tx] = wo[(size_t)(k0 + r) * D_ + n0 + tx];
        __syncthreads();
        for (int r = ty; r < 32; r += 8) {
            float v = tile[tx][r];
            __nv_bfloat16 h = __float2bfloat16(v);
            size_t idx = (size_t)(n0 + r) * D_ + k0 + tx;
            g_wothi[idx] = h;
            g_wotlo[idx] = __float2bfloat16(v - __bfloat162float(h));
        }
    }
}

// ---------------------------------------------------------------------------
// HMMA bf16 split GEMM v2: 128x64 tile, BK=64, 128 threads (4 warps),
// warp tile 32x64 (4 warps stacked along M). 2-stage cp.async pipeline,
// stage = 48KB -> 96KB/CTA -> 2 CTAs/SM for bubble overlap.
// MODE=1 fuses softmax(q)/exp(k) epilogue (warp spans one full 64-col head).
// ---------------------------------------------------------------------------
#define GA_TILE 16384                 // A: 128 rows x 128B
#define GB_TILE 8192                  // B:  64 rows x 128B
#define G_STAGE (2*GA_TILE + 2*GB_TILE)     // 49152
#define G_SMEM  (2 * G_STAGE)               // 98304

template<int MODE>
__global__ void __launch_bounds__(128, 2)
gemm_mma(const __nv_bfloat16* __restrict__ Ahi, const __nv_bfloat16* __restrict__ Alo,
         const __nv_bfloat16* __restrict__ Bhi, const __nv_bfloat16* __restrict__ Blo,
         float* __restrict__ C, int N, int K)
{
    extern __shared__ char smem[];
    const uint32_t smem_base = smem_u32(smem);
    const int tid = threadIdx.x;
    const int wid = tid >> 5, lane = tid & 31;
    const int m0 = blockIdx.y * 128, n0 = blockIdx.x * 64;
    const int wm = wid * 32;           // 4 warps stacked along M

    auto load_stage = [&](int kt, int s) {
        const int k0 = kt << 6;
        const uint32_t sb = smem_base + s * G_STAGE;
        // A hi/lo: 128 rows x 8 chunks = 1024 chunks, 8 per thread
#pragma unroll
        for (int tI = 0; tI < 2; tI++) {
            const __nv_bfloat16* src = tI ? Alo : Ahi;
            const uint32_t tb = sb + tI * GA_TILE;
#pragma unroll
            for (int ii = 0; ii < 8; ii++) {
                int j = tid + ii * 128;
                int r = j >> 3, c = j & 7;
                const void* g = &src[(size_t)(m0 + r) * K + k0 + c * 8];
                cp_async16(tb + (uint32_t)(r * 128 + ((c ^ (r & 7)) << 4)), g);
            }
        }
        // B hi/lo: 64 rows x 8 chunks = 512 chunks, 4 per thread
#pragma unroll
        for (int tI = 0; tI < 2; tI++) {
            const __nv_bfloat16* src = tI ? Blo : Bhi;
            const uint32_t tb = sb + 2 * GA_TILE + tI * GB_TILE;
#pragma unroll
            for (int ii = 0; ii < 4; ii++) {
                int j = tid + ii * 128;
                int r = j >> 3, c = j & 7;
                const void* g = &src[(size_t)(n0 + r) * K + k0 + c * 8];
                cp_async16(tb + (uint32_t)(r * 128 + ((c ^ (r & 7)) << 4)), g);
            }
        }
    };

    float acc[2][8][4];
#pragma unroll
    for (int mt = 0; mt < 2; mt++)
#pragma unroll
        for (int nt = 0; nt < 8; nt++)
#pragma unroll
            for (int e = 0; e < 4; e++) acc[mt][nt][e] = 0.f;

    const int NKT = K >> 6;
    load_stage(0, 0); cp_commit();

    const int a_row = (lane & 15);
    const int a_khalf = lane >> 4;
    const int b_grp = (lane >> 4) & 1;
    const int b_khalf = (lane >> 3) & 1;
    const int b_row = lane & 7;

    for (int kt = 0; kt < NKT; kt++) {
        if (kt + 1 < NKT) {
            load_stage(kt + 1, (kt + 1) & 1);
            cp_commit();
            cp_wait1();          // stage kt resident; kt+1 in flight
        } else {
            cp_wait0();
        }
        __syncthreads();

        const uint32_t st = smem_base + (kt & 1) * G_STAGE;
        const uint32_t aA = st;
        const uint32_t aB = st + 2 * GA_TILE;

#pragma unroll
        for (int kk = 0; kk < 4; kk++) {
            uint32_t ah[2][4], al[2][4];
#pragma unroll
            for (int mt = 0; mt < 2; mt++) {
                int row = wm + mt * 16 + a_row;
                int chunk = 2 * kk + a_khalf;
                uint32_t off = (uint32_t)(row * 128 + ((chunk ^ (row & 7)) << 4));
                ldsm_x4(aA + off, ah[mt][0], ah[mt][1], ah[mt][2], ah[mt][3]);
                ldsm_x4(aA + GA_TILE + off, al[mt][0], al[mt][1], al[mt][2], al[mt][3]);
            }
            uint32_t bh[4][4], bl[4][4];
#pragma unroll
            for (int np = 0; np < 4; np++) {
                int row = np * 16 + b_grp * 8 + b_row;
                int chunk = 2 * kk + b_khalf;
                uint32_t off = (uint32_t)(row * 128 + ((chunk ^ (row & 7)) << 4));
                ldsm_x4(aB + off, bh[np][0], bh[np][1], bh[np][2], bh[np][3]);
                ldsm_x4(aB + GB_TILE + off, bl[np][0], bl[np][1], bl[np][2], bl[np][3]);
            }
#pragma unroll
            for (int p = 0; p < 3; p++) {
#pragma unroll
                for (int mt = 0; mt < 2; mt++) {
                    const uint32_t* af = (p == 2) ? al[mt] : ah[mt];
#pragma unroll
                    for (int nt = 0; nt < 8; nt++) {
                        const uint32_t* bf = (p == 1) ? &bl[nt >> 1][(nt & 1) * 2]
                                                      : &bh[nt >> 1][(nt & 1) * 2];
                        mma_bf16(acc[mt][nt], af, bf);
                    }
                }
            }
        }
        __syncthreads();   // protect stage (kt&1) from being overwritten next iter
    }

    const int g = lane >> 2, tig = lane & 3;
    const int gcol0 = n0;              // warp spans the full 64-col tile (one head)

    if (MODE == 1 && gcol0 < D_) {
#pragma unroll
        for (int mt = 0; mt < 2; mt++) {
            float vA[16], vB[16];
#pragma unroll
            for (int nt = 0; nt < 8; nt++) {
                vA[2*nt]   = acc[mt][nt][0] * 0.125f;
                vA[2*nt+1] = acc[mt][nt][1] * 0.125f;
                vB[2*nt]   = acc[mt][nt][2] * 0.125f;
                vB[2*nt+1] = acc[mt][nt][3] * 0.125f;
            }
            float mA = vA[0], mB = vB[0];
#pragma unroll
            for (int i = 1; i < 16; i++) { mA = fmaxf(mA, vA[i]); mB = fmaxf(mB, vB[i]); }
            mA = fmaxf(mA, __shfl_xor_sync(0xffffffffu, mA, 1));
            mA = fmaxf(mA, __shfl_xor_sync(0xffffffffu, mA, 2));
            mB = fmaxf(mB, __shfl_xor_sync(0xffffffffu, mB, 1));
            mB = fmaxf(mB, __shfl_xor_sync(0xffffffffu, mB, 2));
            float sA = 0.f, sB = 0.f;
#pragma unroll
            for (int i = 0; i < 16; i++) {
                vA[i] = expf(vA[i] - mA); sA += vA[i];
                vB[i] = expf(vB[i] - mB); sB += vB[i];
            }
            sA += __shfl_xor_sync(0xffffffffu, sA, 1);
            sA += __shfl_xor_sync(0xffffffffu, sA, 2);
            sB += __shfl_xor_sync(0xffffffffu, sB, 1);
            sB += __shfl_xor_sync(0xffffffffu, sB, 2);
            float iA = 1.f / sA, iB = 1.f / sB;
            int row = m0 + wm + mt * 16 + g;
#pragma unroll
            for (int nt = 0; nt < 8; nt++) {
                int col = gcol0 + nt * 8 + 2 * tig;
                *(float2*)&C[(size_t)row * N + col]       = make_float2(vA[2*nt]*iA, vA[2*nt+1]*iA);
                *(float2*)&C[(size_t)(row + 8) * N + col] = make_float2(vB[2*nt]*iB, vB[2*nt+1]*iB);
            }
        }
    } else if (MODE == 1 && gcol0 < 2 * D_) {
#pragma unroll
        for (int mt = 0; mt < 2; mt++) {
            int row = m0 + wm + mt * 16 + g;
#pragma unroll
            for (int nt = 0; nt < 8; nt++) {
                int col = gcol0 + nt * 8 + 2 * tig;
                float* c = acc[mt][nt];
                *(float2*)&C[(size_t)row * N + col] =
                    make_float2(expf(c[0]*0.125f)+1e-6f, expf(c[1]*0.125f)+1e-6f);
                *(float2*)&C[(size_t)(row + 8) * N + col] =
                    make_float2(expf(c[2]*0.125f)+1e-6f, expf(c[3]*0.125f)+1e-6f);
            }
        }
    } else {
#pragma unroll
        for (int mt = 0; mt < 2; mt++) {
            int row = m0 + wm + mt * 16 + g;
#pragma unroll
            for (int nt = 0; nt < 8; nt++) {
                int col = gcol0 + nt * 8 + 2 * tig;
                float* c = acc[mt][nt];
                *(float2*)&C[(size_t)row * N + col]       = make_float2(c[0], c[1]);
                *(float2*)&C[(size_t)(row + 8) * N + col] = make_float2(c[2], c[3]);
            }
        }
    }
}

// ---------------------------------------------------------------------------
// Per-chunk state (CHUNK=64) — unchanged
// ---------------------------------------------------------------------------
__global__ void __launch_bounds__(256)
chunkstate_kernel(const float* __restrict__ qkv,
                  float* __restrict__ Sc, float* __restrict__ ks)
{
    extern __shared__ float sm[];
    float* Ks = sm;
    float* Vs = sm + CHUNK * L_;
    const int c = blockIdx.x, bh = blockIdx.y;
    const int b = bh >> 4, h = bh & 15;
    const size_t rowbase = ((size_t)(b * T_ + c * CHUNK)) * (3 * D_) + h * L_;

    for (int i = threadIdx.x; i < CHUNK * 16; i += 256) {
        int t = i >> 4, f = (i & 15) << 2;
        size_t g = rowbase + (size_t)t * (3 * D_) + f;
        *(float4*)&Ks[t * L_ + f] = *(const float4*)&qkv[g + D_];
        *(float4*)&Vs[t * L_ + f] = *(const float4*)&qkv[g + 2 * D_];
    }
    __syncthreads();

    const int l0 = (threadIdx.x >> 4) << 2;
    const int m0 = (threadIdx.x & 15) << 2;
    float acc[4][4];
#pragma unroll
    for (int i = 0; i < 4; i++)
#pragma unroll
        for (int j = 0; j < 4; j++) acc[i][j] = 0.f;
    for (int t = 0; t < CHUNK; t++) {
        float a[4], v[4];
#pragma unroll
        for (int i = 0; i < 4; i++) a[i] = Ks[t * L_ + l0 + i];
#pragma unroll
        for (int j = 0; j < 4; j++) v[j] = Vs[t * L_ + m0 + j];
#pragma unroll
        for (int i = 0; i < 4; i++)
#pragma unroll
            for (int j = 0; j < 4; j++) acc[i][j] += a[i] * v[j];
    }
    const size_t sbase = ((size_t)bh * NC + c) * (L_ * L_);
#pragma unroll
    for (int i = 0; i < 4; i++)
#pragma unroll
        for (int j = 0; j < 4; j++)
            Sc[sbase + (size_t)(l0 + i) * L_ + m0 + j] = acc[i][j];

    if (threadIdx.x < L_) {
        float s = 0.f;
        for (int t = 0; t < CHUNK; t++) s += Ks[t * L_ + threadIdx.x];
        ks[((size_t)bh * NC + c) * L_ + threadIdx.x] = s;
    }
}

// ---------------------------------------------------------------------------
// Exclusive prefix over chunks — unchanged
// ---------------------------------------------------------------------------
__global__ void prefix_kernel(float* __restrict__ Sc, float* __restrict__ ks)
{
    const int bh = blockIdx.x;
    const int e = blockIdx.y * 256 + threadIdx.x;
    const size_t base = (size_t)bh * NC * (L_ * L_);
    {
        float acc = 0.f;
#pragma unroll
        for (int c = 0; c < NC; c++) {
            size_t idx = base + (size_t)c * (L_ * L_) + e;
            float tmp = Sc[idx];
            Sc[idx] = acc;
            acc += tmp;
        }
    }
    if (blockIdx.y == 0 && threadIdx.x < L_) {
        const size_t kb = (size_t)bh * NC * L_;
        float acc = 0.f;
#pragma unroll
        for (int c = 0; c < NC; c++) {
            size_t idx = kb + (size_t)c * L_ + threadIdx.x;
            float tmp = ks[idx];
            ks[idx] = acc;
            acc += tmp;
        }
    }
}

// ---------------------------------------------------------------------------
// Tensor-core chunk attention (unchanged from R11; 81920B smem -> 2 blocks/SM)
// ---------------------------------------------------------------------------
#define AT_SMEM 81920

__global__ void __launch_bounds__(128)
attn_kernel(const float* __restrict__ qkv, const float* __restrict__ Sprev,
            const float* __restrict__ kpre,
            __nv_bfloat16* __restrict__ yhi, __nv_bfloat16* __restrict__ ylo)
{
    extern __shared__ char smc[];
    float* qsf = (float*)smc;
    const uint32_t sb  = smem_u32(smc);
    const uint32_t PH  = sb,           PL  = sb + 8192;
    const uint32_t QH  = sb + 16384,   QL  = sb + 24576;
    const uint32_t KH  = sb + 32768,   KL  = sb + 40960;
    const uint32_t VTH = sb + 49152,   VTL = sb + 57344;
    const uint32_t STH = sb + 65536,   STL = sb + 73728;

    const int c = blockIdx.x, bh = blockIdx.y;
    const int b = bh >> 4, h = bh & 15;
    const int tid = threadIdx.x;
    const int wid = tid >> 5, lane = tid & 31;
    const size_t rowbase = ((size_t)(b * T_ + c * CHUNK)) * (3 * D_) + h * L_;
    const size_t sbase = ((size_t)bh * NC + c) * (L_ * L_);

    for (int i = tid; i < CHUNK * 16; i += 128) {
        int t = i >> 4, f = (i & 15) << 2;
        *(float4*)&qsf[t * L_ + f] =
            *(const float4*)&qkv[rowbase + (size_t)t * (3 * D_) + f];
    }
    for (int i = tid; i < 1024; i += 128) {
        int t = i >> 4, f = (i & 15) << 2;
        float4 kv4 = *(const float4*)&qkv[rowbase + (size_t)t * (3 * D_) + D_ + f];
        uint32_t hp, lp;
        split2(kv4.x, kv4.y, hp, lp);
        sts32(sw_addr(KH, t, f), hp);     sts32(sw_addr(KL, t, f), lp);
        split2(kv4.z, kv4.w, hp, lp);
        sts32(sw_addr(KH, t, f + 2), hp); sts32(sw_addr(KL, t, f + 2), lp);
    }
    for (int i = tid; i < 512; i += 128) {
        int t0 = (i >> 4) * 2;
        int m0 = (i & 15) << 2;
        const float* v0 = &qkv[rowbase + (size_t)t0 * (3 * D_) + 2 * D_];
        float4 a = *(const float4*)&v0[m0];
        float4 bvec = *(const float4*)&v0[3 * D_ + m0];
        uint32_t hp, lp;
        split2(a.x, bvec.x, hp, lp);
        sts32(sw_addr(VTH, m0 + 0, t0), hp); sts32(sw_addr(VTL, m0 + 0, t0), lp);
        split2(a.y, bvec.y, hp, lp);
        sts32(sw_addr(VTH, m0 + 1, t0), hp); sts32(sw_addr(VTL, m0 + 1, t0), lp);
        split2(a.z, bvec.z, hp, lp);
        sts32(sw_addr(VTH, m0 + 2, t0), hp); sts32(sw_addr(VTL, m0 + 2, t0), lp);
        split2(a.w, bvec.w, hp, lp);
        sts32(sw_addr(VTH, m0 + 3, t0), hp); sts32(sw_addr(VTL, m0 + 3, t0), lp);
    }
    for (int i = tid; i < 512; i += 128) {
        int l0 = (i >> 4) * 2;
        int m0 = (i & 15) << 2;
        const float* s0 = &Sprev[sbase + (size_t)l0 * L_];
        float4 a = *(const float4*)&s0[m0];
        float4 bvec = *(const float4*)&s0[L_ + m0];
        uint32_t hp, lp;
        split2(a.x, bvec.x, hp, lp);
        sts32(sw_addr(STH, m0 + 0, l0), hp); sts32(sw_addr(STL, m0 + 0, l0), lp);
        split2(a.y, bvec.y, hp, lp);
        sts32(sw_addr(STH, m0 + 1, l0), hp); sts32(sw_addr(STL, m0 + 1, l0), lp);
        split2(a.z, bvec.z, hp, lp);
        sts32(sw_addr(STH, m0 + 2, l0), hp); sts32(sw_addr(STL, m0 + 2, l0), lp);
        split2(a.w, bvec.w, hp, lp);
        sts32(sw_addr(STH, m0 + 3, l0), hp); sts32(sw_addr(STL, m0 + 3, l0), lp);
    }
    __syncthreads();

    if (tid < L_) {
        const int l = tid;
        float acc = kpre[((size_t)bh * NC + c) * L_ + l];
        for (int t = 0; t < CHUNK; t++) {
            acc += lds_bf16(sw_addr(KH, t, l)) + lds_bf16(sw_addr(KL, t, l));
            qsf[t * L_ + l] = __fdividef(qsf[t * L_ + l], acc);
        }
    }
    __syncthreads();

    for (int i = tid; i < 2048; i += 128) {
        int row = i >> 5, col = (i & 31) * 2;
        uint32_t hp, lp;
        split2(qsf[row * L_ + col], qsf[row * L_ + col + 1], hp, lp);
        sts32(sw_addr(QH, row, col), hp);
        sts32(sw_addr(QL, row, col), lp);
    }
    __syncthreads();

    const int wm = wid * 16;
    const int a_row = (lane & 15);
    const int a_khalf = lane >> 4;
    const int b_grp = (lane >> 4) & 1;
    const int b_khalf = (lane >> 3) & 1;
    const int b_row = lane & 7;
    const int g = lane >> 2, tig = lane & 3;

    float accP[8][4];
#pragma unroll
    for (int nt = 0; nt < 8; nt++)
#pragma unroll
        for (int e = 0; e < 4; e++) accP[nt][e] = 0.f;

#pragma unroll
    for (int kk = 0; kk < 4; kk++) {
        uint32_t ah[4], al[4];
        {
            int row = wm + a_row;
            int chunk = 2 * kk + a_khalf;
            uint32_t off = (uint32_t)(row * 128 + ((chunk ^ (row & 7)) << 4));
            ldsm_x4(QH + off, ah[0], ah[1], ah[2], ah[3]);
            ldsm_x4(QL + off, al[0], al[1], al[2], al[3]);
        }
        uint32_t bh_[4][4], bl_[4][4];
#pragma unroll
        for (int np = 0; np < 4; np++) {
            int row = np * 16 + b_grp * 8 + b_row;
            int chunk = 2 * kk + b_khalf;
            uint32_t off = (uint32_t)(row * 128 + ((chunk ^ (row & 7)) << 4));
            ldsm_x4(KH + off, bh_[np][0], bh_[np][1], bh_[np][2], bh_[np][3]);
            ldsm_x4(KL + off, bl_[np][0], bl_[np][1], bl_[np][2], bl_[np][3]);
        }
#pragma unroll
        for (int p = 0; p < 3; p++) {
            const uint32_t* af = (p == 2) ? al : ah;
#pragma unroll
            for (int nt = 0; nt < 8; nt++) {
                const uint32_t* bf = (p == 1) ? &bl_[nt >> 1][(nt & 1) * 2]
                                              : &bh_[nt >> 1][(nt & 1) * 2];
                mma_bf16(accP[nt], af, bf);
            }
        }
    }

    {
        int r0 = wm + g, r1 = wm + g + 8;
#pragma unroll
        for (int nt = 0; nt < 8; nt++) {
            int colp = nt * 8 + 2 * tig;
            float p00 = (colp     <= r0) ? accP[nt][0] : 0.f;
            float p01 = (colp + 1 <= r0) ? accP[nt][1] : 0.f;
            float p10 = (colp     <= r1) ? accP[nt][2] : 0.f;
            float p11 = (colp + 1 <= r1) ? accP[nt][3] : 0.f;
            uint32_t hp, lp;
            split2(p00, p01, hp, lp);
            sts32(sw_addr(PH, r0, colp), hp);
            sts32(sw_addr(PL, r0, colp), lp);
            split2(p10, p11, hp, lp);
            sts32(sw_addr(PH, r1, colp), hp);
            sts32(sw_addr(PL, r1, colp), lp);
        }
    }
    __syncthreads();

    float acc[8][4];
#pragma unroll
    for (int nt = 0; nt < 8; nt++)
#pragma unroll
        for (int e = 0; e < 4; e++) acc[nt][e] = 0.f;

#pragma unroll
    for (int half = 0; half < 2; half++) {
        const uint32_t AH = half ? QH : PH, AL = half ? QL : PL;
        const uint32_t BH = half ? STH : VTH, BL = half ? STL : VTL;
#pragma unroll
        for (int kk = 0; kk < 4; kk++) {
            uint32_t ah[4], al[4];
            {
                int row = wm + a_row;
                int chunk = 2 * kk + a_khalf;
                uint32_t off = (uint32_t)(row * 128 + ((chunk ^ (row & 7)) << 4));
                ldsm_x4(AH + off, ah[0], ah[1], ah[2], ah[3]);
                ldsm_x4(AL + off, al[0], al[1], al[2], al[3]);
            }
            uint32_t bh_[4][4], bl_[4][4];
#pragma unroll
            for (int np = 0; np < 4; np++) {
                int row = np * 16 + b_grp * 8 + b_row;
                int chunk = 2 * kk + b_khalf;
                uint32_t off = (uint32_t)(row * 128 + ((chunk ^ (row & 7)) << 4));
                ldsm_x4(BH + off, bh_[np][0], bh_[np][1], bh_[np][2], bh_[np][3]);
                ldsm_x4(BL + off, bl_[np][0], bl_[np][1], bl_[np][2], bl_[np][3]);
            }
#pragma unroll
            for (int p = 0; p < 3; p++) {
                const uint32_t* af = (p == 2) ? al : ah;
#pragma unroll
                for (int nt = 0; nt < 8; nt++) {
                    const uint32_t* bf = (p == 1) ? &bl_[nt >> 1][(nt & 1) * 2]
                                                  : &bh_[nt >> 1][(nt & 1) * 2];
                    mma_bf16(acc[nt], af, bf);
                }
            }
        }
    }

    {
        int r0 = wm + g;
#pragma unroll
        for (int dr = 0; dr < 2; dr++) {
            int row = r0 + dr * 8;
            size_t ybase = ((size_t)(b * T_ + c * CHUNK + row)) * D_ + h * L_;
#pragma unroll
            for (int nt = 0; nt < 8; nt++) {
                int colp = nt * 8 + 2 * tig;
                float v0 = acc[nt][2 * dr], v1 = acc[nt][2 * dr + 1];
                uint32_t hp, lp;
                split2(v0, v1, hp, lp);
                *(uint32_t*)&yhi[ybase + colp] = hp;
                *(uint32_t*)&ylo[ybase + colp] = lp;
            }
        }
    }
}

// ---------------------------------------------------------------------------
extern "C" void kernel_launch(void* const* d_in, const int* in_sizes, int n_in,
                              void* d_out, int out_size)
{
    const float* x  = (const float*)d_in[0];
    const float* w  = (const float*)d_in[1];
    const float* wo = (const float*)d_in[2];
    float* out = (float*)d_out;

    float *qkv, *Sc, *ks;
    __nv_bfloat16 *xhi, *xlo, *whi, *wlo, *wothi, *wotlo, *yhi, *ylo;
    cudaGetSymbolAddress((void**)&qkv, g_qkv);
    cudaGetSymbolAddress((void**)&Sc,  g_Sc);
    cudaGetSymbolAddress((void**)&ks,  g_ks);
    cudaGetSymbolAddress((void**)&xhi, g_xhi);
    cudaGetSymbolAddress((void**)&xlo, g_xlo);
    cudaGetSymbolAddress((void**)&whi, g_whi);
    cudaGetSymbolAddress((void**)&wlo, g_wlo);
    cudaGetSymbolAddress((void**)&wothi, g_wothi);
    cudaGetSymbolAddress((void**)&wotlo, g_wotlo);
    cudaGetSymbolAddress((void**)&yhi, g_yhi);
    cudaGetSymbolAddress((void**)&ylo, g_ylo);

    cudaFuncSetAttribute(gemm_mma<0>,
                         cudaFuncAttributeMaxDynamicSharedMemorySize, G_SMEM);
    cudaFuncSetAttribute(gemm_mma<1>,
                         cudaFuncAttributeMaxDynamicSharedMemorySize, G_SMEM);
    cudaFuncSetAttribute(chunkstate_kernel,
                         cudaFuncAttributeMaxDynamicSharedMemorySize, 32768);
    cudaFuncSetAttribute(attn_kernel,
                         cudaFuncAttributeMaxDynamicSharedMemorySize, AT_SMEM);

    // 0) fused split of x, w, w_out^T
    prep_inputs_kernel<<<NBX + NBW + 1024, 256>>>(x, w, wo);
    // 1) qkv = x @ w^T with fused softmax(q)/exp(k) epilogue (2 CTAs/SM)
    gemm_mma<1><<<dim3(3 * D_ / 64, BT_ / 128), 128, G_SMEM>>>(
        xhi, xlo, whi, wlo, qkv, 3 * D_, D_);
    // 2) per-chunk states + k sums
    chunkstate_kernel<<<dim3(NC, BH_), 256, 32768>>>(qkv, Sc, ks);
    // 3) exclusive prefix over chunks
    prefix_kernel<<<dim3(BH_, 16), 256>>>(Sc, ks);
    // 4) tensor-core chunk attention -> y (bf16 split)
    attn_kernel<<<dim3(NC, BH_), 128, AT_SMEM>>>(qkv, Sc, ks, yhi, ylo);
    // 5) out = y @ w_out
    gemm_mma<0><<<dim3(D_ / 64, BT_ / 128), 128, G_SMEM>>>(
        yhi, ylo, wothi, wotlo, out, D_, D_);
}

// round 13
// speedup vs baseline: 1.7265x; 1.1591x over previous
#include <cuda_runtime.h>
#include <cuda_bf16.h>
#include <cuda_fp16.h>
#include <cstdint>

// Problem constants
#define B_   4
#define T_   2048
#define D_   1024
#define H_   16
#define L_   64
#define BT_  (B_*T_)        // 8192
#define BH_  (B_*H_)        // 64
#define CHUNK 64
#define NC   (T_/CHUNK)     // 32

// ---------------------------------------------------------------------------
// Scratch (device globals; no allocation allowed)
// ---------------------------------------------------------------------------
__device__ float g_qkv[(size_t)BT_ * 3 * D_];        // (8192, 3072)  qs|k_exp|v fp32
__device__ float g_Sc [(size_t)BH_ * NC * L_ * L_];  // chunk states -> excl prefix
__device__ float g_ks [(size_t)BH_ * NC * L_];       // chunk k-sums -> excl prefix
__device__ __half g_xh[(size_t)BT_ * D_];            // fp16 hi of x (no lo needed)
__device__ __half g_wh[(size_t)3 * D_ * D_];         // fp16 hi of w
__device__ __half g_wl[(size_t)3 * D_ * D_];         // fp16 lo of w
__device__ __nv_bfloat16 g_wothi[(size_t)D_ * D_];   // w_out^T (bf16 3-pass path)
__device__ __nv_bfloat16 g_wotlo[(size_t)D_ * D_];
__device__ __nv_bfloat16 g_yhi[(size_t)BT_ * D_];
__device__ __nv_bfloat16 g_ylo[(size_t)BT_ * D_];

// ---------------------------------------------------------------------------
// PTX helpers (baseline sm_80+ instructions only — harness targets plain sm_103)
// ---------------------------------------------------------------------------
__device__ __forceinline__ uint32_t smem_u32(const void* p) {
    uint32_t a;
    asm("{ .reg .u64 t; cvta.to.shared.u64 t, %1; cvt.u32.u64 %0, t; }" : "=r"(a) : "l"(p));
    return a;
}

__device__ __forceinline__ void cp_async16(uint32_t dst, const void* src) {
    asm volatile("cp.async.cg.shared.global [%0], [%1], 16;" :: "r"(dst), "l"(src) : "memory");
}
__device__ __forceinline__ void cp_commit() {
    asm volatile("cp.async.commit_group;" ::: "memory");
}
__device__ __forceinline__ void cp_wait1() {
    asm volatile("cp.async.wait_group 1;" ::: "memory");
}
__device__ __forceinline__ void cp_wait0() {
    asm volatile("cp.async.wait_group 0;" ::: "memory");
}

__device__ __forceinline__ void ldsm_x4(uint32_t addr, uint32_t& r0, uint32_t& r1,
                                        uint32_t& r2, uint32_t& r3) {
    asm volatile("ldmatrix.sync.aligned.m8n8.x4.shared.b16 {%0,%1,%2,%3}, [%4];"
                 : "=r"(r0), "=r"(r1), "=r"(r2), "=r"(r3) : "r"(addr));
}

__device__ __forceinline__ void mma_bf16(float* c, const uint32_t* a, const uint32_t* b) {
    asm volatile(
        "mma.sync.aligned.m16n8k16.row.col.f32.bf16.bf16.f32 "
        "{%0,%1,%2,%3}, {%4,%5,%6,%7}, {%8,%9}, {%0,%1,%2,%3};"
        : "+f"(c[0]), "+f"(c[1]), "+f"(c[2]), "+f"(c[3])
        : "r"(a[0]), "r"(a[1]), "r"(a[2]), "r"(a[3]), "r"(b[0]), "r"(b[1]));
}

__device__ __forceinline__ void mma_f16(float* c, const uint32_t* a, const uint32_t* b) {
    asm volatile(
        "mma.sync.aligned.m16n8k16.row.col.f32.f16.f16.f32 "
        "{%0,%1,%2,%3}, {%4,%5,%6,%7}, {%8,%9}, {%0,%1,%2,%3};"
        : "+f"(c[0]), "+f"(c[1]), "+f"(c[2]), "+f"(c[3])
        : "r"(a[0]), "r"(a[1]), "r"(a[2]), "r"(a[3]), "r"(b[0]), "r"(b[1]));
}

__device__ __forceinline__ void sts32(uint32_t addr, uint32_t v) {
    asm volatile("st.shared.b32 [%0], %1;" :: "r"(addr), "r"(v) : "memory");
}

__device__ __forceinline__ float lds_bf16(uint32_t addr) {
    uint16_t v;
    asm volatile("ld.shared.u16 %0, [%1];" : "=h"(v) : "r"(addr));
    __nv_bfloat16 b = *(__nv_bfloat16*)&v;
    return __bfloat162float(b);
}

// split two floats -> packed bf16x2 hi and lo words
__device__ __forceinline__ void split2(float a, float b, uint32_t& hp, uint32_t& lp) {
    __nv_bfloat16 h0 = __float2bfloat16(a), h1 = __float2bfloat16(b);
    __nv_bfloat16 l0 = __float2bfloat16(a - __bfloat162float(h0));
    __nv_bfloat16 l1 = __float2bfloat16(b - __bfloat162float(h1));
    __nv_bfloat162 hv = __halves2bfloat162(h0, h1);
    __nv_bfloat162 lv = __halves2bfloat162(l0, l1);
    hp = *(uint32_t*)&hv;
    lp = *(uint32_t*)&lv;
}

// split two floats -> packed fp16x2 hi and lo words
__device__ __forceinline__ void split2h(float a, float b, uint32_t& hp, uint32_t& lp) {
    __half h0 = __float2half(a), h1 = __float2half(b);
    __half l0 = __float2half(a - __half2float(h0));
    __half l1 = __float2half(b - __half2float(h1));
    __half2 hv = __halves2half2(h0, h1);
    __half2 lv = __halves2half2(l0, l1);
    hp = *(uint32_t*)&hv;
    lp = *(uint32_t*)&lv;
}

// swizzled byte address of bf16/fp16 (row, col) in a 64-col (128B-row) tile
__device__ __forceinline__ uint32_t sw_addr(uint32_t base, int row, int col) {
    return base + (uint32_t)(row * 128 + ((((col >> 3) ^ (row & 7))) << 4) + ((col & 7) * 2));
}

// ---------------------------------------------------------------------------
// ONE fused input-prep kernel:
//   blocks [0, NBX)          : x -> fp16 hi only
//   blocks [NBX, NBX+NBW)    : w -> fp16 hi + lo
//   blocks [.., +1024)       : w_out^T -> bf16 hi + lo
// ---------------------------------------------------------------------------
#define NBX (BT_ * D_ / 4 / 256)          // 8192
#define NBW (3 * D_ * D_ / 4 / 256)       // 3072

__global__ void __launch_bounds__(256)
prep_inputs_kernel(const float* __restrict__ x, const float* __restrict__ w,
                   const float* __restrict__ wo)
{
    const int bid = blockIdx.x;
    if (bid < NBX) {
        int i = bid * 256 + threadIdx.x;
        float4 v = ((const float4*)x)[i];
        __half2 h01 = __halves2half2(__float2half(v.x), __float2half(v.y));
        __half2 h23 = __halves2half2(__float2half(v.z), __float2half(v.w));
        ((__half2*)g_xh)[2 * i]     = h01;
        ((__half2*)g_xh)[2 * i + 1] = h23;
    } else if (bid < NBX + NBW) {
        int i = (bid - NBX) * 256 + threadIdx.x;
        float4 v = ((const float4*)w)[i];
        uint32_t h01, l01, h23, l23;
        split2h(v.x, v.y, h01, l01);
        split2h(v.z, v.w, h23, l23);
        ((uint32_t*)g_wh)[2 * i]     = h01;
        ((uint32_t*)g_wh)[2 * i + 1] = h23;
        ((uint32_t*)g_wl)[2 * i]     = l01;
        ((uint32_t*)g_wl)[2 * i + 1] = l23;
    } else {
        __shared__ float tile[32][33];
        int tb = bid - NBX - NBW;            // 0..1023
        int n0 = (tb & 31) * 32, k0 = (tb >> 5) * 32;
        int tx = threadIdx.x & 31, ty = threadIdx.x >> 5;   // (32,8)
        for (int r = ty; r < 32; r += 8)
            tile[r][tx] = wo[(size_t)(k0 + r) * D_ + n0 + tx];
        __syncthreads();
        for (int r = ty; r < 32; r += 8) {
            float v = tile[tx][r];
            __nv_bfloat16 h = __float2bfloat16(v);
            size_t idx = (size_t)(n0 + r) * D_ + k0 + tx;
            g_wothi[idx] = h;
            g_wotlo[idx] = __float2bfloat16(v - __bfloat162float(h));
        }
    }
}

// ---------------------------------------------------------------------------
// GEMM1 (qkv): fp16 2-pass split. C = xh*(wh+wl)^T.
// 128x64 tile, BK=64, 128 threads (4 warps along M), 3-stage cp.async,
// stage = 32KB (Ah 16K, Bh 8K, Bl 8K) -> 96KB/CTA -> 2 CTAs/SM.
// Fused epilogue: softmax(q*0.125) / exp(k*0.125)+1e-6 / passthrough v.
// ---------------------------------------------------------------------------
#define GQ_A 16384
#define GQ_B 8192
#define GQ_STAGE (GQ_A + 2 * GQ_B)          // 32768
#define GQ_SMEM  (3 * GQ_STAGE)             // 98304

__global__ void __launch_bounds__(128, 2)
gemm_qkv(const __half* __restrict__ Ah, const __half* __restrict__ Bh,
         const __half* __restrict__ Bl, float* __restrict__ C, int N, int K)
{
    extern __shared__ char smem[];
    const uint32_t smem_base = smem_u32(smem);
    const int tid = threadIdx.x;
    const int wid = tid >> 5, lane = tid & 31;
    const int m0 = blockIdx.y * 128, n0 = blockIdx.x * 64;
    const int wm = wid * 32;

    auto load_stage = [&](int kt, int s) {
        const int k0 = kt << 6;
        const uint32_t sb = smem_base + s * GQ_STAGE;
        // A hi: 1024 chunks, 8/thread
#pragma unroll
        for (int ii = 0; ii < 8; ii++) {
            int j = tid + ii * 128;
            int r = j >> 3, c = j & 7;
            const void* g = &Ah[(size_t)(m0 + r) * K + k0 + c * 8];
            cp_async16(sb + (uint32_t)(r * 128 + ((c ^ (r & 7)) << 4)), g);
        }
        // B hi/lo: 512 chunks each, 4/thread
#pragma unroll
        for (int tI = 0; tI < 2; tI++) {
            const __half* src = tI ? Bl : Bh;
            const uint32_t tb = sb + GQ_A + tI * GQ_B;
#pragma unroll
            for (int ii = 0; ii < 4; ii++) {
                int j = tid + ii * 128;
                int r = j >> 3, c = j & 7;
                const void* g = &src[(size_t)(n0 + r) * K + k0 + c * 8];
                cp_async16(tb + (uint32_t)(r * 128 + ((c ^ (r & 7)) << 4)), g);
            }
        }
    };

    float acc[2][8][4];
#pragma unroll
    for (int mt = 0; mt < 2; mt++)
#pragma unroll
        for (int nt = 0; nt < 8; nt++)
#pragma unroll
            for (int e = 0; e < 4; e++) acc[mt][nt][e] = 0.f;

    const int NKT = K >> 6;   // 16
    load_stage(0, 0); cp_commit();
    load_stage(1, 1); cp_commit();

    const int a_row = (lane & 15);
    const int a_khalf = lane >> 4;
    const int b_grp = (lane >> 4) & 1;
    const int b_khalf = (lane >> 3) & 1;
    const int b_row = lane & 7;

    int s = 0, sload = 2;
    for (int kt = 0; kt < NKT; kt++) {
        const uint32_t st = smem_base + s * GQ_STAGE;
        cp_wait1();
        __syncthreads();

        if (kt + 2 < NKT) load_stage(kt + 2, sload);
        cp_commit();

        const uint32_t aA = st;
        const uint32_t aB = st + GQ_A;

#pragma unroll
        for (int kk = 0; kk < 4; kk++) {
            uint32_t ah[2][4];
#pragma unroll
            for (int mt = 0; mt < 2; mt++) {
                int row = wm + mt * 16 + a_row;
                int chunk = 2 * kk + a_khalf;
                uint32_t off = (uint32_t)(row * 128 + ((chunk ^ (row & 7)) << 4));
                ldsm_x4(aA + off, ah[mt][0], ah[mt][1], ah[mt][2], ah[mt][3]);
            }
            uint32_t bh[4][4], bl[4][4];
#pragma unroll
            for (int np = 0; np < 4; np++) {
                int row = np * 16 + b_grp * 8 + b_row;
                int chunk = 2 * kk + b_khalf;
                uint32_t off = (uint32_t)(row * 128 + ((chunk ^ (row & 7)) << 4));
                ldsm_x4(aB + off, bh[np][0], bh[np][1], bh[np][2], bh[np][3]);
                ldsm_x4(aB + GQ_B + off, bl[np][0], bl[np][1], bl[np][2], bl[np][3]);
            }
            // 2 passes: ah*bh, ah*bl — reuse distance 16 MMAs
#pragma unroll
            for (int p = 0; p < 2; p++) {
#pragma unroll
                for (int mt = 0; mt < 2; mt++) {
#pragma unroll
                    for (int nt = 0; nt < 8; nt++) {
                        const uint32_t* bf = p ? &bl[nt >> 1][(nt & 1) * 2]
                                               : &bh[nt >> 1][(nt & 1) * 2];
                        mma_f16(acc[mt][nt], ah[mt], bf);
                    }
                }
            }
        }
        s = (s == 2) ? 0 : s + 1;
        sload = (sload == 2) ? 0 : sload + 1;
    }

    const int g = lane >> 2, tig = lane & 3;
    const int gcol0 = n0;              // warp spans full 64-col tile (one head)

    if (gcol0 < D_) {
        // q region: per-head softmax
#pragma unroll
        for (int mt = 0; mt < 2; mt++) {
            float vA[16], vB[16];
#pragma unroll
            for (int nt = 0; nt < 8; nt++) {
                vA[2*nt]   = acc[mt][nt][0] * 0.125f;
                vA[2*nt+1] = acc[mt][nt][1] * 0.125f;
                vB[2*nt]   = acc[mt][nt][2] * 0.125f;
                vB[2*nt+1] = acc[mt][nt][3] * 0.125f;
            }
            float mA = vA[0], mB = vB[0];
#pragma unroll
            for (int i = 1; i < 16; i++) { mA = fmaxf(mA, vA[i]); mB = fmaxf(mB, vB[i]); }
            mA = fmaxf(mA, __shfl_xor_sync(0xffffffffu, mA, 1));
            mA = fmaxf(mA, __shfl_xor_sync(0xffffffffu, mA, 2));
            mB = fmaxf(mB, __shfl_xor_sync(0xffffffffu, mB, 1));
            mB = fmaxf(mB, __shfl_xor_sync(0xffffffffu, mB, 2));
            float sA = 0.f, sB = 0.f;
#pragma unroll
            for (int i = 0; i < 16; i++) {
                vA[i] = expf(vA[i] - mA); sA += vA[i];
                vB[i] = expf(vB[i] - mB); sB += vB[i];
            }
            sA += __shfl_xor_sync(0xffffffffu, sA, 1);
            sA += __shfl_xor_sync(0xffffffffu, sA, 2);
            sB += __shfl_xor_sync(0xffffffffu, sB, 1);
            sB += __shfl_xor_sync(0xffffffffu, sB, 2);
            float iA = 1.f / sA, iB = 1.f / sB;
            int row = m0 + wm + mt * 16 + g;
#pragma unroll
            for (int nt = 0; nt < 8; nt++) {
                int col = gcol0 + nt * 8 + 2 * tig;
                *(float2*)&C[(size_t)row * N + col]       = make_float2(vA[2*nt]*iA, vA[2*nt+1]*iA);
                *(float2*)&C[(size_t)(row + 8) * N + col] = make_float2(vB[2*nt]*iB, vB[2*nt+1]*iB);
            }
        }
    } else if (gcol0 < 2 * D_) {
        // k region: exp(v*0.125)+1e-6
#pragma unroll
        for (int mt = 0; mt < 2; mt++) {
            int row = m0 + wm + mt * 16 + g;
#pragma unroll
            for (int nt = 0; nt < 8; nt++) {
                int col = gcol0 + nt * 8 + 2 * tig;
                float* c = acc[mt][nt];
                *(float2*)&C[(size_t)row * N + col] =
                    make_float2(expf(c[0]*0.125f)+1e-6f, expf(c[1]*0.125f)+1e-6f);
                *(float2*)&C[(size_t)(row + 8) * N + col] =
                    make_float2(expf(c[2]*0.125f)+1e-6f, expf(c[3]*0.125f)+1e-6f);
            }
        }
    } else {
        // v region: plain store
#pragma unroll
        for (int mt = 0; mt < 2; mt++) {
            int row = m0 + wm + mt * 16 + g;
#pragma unroll
            for (int nt = 0; nt < 8; nt++) {
                int col = gcol0 + nt * 8 + 2 * tig;
                float* c = acc[mt][nt];
                *(float2*)&C[(size_t)row * N + col]       = make_float2(c[0], c[1]);
                *(float2*)&C[(size_t)(row + 8) * N + col] = make_float2(c[2], c[3]);
            }
        }
    }
}

// ---------------------------------------------------------------------------
// GEMM2 (out): bf16 3-pass (unchanged R12 kernel, plain-store epilogue).
// 128x64 tile, 128 threads, 2-stage, 2 CTAs/SM.
// ---------------------------------------------------------------------------
#define GA_TILE 16384
#define GB_TILE 8192
#define G_STAGE (2*GA_TILE + 2*GB_TILE)     // 49152
#define G_SMEM  (2 * G_STAGE)               // 98304

__global__ void __launch_bounds__(128, 2)
gemm_out(const __nv_bfloat16* __restrict__ Ahi, const __nv_bfloat16* __restrict__ Alo,
         const __nv_bfloat16* __restrict__ Bhi, const __nv_bfloat16* __restrict__ Blo,
         float* __restrict__ C, int N, int K)
{
    extern __shared__ char smem[];
    const uint32_t smem_base = smem_u32(smem);
    const int tid = threadIdx.x;
    const int wid = tid >> 5, lane = tid & 31;
    const int m0 = blockIdx.y * 128, n0 = blockIdx.x * 64;
    const int wm = wid * 32;

    auto load_stage = [&](int kt, int s) {
        const int k0 = kt << 6;
        const uint32_t sb = smem_base + s * G_STAGE;
#pragma unroll
        for (int tI = 0; tI < 2; tI++) {
            const __nv_bfloat16* src = tI ? Alo : Ahi;
            const uint32_t tb = sb + tI * GA_TILE;
#pragma unroll
            for (int ii = 0; ii < 8; ii++) {
                int j = tid + ii * 128;
                int r = j >> 3, c = j & 7;
                const void* g = &src[(size_t)(m0 + r) * K + k0 + c * 8];
                cp_async16(tb + (uint32_t)(r * 128 + ((c ^ (r & 7)) << 4)), g);
            }
        }
#pragma unroll
        for (int tI = 0; tI < 2; tI++) {
            const __nv_bfloat16* src = tI ? Blo : Bhi;
            const uint32_t tb = sb + 2 * GA_TILE + tI * GB_TILE;
#pragma unroll
            for (int ii = 0; ii < 4; ii++) {
                int j = tid + ii * 128;
                int r = j >> 3, c = j & 7;
                const void* g = &src[(size_t)(n0 + r) * K + k0 + c * 8];
                cp_async16(tb + (uint32_t)(r * 128 + ((c ^ (r & 7)) << 4)), g);
            }
        }
    };

    float acc[2][8][4];
#pragma unroll
    for (int mt = 0; mt < 2; mt++)
#pragma unroll
        for (int nt = 0; nt < 8; nt++)
#pragma unroll
            for (int e = 0; e < 4; e++) acc[mt][nt][e] = 0.f;

    const int NKT = K >> 6;
    load_stage(0, 0); cp_commit();

    const int a_row = (lane & 15);
    const int a_khalf = lane >> 4;
    const int b_grp = (lane >> 4) & 1;
    const int b_khalf = (lane >> 3) & 1;
    const int b_row = lane & 7;

    for (int kt = 0; kt < NKT; kt++) {
        if (kt + 1 < NKT) {
            load_stage(kt + 1, (kt + 1) & 1);
            cp_commit();
            cp_wait1();
        } else {
            cp_wait0();
        }
        __syncthreads();

        const uint32_t st = smem_base + (kt & 1) * G_STAGE;
        const uint32_t aA = st;
        const uint32_t aB = st + 2 * GA_TILE;

#pragma unroll
        for (int kk = 0; kk < 4; kk++) {
            uint32_t ah[2][4], al[2][4];
#pragma unroll
            for (int mt = 0; mt < 2; mt++) {
                int row = wm + mt * 16 + a_row;
                int chunk = 2 * kk + a_khalf;
                uint32_t off = (uint32_t)(row * 128 + ((chunk ^ (row & 7)) << 4));
                ldsm_x4(aA + off, ah[mt][0], ah[mt][1], ah[mt][2], ah[mt][3]);
                ldsm_x4(aA + GA_TILE + off, al[mt][0], al[mt][1], al[mt][2], al[mt][3]);
            }
            uint32_t bh[4][4], bl[4][4];
#pragma unroll
            for (int np = 0; np < 4; np++) {
                int row = np * 16 + b_grp * 8 + b_row;
                int chunk = 2 * kk + b_khalf;
                uint32_t off = (uint32_t)(row * 128 + ((chunk ^ (row & 7)) << 4));
                ldsm_x4(aB + off, bh[np][0], bh[np][1], bh[np][2], bh[np][3]);
                ldsm_x4(aB + GB_TILE + off, bl[np][0], bl[np][1], bl[np][2], bl[np][3]);
            }
#pragma unroll
            for (int p = 0; p < 3; p++) {
#pragma unroll
                for (int mt = 0; mt < 2; mt++) {
                    const uint32_t* af = (p == 2) ? al[mt] : ah[mt];
#pragma unroll
                    for (int nt = 0; nt < 8; nt++) {
                        const uint32_t* bf = (p == 1) ? &bl[nt >> 1][(nt & 1) * 2]
                                                      : &bh[nt >> 1][(nt & 1) * 2];
                        mma_bf16(acc[mt][nt], af, bf);
                    }
                }
            }
        }
        __syncthreads();
    }

    const int g = lane >> 2, tig = lane & 3;
#pragma unroll
    for (int mt = 0; mt < 2; mt++) {
        int row = m0 + wm + mt * 16 + g;
#pragma unroll
        for (int nt = 0; nt < 8; nt++) {
            int col = n0 + nt * 8 + 2 * tig;
            float* c = acc[mt][nt];
            *(float2*)&C[(size_t)row * N + col]       = make_float2(c[0], c[1]);
            *(float2*)&C[(size_t)(row + 8) * N + col] = make_float2(c[2], c[3]);
        }
    }
}

// ---------------------------------------------------------------------------
// Per-chunk state (CHUNK=64) — unchanged
// ---------------------------------------------------------------------------
__global__ void __launch_bounds__(256)
chunkstate_kernel(const float* __restrict__ qkv,
                  float* __restrict__ Sc, float* __restrict__ ks)
{
    extern __shared__ float sm[];
    float* Ks = sm;
    float* Vs = sm + CHUNK * L_;
    const int c = blockIdx.x, bh = blockIdx.y;
    const int b = bh >> 4, h = bh & 15;
    const size_t rowbase = ((size_t)(b * T_ + c * CHUNK)) * (3 * D_) + h * L_;

    for (int i = threadIdx.x; i < CHUNK * 16; i += 256) {
        int t = i >> 4, f = (i & 15) << 2;
        size_t g = rowbase + (size_t)t * (3 * D_) + f;
        *(float4*)&Ks[t * L_ + f] = *(const float4*)&qkv[g + D_];
        *(float4*)&Vs[t * L_ + f] = *(const float4*)&qkv[g + 2 * D_];
    }
    __syncthreads();

    const int l0 = (threadIdx.x >> 4) << 2;
    const int m0 = (threadIdx.x & 15) << 2;
    float acc[4][4];
#pragma unroll
    for (int i = 0; i < 4; i++)
#pragma unroll
        for (int j = 0; j < 4; j++) acc[i][j] = 0.f;
    for (int t = 0; t < CHUNK; t++) {
        float a[4], v[4];
#pragma unroll
        for (int i = 0; i < 4; i++) a[i] = Ks[t * L_ + l0 + i];
#pragma unroll
        for (int j = 0; j < 4; j++) v[j] = Vs[t * L_ + m0 + j];
#pragma unroll
        for (int i = 0; i < 4; i++)
#pragma unroll
            for (int j = 0; j < 4; j++) acc[i][j] += a[i] * v[j];
    }
    const size_t sbase = ((size_t)bh * NC + c) * (L_ * L_);
#pragma unroll
    for (int i = 0; i < 4; i++)
#pragma unroll
        for (int j = 0; j < 4; j++)
            Sc[sbase + (size_t)(l0 + i) * L_ + m0 + j] = acc[i][j];

    if (threadIdx.x < L_) {
        float s = 0.f;
        for (int t = 0; t < CHUNK; t++) s += Ks[t * L_ + threadIdx.x];
        ks[((size_t)bh * NC + c) * L_ + threadIdx.x] = s;
    }
}

// ---------------------------------------------------------------------------
// Exclusive prefix over chunks — unchanged
// ---------------------------------------------------------------------------
__global__ void prefix_kernel(float* __restrict__ Sc, float* __restrict__ ks)
{
    const int bh = blockIdx.x;
    const int e = blockIdx.y * 256 + threadIdx.x;
    const size_t base = (size_t)bh * NC * (L_ * L_);
    {
        float acc = 0.f;
#pragma unroll
        for (int c = 0; c < NC; c++) {
            size_t idx = base + (size_t)c * (L_ * L_) + e;
            float tmp = Sc[idx];
            Sc[idx] = acc;
            acc += tmp;
        }
    }
    if (blockIdx.y == 0 && threadIdx.x < L_) {
        const size_t kb = (size_t)bh * NC * L_;
        float acc = 0.f;
#pragma unroll
        for (int c = 0; c < NC; c++) {
            size_t idx = kb + (size_t)c * L_ + threadIdx.x;
            float tmp = ks[idx];
            ks[idx] = acc;
            acc += tmp;
        }
    }
}

// ---------------------------------------------------------------------------
// Tensor-core chunk attention (unchanged from R12; 81920B smem -> 2 blocks/SM)
// ---------------------------------------------------------------------------
#define AT_SMEM 81920

__global__ void __launch_bounds__(128)
attn_kernel(const float* __restrict__ qkv, const float* __restrict__ Sprev,
            const float* __restrict__ kpre,
            __nv_bfloat16* __restrict__ yhi, __nv_bfloat16* __restrict__ ylo)
{
    extern __shared__ char smc[];
    float* qsf = (float*)smc;
    const uint32_t sb  = smem_u32(smc);
    const uint32_t PH  = sb,           PL  = sb + 8192;
    const uint32_t QH  = sb + 16384,   QL  = sb + 24576;
    const uint32_t KH  = sb + 32768,   KL  = sb + 40960;
    const uint32_t VTH = sb + 49152,   VTL = sb + 57344;
    const uint32_t STH = sb + 65536,   STL = sb + 73728;

    const int c = blockIdx.x, bh = blockIdx.y;
    const int b = bh >> 4, h = bh & 15;
    const int tid = threadIdx.x;
    const int wid = tid >> 5, lane = tid & 31;
    const size_t rowbase = ((size_t)(b * T_ + c * CHUNK)) * (3 * D_) + h * L_;
    const size_t sbase = ((size_t)bh * NC + c) * (L_ * L_);

    for (int i = tid; i < CHUNK * 16; i += 128) {
        int t = i >> 4, f = (i & 15) << 2;
        *(float4*)&qsf[t * L_ + f] =
            *(const float4*)&qkv[rowbase + (size_t)t * (3 * D_) + f];
    }
    for (int i = tid; i < 1024; i += 128) {
        int t = i >> 4, f = (i & 15) << 2;
        float4 kv4 = *(const float4*)&qkv[rowbase + (size_t)t * (3 * D_) + D_ + f];
        uint32_t hp, lp;
        split2(kv4.x, kv4.y, hp, lp);
        sts32(sw_addr(KH, t, f), hp);     sts32(sw_addr(KL, t, f), lp);
        split2(kv4.z, kv4.w, hp, lp);
        sts32(sw_addr(KH, t, f + 2), hp); sts32(sw_addr(KL, t, f + 2), lp);
    }
    for (int i = tid; i < 512; i += 128) {
        int t0 = (i >> 4) * 2;
        int m0 = (i & 15) << 2;
        const float* v0 = &qkv[rowbase + (size_t)t0 * (3 * D_) + 2 * D_];
        float4 a = *(const float4*)&v0[m0];
        float4 bvec = *(const float4*)&v0[3 * D_ + m0];
        uint32_t hp, lp;
        split2(a.x, bvec.x, hp, lp);
        sts32(sw_addr(VTH, m0 + 0, t0), hp); sts32(sw_addr(VTL, m0 + 0, t0), lp);
        split2(a.y, bvec.y, hp, lp);
        sts32(sw_addr(VTH, m0 + 1, t0), hp); sts32(sw_addr(VTL, m0 + 1, t0), lp);
        split2(a.z, bvec.z, hp, lp);
        sts32(sw_addr(VTH, m0 + 2, t0), hp); sts32(sw_addr(VTL, m0 + 2, t0), lp);
        split2(a.w, bvec.w, hp, lp);
        sts32(sw_addr(VTH, m0 + 3, t0), hp); sts32(sw_addr(VTL, m0 + 3, t0), lp);
    }
    for (int i = tid; i < 512; i += 128) {
        int l0 = (i >> 4) * 2;
        int m0 = (i & 15) << 2;
        const float* s0 = &Sprev[sbase + (size_t)l0 * L_];
        float4 a = *(const float4*)&s0[m0];
        float4 bvec = *(const float4*)&s0[L_ + m0];
        uint32_t hp, lp;
        split2(a.x, bvec.x, hp, lp);
        sts32(sw_addr(STH, m0 + 0, l0), hp); sts32(sw_addr(STL, m0 + 0, l0), lp);
        split2(a.y, bvec.y, hp, lp);
        sts32(sw_addr(STH, m0 + 1, l0), hp); sts32(sw_addr(STL, m0 + 1, l0), lp);
        split2(a.z, bvec.z, hp, lp);
        sts32(sw_addr(STH, m0 + 2, l0), hp); sts32(sw_addr(STL, m0 + 2, l0), lp);
        split2(a.w, bvec.w, hp, lp);
        sts32(sw_addr(STH, m0 + 3, l0), hp); sts32(sw_addr(STL, m0 + 3, l0), lp);
    }
    __syncthreads();

    if (tid < L_) {
        const int l = tid;
        float acc = kpre[((size_t)bh * NC + c) * L_ + l];
        for (int t = 0; t < CHUNK; t++) {
            acc += lds_bf16(sw_addr(KH, t, l)) + lds_bf16(sw_addr(KL, t, l));
            qsf[t * L_ + l] = __fdividef(qsf[t * L_ + l], acc);
        }
    }
    __syncthreads();

    for (int i = tid; i < 2048; i += 128) {
        int row = i >> 5, col = (i & 31) * 2;
        uint32_t hp, lp;
        split2(qsf[row * L_ + col], qsf[row * L_ + col + 1], hp, lp);
        sts32(sw_addr(QH, row, col), hp);
        sts32(sw_addr(QL, row, col), lp);
    }
    __syncthreads();

    const int wm = wid * 16;
    const int a_row = (lane & 15);
    const int a_khalf = lane >> 4;
    const int b_grp = (lane >> 4) & 1;
    const int b_khalf = (lane >> 3) & 1;
    const int b_row = lane & 7;
    const int g = lane >> 2, tig = lane & 3;

    float accP[8][4];
#pragma unroll
    for (int nt = 0; nt < 8; nt++)
#pragma unroll
        for (int e = 0; e < 4; e++) accP[nt][e] = 0.f;

#pragma unroll
    for (int kk = 0; kk < 4; kk++) {
        uint32_t ah[4], al[4];
        {
            int row = wm + a_row;
            int chunk = 2 * kk + a_khalf;
            uint32_t off = (uint32_t)(row * 128 + ((chunk ^ (row & 7)) << 4));
            ldsm_x4(QH + off, ah[0], ah[1], ah[2], ah[3]);
            ldsm_x4(QL + off, al[0], al[1], al[2], al[3]);
        }
        uint32_t bh_[4][4], bl_[4][4];
#pragma unroll
        for (int np = 0; np < 4; np++) {
            int row = np * 16 + b_grp * 8 + b_row;
            int chunk = 2 * kk + b_khalf;
            uint32_t off = (uint32_t)(row * 128 + ((chunk ^ (row & 7)) << 4));
            ldsm_x4(KH + off, bh_[np][0], bh_[np][1], bh_[np][2], bh_[np][3]);
            ldsm_x4(KL + off, bl_[np][0], bl_[np][1], bl_[np][2], bl_[np][3]);
        }
#pragma unroll
        for (int p = 0; p < 3; p++) {
            const uint32_t* af = (p == 2) ? al : ah;
#pragma unroll
            for (int nt = 0; nt < 8; nt++) {
                const uint32_t* bf = (p == 1) ? &bl_[nt >> 1][(nt & 1) * 2]
                                              : &bh_[nt >> 1][(nt & 1) * 2];
                mma_bf16(accP[nt], af, bf);
            }
        }
    }

    {
        int r0 = wm + g, r1 = wm + g + 8;
#pragma unroll
        for (int nt = 0; nt < 8; nt++) {
            int colp = nt * 8 + 2 * tig;
            float p00 = (colp     <= r0) ? accP[nt][0] : 0.f;
            float p01 = (colp + 1 <= r0) ? accP[nt][1] : 0.f;
            float p10 = (colp     <= r1) ? accP[nt][2] : 0.f;
            float p11 = (colp + 1 <= r1) ? accP[nt][3] : 0.f;
            uint32_t hp, lp;
            split2(p00, p01, hp, lp);
            sts32(sw_addr(PH, r0, colp), hp);
            sts32(sw_addr(PL, r0, colp), lp);
            split2(p10, p11, hp, lp);
            sts32(sw_addr(PH, r1, colp), hp);
            sts32(sw_addr(PL, r1, colp), lp);
        }
    }
    __syncthreads();

    float acc[8][4];
#pragma unroll
    for (int nt = 0; nt < 8; nt++)
#pragma unroll
        for (int e = 0; e < 4; e++) acc[nt][e] = 0.f;

#pragma unroll
    for (int half = 0; half < 2; half++) {
        const uint32_t AH = half ? QH : PH, AL = half ? QL : PL;
        const uint32_t BH = half ? STH : VTH, BL = half ? STL : VTL;
#pragma unroll
        for (int kk = 0; kk < 4; kk++) {
            uint32_t ah[4], al[4];
            {
                int row = wm + a_row;
                int chunk = 2 * kk + a_khalf;
                uint32_t off = (uint32_t)(row * 128 + ((chunk ^ (row & 7)) << 4));
                ldsm_x4(AH + off, ah[0], ah[1], ah[2], ah[3]);
                ldsm_x4(AL + off, al[0], al[1], al[2], al[3]);
            }
            uint32_t bh_[4][4], bl_[4][4];
#pragma unroll
            for (int np = 0; np < 4; np++) {
                int row = np * 16 + b_grp * 8 + b_row;
                int chunk = 2 * kk + b_khalf;
                uint32_t off = (uint32_t)(row * 128 + ((chunk ^ (row & 7)) << 4));
                ldsm_x4(BH + off, bh_[np][0], bh_[np][1], bh_[np][2], bh_[np][3]);
                ldsm_x4(BL + off, bl_[np][0], bl_[np][1], bl_[np][2], bl_[np][3]);
            }
#pragma unroll
            for (int p = 0; p < 3; p++) {
                const uint32_t* af = (p == 2) ? al : ah;
#pragma unroll
                for (int nt = 0; nt < 8; nt++) {
                    const uint32_t* bf = (p == 1) ? &bl_[nt >> 1][(nt & 1) * 2]
                                                  : &bh_[nt >> 1][(nt & 1) * 2];
                    mma_bf16(acc[nt], af, bf);
                }
            }
        }
    }

    {
        int r0 = wm + g;
#pragma unroll
        for (int dr = 0; dr < 2; dr++) {
            int row = r0 + dr * 8;
            size_t ybase = ((size_t)(b * T_ + c * CHUNK + row)) * D_ + h * L_;
#pragma unroll
            for (int nt = 0; nt < 8; nt++) {
                int colp = nt * 8 + 2 * tig;
                float v0 = acc[nt][2 * dr], v1 = acc[nt][2 * dr + 1];
                uint32_t hp, lp;
                split2(v0, v1, hp, lp);
                *(uint32_t*)&yhi[ybase + colp] = hp;
                *(uint32_t*)&ylo[ybase + colp] = lp;
            }
        }
    }
}

// ---------------------------------------------------------------------------
extern "C" void kernel_launch(void* const* d_in, const int* in_sizes, int n_in,
                              void* d_out, int out_size)
{
    const float* x  = (const float*)d_in[0];
    const float* w  = (const float*)d_in[1];
    const float* wo = (const float*)d_in[2];
    float* out = (float*)d_out;

    float *qkv, *Sc, *ks;
    __half *xh, *wh, *wl;
    __nv_bfloat16 *wothi, *wotlo, *yhi, *ylo;
    cudaGetSymbolAddress((void**)&qkv, g_qkv);
    cudaGetSymbolAddress((void**)&Sc,  g_Sc);
    cudaGetSymbolAddress((void**)&ks,  g_ks);
    cudaGetSymbolAddress((void**)&xh,  g_xh);
    cudaGetSymbolAddress((void**)&wh,  g_wh);
    cudaGetSymbolAddress((void**)&wl,  g_wl);
    cudaGetSymbolAddress((void**)&wothi, g_wothi);
    cudaGetSymbolAddress((void**)&wotlo, g_wotlo);
    cudaGetSymbolAddress((void**)&yhi, g_yhi);
    cudaGetSymbolAddress((void**)&ylo, g_ylo);

    cudaFuncSetAttribute(gemm_qkv,
                         cudaFuncAttributeMaxDynamicSharedMemorySize, GQ_SMEM);
    cudaFuncSetAttribute(gemm_out,
                         cudaFuncAttributeMaxDynamicSharedMemorySize, G_SMEM);
    cudaFuncSetAttribute(chunkstate_kernel,
                         cudaFuncAttributeMaxDynamicSharedMemorySize, 32768);
    cudaFuncSetAttribute(attn_kernel,
                         cudaFuncAttributeMaxDynamicSharedMemorySize, AT_SMEM);

    // 0) fused prep: x->fp16 hi, w->fp16 hi/lo, wo^T->bf16 hi/lo
    prep_inputs_kernel<<<NBX + NBW + 1024, 256>>>(x, w, wo);
    // 1) qkv = xh @ (wh+wl)^T  (fp16 2-pass) + fused softmax/exp epilogue
    gemm_qkv<<<dim3(3 * D_ / 64, BT_ / 128), 128, GQ_SMEM>>>(
        xh, wh, wl, qkv, 3 * D_, D_);
    // 2) per-chunk states + k sums
    chunkstate_kernel<<<dim3(NC, BH_), 256, 32768>>>(qkv, Sc, ks);
    // 3) exclusive prefix over chunks
    prefix_kernel<<<dim3(BH_, 16), 256>>>(Sc, ks);
    // 4) tensor-core chunk attention -> y (bf16 split)
    attn_kernel<<<dim3(NC, BH_), 128, AT_SMEM>>>(qkv, Sc, ks, yhi, ylo);
    // 5) out = y @ w_out  (bf16 3-pass, full accuracy)
    gemm_out<<<dim3(D_ / 64, BT_ / 128), 128, G_SMEM>>>(
        yhi, ylo, wothi, wotlo, out, D_, D_);
}

// round 14
// speedup vs baseline: 1.8429x; 1.0674x over previous
#include <cuda_runtime.h>
#include <cuda_bf16.h>
#include <cuda_fp16.h>
#include <cstdint>

// Problem constants
#define B_   4
#define T_   2048
#define D_   1024
#define H_   16
#define L_   64
#define BT_  (B_*T_)        // 8192
#define BH_  (B_*H_)        // 64
#define CHUNK 64
#define NC   (T_/CHUNK)     // 32

// ---------------------------------------------------------------------------
// Scratch (device globals; no allocation allowed)
// ---------------------------------------------------------------------------
__device__ float g_qkv[(size_t)BT_ * 3 * D_];        // (8192, 3072)  qs|k_exp|v fp32
__device__ float g_Sc [(size_t)BH_ * NC * L_ * L_];  // chunk states -> excl prefix
__device__ float g_ks [(size_t)BH_ * NC * L_];       // chunk k-sums -> excl prefix
__device__ __half g_xh[(size_t)BT_ * D_];            // fp16 of x (hi only)
__device__ __half g_wh[(size_t)3 * D_ * D_];         // fp16 hi of w
__device__ __half g_wl[(size_t)3 * D_ * D_];         // fp16 lo of w
__device__ __half g_woth[(size_t)D_ * D_];           // fp16 hi of w_out^T
__device__ __half g_wotl[(size_t)D_ * D_];           // fp16 lo of w_out^T
__device__ __half g_yh[(size_t)BT_ * D_];            // fp16 of y (hi only)

// ---------------------------------------------------------------------------
// PTX helpers (baseline sm_80+ instructions only — harness targets plain sm_103)
// ---------------------------------------------------------------------------
__device__ __forceinline__ uint32_t smem_u32(const void* p) {
    uint32_t a;
    asm("{ .reg .u64 t; cvta.to.shared.u64 t, %1; cvt.u32.u64 %0, t; }" : "=r"(a) : "l"(p));
    return a;
}

__device__ __forceinline__ void cp_async16(uint32_t dst, const void* src) {
    asm volatile("cp.async.cg.shared.global [%0], [%1], 16;" :: "r"(dst), "l"(src) : "memory");
}
__device__ __forceinline__ void cp_commit() {
    asm volatile("cp.async.commit_group;" ::: "memory");
}
__device__ __forceinline__ void cp_wait1() {
    asm volatile("cp.async.wait_group 1;" ::: "memory");
}

__device__ __forceinline__ void ldsm_x4(uint32_t addr, uint32_t& r0, uint32_t& r1,
                                        uint32_t& r2, uint32_t& r3) {
    asm volatile("ldmatrix.sync.aligned.m8n8.x4.shared.b16 {%0,%1,%2,%3}, [%4];"
                 : "=r"(r0), "=r"(r1), "=r"(r2), "=r"(r3) : "r"(addr));
}

__device__ __forceinline__ void mma_bf16(float* c, const uint32_t* a, const uint32_t* b) {
    asm volatile(
        "mma.sync.aligned.m16n8k16.row.col.f32.bf16.bf16.f32 "
        "{%0,%1,%2,%3}, {%4,%5,%6,%7}, {%8,%9}, {%0,%1,%2,%3};"
        : "+f"(c[0]), "+f"(c[1]), "+f"(c[2]), "+f"(c[3])
        : "r"(a[0]), "r"(a[1]), "r"(a[2]), "r"(a[3]), "r"(b[0]), "r"(b[1]));
}

__device__ __forceinline__ void mma_f16(float* c, const uint32_t* a, const uint32_t* b) {
    asm volatile(
        "mma.sync.aligned.m16n8k16.row.col.f32.f16.f16.f32 "
        "{%0,%1,%2,%3}, {%4,%5,%6,%7}, {%8,%9}, {%0,%1,%2,%3};"
        : "+f"(c[0]), "+f"(c[1]), "+f"(c[2]), "+f"(c[3])
        : "r"(a[0]), "r"(a[1]), "r"(a[2]), "r"(a[3]), "r"(b[0]), "r"(b[1]));
}

__device__ __forceinline__ void sts32(uint32_t addr, uint32_t v) {
    asm volatile("st.shared.b32 [%0], %1;" :: "r"(addr), "r"(v) : "memory");
}

__device__ __forceinline__ float lds_bf16(uint32_t addr) {
    uint16_t v;
    asm volatile("ld.shared.u16 %0, [%1];" : "=h"(v) : "r"(addr));
    __nv_bfloat16 b = *(__nv_bfloat16*)&v;
    return __bfloat162float(b);
}

// split two floats -> packed bf16x2 hi and lo words
__device__ __forceinline__ void split2(float a, float b, uint32_t& hp, uint32_t& lp) {
    __nv_bfloat16 h0 = __float2bfloat16(a), h1 = __float2bfloat16(b);
    __nv_bfloat16 l0 = __float2bfloat16(a - __bfloat162float(h0));
    __nv_bfloat16 l1 = __float2bfloat16(b - __bfloat162float(h1));
    __nv_bfloat162 hv = __halves2bfloat162(h0, h1);
    __nv_bfloat162 lv = __halves2bfloat162(l0, l1);
    hp = *(uint32_t*)&hv;
    lp = *(uint32_t*)&lv;
}

// split two floats -> packed fp16x2 hi and lo words
__device__ __forceinline__ void split2h(float a, float b, uint32_t& hp, uint32_t& lp) {
    __half h0 = __float2half(a), h1 = __float2half(b);
    __half l0 = __float2half(a - __half2float(h0));
    __half l1 = __float2half(b - __half2float(h1));
    __half2 hv = __halves2half2(h0, h1);
    __half2 lv = __halves2half2(l0, l1);
    hp = *(uint32_t*)&hv;
    lp = *(uint32_t*)&lv;
}

// swizzled byte address of bf16/fp16 (row, col) in a 64-col (128B-row) tile
__device__ __forceinline__ uint32_t sw_addr(uint32_t base, int row, int col) {
    return base + (uint32_t)(row * 128 + ((((col >> 3) ^ (row & 7))) << 4) + ((col & 7) * 2));
}

// ---------------------------------------------------------------------------
// ONE fused input-prep kernel:
//   blocks [0, NBX)          : x -> fp16 hi only
//   blocks [NBX, NBX+NBW)    : w -> fp16 hi + lo
//   blocks [.., +1024)       : w_out^T -> fp16 hi + lo
// ---------------------------------------------------------------------------
#define NBX (BT_ * D_ / 4 / 256)          // 8192
#define NBW (3 * D_ * D_ / 4 / 256)       // 3072

__global__ void __launch_bounds__(256)
prep_inputs_kernel(const float* __restrict__ x, const float* __restrict__ w,
                   const float* __restrict__ wo)
{
    const int bid = blockIdx.x;
    if (bid < NBX) {
        int i = bid * 256 + threadIdx.x;
        float4 v = ((const float4*)x)[i];
        __half2 h01 = __halves2half2(__float2half(v.x), __float2half(v.y));
        __half2 h23 = __halves2half2(__float2half(v.z), __float2half(v.w));
        ((__half2*)g_xh)[2 * i]     = h01;
        ((__half2*)g_xh)[2 * i + 1] = h23;
    } else if (bid < NBX + NBW) {
        int i = (bid - NBX) * 256 + threadIdx.x;
        float4 v = ((const float4*)w)[i];
        uint32_t h01, l01, h23, l23;
        split2h(v.x, v.y, h01, l01);
        split2h(v.z, v.w, h23, l23);
        ((uint32_t*)g_wh)[2 * i]     = h01;
        ((uint32_t*)g_wh)[2 * i + 1] = h23;
        ((uint32_t*)g_wl)[2 * i]     = l01;
        ((uint32_t*)g_wl)[2 * i + 1] = l23;
    } else {
        __shared__ float tile[32][33];
        int tb = bid - NBX - NBW;            // 0..1023
        int n0 = (tb & 31) * 32, k0 = (tb >> 5) * 32;
        int tx = threadIdx.x & 31, ty = threadIdx.x >> 5;   // (32,8)
        for (int r = ty; r < 32; r += 8)
            tile[r][tx] = wo[(size_t)(k0 + r) * D_ + n0 + tx];
        __syncthreads();
        for (int r = ty; r < 32; r += 8) {
            float v = tile[tx][r];
            __half h = __float2half(v);
            size_t idx = (size_t)(n0 + r) * D_ + k0 + tx;
            g_woth[idx] = h;
            g_wotl[idx] = __float2half(v - __half2float(h));
        }
    }
}

// ---------------------------------------------------------------------------
// fp16 2-pass split GEMM: C = Ah*(Bh+Bl)^T.
// 128x64 tile, BK=64, 128 threads (4 warps along M), 3-stage cp.async,
// stage = 32KB -> 96KB/CTA -> 2 CTAs/SM.
// MODE=1: fused qkv epilogue (softmax/exp/pass). MODE=0: plain store.
// ---------------------------------------------------------------------------
#define GQ_A 16384
#define GQ_B 8192
#define GQ_STAGE (GQ_A + 2 * GQ_B)          // 32768
#define GQ_SMEM  (3 * GQ_STAGE)             // 98304

template<int MODE>
__global__ void __launch_bounds__(128, 2)
gemm_f16(const __half* __restrict__ Ah, const __half* __restrict__ Bh,
         const __half* __restrict__ Bl, float* __restrict__ C, int N, int K)
{
    extern __shared__ char smem[];
    const uint32_t smem_base = smem_u32(smem);
    const int tid = threadIdx.x;
    const int wid = tid >> 5, lane = tid & 31;
    const int m0 = blockIdx.y * 128, n0 = blockIdx.x * 64;
    const int wm = wid * 32;

    auto load_stage = [&](int kt, int s) {
        const int k0 = kt << 6;
        const uint32_t sb = smem_base + s * GQ_STAGE;
#pragma unroll
        for (int ii = 0; ii < 8; ii++) {
            int j = tid + ii * 128;
            int r = j >> 3, c = j & 7;
            const void* g = &Ah[(size_t)(m0 + r) * K + k0 + c * 8];
            cp_async16(sb + (uint32_t)(r * 128 + ((c ^ (r & 7)) << 4)), g);
        }
#pragma unroll
        for (int tI = 0; tI < 2; tI++) {
            const __half* src = tI ? Bl : Bh;
            const uint32_t tb = sb + GQ_A + tI * GQ_B;
#pragma unroll
            for (int ii = 0; ii < 4; ii++) {
                int j = tid + ii * 128;
                int r = j >> 3, c = j & 7;
                const void* g = &src[(size_t)(n0 + r) * K + k0 + c * 8];
                cp_async16(tb + (uint32_t)(r * 128 + ((c ^ (r & 7)) << 4)), g);
            }
        }
    };

    float acc[2][8][4];
#pragma unroll
    for (int mt = 0; mt < 2; mt++)
#pragma unroll
        for (int nt = 0; nt < 8; nt++)
#pragma unroll
            for (int e = 0; e < 4; e++) acc[mt][nt][e] = 0.f;

    const int NKT = K >> 6;   // 16
    load_stage(0, 0); cp_commit();
    load_stage(1, 1); cp_commit();

    const int a_row = (lane & 15);
    const int a_khalf = lane >> 4;
    const int b_grp = (lane >> 4) & 1;
    const int b_khalf = (lane >> 3) & 1;
    const int b_row = lane & 7;

    int s = 0, sload = 2;
    for (int kt = 0; kt < NKT; kt++) {
        const uint32_t st = smem_base + s * GQ_STAGE;
        cp_wait1();
        __syncthreads();

        if (kt + 2 < NKT) load_stage(kt + 2, sload);
        cp_commit();

        const uint32_t aA = st;
        const uint32_t aB = st + GQ_A;

#pragma unroll
        for (int kk = 0; kk < 4; kk++) {
            uint32_t ah[2][4];
#pragma unroll
            for (int mt = 0; mt < 2; mt++) {
                int row = wm + mt * 16 + a_row;
                int chunk = 2 * kk + a_khalf;
                uint32_t off = (uint32_t)(row * 128 + ((chunk ^ (row & 7)) << 4));
                ldsm_x4(aA + off, ah[mt][0], ah[mt][1], ah[mt][2], ah[mt][3]);
            }
            uint32_t bh[4][4], bl[4][4];
#pragma unroll
            for (int np = 0; np < 4; np++) {
                int row = np * 16 + b_grp * 8 + b_row;
                int chunk = 2 * kk + b_khalf;
                uint32_t off = (uint32_t)(row * 128 + ((chunk ^ (row & 7)) << 4));
                ldsm_x4(aB + off, bh[np][0], bh[np][1], bh[np][2], bh[np][3]);
                ldsm_x4(aB + GQ_B + off, bl[np][0], bl[np][1], bl[np][2], bl[np][3]);
            }
#pragma unroll
            for (int p = 0; p < 2; p++) {
#pragma unroll
                for (int mt = 0; mt < 2; mt++) {
#pragma unroll
                    for (int nt = 0; nt < 8; nt++) {
                        const uint32_t* bf = p ? &bl[nt >> 1][(nt & 1) * 2]
                                               : &bh[nt >> 1][(nt & 1) * 2];
                        mma_f16(acc[mt][nt], ah[mt], bf);
                    }
                }
            }
        }
        s = (s == 2) ? 0 : s + 1;
        sload = (sload == 2) ? 0 : sload + 1;
    }

    const int g = lane >> 2, tig = lane & 3;
    const int gcol0 = n0;

    if (MODE == 1 && gcol0 < D_) {
        // q region: per-head softmax
#pragma unroll
        for (int mt = 0; mt < 2; mt++) {
            float vA[16], vB[16];
#pragma unroll
            for (int nt = 0; nt < 8; nt++) {
                vA[2*nt]   = acc[mt][nt][0] * 0.125f;
                vA[2*nt+1] = acc[mt][nt][1] * 0.125f;
                vB[2*nt]   = acc[mt][nt][2] * 0.125f;
                vB[2*nt+1] = acc[mt][nt][3] * 0.125f;
            }
            float mA = vA[0], mB = vB[0];
#pragma unroll
            for (int i = 1; i < 16; i++) { mA = fmaxf(mA, vA[i]); mB = fmaxf(mB, vB[i]); }
            mA = fmaxf(mA, __shfl_xor_sync(0xffffffffu, mA, 1));
            mA = fmaxf(mA, __shfl_xor_sync(0xffffffffu, mA, 2));
            mB = fmaxf(mB, __shfl_xor_sync(0xffffffffu, mB, 1));
            mB = fmaxf(mB, __shfl_xor_sync(0xffffffffu, mB, 2));
            float sA = 0.f, sB = 0.f;
#pragma unroll
            for (int i = 0; i < 16; i++) {
                vA[i] = expf(vA[i] - mA); sA += vA[i];
                vB[i] = expf(vB[i] - mB); sB += vB[i];
            }
            sA += __shfl_xor_sync(0xffffffffu, sA, 1);
            sA += __shfl_xor_sync(0xffffffffu, sA, 2);
            sB += __shfl_xor_sync(0xffffffffu, sB, 1);
            sB += __shfl_xor_sync(0xffffffffu, sB, 2);
            float iA = 1.f / sA, iB = 1.f / sB;
            int row = m0 + wm + mt * 16 + g;
#pragma unroll
            for (int nt = 0; nt < 8; nt++) {
                int col = gcol0 + nt * 8 + 2 * tig;
                *(float2*)&C[(size_t)row * N + col]       = make_float2(vA[2*nt]*iA, vA[2*nt+1]*iA);
                *(float2*)&C[(size_t)(row + 8) * N + col] = make_float2(vB[2*nt]*iB, vB[2*nt+1]*iB);
            }
        }
    } else if (MODE == 1 && gcol0 < 2 * D_) {
        // k region: exp(v*0.125)+1e-6
#pragma unroll
        for (int mt = 0; mt < 2; mt++) {
            int row = m0 + wm + mt * 16 + g;
#pragma unroll
            for (int nt = 0; nt < 8; nt++) {
                int col = gcol0 + nt * 8 + 2 * tig;
                float* c = acc[mt][nt];
                *(float2*)&C[(size_t)row * N + col] =
                    make_float2(expf(c[0]*0.125f)+1e-6f, expf(c[1]*0.125f)+1e-6f);
                *(float2*)&C[(size_t)(row + 8) * N + col] =
                    make_float2(expf(c[2]*0.125f)+1e-6f, expf(c[3]*0.125f)+1e-6f);
            }
        }
    } else {
        // v region / MODE 0: plain store
#pragma unroll
        for (int mt = 0; mt < 2; mt++) {
            int row = m0 + wm + mt * 16 + g;
#pragma unroll
            for (int nt = 0; nt < 8; nt++) {
                int col = gcol0 + nt * 8 + 2 * tig;
                float* c = acc[mt][nt];
                *(float2*)&C[(size_t)row * N + col]       = make_float2(c[0], c[1]);
                *(float2*)&C[(size_t)(row + 8) * N + col] = make_float2(c[2], c[3]);
            }
        }
    }
}

// ---------------------------------------------------------------------------
// Per-chunk state (CHUNK=64) — unchanged
// ---------------------------------------------------------------------------
__global__ void __launch_bounds__(256)
chunkstate_kernel(const float* __restrict__ qkv,
                  float* __restrict__ Sc, float* __restrict__ ks)
{
    extern __shared__ float sm[];
    float* Ks = sm;
    float* Vs = sm + CHUNK * L_;
    const int c = blockIdx.x, bh = blockIdx.y;
    const int b = bh >> 4, h = bh & 15;
    const size_t rowbase = ((size_t)(b * T_ + c * CHUNK)) * (3 * D_) + h * L_;

    for (int i = threadIdx.x; i < CHUNK * 16; i += 256) {
        int t = i >> 4, f = (i & 15) << 2;
        size_t g = rowbase + (size_t)t * (3 * D_) + f;
        *(float4*)&Ks[t * L_ + f] = *(const float4*)&qkv[g + D_];
        *(float4*)&Vs[t * L_ + f] = *(const float4*)&qkv[g + 2 * D_];
    }
    __syncthreads();

    const int l0 = (threadIdx.x >> 4) << 2;
    const int m0 = (threadIdx.x & 15) << 2;
    float acc[4][4];
#pragma unroll
    for (int i = 0; i < 4; i++)
#pragma unroll
        for (int j = 0; j < 4; j++) acc[i][j] = 0.f;
    for (int t = 0; t < CHUNK; t++) {
        float a[4], v[4];
#pragma unroll
        for (int i = 0; i < 4; i++) a[i] = Ks[t * L_ + l0 + i];
#pragma unroll
        for (int j = 0; j < 4; j++) v[j] = Vs[t * L_ + m0 + j];
#pragma unroll
        for (int i = 0; i < 4; i++)
#pragma unroll
            for (int j = 0; j < 4; j++) acc[i][j] += a[i] * v[j];
    }
    const size_t sbase = ((size_t)bh * NC + c) * (L_ * L_);
#pragma unroll
    for (int i = 0; i < 4; i++)
#pragma unroll
        for (int j = 0; j < 4; j++)
            Sc[sbase + (size_t)(l0 + i) * L_ + m0 + j] = acc[i][j];

    if (threadIdx.x < L_) {
        float s = 0.f;
        for (int t = 0; t < CHUNK; t++) s += Ks[t * L_ + threadIdx.x];
        ks[((size_t)bh * NC + c) * L_ + threadIdx.x] = s;
    }
}

// ---------------------------------------------------------------------------
// Exclusive prefix over chunks — unchanged
// ---------------------------------------------------------------------------
__global__ void prefix_kernel(float* __restrict__ Sc, float* __restrict__ ks)
{
    const int bh = blockIdx.x;
    const int e = blockIdx.y * 256 + threadIdx.x;
    const size_t base = (size_t)bh * NC * (L_ * L_);
    {
        float acc = 0.f;
#pragma unroll
        for (int c = 0; c < NC; c++) {
            size_t idx = base + (size_t)c * (L_ * L_) + e;
            float tmp = Sc[idx];
            Sc[idx] = acc;
            acc += tmp;
        }
    }
    if (blockIdx.y == 0 && threadIdx.x < L_) {
        const size_t kb = (size_t)bh * NC * L_;
        float acc = 0.f;
#pragma unroll
        for (int c = 0; c < NC; c++) {
            size_t idx = kb + (size_t)c * L_ + threadIdx.x;
            float tmp = ks[idx];
            ks[idx] = acc;
            acc += tmp;
        }
    }
}

// ---------------------------------------------------------------------------
// Tensor-core chunk attention (internals unchanged from R12/13; output now
// SINGLE fp16 y — halves attn's global writes).
// ---------------------------------------------------------------------------
#define AT_SMEM 81920

__global__ void __launch_bounds__(128)
attn_kernel(const float* __restrict__ qkv, const float* __restrict__ Sprev,
            const float* __restrict__ kpre, __half* __restrict__ yh)
{
    extern __shared__ char smc[];
    float* qsf = (float*)smc;
    const uint32_t sb  = smem_u32(smc);
    const uint32_t PH  = sb,           PL  = sb + 8192;
    const uint32_t QH  = sb + 16384,   QL  = sb + 24576;
    const uint32_t KH  = sb + 32768,   KL  = sb + 40960;
    const uint32_t VTH = sb + 49152,   VTL = sb + 57344;
    const uint32_t STH = sb + 65536,   STL = sb + 73728;

    const int c = blockIdx.x, bh = blockIdx.y;
    const int b = bh >> 4, h = bh & 15;
    const int tid = threadIdx.x;
    const int wid = tid >> 5, lane = tid & 31;
    const size_t rowbase = ((size_t)(b * T_ + c * CHUNK)) * (3 * D_) + h * L_;
    const size_t sbase = ((size_t)bh * NC + c) * (L_ * L_);

    for (int i = tid; i < CHUNK * 16; i += 128) {
        int t = i >> 4, f = (i & 15) << 2;
        *(float4*)&qsf[t * L_ + f] =
            *(const float4*)&qkv[rowbase + (size_t)t * (3 * D_) + f];
    }
    for (int i = tid; i < 1024; i += 128) {
        int t = i >> 4, f = (i & 15) << 2;
        float4 kv4 = *(const float4*)&qkv[rowbase + (size_t)t * (3 * D_) + D_ + f];
        uint32_t hp, lp;
        split2(kv4.x, kv4.y, hp, lp);
        sts32(sw_addr(KH, t, f), hp);     sts32(sw_addr(KL, t, f), lp);
        split2(kv4.z, kv4.w, hp, lp);
        sts32(sw_addr(KH, t, f + 2), hp); sts32(sw_addr(KL, t, f + 2), lp);
    }
    for (int i = tid; i < 512; i += 128) {
        int t0 = (i >> 4) * 2;
        int m0 = (i & 15) << 2;
        const float* v0 = &qkv[rowbase + (size_t)t0 * (3 * D_) + 2 * D_];
        float4 a = *(const float4*)&v0[m0];
        float4 bvec = *(const float4*)&v0[3 * D_ + m0];
        uint32_t hp, lp;
        split2(a.x, bvec.x, hp, lp);
        sts32(sw_addr(VTH, m0 + 0, t0), hp); sts32(sw_addr(VTL, m0 + 0, t0), lp);
        split2(a.y, bvec.y, hp, lp);
        sts32(sw_addr(VTH, m0 + 1, t0), hp); sts32(sw_addr(VTL, m0 + 1, t0), lp);
        split2(a.z, bvec.z, hp, lp);
        sts32(sw_addr(VTH, m0 + 2, t0), hp); sts32(sw_addr(VTL, m0 + 2, t0), lp);
        split2(a.w, bvec.w, hp, lp);
        sts32(sw_addr(VTH, m0 + 3, t0), hp); sts32(sw_addr(VTL, m0 + 3, t0), lp);
    }
    for (int i = tid; i < 512; i += 128) {
        int l0 = (i >> 4) * 2;
        int m0 = (i & 15) << 2;
        const float* s0 = &Sprev[sbase + (size_t)l0 * L_];
        float4 a = *(const float4*)&s0[m0];
        float4 bvec = *(const float4*)&s0[L_ + m0];
        uint32_t hp, lp;
        split2(a.x, bvec.x, hp, lp);
        sts32(sw_addr(STH, m0 + 0, l0), hp); sts32(sw_addr(STL, m0 + 0, l0), lp);
        split2(a.y, bvec.y, hp, lp);
        sts32(sw_addr(STH, m0 + 1, l0), hp); sts32(sw_addr(STL, m0 + 1, l0), lp);
        split2(a.z, bvec.z, hp, lp);
        sts32(sw_addr(STH, m0 + 2, l0), hp); sts32(sw_addr(STL, m0 + 2, l0), lp);
        split2(a.w, bvec.w, hp, lp);
        sts32(sw_addr(STH, m0 + 3, l0), hp); sts32(sw_addr(STL, m0 + 3, l0), lp);
    }
    __syncthreads();

    if (tid < L_) {
        const int l = tid;
        float acc = kpre[((size_t)bh * NC + c) * L_ + l];
        for (int t = 0; t < CHUNK; t++) {
            acc += lds_bf16(sw_addr(KH, t, l)) + lds_bf16(sw_addr(KL, t, l));
            qsf[t * L_ + l] = __fdividef(qsf[t * L_ + l], acc);
        }
    }
    __syncthreads();

    for (int i = tid; i < 2048; i += 128) {
        int row = i >> 5, col = (i & 31) * 2;
        uint32_t hp, lp;
        split2(qsf[row * L_ + col], qsf[row * L_ + col + 1], hp, lp);
        sts32(sw_addr(QH, row, col), hp);
        sts32(sw_addr(QL, row, col), lp);
    }
    __syncthreads();

    const int wm = wid * 16;
    const int a_row = (lane & 15);
    const int a_khalf = lane >> 4;
    const int b_grp = (lane >> 4) & 1;
    const int b_khalf = (lane >> 3) & 1;
    const int b_row = lane & 7;
    const int g = lane >> 2, tig = lane & 3;

    float accP[8][4];
#pragma unroll
    for (int nt = 0; nt < 8; nt++)
#pragma unroll
        for (int e = 0; e < 4; e++) accP[nt][e] = 0.f;

#pragma unroll
    for (int kk = 0; kk < 4; kk++) {
        uint32_t ah[4], al[4];
        {
            int row = wm + a_row;
            int chunk = 2 * kk + a_khalf;
            uint32_t off = (uint32_t)(row * 128 + ((chunk ^ (row & 7)) << 4));
            ldsm_x4(QH + off, ah[0], ah[1], ah[2], ah[3]);
            ldsm_x4(QL + off, al[0], al[1], al[2], al[3]);
        }
        uint32_t bh_[4][4], bl_[4][4];
#pragma unroll
        for (int np = 0; np < 4; np++) {
            int row = np * 16 + b_grp * 8 + b_row;
            int chunk = 2 * kk + b_khalf;
            uint32_t off = (uint32_t)(row * 128 + ((chunk ^ (row & 7)) << 4));
            ldsm_x4(KH + off, bh_[np][0], bh_[np][1], bh_[np][2], bh_[np][3]);
            ldsm_x4(KL + off, bl_[np][0], bl_[np][1], bl_[np][2], bl_[np][3]);
        }
#pragma unroll
        for (int p = 0; p < 3; p++) {
            const uint32_t* af = (p == 2) ? al : ah;
#pragma unroll
            for (int nt = 0; nt < 8; nt++) {
                const uint32_t* bf = (p == 1) ? &bl_[nt >> 1][(nt & 1) * 2]
                                              : &bh_[nt >> 1][(nt & 1) * 2];
                mma_bf16(accP[nt], af, bf);
            }
        }
    }

    {
        int r0 = wm + g, r1 = wm + g + 8;
#pragma unroll
        for (int nt = 0; nt < 8; nt++) {
            int colp = nt * 8 + 2 * tig;
            float p00 = (colp     <= r0) ? accP[nt][0] : 0.f;
            float p01 = (colp + 1 <= r0) ? accP[nt][1] : 0.f;
            float p10 = (colp     <= r1) ? accP[nt][2] : 0.f;
            float p11 = (colp + 1 <= r1) ? accP[nt][3] : 0.f;
            uint32_t hp, lp;
            split2(p00, p01, hp, lp);
            sts32(sw_addr(PH, r0, colp), hp);
            sts32(sw_addr(PL, r0, colp), lp);
            split2(p10, p11, hp, lp);
            sts32(sw_addr(PH, r1, colp), hp);
            sts32(sw_addr(PL, r1, colp), lp);
        }
    }
    __syncthreads();

    float acc[8][4];
#pragma unroll
    for (int nt = 0; nt < 8; nt++)
#pragma unroll
        for (int e = 0; e < 4; e++) acc[nt][e] = 0.f;

#pragma unroll
    for (int half = 0; half < 2; half++) {
        const uint32_t AH = half ? QH : PH, AL = half ? QL : PL;
        const uint32_t BH = half ? STH : VTH, BL = half ? STL : VTL;
#pragma unroll
        for (int kk = 0; kk < 4; kk++) {
            uint32_t ah[4], al[4];
            {
                int row = wm + a_row;
                int chunk = 2 * kk + a_khalf;
                uint32_t off = (uint32_t)(row * 128 + ((chunk ^ (row & 7)) << 4));
                ldsm_x4(AH + off, ah[0], ah[1], ah[2], ah[3]);
                ldsm_x4(AL + off, al[0], al[1], al[2], al[3]);
            }
            uint32_t bh_[4][4], bl_[4][4];
#pragma unroll
            for (int np = 0; np < 4; np++) {
                int row = np * 16 + b_grp * 8 + b_row;
                int chunk = 2 * kk + b_khalf;
                uint32_t off = (uint32_t)(row * 128 + ((chunk ^ (row & 7)) << 4));
                ldsm_x4(BH + off, bh_[np][0], bh_[np][1], bh_[np][2], bh_[np][3]);
                ldsm_x4(BL + off, bl_[np][0], bl_[np][1], bl_[np][2], bl_[np][3]);
            }
#pragma unroll
            for (int p = 0; p < 3; p++) {
                const uint32_t* af = (p == 2) ? al : ah;
#pragma unroll
                for (int nt = 0; nt < 8; nt++) {
                    const uint32_t* bf = (p == 1) ? &bl_[nt >> 1][(nt & 1) * 2]
                                                  : &bh_[nt >> 1][(nt & 1) * 2];
                    mma_bf16(acc[nt], af, bf);
                }
            }
        }
    }

    // epilogue: single-fp16 y
    {
        int r0 = wm + g;
#pragma unroll
        for (int dr = 0; dr < 2; dr++) {
            int row = r0 + dr * 8;
            size_t ybase = ((size_t)(b * T_ + c * CHUNK + row)) * D_ + h * L_;
#pragma unroll
            for (int nt = 0; nt < 8; nt++) {
                int colp = nt * 8 + 2 * tig;
                __half2 hv = __halves2half2(__float2half(acc[nt][2 * dr]),
                                            __float2half(acc[nt][2 * dr + 1]));
                *(uint32_t*)&yh[ybase + colp] = *(uint32_t*)&hv;
            }
        }
    }
}

// ---------------------------------------------------------------------------
extern "C" void kernel_launch(void* const* d_in, const int* in_sizes, int n_in,
                              void* d_out, int out_size)
{
    const float* x  = (const float*)d_in[0];
    const float* w  = (const float*)d_in[1];
    const float* wo = (const float*)d_in[2];
    float* out = (float*)d_out;

    float *qkv, *Sc, *ks;
    __half *xh, *wh, *wl, *woth, *wotl, *yh;
    cudaGetSymbolAddress((void**)&qkv, g_qkv);
    cudaGetSymbolAddress((void**)&Sc,  g_Sc);
    cudaGetSymbolAddress((void**)&ks,  g_ks);
    cudaGetSymbolAddress((void**)&xh,  g_xh);
    cudaGetSymbolAddress((void**)&wh,  g_wh);
    cudaGetSymbolAddress((void**)&wl,  g_wl);
    cudaGetSymbolAddress((void**)&woth, g_woth);
    cudaGetSymbolAddress((void**)&wotl, g_wotl);
    cudaGetSymbolAddress((void**)&yh,  g_yh);

    cudaFuncSetAttribute(gemm_f16<0>,
                         cudaFuncAttributeMaxDynamicSharedMemorySize, GQ_SMEM);
    cudaFuncSetAttribute(gemm_f16<1>,
                         cudaFuncAttributeMaxDynamicSharedMemorySize, GQ_SMEM);
    cudaFuncSetAttribute(chunkstate_kernel,
                         cudaFuncAttributeMaxDynamicSharedMemorySize, 32768);
    cudaFuncSetAttribute(attn_kernel,
                         cudaFuncAttributeMaxDynamicSharedMemorySize, AT_SMEM);

    // 0) fused prep: x->fp16, w->fp16 hi/lo, wo^T->fp16 hi/lo
    prep_inputs_kernel<<<NBX + NBW + 1024, 256>>>(x, w, wo);
    // 1) qkv = xh @ (wh+wl)^T  (fp16 2-pass) + fused softmax/exp epilogue
    gemm_f16<1><<<dim3(3 * D_ / 64, BT_ / 128), 128, GQ_SMEM>>>(
        xh, wh, wl, qkv, 3 * D_, D_);
    // 2) per-chunk states + k sums
    chunkstate_kernel<<<dim3(NC, BH_), 256, 32768>>>(qkv, Sc, ks);
    // 3) exclusive prefix over chunks
    prefix_kernel<<<dim3(BH_, 16), 256>>>(Sc, ks);
    // 4) tensor-core chunk attention -> y (single fp16)
    attn_kernel<<<dim3(NC, BH_), 128, AT_SMEM>>>(qkv, Sc, ks, yh);
    // 5) out = yh @ (woth+wotl)^T  (fp16 2-pass)
    gemm_f16<0><<<dim3(D_ / 64, BT_ / 128), 128, GQ_SMEM>>>(
        yh, woth, wotl, out, D_, D_);
}

// round 15
// speedup vs baseline: 2.0341x; 1.1037x over previous
#include <cuda_runtime.h>
#include <cuda_bf16.h>
#include <cuda_fp16.h>
#include <cstdint>

// Problem constants
#define B_   4
#define T_   2048
#define D_   1024
#define H_   16
#define L_   64
#define BT_  (B_*T_)        // 8192
#define BH_  (B_*H_)        // 64
#define CHUNK 64
#define NC   (T_/CHUNK)     // 32

// ---------------------------------------------------------------------------
// Scratch (device globals; no allocation allowed)
// ---------------------------------------------------------------------------
__device__ float g_qkv[(size_t)BT_ * 3 * D_];        // (8192, 3072)  qs|k_exp|v fp32
__device__ float g_Sc [(size_t)BH_ * NC * L_ * L_];  // chunk states -> excl prefix
__device__ float g_ks [(size_t)BH_ * NC * L_];       // chunk k-sums -> excl prefix
__device__ __half g_xh[(size_t)BT_ * D_];            // fp16 of x
__device__ __half g_wh[(size_t)3 * D_ * D_];         // fp16 hi of w
__device__ __half g_wl[(size_t)3 * D_ * D_];         // fp16 lo of w
__device__ __half g_woth[(size_t)D_ * D_];           // fp16 hi of w_out^T
__device__ __half g_wotl[(size_t)D_ * D_];           // fp16 lo of w_out^T
__device__ __half g_yh[(size_t)BT_ * D_];            // fp16 of y

// ---------------------------------------------------------------------------
// PTX helpers
// ---------------------------------------------------------------------------
__device__ __forceinline__ uint32_t smem_u32(const void* p) {
    uint32_t a;
    asm("{ .reg .u64 t; cvta.to.shared.u64 t, %1; cvt.u32.u64 %0, t; }" : "=r"(a) : "l"(p));
    return a;
}

__device__ __forceinline__ void cp_async16(uint32_t dst, const void* src) {
    asm volatile("cp.async.cg.shared.global [%0], [%1], 16;" :: "r"(dst), "l"(src) : "memory");
}
__device__ __forceinline__ void cp_commit() {
    asm volatile("cp.async.commit_group;" ::: "memory");
}
__device__ __forceinline__ void cp_wait1() {
    asm volatile("cp.async.wait_group 1;" ::: "memory");
}

__device__ __forceinline__ void ldsm_x4(uint32_t addr, uint32_t& r0, uint32_t& r1,
                                        uint32_t& r2, uint32_t& r3) {
    asm volatile("ldmatrix.sync.aligned.m8n8.x4.shared.b16 {%0,%1,%2,%3}, [%4];"
                 : "=r"(r0), "=r"(r1), "=r"(r2), "=r"(r3) : "r"(addr));
}

__device__ __forceinline__ void mma_f16(float* c, const uint32_t* a, const uint32_t* b) {
    asm volatile(
        "mma.sync.aligned.m16n8k16.row.col.f32.f16.f16.f32 "
        "{%0,%1,%2,%3}, {%4,%5,%6,%7}, {%8,%9}, {%0,%1,%2,%3};"
        : "+f"(c[0]), "+f"(c[1]), "+f"(c[2]), "+f"(c[3])
        : "r"(a[0]), "r"(a[1]), "r"(a[2]), "r"(a[3]), "r"(b[0]), "r"(b[1]));
}

__device__ __forceinline__ void sts32(uint32_t addr, uint32_t v) {
    asm volatile("st.shared.b32 [%0], %1;" :: "r"(addr), "r"(v) : "memory");
}

// pack two floats -> fp16x2 word
__device__ __forceinline__ uint32_t pack_h2(float a, float b) {
    __half2 hv = __halves2half2(__float2half(a), __float2half(b));
    return *(uint32_t*)&hv;
}

// split two floats -> packed fp16x2 hi and lo words
__device__ __forceinline__ void split2h(float a, float b, uint32_t& hp, uint32_t& lp) {
    __half h0 = __float2half(a), h1 = __float2half(b);
    __half l0 = __float2half(a - __half2float(h0));
    __half l1 = __float2half(b - __half2float(h1));
    __half2 hv = __halves2half2(h0, h1);
    __half2 lv = __halves2half2(l0, l1);
    hp = *(uint32_t*)&hv;
    lp = *(uint32_t*)&lv;
}

// swizzled byte address of a 16-bit elem (row, col) in a 64-col (128B-row) tile
__device__ __forceinline__ uint32_t sw_addr(uint32_t base, int row, int col) {
    return base + (uint32_t)(row * 128 + ((((col >> 3) ^ (row & 7))) << 4) + ((col & 7) * 2));
}

// ---------------------------------------------------------------------------
// ONE fused input-prep kernel:
//   x -> fp16 ; w -> fp16 hi+lo ; w_out^T -> fp16 hi+lo
// ---------------------------------------------------------------------------
#define NBX (BT_ * D_ / 4 / 256)          // 8192
#define NBW (3 * D_ * D_ / 4 / 256)       // 3072

__global__ void __launch_bounds__(256)
prep_inputs_kernel(const float* __restrict__ x, const float* __restrict__ w,
                   const float* __restrict__ wo)
{
    const int bid = blockIdx.x;
    if (bid < NBX) {
        int i = bid * 256 + threadIdx.x;
        float4 v = ((const float4*)x)[i];
        ((uint32_t*)g_xh)[2 * i]     = pack_h2(v.x, v.y);
        ((uint32_t*)g_xh)[2 * i + 1] = pack_h2(v.z, v.w);
    } else if (bid < NBX + NBW) {
        int i = (bid - NBX) * 256 + threadIdx.x;
        float4 v = ((const float4*)w)[i];
        uint32_t h01, l01, h23, l23;
        split2h(v.x, v.y, h01, l01);
        split2h(v.z, v.w, h23, l23);
        ((uint32_t*)g_wh)[2 * i]     = h01;
        ((uint32_t*)g_wh)[2 * i + 1] = h23;
        ((uint32_t*)g_wl)[2 * i]     = l01;
        ((uint32_t*)g_wl)[2 * i + 1] = l23;
    } else {
        __shared__ float tile[32][33];
        int tb = bid - NBX - NBW;            // 0..1023
        int n0 = (tb & 31) * 32, k0 = (tb >> 5) * 32;
        int tx = threadIdx.x & 31, ty = threadIdx.x >> 5;
        for (int r = ty; r < 32; r += 8)
            tile[r][tx] = wo[(size_t)(k0 + r) * D_ + n0 + tx];
        __syncthreads();
        for (int r = ty; r < 32; r += 8) {
            float v = tile[tx][r];
            __half h = __float2half(v);
            size_t idx = (size_t)(n0 + r) * D_ + k0 + tx;
            g_woth[idx] = h;
            g_wotl[idx] = __float2half(v - __half2float(h));
        }
    }
}

// ---------------------------------------------------------------------------
// fp16 2-pass split GEMM: C = Ah*(Bh+Bl)^T.  (unchanged from R14)
// 128x64 tile, BK=64, 128 threads, 3-stage cp.async, 2 CTAs/SM.
// MODE=1: fused qkv epilogue. MODE=0: plain store.
// ---------------------------------------------------------------------------
#define GQ_A 16384
#define GQ_B 8192
#define GQ_STAGE (GQ_A + 2 * GQ_B)          // 32768
#define GQ_SMEM  (3 * GQ_STAGE)             // 98304

template<int MODE>
__global__ void __launch_bounds__(128, 2)
gemm_f16(const __half* __restrict__ Ah, const __half* __restrict__ Bh,
         const __half* __restrict__ Bl, float* __restrict__ C, int N, int K)
{
    extern __shared__ char smem[];
    const uint32_t smem_base = smem_u32(smem);
    const int tid = threadIdx.x;
    const int wid = tid >> 5, lane = tid & 31;
    const int m0 = blockIdx.y * 128, n0 = blockIdx.x * 64;
    const int wm = wid * 32;

    auto load_stage = [&](int kt, int s) {
        const int k0 = kt << 6;
        const uint32_t sb = smem_base + s * GQ_STAGE;
#pragma unroll
        for (int ii = 0; ii < 8; ii++) {
            int j = tid + ii * 128;
            int r = j >> 3, c = j & 7;
            const void* g = &Ah[(size_t)(m0 + r) * K + k0 + c * 8];
            cp_async16(sb + (uint32_t)(r * 128 + ((c ^ (r & 7)) << 4)), g);
        }
#pragma unroll
        for (int tI = 0; tI < 2; tI++) {
            const __half* src = tI ? Bl : Bh;
            const uint32_t tb = sb + GQ_A + tI * GQ_B;
#pragma unroll
            for (int ii = 0; ii < 4; ii++) {
                int j = tid + ii * 128;
                int r = j >> 3, c = j & 7;
                const void* g = &src[(size_t)(n0 + r) * K + k0 + c * 8];
                cp_async16(tb + (uint32_t)(r * 128 + ((c ^ (r & 7)) << 4)), g);
            }
        }
    };

    float acc[2][8][4];
#pragma unroll
    for (int mt = 0; mt < 2; mt++)
#pragma unroll
        for (int nt = 0; nt < 8; nt++)
#pragma unroll
            for (int e = 0; e < 4; e++) acc[mt][nt][e] = 0.f;

    const int NKT = K >> 6;   // 16
    load_stage(0, 0); cp_commit();
    load_stage(1, 1); cp_commit();

    const int a_row = (lane & 15);
    const int a_khalf = lane >> 4;
    const int b_grp = (lane >> 4) & 1;
    const int b_khalf = (lane >> 3) & 1;
    const int b_row = lane & 7;

    int s = 0, sload = 2;
    for (int kt = 0; kt < NKT; kt++) {
        const uint32_t st = smem_base + s * GQ_STAGE;
        cp_wait1();
        __syncthreads();

        if (kt + 2 < NKT) load_stage(kt + 2, sload);
        cp_commit();

        const uint32_t aA = st;
        const uint32_t aB = st + GQ_A;

#pragma unroll
        for (int kk = 0; kk < 4; kk++) {
            uint32_t ah[2][4];
#pragma unroll
            for (int mt = 0; mt < 2; mt++) {
                int row = wm + mt * 16 + a_row;
                int chunk = 2 * kk + a_khalf;
                uint32_t off = (uint32_t)(row * 128 + ((chunk ^ (row & 7)) << 4));
                ldsm_x4(aA + off, ah[mt][0], ah[mt][1], ah[mt][2], ah[mt][3]);
            }
            uint32_t bh[4][4], bl[4][4];
#pragma unroll
            for (int np = 0; np < 4; np++) {
                int row = np * 16 + b_grp * 8 + b_row;
                int chunk = 2 * kk + b_khalf;
                uint32_t off = (uint32_t)(row * 128 + ((chunk ^ (row & 7)) << 4));
                ldsm_x4(aB + off, bh[np][0], bh[np][1], bh[np][2], bh[np][3]);
                ldsm_x4(aB + GQ_B + off, bl[np][0], bl[np][1], bl[np][2], bl[np][3]);
            }
#pragma unroll
            for (int p = 0; p < 2; p++) {
#pragma unroll
                for (int mt = 0; mt < 2; mt++) {
#pragma unroll
                    for (int nt = 0; nt < 8; nt++) {
                        const uint32_t* bf = p ? &bl[nt >> 1][(nt & 1) * 2]
                                               : &bh[nt >> 1][(nt & 1) * 2];
                        mma_f16(acc[mt][nt], ah[mt], bf);
                    }
                }
            }
        }
        s = (s == 2) ? 0 : s + 1;
        sload = (sload == 2) ? 0 : sload + 1;
    }

    const int g = lane >> 2, tig = lane & 3;
    const int gcol0 = n0;

    if (MODE == 1 && gcol0 < D_) {
#pragma unroll
        for (int mt = 0; mt < 2; mt++) {
            float vA[16], vB[16];
#pragma unroll
            for (int nt = 0; nt < 8; nt++) {
                vA[2*nt]   = acc[mt][nt][0] * 0.125f;
                vA[2*nt+1] = acc[mt][nt][1] * 0.125f;
                vB[2*nt]   = acc[mt][nt][2] * 0.125f;
                vB[2*nt+1] = acc[mt][nt][3] * 0.125f;
            }
            float mA = vA[0], mB = vB[0];
#pragma unroll
            for (int i = 1; i < 16; i++) { mA = fmaxf(mA, vA[i]); mB = fmaxf(mB, vB[i]); }
            mA = fmaxf(mA, __shfl_xor_sync(0xffffffffu, mA, 1));
            mA = fmaxf(mA, __shfl_xor_sync(0xffffffffu, mA, 2));
            mB = fmaxf(mB, __shfl_xor_sync(0xffffffffu, mB, 1));
            mB = fmaxf(mB, __shfl_xor_sync(0xffffffffu, mB, 2));
            float sA = 0.f, sB = 0.f;
#pragma unroll
            for (int i = 0; i < 16; i++) {
                vA[i] = expf(vA[i] - mA); sA += vA[i];
                vB[i] = expf(vB[i] - mB); sB += vB[i];
            }
            sA += __shfl_xor_sync(0xffffffffu, sA, 1);
            sA += __shfl_xor_sync(0xffffffffu, sA, 2);
            sB += __shfl_xor_sync(0xffffffffu, sB, 1);
            sB += __shfl_xor_sync(0xffffffffu, sB, 2);
            float iA = 1.f / sA, iB = 1.f / sB;
            int row = m0 + wm + mt * 16 + g;
#pragma unroll
            for (int nt = 0; nt < 8; nt++) {
                int col = gcol0 + nt * 8 + 2 * tig;
                *(float2*)&C[(size_t)row * N + col]       = make_float2(vA[2*nt]*iA, vA[2*nt+1]*iA);
                *(float2*)&C[(size_t)(row + 8) * N + col] = make_float2(vB[2*nt]*iB, vB[2*nt+1]*iB);
            }
        }
    } else if (MODE == 1 && gcol0 < 2 * D_) {
#pragma unroll
        for (int mt = 0; mt < 2; mt++) {
            int row = m0 + wm + mt * 16 + g;
#pragma unroll
            for (int nt = 0; nt < 8; nt++) {
                int col = gcol0 + nt * 8 + 2 * tig;
                float* c = acc[mt][nt];
                *(float2*)&C[(size_t)row * N + col] =
                    make_float2(expf(c[0]*0.125f)+1e-6f, expf(c[1]*0.125f)+1e-6f);
                *(float2*)&C[(size_t)(row + 8) * N + col] =
                    make_float2(expf(c[2]*0.125f)+1e-6f, expf(c[3]*0.125f)+1e-6f);
            }
        }
    } else {
#pragma unroll
        for (int mt = 0; mt < 2; mt++) {
            int row = m0 + wm + mt * 16 + g;
#pragma unroll
            for (int nt = 0; nt < 8; nt++) {
                int col = gcol0 + nt * 8 + 2 * tig;
                float* c = acc[mt][nt];
                *(float2*)&C[(size_t)row * N + col]       = make_float2(c[0], c[1]);
                *(float2*)&C[(size_t)(row + 8) * N + col] = make_float2(c[2], c[3]);
            }
        }
    }
}

// ---------------------------------------------------------------------------
// Per-chunk state (CHUNK=64) — unchanged
// ---------------------------------------------------------------------------
__global__ void __launch_bounds__(256)
chunkstate_kernel(const float* __restrict__ qkv,
                  float* __restrict__ Sc, float* __restrict__ ks)
{
    extern __shared__ float sm[];
    float* Ks = sm;
    float* Vs = sm + CHUNK * L_;
    const int c = blockIdx.x, bh = blockIdx.y;
    const int b = bh >> 4, h = bh & 15;
    const size_t rowbase = ((size_t)(b * T_ + c * CHUNK)) * (3 * D_) + h * L_;

    for (int i = threadIdx.x; i < CHUNK * 16; i += 256) {
        int t = i >> 4, f = (i & 15) << 2;
        size_t g = rowbase + (size_t)t * (3 * D_) + f;
        *(float4*)&Ks[t * L_ + f] = *(const float4*)&qkv[g + D_];
        *(float4*)&Vs[t * L_ + f] = *(const float4*)&qkv[g + 2 * D_];
    }
    __syncthreads();

    const int l0 = (threadIdx.x >> 4) << 2;
    const int m0 = (threadIdx.x & 15) << 2;
    float acc[4][4];
#pragma unroll
    for (int i = 0; i < 4; i++)
#pragma unroll
        for (int j = 0; j < 4; j++) acc[i][j] = 0.f;
    for (int t = 0; t < CHUNK; t++) {
        float a[4], v[4];
#pragma unroll
        for (int i = 0; i < 4; i++) a[i] = Ks[t * L_ + l0 + i];
#pragma unroll
        for (int j = 0; j < 4; j++) v[j] = Vs[t * L_ + m0 + j];
#pragma unroll
        for (int i = 0; i < 4; i++)
#pragma unroll
            for (int j = 0; j < 4; j++) acc[i][j] += a[i] * v[j];
    }
    const size_t sbase = ((size_t)bh * NC + c) * (L_ * L_);
#pragma unroll
    for (int i = 0; i < 4; i++)
#pragma unroll
        for (int j = 0; j < 4; j++)
            Sc[sbase + (size_t)(l0 + i) * L_ + m0 + j] = acc[i][j];

    if (threadIdx.x < L_) {
        float s = 0.f;
        for (int t = 0; t < CHUNK; t++) s += Ks[t * L_ + threadIdx.x];
        ks[((size_t)bh * NC + c) * L_ + threadIdx.x] = s;
    }
}

// ---------------------------------------------------------------------------
// Exclusive prefix over chunks — unchanged
// ---------------------------------------------------------------------------
__global__ void prefix_kernel(float* __restrict__ Sc, float* __restrict__ ks)
{
    const int bh = blockIdx.x;
    const int e = blockIdx.y * 256 + threadIdx.x;
    const size_t base = (size_t)bh * NC * (L_ * L_);
    {
        float acc = 0.f;
#pragma unroll
        for (int c = 0; c < NC; c++) {
            size_t idx = base + (size_t)c * (L_ * L_) + e;
            float tmp = Sc[idx];
            Sc[idx] = acc;
            acc += tmp;
        }
    }
    if (blockIdx.y == 0 && threadIdx.x < L_) {
        const size_t kb = (size_t)bh * NC * L_;
        float acc = 0.f;
#pragma unroll
        for (int c = 0; c < NC; c++) {
            size_t idx = kb + (size_t)c * L_ + threadIdx.x;
            float tmp = ks[idx];
            ks[idx] = acc;
            acc += tmp;
        }
    }
}

// ---------------------------------------------------------------------------
// Tensor-core chunk attention, single-fp16 operands (CHUNK=64, 128 threads):
//   P = causal(qs_norm @ K^T); Y = P @ V + qs_norm @ S_prev.  One MMA pass
//   per GEMM. Normalizer uses fp32 k staged in smem (exact divisor).
// smem (65536 B -> 3 blocks/SM):
//   [0:16384)      qsf fp32   -> P16 reuses [0:8192)
//   [16384:32768)  kf fp32    (normalizer)
//   [32768:40960)  Q16
//   [40960:49152)  K16
//   [49152:57344)  VT16
//   [57344:65536)  ST16
// ---------------------------------------------------------------------------
#define AT_SMEM 65536

__global__ void __launch_bounds__(128)
attn_kernel(const float* __restrict__ qkv, const float* __restrict__ Sprev,
            const float* __restrict__ kpre, __half* __restrict__ yh)
{
    extern __shared__ char smc[];
    float* qsf = (float*)smc;
    float* kf  = (float*)(smc + 16384);
    const uint32_t sb   = smem_u32(smc);
    const uint32_t P16  = sb;
    const uint32_t Q16  = sb + 32768;
    const uint32_t K16  = sb + 40960;
    const uint32_t VT16 = sb + 49152;
    const uint32_t ST16 = sb + 57344;

    const int c = blockIdx.x, bh = blockIdx.y;
    const int b = bh >> 4, h = bh & 15;
    const int tid = threadIdx.x;
    const int wid = tid >> 5, lane = tid & 31;
    const size_t rowbase = ((size_t)(b * T_ + c * CHUNK)) * (3 * D_) + h * L_;
    const size_t sbase = ((size_t)bh * NC + c) * (L_ * L_);

    // qs fp32 stage
    for (int i = tid; i < CHUNK * 16; i += 128) {
        int t = i >> 4, f = (i & 15) << 2;
        *(float4*)&qsf[t * L_ + f] =
            *(const float4*)&qkv[rowbase + (size_t)t * (3 * D_) + f];
    }
    // k: fp32 stage + fp16 tile
    for (int i = tid; i < 1024; i += 128) {
        int t = i >> 4, f = (i & 15) << 2;
        float4 kv4 = *(const float4*)&qkv[rowbase + (size_t)t * (3 * D_) + D_ + f];
        *(float4*)&kf[t * L_ + f] = kv4;
        sts32(sw_addr(K16, t, f),     pack_h2(kv4.x, kv4.y));
        sts32(sw_addr(K16, t, f + 2), pack_h2(kv4.z, kv4.w));
    }
    // V^T fp16: read rows t0,t0+1; word packs (t0,t0+1) along columns
    for (int i = tid; i < 512; i += 128) {
        int t0 = (i >> 4) * 2;
        int m0 = (i & 15) << 2;
        const float* v0 = &qkv[rowbase + (size_t)t0 * (3 * D_) + 2 * D_];
        float4 a = *(const float4*)&v0[m0];
        float4 bv = *(const float4*)&v0[3 * D_ + m0];
        sts32(sw_addr(VT16, m0 + 0, t0), pack_h2(a.x, bv.x));
        sts32(sw_addr(VT16, m0 + 1, t0), pack_h2(a.y, bv.y));
        sts32(sw_addr(VT16, m0 + 2, t0), pack_h2(a.z, bv.z));
        sts32(sw_addr(VT16, m0 + 3, t0), pack_h2(a.w, bv.w));
    }
    // S_prev^T fp16
    for (int i = tid; i < 512; i += 128) {
        int l0 = (i >> 4) * 2;
        int m0 = (i & 15) << 2;
        const float* s0 = &Sprev[sbase + (size_t)l0 * L_];
        float4 a = *(const float4*)&s0[m0];
        float4 bv = *(const float4*)&s0[L_ + m0];
        sts32(sw_addr(ST16, m0 + 0, l0), pack_h2(a.x, bv.x));
        sts32(sw_addr(ST16, m0 + 1, l0), pack_h2(a.y, bv.y));
        sts32(sw_addr(ST16, m0 + 2, l0), pack_h2(a.z, bv.z));
        sts32(sw_addr(ST16, m0 + 3, l0), pack_h2(a.w, bv.w));
    }
    __syncthreads();

    // normalize qs with exact fp32 cumsum
    if (tid < L_) {
        const int l = tid;
        float acc = kpre[((size_t)bh * NC + c) * L_ + l];
        for (int t = 0; t < CHUNK; t++) {
            acc += kf[t * L_ + l];
            qsf[t * L_ + l] = __fdividef(qsf[t * L_ + l], acc);
        }
    }
    __syncthreads();

    // qs -> fp16 tile
    for (int i = tid; i < 1024; i += 128) {
        int row = i >> 3, col = (i & 7) * 8;
        const float* q = &qsf[row * L_ + col];
        sts32(sw_addr(Q16, row, col),     pack_h2(q[0], q[1]));
        sts32(sw_addr(Q16, row, col + 2), pack_h2(q[2], q[3]));
        sts32(sw_addr(Q16, row, col + 4), pack_h2(q[4], q[5]));
        sts32(sw_addr(Q16, row, col + 6), pack_h2(q[6], q[7]));
    }
    __syncthreads();    // qsf dead; region becomes P

    const int wm = wid * 16;
    const int a_row = (lane & 15);
    const int a_khalf = lane >> 4;
    const int b_grp = (lane >> 4) & 1;
    const int b_khalf = (lane >> 3) & 1;
    const int b_row = lane & 7;
    const int g = lane >> 2, tig = lane & 3;

    // ---- P = qs_norm @ K^T (single pass) ----
    float accP[8][4];
#pragma unroll
    for (int nt = 0; nt < 8; nt++)
#pragma unroll
        for (int e = 0; e < 4; e++) accP[nt][e] = 0.f;

#pragma unroll
    for (int kk = 0; kk < 4; kk++) {
        uint32_t ah[4];
        {
            int row = wm + a_row;
            int chunk = 2 * kk + a_khalf;
            uint32_t off = (uint32_t)(row * 128 + ((chunk ^ (row & 7)) << 4));
            ldsm_x4(Q16 + off, ah[0], ah[1], ah[2], ah[3]);
        }
        uint32_t bh_[4][4];
#pragma unroll
        for (int np = 0; np < 4; np++) {
            int row = np * 16 + b_grp * 8 + b_row;
            int chunk = 2 * kk + b_khalf;
            uint32_t off = (uint32_t)(row * 128 + ((chunk ^ (row & 7)) << 4));
            ldsm_x4(K16 + off, bh_[np][0], bh_[np][1], bh_[np][2], bh_[np][3]);
        }
#pragma unroll
        for (int nt = 0; nt < 8; nt++)
            mma_f16(accP[nt], ah, &bh_[nt >> 1][(nt & 1) * 2]);
    }

    // ---- causal mask + store P fp16 ----
    {
        int r0 = wm + g, r1 = wm + g + 8;
#pragma unroll
        for (int nt = 0; nt < 8; nt++) {
            int colp = nt * 8 + 2 * tig;
            float p00 = (colp     <= r0) ? accP[nt][0] : 0.f;
            float p01 = (colp + 1 <= r0) ? accP[nt][1] : 0.f;
            float p10 = (colp     <= r1) ? accP[nt][2] : 0.f;
            float p11 = (colp + 1 <= r1) ? accP[nt][3] : 0.f;
            sts32(sw_addr(P16, r0, colp), pack_h2(p00, p01));
            sts32(sw_addr(P16, r1, colp), pack_h2(p10, p11));
        }
    }
    __syncthreads();

    // ---- Y = P @ V + qs_norm @ S_prev (single pass each) ----
    float acc[8][4];
#pragma unroll
    for (int nt = 0; nt < 8; nt++)
#pragma unroll
        for (int e = 0; e < 4; e++) acc[nt][e] = 0.f;

#pragma unroll
    for (int half = 0; half < 2; half++) {
        const uint32_t A16 = half ? Q16 : P16;
        const uint32_t B16 = half ? ST16 : VT16;
#pragma unroll
        for (int kk = 0; kk < 4; kk++) {
            uint32_t ah[4];
            {
                int row = wm + a_row;
                int chunk = 2 * kk + a_khalf;
                uint32_t off = (uint32_t)(row * 128 + ((chunk ^ (row & 7)) << 4));
                ldsm_x4(A16 + off, ah[0], ah[1], ah[2], ah[3]);
            }
            uint32_t bh_[4][4];
#pragma unroll
            for (int np = 0; np < 4; np++) {
                int row = np * 16 + b_grp * 8 + b_row;
                int chunk = 2 * kk + b_khalf;
                uint32_t off = (uint32_t)(row * 128 + ((chunk ^ (row & 7)) << 4));
                ldsm_x4(B16 + off, bh_[np][0], bh_[np][1], bh_[np][2], bh_[np][3]);
            }
#pragma unroll
            for (int nt = 0; nt < 8; nt++)
                mma_f16(acc[nt], ah, &bh_[nt >> 1][(nt & 1) * 2]);
        }
    }

    // epilogue: single-fp16 y
    {
        int r0 = wm + g;
#pragma unroll
        for (int dr = 0; dr < 2; dr++) {
            int row = r0 + dr * 8;
            size_t ybase = ((size_t)(b * T_ + c * CHUNK + row)) * D_ + h * L_;
#pragma unroll
            for (int nt = 0; nt < 8; nt++) {
                int colp = nt * 8 + 2 * tig;
                *(uint32_t*)&yh[ybase + colp] =
                    pack_h2(acc[nt][2 * dr], acc[nt][2 * dr + 1]);
            }
        }
    }
}

// ---------------------------------------------------------------------------
extern "C" void kernel_launch(void* const* d_in, const int* in_sizes, int n_in,
                              void* d_out, int out_size)
{
    const float* x  = (const float*)d_in[0];
    const float* w  = (const float*)d_in[1];
    const float* wo = (const float*)d_in[2];
    float* out = (float*)d_out;

    float *qkv, *Sc, *ks;
    __half *xh, *wh, *wl, *woth, *wotl, *yh;
    cudaGetSymbolAddress((void**)&qkv, g_qkv);
    cudaGetSymbolAddress((void**)&Sc,  g_Sc);
    cudaGetSymbolAddress((void**)&ks,  g_ks);
    cudaGetSymbolAddress((void**)&xh,  g_xh);
    cudaGetSymbolAddress((void**)&wh,  g_wh);
    cudaGetSymbolAddress((void**)&wl,  g_wl);
    cudaGetSymbolAddress((void**)&woth, g_woth);
    cudaGetSymbolAddress((void**)&wotl, g_wotl);
    cudaGetSymbolAddress((void**)&yh,  g_yh);

    cudaFuncSetAttribute(gemm_f16<0>,
                         cudaFuncAttributeMaxDynamicSharedMemorySize, GQ_SMEM);
    cudaFuncSetAttribute(gemm_f16<1>,
                         cudaFuncAttributeMaxDynamicSharedMemorySize, GQ_SMEM);
    cudaFuncSetAttribute(chunkstate_kernel,
                         cudaFuncAttributeMaxDynamicSharedMemorySize, 32768);
    cudaFuncSetAttribute(attn_kernel,
                         cudaFuncAttributeMaxDynamicSharedMemorySize, AT_SMEM);

    // 0) fused prep
    prep_inputs_kernel<<<NBX + NBW + 1024, 256>>>(x, w, wo);
    // 1) qkv = xh @ (wh+wl)^T + fused softmax/exp epilogue
    gemm_f16<1><<<dim3(3 * D_ / 64, BT_ / 128), 128, GQ_SMEM>>>(
        xh, wh, wl, qkv, 3 * D_, D_);
    // 2) per-chunk states + k sums
    chunkstate_kernel<<<dim3(NC, BH_), 256, 32768>>>(qkv, Sc, ks);
    // 3) exclusive prefix over chunks
    prefix_kernel<<<dim3(BH_, 16), 256>>>(Sc, ks);
    // 4) single-fp16 tensor-core chunk attention -> y
    attn_kernel<<<dim3(NC, BH_), 128, AT_SMEM>>>(qkv, Sc, ks, yh);
    // 5) out = yh @ (woth+wotl)^T
    gemm_f16<0><<<dim3(D_ / 64, BT_ / 128), 128, GQ_SMEM>>>(
        yh, woth, wotl, out, D_, D_);
}

// round 16
// speedup vs baseline: 2.8687x; 1.4103x over previous
#include <cuda_runtime.h>
#include <cuda_bf16.h>
#include <cuda_fp16.h>
#include <cstdint>

// Problem constants
#define B_   4
#define T_   2048
#define D_   1024
#define H_   16
#define L_   64
#define BT_  (B_*T_)        // 8192
#define BH_  (B_*H_)        // 64
#define CHUNK 64
#define NC   (T_/CHUNK)     // 32

// ---------------------------------------------------------------------------
// Scratch (device globals; no allocation allowed)
// ---------------------------------------------------------------------------
__device__ float g_qkv[(size_t)BT_ * 3 * D_];        // (8192, 3072)  qs|k_exp|v fp32
__device__ float g_Sc [(size_t)BH_ * NC * L_ * L_];  // chunk states -> excl prefix
__device__ float g_ks [(size_t)BH_ * NC * L_];       // chunk k-sums -> excl prefix
__device__ __half g_xh[(size_t)BT_ * D_];            // fp16 of x
__device__ __half g_wh[(size_t)3 * D_ * D_];         // fp16 of w
__device__ __half g_woth[(size_t)D_ * D_];           // fp16 of w_out^T
__device__ __half g_yh[(size_t)BT_ * D_];            // fp16 of y

// ---------------------------------------------------------------------------
// PTX helpers
// ---------------------------------------------------------------------------
__device__ __forceinline__ uint32_t smem_u32(const void* p) {
    uint32_t a;
    asm("{ .reg .u64 t; cvta.to.shared.u64 t, %1; cvt.u32.u64 %0, t; }" : "=r"(a) : "l"(p));
    return a;
}

__device__ __forceinline__ void cp_async16(uint32_t dst, const void* src) {
    asm volatile("cp.async.cg.shared.global [%0], [%1], 16;" :: "r"(dst), "l"(src) : "memory");
}
__device__ __forceinline__ void cp_commit() {
    asm volatile("cp.async.commit_group;" ::: "memory");
}
__device__ __forceinline__ void cp_wait1() {
    asm volatile("cp.async.wait_group 1;" ::: "memory");
}

__device__ __forceinline__ void ldsm_x4(uint32_t addr, uint32_t& r0, uint32_t& r1,
                                        uint32_t& r2, uint32_t& r3) {
    asm volatile("ldmatrix.sync.aligned.m8n8.x4.shared.b16 {%0,%1,%2,%3}, [%4];"
                 : "=r"(r0), "=r"(r1), "=r"(r2), "=r"(r3) : "r"(addr));
}

__device__ __forceinline__ void mma_f16(float* c, const uint32_t* a, const uint32_t* b) {
    asm volatile(
        "mma.sync.aligned.m16n8k16.row.col.f32.f16.f16.f32 "
        "{%0,%1,%2,%3}, {%4,%5,%6,%7}, {%8,%9}, {%0,%1,%2,%3};"
        : "+f"(c[0]), "+f"(c[1]), "+f"(c[2]), "+f"(c[3])
        : "r"(a[0]), "r"(a[1]), "r"(a[2]), "r"(a[3]), "r"(b[0]), "r"(b[1]));
}

__device__ __forceinline__ void sts32(uint32_t addr, uint32_t v) {
    asm volatile("st.shared.b32 [%0], %1;" :: "r"(addr), "r"(v) : "memory");
}

// pack two floats -> fp16x2 word
__device__ __forceinline__ uint32_t pack_h2(float a, float b) {
    __half2 hv = __halves2half2(__float2half(a), __float2half(b));
    return *(uint32_t*)&hv;
}

// swizzled byte address of a 16-bit elem (row, col) in a 64-col (128B-row) tile
__device__ __forceinline__ uint32_t sw_addr(uint32_t base, int row, int col) {
    return base + (uint32_t)(row * 128 + ((((col >> 3) ^ (row & 7))) << 4) + ((col & 7) * 2));
}

// ---------------------------------------------------------------------------
// ONE fused input-prep kernel:
//   x -> fp16 ; w -> fp16 ; w_out^T -> fp16
// ---------------------------------------------------------------------------
#define NBX (BT_ * D_ / 4 / 256)          // 8192
#define NBW (3 * D_ * D_ / 4 / 256)       // 3072

__global__ void __launch_bounds__(256)
prep_inputs_kernel(const float* __restrict__ x, const float* __restrict__ w,
                   const float* __restrict__ wo)
{
    const int bid = blockIdx.x;
    if (bid < NBX + NBW) {
        const float* src;
        __half* dst;
        int i;
        if (bid < NBX) {
            src = x; dst = g_xh;
            i = bid * 256 + threadIdx.x;
        } else {
            src = w; dst = g_wh;
            i = (bid - NBX) * 256 + threadIdx.x;
        }
        float4 v = ((const float4*)src)[i];
        ((uint32_t*)dst)[2 * i]     = pack_h2(v.x, v.y);
        ((uint32_t*)dst)[2 * i + 1] = pack_h2(v.z, v.w);
    } else {
        __shared__ float tile[32][33];
        int tb = bid - NBX - NBW;            // 0..1023
        int n0 = (tb & 31) * 32, k0 = (tb >> 5) * 32;
        int tx = threadIdx.x & 31, ty = threadIdx.x >> 5;
        for (int r = ty; r < 32; r += 8)
            tile[r][tx] = wo[(size_t)(k0 + r) * D_ + n0 + tx];
        __syncthreads();
        for (int r = ty; r < 32; r += 8)
            g_woth[(size_t)(n0 + r) * D_ + k0 + tx] = __float2half(tile[tx][r]);
    }
}

// ---------------------------------------------------------------------------
// Single-pass fp16 GEMM: C = Ah*Bh^T (fp32 accum).
// 128x64 tile, BK=64, 128 threads (4 warps along M), 3-stage cp.async,
// stage = 24KB -> 72KB/CTA -> 3 CTAs/SM.
// MODE=1: fused qkv epilogue (softmax/exp/pass). MODE=0: plain store.
// ---------------------------------------------------------------------------
#define GQ_A 16384
#define GQ_B 8192
#define GQ_STAGE (GQ_A + GQ_B)              // 24576
#define GQ_SMEM  (3 * GQ_STAGE)             // 73728

template<int MODE>
__global__ void __launch_bounds__(128, 3)
gemm_f16(const __half* __restrict__ Ah, const __half* __restrict__ Bh,
         float* __restrict__ C, int N, int K)
{
    extern __shared__ char smem[];
    const uint32_t smem_base = smem_u32(smem);
    const int tid = threadIdx.x;
    const int wid = tid >> 5, lane = tid & 31;
    const int m0 = blockIdx.y * 128, n0 = blockIdx.x * 64;
    const int wm = wid * 32;

    auto load_stage = [&](int kt, int s) {
        const int k0 = kt << 6;
        const uint32_t sb = smem_base + s * GQ_STAGE;
#pragma unroll
        for (int ii = 0; ii < 8; ii++) {
            int j = tid + ii * 128;
            int r = j >> 3, c = j & 7;
            const void* g = &Ah[(size_t)(m0 + r) * K + k0 + c * 8];
            cp_async16(sb + (uint32_t)(r * 128 + ((c ^ (r & 7)) << 4)), g);
        }
        const uint32_t tb = sb + GQ_A;
#pragma unroll
        for (int ii = 0; ii < 4; ii++) {
            int j = tid + ii * 128;
            int r = j >> 3, c = j & 7;
            const void* g = &Bh[(size_t)(n0 + r) * K + k0 + c * 8];
            cp_async16(tb + (uint32_t)(r * 128 + ((c ^ (r & 7)) << 4)), g);
        }
    };

    float acc[2][8][4];
#pragma unroll
    for (int mt = 0; mt < 2; mt++)
#pragma unroll
        for (int nt = 0; nt < 8; nt++)
#pragma unroll
            for (int e = 0; e < 4; e++) acc[mt][nt][e] = 0.f;

    const int NKT = K >> 6;   // 16
    load_stage(0, 0); cp_commit();
    load_stage(1, 1); cp_commit();

    const int a_row = (lane & 15);
    const int a_khalf = lane >> 4;
    const int b_grp = (lane >> 4) & 1;
    const int b_khalf = (lane >> 3) & 1;
    const int b_row = lane & 7;

    int s = 0, sload = 2;
    for (int kt = 0; kt < NKT; kt++) {
        const uint32_t st = smem_base + s * GQ_STAGE;
        cp_wait1();
        __syncthreads();

        if (kt + 2 < NKT) load_stage(kt + 2, sload);
        cp_commit();

        const uint32_t aA = st;
        const uint32_t aB = st + GQ_A;

#pragma unroll
        for (int kk = 0; kk < 4; kk++) {
            uint32_t ah[2][4];
#pragma unroll
            for (int mt = 0; mt < 2; mt++) {
                int row = wm + mt * 16 + a_row;
                int chunk = 2 * kk + a_khalf;
                uint32_t off = (uint32_t)(row * 128 + ((chunk ^ (row & 7)) << 4));
                ldsm_x4(aA + off, ah[mt][0], ah[mt][1], ah[mt][2], ah[mt][3]);
            }
            uint32_t bh[4][4];
#pragma unroll
            for (int np = 0; np < 4; np++) {
                int row = np * 16 + b_grp * 8 + b_row;
                int chunk = 2 * kk + b_khalf;
                uint32_t off = (uint32_t)(row * 128 + ((chunk ^ (row & 7)) << 4));
                ldsm_x4(aB + off, bh[np][0], bh[np][1], bh[np][2], bh[np][3]);
            }
#pragma unroll
            for (int mt = 0; mt < 2; mt++)
#pragma unroll
                for (int nt = 0; nt < 8; nt++)
                    mma_f16(acc[mt][nt], ah[mt], &bh[nt >> 1][(nt & 1) * 2]);
        }
        s = (s == 2) ? 0 : s + 1;
        sload = (sload == 2) ? 0 : sload + 1;
    }

    const int g = lane >> 2, tig = lane & 3;
    const int gcol0 = n0;

    if (MODE == 1 && gcol0 < D_) {
        // q region: per-head softmax
#pragma unroll
        for (int mt = 0; mt < 2; mt++) {
            float vA[16], vB[16];
#pragma unroll
            for (int nt = 0; nt < 8; nt++) {
                vA[2*nt]   = acc[mt][nt][0] * 0.125f;
                vA[2*nt+1] = acc[mt][nt][1] * 0.125f;
                vB[2*nt]   = acc[mt][nt][2] * 0.125f;
                vB[2*nt+1] = acc[mt][nt][3] * 0.125f;
            }
            float mA = vA[0], mB = vB[0];
#pragma unroll
            for (int i = 1; i < 16; i++) { mA = fmaxf(mA, vA[i]); mB = fmaxf(mB, vB[i]); }
            mA = fmaxf(mA, __shfl_xor_sync(0xffffffffu, mA, 1));
            mA = fmaxf(mA, __shfl_xor_sync(0xffffffffu, mA, 2));
            mB = fmaxf(mB, __shfl_xor_sync(0xffffffffu, mB, 1));
            mB = fmaxf(mB, __shfl_xor_sync(0xffffffffu, mB, 2));
            float sA = 0.f, sB = 0.f;
#pragma unroll
            for (int i = 0; i < 16; i++) {
                vA[i] = expf(vA[i] - mA); sA += vA[i];
                vB[i] = expf(vB[i] - mB); sB += vB[i];
            }
            sA += __shfl_xor_sync(0xffffffffu, sA, 1);
            sA += __shfl_xor_sync(0xffffffffu, sA, 2);
            sB += __shfl_xor_sync(0xffffffffu, sB, 1);
            sB += __shfl_xor_sync(0xffffffffu, sB, 2);
            float iA = 1.f / sA, iB = 1.f / sB;
            int row = m0 + wm + mt * 16 + g;
#pragma unroll
            for (int nt = 0; nt < 8; nt++) {
                int col = gcol0 + nt * 8 + 2 * tig;
                *(float2*)&C[(size_t)row * N + col]       = make_float2(vA[2*nt]*iA, vA[2*nt+1]*iA);
                *(float2*)&C[(size_t)(row + 8) * N + col] = make_float2(vB[2*nt]*iB, vB[2*nt+1]*iB);
            }
        }
    } else if (MODE == 1 && gcol0 < 2 * D_) {
        // k region: exp(v*0.125)+1e-6
#pragma unroll
        for (int mt = 0; mt < 2; mt++) {
            int row = m0 + wm + mt * 16 + g;
#pragma unroll
            for (int nt = 0; nt < 8; nt++) {
                int col = gcol0 + nt * 8 + 2 * tig;
                float* c = acc[mt][nt];
                *(float2*)&C[(size_t)row * N + col] =
                    make_float2(expf(c[0]*0.125f)+1e-6f, expf(c[1]*0.125f)+1e-6f);
                *(float2*)&C[(size_t)(row + 8) * N + col] =
                    make_float2(expf(c[2]*0.125f)+1e-6f, expf(c[3]*0.125f)+1e-6f);
            }
        }
    } else {
        // v region / MODE 0: plain store
#pragma unroll
        for (int mt = 0; mt < 2; mt++) {
            int row = m0 + wm + mt * 16 + g;
#pragma unroll
            for (int nt = 0; nt < 8; nt++) {
                int col = gcol0 + nt * 8 + 2 * tig;
                float* c = acc[mt][nt];
                *(float2*)&C[(size_t)row * N + col]       = make_float2(c[0], c[1]);
                *(float2*)&C[(size_t)(row + 8) * N + col] = make_float2(c[2], c[3]);
            }
        }
    }
}

// ---------------------------------------------------------------------------
// Per-chunk state (CHUNK=64) — unchanged
// ---------------------------------------------------------------------------
__global__ void __launch_bounds__(256)
chunkstate_kernel(const float* __restrict__ qkv,
                  float* __restrict__ Sc, float* __restrict__ ks)
{
    extern __shared__ float sm[];
    float* Ks = sm;
    float* Vs = sm + CHUNK * L_;
    const int c = blockIdx.x, bh = blockIdx.y;
    const int b = bh >> 4, h = bh & 15;
    const size_t rowbase = ((size_t)(b * T_ + c * CHUNK)) * (3 * D_) + h * L_;

    for (int i = threadIdx.x; i < CHUNK * 16; i += 256) {
        int t = i >> 4, f = (i & 15) << 2;
        size_t g = rowbase + (size_t)t * (3 * D_) + f;
        *(float4*)&Ks[t * L_ + f] = *(const float4*)&qkv[g + D_];
        *(float4*)&Vs[t * L_ + f] = *(const float4*)&qkv[g + 2 * D_];
    }
    __syncthreads();

    const int l0 = (threadIdx.x >> 4) << 2;
    const int m0 = (threadIdx.x & 15) << 2;
    float acc[4][4];
#pragma unroll
    for (int i = 0; i < 4; i++)
#pragma unroll
        for (int j = 0; j < 4; j++) acc[i][j] = 0.f;
    for (int t = 0; t < CHUNK; t++) {
        float a[4], v[4];
#pragma unroll
        for (int i = 0; i < 4; i++) a[i] = Ks[t * L_ + l0 + i];
#pragma unroll
        for (int j = 0; j < 4; j++) v[j] = Vs[t * L_ + m0 + j];
#pragma unroll
        for (int i = 0; i < 4; i++)
#pragma unroll
            for (int j = 0; j < 4; j++) acc[i][j] += a[i] * v[j];
    }
    const size_t sbase = ((size_t)bh * NC + c) * (L_ * L_);
#pragma unroll
    for (int i = 0; i < 4; i++)
#pragma unroll
        for (int j = 0; j < 4; j++)
            Sc[sbase + (size_t)(l0 + i) * L_ + m0 + j] = acc[i][j];

    if (threadIdx.x < L_) {
        float s = 0.f;
        for (int t = 0; t < CHUNK; t++) s += Ks[t * L_ + threadIdx.x];
        ks[((size_t)bh * NC + c) * L_ + threadIdx.x] = s;
    }
}

// ---------------------------------------------------------------------------
// Exclusive prefix over chunks — unchanged
// ---------------------------------------------------------------------------
__global__ void prefix_kernel(float* __restrict__ Sc, float* __restrict__ ks)
{
    const int bh = blockIdx.x;
    const int e = blockIdx.y * 256 + threadIdx.x;
    const size_t base = (size_t)bh * NC * (L_ * L_);
    {
        float acc = 0.f;
#pragma unroll
        for (int c = 0; c < NC; c++) {
            size_t idx = base + (size_t)c * (L_ * L_) + e;
            float tmp = Sc[idx];
            Sc[idx] = acc;
            acc += tmp;
        }
    }
    if (blockIdx.y == 0 && threadIdx.x < L_) {
        const size_t kb = (size_t)bh * NC * L_;
        float acc = 0.f;
#pragma unroll
        for (int c = 0; c < NC; c++) {
            size_t idx = kb + (size_t)c * L_ + threadIdx.x;
            float tmp = ks[idx];
            ks[idx] = acc;
            acc += tmp;
        }
    }
}

// ---------------------------------------------------------------------------
// Tensor-core chunk attention, single-fp16 operands — unchanged from R15.
// smem 65536 B -> 3 blocks/SM.
// ---------------------------------------------------------------------------
#define AT_SMEM 65536

__global__ void __launch_bounds__(128)
attn_kernel(const float* __restrict__ qkv, const float* __restrict__ Sprev,
            const float* __restrict__ kpre, __half* __restrict__ yh)
{
    extern __shared__ char smc[];
    float* qsf = (float*)smc;
    float* kf  = (float*)(smc + 16384);
    const uint32_t sb   = smem_u32(smc);
    const uint32_t P16  = sb;
    const uint32_t Q16  = sb + 32768;
    const uint32_t K16  = sb + 40960;
    const uint32_t VT16 = sb + 49152;
    const uint32_t ST16 = sb + 57344;

    const int c = blockIdx.x, bh = blockIdx.y;
    const int b = bh >> 4, h = bh & 15;
    const int tid = threadIdx.x;
    const int wid = tid >> 5, lane = tid & 31;
    const size_t rowbase = ((size_t)(b * T_ + c * CHUNK)) * (3 * D_) + h * L_;
    const size_t sbase = ((size_t)bh * NC + c) * (L_ * L_);

    for (int i = tid; i < CHUNK * 16; i += 128) {
        int t = i >> 4, f = (i & 15) << 2;
        *(float4*)&qsf[t * L_ + f] =
            *(const float4*)&qkv[rowbase + (size_t)t * (3 * D_) + f];
    }
    for (int i = tid; i < 1024; i += 128) {
        int t = i >> 4, f = (i & 15) << 2;
        float4 kv4 = *(const float4*)&qkv[rowbase + (size_t)t * (3 * D_) + D_ + f];
        *(float4*)&kf[t * L_ + f] = kv4;
        sts32(sw_addr(K16, t, f),     pack_h2(kv4.x, kv4.y));
        sts32(sw_addr(K16, t, f + 2), pack_h2(kv4.z, kv4.w));
    }
    for (int i = tid; i < 512; i += 128) {
        int t0 = (i >> 4) * 2;
        int m0 = (i & 15) << 2;
        const float* v0 = &qkv[rowbase + (size_t)t0 * (3 * D_) + 2 * D_];
        float4 a = *(const float4*)&v0[m0];
        float4 bv = *(const float4*)&v0[3 * D_ + m0];
        sts32(sw_addr(VT16, m0 + 0, t0), pack_h2(a.x, bv.x));
        sts32(sw_addr(VT16, m0 + 1, t0), pack_h2(a.y, bv.y));
        sts32(sw_addr(VT16, m0 + 2, t0), pack_h2(a.z, bv.z));
        sts32(sw_addr(VT16, m0 + 3, t0), pack_h2(a.w, bv.w));
    }
    for (int i = tid; i < 512; i += 128) {
        int l0 = (i >> 4) * 2;
        int m0 = (i & 15) << 2;
        const float* s0 = &Sprev[sbase + (size_t)l0 * L_];
        float4 a = *(const float4*)&s0[m0];
        float4 bv = *(const float4*)&s0[L_ + m0];
        sts32(sw_addr(ST16, m0 + 0, l0), pack_h2(a.x, bv.x));
        sts32(sw_addr(ST16, m0 + 1, l0), pack_h2(a.y, bv.y));
        sts32(sw_addr(ST16, m0 + 2, l0), pack_h2(a.z, bv.z));
        sts32(sw_addr(ST16, m0 + 3, l0), pack_h2(a.w, bv.w));
    }
    __syncthreads();

    if (tid < L_) {
        const int l = tid;
        float acc = kpre[((size_t)bh * NC + c) * L_ + l];
        for (int t = 0; t < CHUNK; t++) {
            acc += kf[t * L_ + l];
            qsf[t * L_ + l] = __fdividef(qsf[t * L_ + l], acc);
        }
    }
    __syncthreads();

    for (int i = tid; i < 1024; i += 128) {
        int row = i >> 3, col = (i & 7) * 8;
        const float* q = &qsf[row * L_ + col];
        sts32(sw_addr(Q16, row, col),     pack_h2(q[0], q[1]));
        sts32(sw_addr(Q16, row, col + 2), pack_h2(q[2], q[3]));
        sts32(sw_addr(Q16, row, col + 4), pack_h2(q[4], q[5]));
        sts32(sw_addr(Q16, row, col + 6), pack_h2(q[6], q[7]));
    }
    __syncthreads();

    const int wm = wid * 16;
    const int a_row = (lane & 15);
    const int a_khalf = lane >> 4;
    const int b_grp = (lane >> 4) & 1;
    const int b_khalf = (lane >> 3) & 1;
    const int b_row = lane & 7;
    const int g = lane >> 2, tig = lane & 3;

    float accP[8][4];
#pragma unroll
    for (int nt = 0; nt < 8; nt++)
#pragma unroll
        for (int e = 0; e < 4; e++) accP[nt][e] = 0.f;

#pragma unroll
    for (int kk = 0; kk < 4; kk++) {
        uint32_t ah[4];
        {
            int row = wm + a_row;
            int chunk = 2 * kk + a_khalf;
            uint32_t off = (uint32_t)(row * 128 + ((chunk ^ (row & 7)) << 4));
            ldsm_x4(Q16 + off, ah[0], ah[1], ah[2], ah[3]);
        }
        uint32_t bh_[4][4];
#pragma unroll
        for (int np = 0; np < 4; np++) {
            int row = np * 16 + b_grp * 8 + b_row;
            int chunk = 2 * kk + b_khalf;
            uint32_t off = (uint32_t)(row * 128 + ((chunk ^ (row & 7)) << 4));
            ldsm_x4(K16 + off, bh_[np][0], bh_[np][1], bh_[np][2], bh_[np][3]);
        }
#pragma unroll
        for (int nt = 0; nt < 8; nt++)
            mma_f16(accP[nt], ah, &bh_[nt >> 1][(nt & 1) * 2]);
    }

    {
        int r0 = wm + g, r1 = wm + g + 8;
#pragma unroll
        for (int nt = 0; nt < 8; nt++) {
            int colp = nt * 8 + 2 * tig;
            float p00 = (colp     <= r0) ? accP[nt][0] : 0.f;
            float p01 = (colp + 1 <= r0) ? accP[nt][1] : 0.f;
            float p10 = (colp     <= r1) ? accP[nt][2] : 0.f;
            float p11 = (colp + 1 <= r1) ? accP[nt][3] : 0.f;
            sts32(sw_addr(P16, r0, colp), pack_h2(p00, p01));
            sts32(sw_addr(P16, r1, colp), pack_h2(p10, p11));
        }
    }
    __syncthreads();

    float acc[8][4];
#pragma unroll
    for (int nt = 0; nt < 8; nt++)
#pragma unroll
        for (int e = 0; e < 4; e++) acc[nt][e] = 0.f;

#pragma unroll
    for (int half = 0; half < 2; half++) {
        const uint32_t A16 = half ? Q16 : P16;
        const uint32_t B16 = half ? ST16 : VT16;
#pragma unroll
        for (int kk = 0; kk < 4; kk++) {
            uint32_t ah[4];
            {
                int row = wm + a_row;
                int chunk = 2 * kk + a_khalf;
                uint32_t off = (uint32_t)(row * 128 + ((chunk ^ (row & 7)) << 4));
                ldsm_x4(A16 + off, ah[0], ah[1], ah[2], ah[3]);
            }
            uint32_t bh_[4][4];
#pragma unroll
            for (int np = 0; np < 4; np++) {
                int row = np * 16 + b_grp * 8 + b_row;
                int chunk = 2 * kk + b_khalf;
                uint32_t off = (uint32_t)(row * 128 + ((chunk ^ (row & 7)) << 4));
                ldsm_x4(B16 + off, bh_[np][0], bh_[np][1], bh_[np][2], bh_[np][3]);
            }
#pragma unroll
            for (int nt = 0; nt < 8; nt++)
                mma_f16(acc[nt], ah, &bh_[nt >> 1][(nt & 1) * 2]);
        }
    }

    {
        int r0 = wm + g;
#pragma unroll
        for (int dr = 0; dr < 2; dr++) {
            int row = r0 + dr * 8;
            size_t ybase = ((size_t)(b * T_ + c * CHUNK + row)) * D_ + h * L_;
#pragma unroll
            for (int nt = 0; nt < 8; nt++) {
                int colp = nt * 8 + 2 * tig;
                *(uint32_t*)&yh[ybase + colp] =
                    pack_h2(acc[nt][2 * dr], acc[nt][2 * dr + 1]);
            }
        }
    }
}

// ---------------------------------------------------------------------------
extern "C" void kernel_launch(void* const* d_in, const int* in_sizes, int n_in,
                              void* d_out, int out_size)
{
    const float* x  = (const float*)d_in[0];
    const float* w  = (const float*)d_in[1];
    const float* wo = (const float*)d_in[2];
    float* out = (float*)d_out;

    float *qkv, *Sc, *ks;
    __half *xh, *wh, *woth, *yh;
    cudaGetSymbolAddress((void**)&qkv, g_qkv);
    cudaGetSymbolAddress((void**)&Sc,  g_Sc);
    cudaGetSymbolAddress((void**)&ks,  g_ks);
    cudaGetSymbolAddress((void**)&xh,  g_xh);
    cudaGetSymbolAddress((void**)&wh,  g_wh);
    cudaGetSymbolAddress((void**)&woth, g_woth);
    cudaGetSymbolAddress((void**)&yh,  g_yh);

    cudaFuncSetAttribute(gemm_f16<0>,
                         cudaFuncAttributeMaxDynamicSharedMemorySize, GQ_SMEM);
    cudaFuncSetAttribute(gemm_f16<1>,
                         cudaFuncAttributeMaxDynamicSharedMemorySize, GQ_SMEM);
    cudaFuncSetAttribute(chunkstate_kernel,
                         cudaFuncAttributeMaxDynamicSharedMemorySize, 32768);
    cudaFuncSetAttribute(attn_kernel,
                         cudaFuncAttributeMaxDynamicSharedMemorySize, AT_SMEM);

    // 0) fused prep: x,w,wo^T -> fp16
    prep_inputs_kernel<<<NBX + NBW + 1024, 256>>>(x, w, wo);
    // 1) qkv = xh @ wh^T (single-pass fp16) + fused softmax/exp epilogue
    gemm_f16<1><<<dim3(3 * D_ / 64, BT_ / 128), 128, GQ_SMEM>>>(
        xh, wh, qkv, 3 * D_, D_);
    // 2) per-chunk states + k sums
    chunkstate_kernel<<<dim3(NC, BH_), 256, 32768>>>(qkv, Sc, ks);
    // 3) exclusive prefix over chunks
    prefix_kernel<<<dim3(BH_, 16), 256>>>(Sc, ks);
    // 4) single-fp16 tensor-core chunk attention -> y
    attn_kernel<<<dim3(NC, BH_), 128, AT_SMEM>>>(qkv, Sc, ks, yh);
    // 5) out = yh @ woth^T (single-pass fp16)
    gemm_f16<0><<<dim3(D_ / 64, BT_ / 128), 128, GQ_SMEM>>>(
        yh, woth, out, D_, D_);
}

// round 17
// speedup vs baseline: 3.2163x; 1.1212x over previous
#include <cuda_runtime.h>
#include <cuda_bf16.h>
#include <cuda_fp16.h>
#include <cstdint>

// Problem constants
#define B_   4
#define T_   2048
#define D_   1024
#define H_   16
#define L_   64
#define BT_  (B_*T_)        // 8192
#define BH_  (B_*H_)        // 64
#define CHUNK 64
#define NC   (T_/CHUNK)     // 32

// ---------------------------------------------------------------------------
// Scratch (device globals; no allocation allowed)
// ---------------------------------------------------------------------------
__device__ __half g_qkv[(size_t)BT_ * 3 * D_];       // (8192, 3072) qs|k_exp|v fp16
__device__ float  g_Sc [(size_t)BH_ * NC * L_ * L_]; // chunk states -> excl prefix
__device__ float  g_ks [(size_t)BH_ * NC * L_];      // chunk k-sums -> excl prefix
__device__ __half g_xh[(size_t)BT_ * D_];            // fp16 of x
__device__ __half g_wh[(size_t)3 * D_ * D_];         // fp16 of w
__device__ __half g_woth[(size_t)D_ * D_];           // fp16 of w_out^T
__device__ __half g_yh[(size_t)BT_ * D_];            // fp16 of y

// ---------------------------------------------------------------------------
// PTX helpers
// ---------------------------------------------------------------------------
__device__ __forceinline__ uint32_t smem_u32(const void* p) {
    uint32_t a;
    asm("{ .reg .u64 t; cvta.to.shared.u64 t, %1; cvt.u32.u64 %0, t; }" : "=r"(a) : "l"(p));
    return a;
}

__device__ __forceinline__ void cp_async16(uint32_t dst, const void* src) {
    asm volatile("cp.async.cg.shared.global [%0], [%1], 16;" :: "r"(dst), "l"(src) : "memory");
}
__device__ __forceinline__ void cp_commit() {
    asm volatile("cp.async.commit_group;" ::: "memory");
}
__device__ __forceinline__ void cp_wait1() {
    asm volatile("cp.async.wait_group 1;" ::: "memory");
}

__device__ __forceinline__ void ldsm_x4(uint32_t addr, uint32_t& r0, uint32_t& r1,
                                        uint32_t& r2, uint32_t& r3) {
    asm volatile("ldmatrix.sync.aligned.m8n8.x4.shared.b16 {%0,%1,%2,%3}, [%4];"
                 : "=r"(r0), "=r"(r1), "=r"(r2), "=r"(r3) : "r"(addr));
}

__device__ __forceinline__ void mma_f16(float* c, const uint32_t* a, const uint32_t* b) {
    asm volatile(
        "mma.sync.aligned.m16n8k16.row.col.f32.f16.f16.f32 "
        "{%0,%1,%2,%3}, {%4,%5,%6,%7}, {%8,%9}, {%0,%1,%2,%3};"
        : "+f"(c[0]), "+f"(c[1]), "+f"(c[2]), "+f"(c[3])
        : "r"(a[0]), "r"(a[1]), "r"(a[2]), "r"(a[3]), "r"(b[0]), "r"(b[1]));
}

__device__ __forceinline__ void sts32(uint32_t addr, uint32_t v) {
    asm volatile("st.shared.b32 [%0], %1;" :: "r"(addr), "r"(v) : "memory");
}
__device__ __forceinline__ void sts16(uint32_t addr, uint16_t v) {
    asm volatile("st.shared.u16 [%0], %1;" :: "r"(addr), "h"(v) : "memory");
}
__device__ __forceinline__ float lds_f16(uint32_t addr) {
    uint16_t v;
    asm volatile("ld.shared.u16 %0, [%1];" : "=h"(v) : "r"(addr));
    __half h = *(__half*)&v;
    return __half2float(h);
}

// pack two floats -> fp16x2 word
__device__ __forceinline__ uint32_t pack_h2(float a, float b) {
    __half2 hv = __halves2half2(__float2half(a), __float2half(b));
    return *(uint32_t*)&hv;
}

// swizzled byte address of a 16-bit elem (row, col) in a 64-col (128B-row) tile
__device__ __forceinline__ uint32_t sw_addr(uint32_t base, int row, int col) {
    return base + (uint32_t)(row * 128 + ((((col >> 3) ^ (row & 7))) << 4) + ((col & 7) * 2));
}

// ---------------------------------------------------------------------------
// ONE fused input-prep kernel: x -> fp16 ; w -> fp16 ; w_out^T -> fp16
// ---------------------------------------------------------------------------
#define NBX (BT_ * D_ / 4 / 256)          // 8192
#define NBW (3 * D_ * D_ / 4 / 256)       // 3072

__global__ void __launch_bounds__(256)
prep_inputs_kernel(const float* __restrict__ x, const float* __restrict__ w,
                   const float* __restrict__ wo)
{
    const int bid = blockIdx.x;
    if (bid < NBX + NBW) {
        const float* src;
        __half* dst;
        int i;
        if (bid < NBX) {
            src = x; dst = g_xh;
            i = bid * 256 + threadIdx.x;
        } else {
            src = w; dst = g_wh;
            i = (bid - NBX) * 256 + threadIdx.x;
        }
        float4 v = ((const float4*)src)[i];
        ((uint32_t*)dst)[2 * i]     = pack_h2(v.x, v.y);
        ((uint32_t*)dst)[2 * i + 1] = pack_h2(v.z, v.w);
    } else {
        __shared__ float tile[32][33];
        int tb = bid - NBX - NBW;            // 0..1023
        int n0 = (tb & 31) * 32, k0 = (tb >> 5) * 32;
        int tx = threadIdx.x & 31, ty = threadIdx.x >> 5;
        for (int r = ty; r < 32; r += 8)
            tile[r][tx] = wo[(size_t)(k0 + r) * D_ + n0 + tx];
        __syncthreads();
        for (int r = ty; r < 32; r += 8)
            g_woth[(size_t)(n0 + r) * D_ + k0 + tx] = __float2half(tile[tx][r]);
    }
}

// ---------------------------------------------------------------------------
// Single-pass fp16 GEMM: C = Ah*Bh^T (fp32 accum).
// 128x64 tile, BK=64, 128 threads, 3-stage cp.async, 3 CTAs/SM.
// MODE=1: fused qkv epilogue, fp16 output. MODE=0: plain fp32 store.
// ---------------------------------------------------------------------------
#define GQ_A 16384
#define GQ_B 8192
#define GQ_STAGE (GQ_A + GQ_B)              // 24576
#define GQ_SMEM  (3 * GQ_STAGE)             // 73728

template<int MODE>
__global__ void __launch_bounds__(128, 3)
gemm_f16(const __half* __restrict__ Ah, const __half* __restrict__ Bh,
         float* __restrict__ Cf, __half* __restrict__ Ch, int N, int K)
{
    extern __shared__ char smem[];
    const uint32_t smem_base = smem_u32(smem);
    const int tid = threadIdx.x;
    const int wid = tid >> 5, lane = tid & 31;
    const int m0 = blockIdx.y * 128, n0 = blockIdx.x * 64;
    const int wm = wid * 32;

    auto load_stage = [&](int kt, int s) {
        const int k0 = kt << 6;
        const uint32_t sb = smem_base + s * GQ_STAGE;
#pragma unroll
        for (int ii = 0; ii < 8; ii++) {
            int j = tid + ii * 128;
            int r = j >> 3, c = j & 7;
            const void* g = &Ah[(size_t)(m0 + r) * K + k0 + c * 8];
            cp_async16(sb + (uint32_t)(r * 128 + ((c ^ (r & 7)) << 4)), g);
        }
        const uint32_t tb = sb + GQ_A;
#pragma unroll
        for (int ii = 0; ii < 4; ii++) {
            int j = tid + ii * 128;
            int r = j >> 3, c = j & 7;
            const void* g = &Bh[(size_t)(n0 + r) * K + k0 + c * 8];
            cp_async16(tb + (uint32_t)(r * 128 + ((c ^ (r & 7)) << 4)), g);
        }
    };

    float acc[2][8][4];
#pragma unroll
    for (int mt = 0; mt < 2; mt++)
#pragma unroll
        for (int nt = 0; nt < 8; nt++)
#pragma unroll
            for (int e = 0; e < 4; e++) acc[mt][nt][e] = 0.f;

    const int NKT = K >> 6;   // 16
    load_stage(0, 0); cp_commit();
    load_stage(1, 1); cp_commit();

    const int a_row = (lane & 15);
    const int a_khalf = lane >> 4;
    const int b_grp = (lane >> 4) & 1;
    const int b_khalf = (lane >> 3) & 1;
    const int b_row = lane & 7;

    int s = 0, sload = 2;
    for (int kt = 0; kt < NKT; kt++) {
        const uint32_t st = smem_base + s * GQ_STAGE;
        cp_wait1();
        __syncthreads();

        if (kt + 2 < NKT) load_stage(kt + 2, sload);
        cp_commit();

        const uint32_t aA = st;
        const uint32_t aB = st + GQ_A;

#pragma unroll
        for (int kk = 0; kk < 4; kk++) {
            uint32_t ah[2][4];
#pragma unroll
            for (int mt = 0; mt < 2; mt++) {
                int row = wm + mt * 16 + a_row;
                int chunk = 2 * kk + a_khalf;
                uint32_t off = (uint32_t)(row * 128 + ((chunk ^ (row & 7)) << 4));
                ldsm_x4(aA + off, ah[mt][0], ah[mt][1], ah[mt][2], ah[mt][3]);
            }
            uint32_t bh[4][4];
#pragma unroll
            for (int np = 0; np < 4; np++) {
                int row = np * 16 + b_grp * 8 + b_row;
                int chunk = 2 * kk + b_khalf;
                uint32_t off = (uint32_t)(row * 128 + ((chunk ^ (row & 7)) << 4));
                ldsm_x4(aB + off, bh[np][0], bh[np][1], bh[np][2], bh[np][3]);
            }
#pragma unroll
            for (int mt = 0; mt < 2; mt++)
#pragma unroll
                for (int nt = 0; nt < 8; nt++)
                    mma_f16(acc[mt][nt], ah[mt], &bh[nt >> 1][(nt & 1) * 2]);
        }
        s = (s == 2) ? 0 : s + 1;
        sload = (sload == 2) ? 0 : sload + 1;
    }

    const int g = lane >> 2, tig = lane & 3;
    const int gcol0 = n0;

    if (MODE == 1 && gcol0 < D_) {
        // q region: per-head softmax -> fp16
#pragma unroll
        for (int mt = 0; mt < 2; mt++) {
            float vA[16], vB[16];
#pragma unroll
            for (int nt = 0; nt < 8; nt++) {
                vA[2*nt]   = acc[mt][nt][0] * 0.125f;
                vA[2*nt+1] = acc[mt][nt][1] * 0.125f;
                vB[2*nt]   = acc[mt][nt][2] * 0.125f;
                vB[2*nt+1] = acc[mt][nt][3] * 0.125f;
            }
            float mA = vA[0], mB = vB[0];
#pragma unroll
            for (int i = 1; i < 16; i++) { mA = fmaxf(mA, vA[i]); mB = fmaxf(mB, vB[i]); }
            mA = fmaxf(mA, __shfl_xor_sync(0xffffffffu, mA, 1));
            mA = fmaxf(mA, __shfl_xor_sync(0xffffffffu, mA, 2));
            mB = fmaxf(mB, __shfl_xor_sync(0xffffffffu, mB, 1));
            mB = fmaxf(mB, __shfl_xor_sync(0xffffffffu, mB, 2));
            float sA = 0.f, sB = 0.f;
#pragma unroll
            for (int i = 0; i < 16; i++) {
                vA[i] = expf(vA[i] - mA); sA += vA[i];
                vB[i] = expf(vB[i] - mB); sB += vB[i];
            }
            sA += __shfl_xor_sync(0xffffffffu, sA, 1);
            sA += __shfl_xor_sync(0xffffffffu, sA, 2);
            sB += __shfl_xor_sync(0xffffffffu, sB, 1);
            sB += __shfl_xor_sync(0xffffffffu, sB, 2);
            float iA = 1.f / sA, iB = 1.f / sB;
            int row = m0 + wm + mt * 16 + g;
#pragma unroll
            for (int nt = 0; nt < 8; nt++) {
                int col = gcol0 + nt * 8 + 2 * tig;
                *(uint32_t*)&Ch[(size_t)row * N + col] =
                    pack_h2(vA[2*nt] * iA, vA[2*nt+1] * iA);
                *(uint32_t*)&Ch[(size_t)(row + 8) * N + col] =
                    pack_h2(vB[2*nt] * iB, vB[2*nt+1] * iB);
            }
        }
    } else if (MODE == 1 && gcol0 < 2 * D_) {
        // k region: exp(v*0.125)+1e-6 -> fp16
#pragma unroll
        for (int mt = 0; mt < 2; mt++) {
            int row = m0 + wm + mt * 16 + g;
#pragma unroll
            for (int nt = 0; nt < 8; nt++) {
                int col = gcol0 + nt * 8 + 2 * tig;
                float* c = acc[mt][nt];
                *(uint32_t*)&Ch[(size_t)row * N + col] =
                    pack_h2(expf(c[0]*0.125f)+1e-6f, expf(c[1]*0.125f)+1e-6f);
                *(uint32_t*)&Ch[(size_t)(row + 8) * N + col] =
                    pack_h2(expf(c[2]*0.125f)+1e-6f, expf(c[3]*0.125f)+1e-6f);
            }
        }
    } else if (MODE == 1) {
        // v region: fp16 passthrough
#pragma unroll
        for (int mt = 0; mt < 2; mt++) {
            int row = m0 + wm + mt * 16 + g;
#pragma unroll
            for (int nt = 0; nt < 8; nt++) {
                int col = gcol0 + nt * 8 + 2 * tig;
                float* c = acc[mt][nt];
                *(uint32_t*)&Ch[(size_t)row * N + col]       = pack_h2(c[0], c[1]);
                *(uint32_t*)&Ch[(size_t)(row + 8) * N + col] = pack_h2(c[2], c[3]);
            }
        }
    } else {
        // MODE 0: plain fp32 store (final output)
#pragma unroll
        for (int mt = 0; mt < 2; mt++) {
            int row = m0 + wm + mt * 16 + g;
#pragma unroll
            for (int nt = 0; nt < 8; nt++) {
                int col = gcol0 + nt * 8 + 2 * tig;
                float* c = acc[mt][nt];
                *(float2*)&Cf[(size_t)row * N + col]       = make_float2(c[0], c[1]);
                *(float2*)&Cf[(size_t)(row + 8) * N + col] = make_float2(c[2], c[3]);
            }
        }
    }
}

// ---------------------------------------------------------------------------
// Per-chunk state (CHUNK=64), fp16 qkv input, fp32 math.
// ---------------------------------------------------------------------------
__global__ void __launch_bounds__(256)
chunkstate_kernel(const __half* __restrict__ qkv,
                  float* __restrict__ Sc, float* __restrict__ ks)
{
    extern __shared__ float sm[];
    float* Ks = sm;
    float* Vs = sm + CHUNK * L_;
    const int c = blockIdx.x, bh = blockIdx.y;
    const int b = bh >> 4, h = bh & 15;
    const size_t rowbase = ((size_t)(b * T_ + c * CHUNK)) * (3 * D_) + h * L_;

    for (int i = threadIdx.x; i < CHUNK * 16; i += 256) {
        int t = i >> 4, f = (i & 15) << 2;
        size_t g = rowbase + (size_t)t * (3 * D_) + f;
        __half2 a0 = *(const __half2*)&qkv[g + D_];
        __half2 a1 = *(const __half2*)&qkv[g + D_ + 2];
        Ks[t * L_ + f + 0] = __low2float(a0);  Ks[t * L_ + f + 1] = __high2float(a0);
        Ks[t * L_ + f + 2] = __low2float(a1);  Ks[t * L_ + f + 3] = __high2float(a1);
        __half2 b0 = *(const __half2*)&qkv[g + 2 * D_];
        __half2 b1 = *(const __half2*)&qkv[g + 2 * D_ + 2];
        Vs[t * L_ + f + 0] = __low2float(b0);  Vs[t * L_ + f + 1] = __high2float(b0);
        Vs[t * L_ + f + 2] = __low2float(b1);  Vs[t * L_ + f + 3] = __high2float(b1);
    }
    __syncthreads();

    const int l0 = (threadIdx.x >> 4) << 2;
    const int m0 = (threadIdx.x & 15) << 2;
    float acc[4][4];
#pragma unroll
    for (int i = 0; i < 4; i++)
#pragma unroll
        for (int j = 0; j < 4; j++) acc[i][j] = 0.f;
    for (int t = 0; t < CHUNK; t++) {
        float a[4], v[4];
#pragma unroll
        for (int i = 0; i < 4; i++) a[i] = Ks[t * L_ + l0 + i];
#pragma unroll
        for (int j = 0; j < 4; j++) v[j] = Vs[t * L_ + m0 + j];
#pragma unroll
        for (int i = 0; i < 4; i++)
#pragma unroll
            for (int j = 0; j < 4; j++) acc[i][j] += a[i] * v[j];
    }
    const size_t sbase = ((size_t)bh * NC + c) * (L_ * L_);
#pragma unroll
    for (int i = 0; i < 4; i++)
#pragma unroll
        for (int j = 0; j < 4; j++)
            Sc[sbase + (size_t)(l0 + i) * L_ + m0 + j] = acc[i][j];

    if (threadIdx.x < L_) {
        float s = 0.f;
        for (int t = 0; t < CHUNK; t++) s += Ks[t * L_ + threadIdx.x];
        ks[((size_t)bh * NC + c) * L_ + threadIdx.x] = s;
    }
}

// ---------------------------------------------------------------------------
// Exclusive prefix over chunks — unchanged
// ---------------------------------------------------------------------------
__global__ void prefix_kernel(float* __restrict__ Sc, float* __restrict__ ks)
{
    const int bh = blockIdx.x;
    const int e = blockIdx.y * 256 + threadIdx.x;
    const size_t base = (size_t)bh * NC * (L_ * L_);
    {
        float acc = 0.f;
#pragma unroll
        for (int c = 0; c < NC; c++) {
            size_t idx = base + (size_t)c * (L_ * L_) + e;
            float tmp = Sc[idx];
            Sc[idx] = acc;
            acc += tmp;
        }
    }
    if (blockIdx.y == 0 && threadIdx.x < L_) {
        const size_t kb = (size_t)bh * NC * L_;
        float acc = 0.f;
#pragma unroll
        for (int c = 0; c < NC; c++) {
            size_t idx = kb + (size_t)c * L_ + threadIdx.x;
            float tmp = ks[idx];
            ks[idx] = acc;
            acc += tmp;
        }
    }
}

// ---------------------------------------------------------------------------
// Tensor-core chunk attention, fp16 qkv input (CHUNK=64, 128 threads):
// Q/K tiles: direct swizzled uint4 copies. q normalized IN-PLACE in Q16.
// smem 40960 B -> 5 blocks/SM:
//   [0:8192)       P16
//   [8192:16384)   Q16
//   [16384:24576)  K16
//   [24576:32768)  VT16
//   [32768:40960)  ST16
// ---------------------------------------------------------------------------
#define AT_SMEM 40960
#define P16O  0
#define Q16O  8192
#define K16O  16384
#define VT16O 24576
#define ST16O 32768

__global__ void __launch_bounds__(128)
attn_kernel(const __half* __restrict__ qkv, const float* __restrict__ Sprev,
            const float* __restrict__ kpre, __half* __restrict__ yh)
{
    extern __shared__ char smc[];
    const uint32_t sb   = smem_u32(smc);
    const uint32_t P16  = sb + P16O;
    const uint32_t Q16  = sb + Q16O;
    const uint32_t K16  = sb + K16O;
    const uint32_t VT16 = sb + VT16O;
    const uint32_t ST16 = sb + ST16O;

    const int c = blockIdx.x, bh = blockIdx.y;
    const int b = bh >> 4, h = bh & 15;
    const int tid = threadIdx.x;
    const int wid = tid >> 5, lane = tid & 31;
    const size_t rowbase = ((size_t)(b * T_ + c * CHUNK)) * (3 * D_) + h * L_;
    const size_t sbase = ((size_t)bh * NC + c) * (L_ * L_);

    // Q, K: direct swizzled 16B copies (4 per thread each)
    for (int i = tid; i < 512; i += 128) {
        int t = i >> 3, cc = i & 7;
        const size_t g = rowbase + (size_t)t * (3 * D_) + cc * 8;
        uint32_t off = (uint32_t)(t * 128 + ((cc ^ (t & 7)) << 4));
        *(uint4*)(smc + Q16O + off) = *(const uint4*)&qkv[g];
        *(uint4*)(smc + K16O + off) = *(const uint4*)&qkv[g + D_];
    }
    // V^T: element transpose from fp16 rows t0,t0+1
    for (int i = tid; i < 2048; i += 128) {
        int m = i & 63, t0 = (i >> 6) * 2;
        const __half* v0 = &qkv[rowbase + (size_t)t0 * (3 * D_) + 2 * D_];
        __half2 p = __halves2half2(v0[m], v0[3 * D_ + m]);
        sts32(sw_addr(VT16, m, t0), *(uint32_t*)&p);
    }
    // S_prev^T from fp32
    for (int i = tid; i < 2048; i += 128) {
        int m = i & 63, l0 = (i >> 6) * 2;
        const float* s0 = &Sprev[sbase + (size_t)l0 * L_];
        sts32(sw_addr(ST16, m, l0), pack_h2(s0[m], s0[L_ + m]));
    }
    __syncthreads();

    // normalize q in place: acc = kpre + cumsum fp16-k; thread = column l
    if (tid < L_) {
        const int l = tid;
        float acc = kpre[((size_t)bh * NC + c) * L_ + l];
        for (int t = 0; t < CHUNK; t++) {
            acc += lds_f16(sw_addr(K16, t, l));
            uint32_t qa = sw_addr(Q16, t, l);
            float q = lds_f16(qa);
            __half qh = __float2half(__fdividef(q, acc));
            sts16(qa, *(uint16_t*)&qh);
        }
    }
    __syncthreads();

    const int wm = wid * 16;
    const int a_row = (lane & 15);
    const int a_khalf = lane >> 4;
    const int b_grp = (lane >> 4) & 1;
    const int b_khalf = (lane >> 3) & 1;
    const int b_row = lane & 7;
    const int g = lane >> 2, tig = lane & 3;

    // ---- P = qs_norm @ K^T ----
    float accP[8][4];
#pragma unroll
    for (int nt = 0; nt < 8; nt++)
#pragma unroll
        for (int e = 0; e < 4; e++) accP[nt][e] = 0.f;

#pragma unroll
    for (int kk = 0; kk < 4; kk++) {
        uint32_t ah[4];
        {
            int row = wm + a_row;
            int chunk = 2 * kk + a_khalf;
            uint32_t off = (uint32_t)(row * 128 + ((chunk ^ (row & 7)) << 4));
            ldsm_x4(Q16 + off, ah[0], ah[1], ah[2], ah[3]);
        }
        uint32_t bh_[4][4];
#pragma unroll
        for (int np = 0; np < 4; np++) {
            int row = np * 16 + b_grp * 8 + b_row;
            int chunk = 2 * kk + b_khalf;
            uint32_t off = (uint32_t)(row * 128 + ((chunk ^ (row & 7)) << 4));
            ldsm_x4(K16 + off, bh_[np][0], bh_[np][1], bh_[np][2], bh_[np][3]);
        }
#pragma unroll
        for (int nt = 0; nt < 8; nt++)
            mma_f16(accP[nt], ah, &bh_[nt >> 1][(nt & 1) * 2]);
    }

    // ---- causal mask + store P fp16 ----
    {
        int r0 = wm + g, r1 = wm + g + 8;
#pragma unroll
        for (int nt = 0; nt < 8; nt++) {
            int colp = nt * 8 + 2 * tig;
            float p00 = (colp     <= r0) ? accP[nt][0] : 0.f;
            float p01 = (colp + 1 <= r0) ? accP[nt][1] : 0.f;
            float p10 = (colp     <= r1) ? accP[nt][2] : 0.f;
            float p11 = (colp + 1 <= r1) ? accP[nt][3] : 0.f;
            sts32(sw_addr(P16, r0, colp), pack_h2(p00, p01));
            sts32(sw_addr(P16, r1, colp), pack_h2(p10, p11));
        }
    }
    __syncthreads();

    // ---- Y = P @ V + qs_norm @ S_prev ----
    float acc[8][4];
#pragma unroll
    for (int nt = 0; nt < 8; nt++)
#pragma unroll
        for (int e = 0; e < 4; e++) acc[nt][e] = 0.f;

#pragma unroll
    for (int half = 0; half < 2; half++) {
        const uint32_t A16 = half ? Q16 : P16;
        const uint32_t B16 = half ? ST16 : VT16;
#pragma unroll
        for (int kk = 0; kk < 4; kk++) {
            uint32_t ah[4];
            {
                int row = wm + a_row;
                int chunk = 2 * kk + a_khalf;
                uint32_t off = (uint32_t)(row * 128 + ((chunk ^ (row & 7)) << 4));
                ldsm_x4(A16 + off, ah[0], ah[1], ah[2], ah[3]);
            }
            uint32_t bh_[4][4];
#pragma unroll
            for (int np = 0; np < 4; np++) {
                int row = np * 16 + b_grp * 8 + b_row;
                int chunk = 2 * kk + b_khalf;
                uint32_t off = (uint32_t)(row * 128 + ((chunk ^ (row & 7)) << 4));
                ldsm_x4(B16 + off, bh_[np][0], bh_[np][1], bh_[np][2], bh_[np][3]);
            }
#pragma unroll
            for (int nt = 0; nt < 8; nt++)
                mma_f16(acc[nt], ah, &bh_[nt >> 1][(nt & 1) * 2]);
        }
    }

    // epilogue: single-fp16 y
    {
        int r0 = wm + g;
#pragma unroll
        for (int dr = 0; dr < 2; dr++) {
            int row = r0 + dr * 8;
            size_t ybase = ((size_t)(b * T_ + c * CHUNK + row)) * D_ + h * L_;
#pragma unroll
            for (int nt = 0; nt < 8; nt++) {
                int colp = nt * 8 + 2 * tig;
                *(uint32_t*)&yh[ybase + colp] =
                    pack_h2(acc[nt][2 * dr], acc[nt][2 * dr + 1]);
            }
        }
    }
}

// ---------------------------------------------------------------------------
extern "C" void kernel_launch(void* const* d_in, const int* in_sizes, int n_in,
                              void* d_out, int out_size)
{
    const float* x  = (const float*)d_in[0];
    const float* w  = (const float*)d_in[1];
    const float* wo = (const float*)d_in[2];
    float* out = (float*)d_out;

    float *Sc, *ks;
    __half *qkv, *xh, *wh, *woth, *yh;
    cudaGetSymbolAddress((void**)&qkv, g_qkv);
    cudaGetSymbolAddress((void**)&Sc,  g_Sc);
    cudaGetSymbolAddress((void**)&ks,  g_ks);
    cudaGetSymbolAddress((void**)&xh,  g_xh);
    cudaGetSymbolAddress((void**)&wh,  g_wh);
    cudaGetSymbolAddress((void**)&woth, g_woth);
    cudaGetSymbolAddress((void**)&yh,  g_yh);

    cudaFuncSetAttribute(gemm_f16<0>,
                         cudaFuncAttributeMaxDynamicSharedMemorySize, GQ_SMEM);
    cudaFuncSetAttribute(gemm_f16<1>,
                         cudaFuncAttributeMaxDynamicSharedMemorySize, GQ_SMEM);
    cudaFuncSetAttribute(chunkstate_kernel,
                         cudaFuncAttributeMaxDynamicSharedMemorySize, 32768);
    cudaFuncSetAttribute(attn_kernel,
                         cudaFuncAttributeMaxDynamicSharedMemorySize, AT_SMEM);

    // 0) fused prep: x,w,wo^T -> fp16
    prep_inputs_kernel<<<NBX + NBW + 1024, 256>>>(x, w, wo);
    // 1) qkv = xh @ wh^T -> fp16 qkv with fused softmax/exp epilogue
    gemm_f16<1><<<dim3(3 * D_ / 64, BT_ / 128), 128, GQ_SMEM>>>(
        xh, wh, nullptr, qkv, 3 * D_, D_);
    // 2) per-chunk states + k sums (fp16 input)
    chunkstate_kernel<<<dim3(NC, BH_), 256, 32768>>>(qkv, Sc, ks);
    // 3) exclusive prefix over chunks
    prefix_kernel<<<dim3(BH_, 16), 256>>>(Sc, ks);
    // 4) fp16 tensor-core chunk attention -> y
    attn_kernel<<<dim3(NC, BH_), 128, AT_SMEM>>>(qkv, Sc, ks, yh);
    // 5) out = yh @ woth^T (fp32 output)
    gemm_f16<0><<<dim3(D_ / 64, BT_ / 128), 128, GQ_SMEM>>>(
        yh, woth, out, nullptr, D_, D_);
}